// round 8
// baseline (speedup 1.0000x reference)
#include <cuda_runtime.h>
#include <math.h>
#include <float.h>

#define CEILDIV(a,b) (((a)+(b)-1)/(b))
#define BN_EPS 1e-5f

// ----------------------------------------------------------------------------
// Scratch (device globals)
// ----------------------------------------------------------------------------
__device__ float g_xyz[8*2048*3];
__device__ float g_h1[8*2048*64];
__device__ float g_points[8*2048*64];       // RAW conv2 output (BN applied on load)
__device__ int   g_fpsidx[8*512];
__device__ float g_newxyz[8*512*3];
__device__ float g_newxyz2[8*256*3];
__device__ float g_newpts[8*512*64];        // stage2: 8*256*128 (raw gathered feats)
__device__ int   g_knn[8*512*64];
__device__ int   g_knn2[8*256*64];
__device__ float g_U[16384*128];            // stage E: 4096x256
__device__ float g_V[4096*128];             // stage E: 2048x256
__device__ float g_w1a[256*128];
__device__ float g_w1d[256*128];
__device__ float g_part[2*2048*256];        // per-block partial sums / sumsq (shared scratch)
__device__ float g_pool[8*512*384];         // RAW pooled max (BN on load); stage2: 8*256*768
__device__ float g_f0[8*512*128];           // RAW (BN on load)
__device__ float g_f1[8*256*256];           // BN'd in place
__device__ float g_pos[8*256*256];
__device__ float g_x[8*256*256];
__device__ float g_q[8*256*256];
__device__ float g_v[8*256*256];
__device__ float g_xr[8*256*256];
__device__ float g_attn[8*4*256*256];
__device__ float g_cat[8*256*1280];
__device__ float g_fuse[8*256*1024];        // RAW (BN+leaky folded into maxn)
__device__ float g_gmax[8*1024];
__device__ float g_l1[8*512];
__device__ float g_l2[8*256];
__device__ double g_sum[1024];
__device__ double g_sumsq[1024];
__device__ float g_m1[1280];
__device__ float g_i1[1280];
__device__ float g_s1m[3*256];
__device__ float g_s1i[3*256];

// ----------------------------------------------------------------------------
// BN stats plumbing
// ----------------------------------------------------------------------------
__global__ void zero_stats_kernel() {
    int t = threadIdx.x;
    g_sum[t] = 0.0; g_sumsq[t] = 0.0;
}

__global__ void stats_h1_kernel(const float* __restrict__ X, int R, int C, int rpb) {
    int r0 = blockIdx.x * rpb;
    int r1 = r0 + rpb; if (r1 > R) r1 = R;
    int c = threadIdx.x;   // blockDim == C (64)
    float acc = 0.f, accsq = 0.f;
    for (int r = r0; r < r1; r++) {
        float v = X[(long)r * C + c];
        acc += v; accsq += v * v;
    }
    atomicAdd(&g_sum[c], (double)acc);
    atomicAdd(&g_sumsq[c], (double)accsq);
}

__global__ void finalize1_kernel(int C, int statN) {
    int c = blockIdx.x * 256 + threadIdx.x;
    if (c >= C) return;
    double m = g_sum[c] / statN;
    double var = g_sumsq[c] / statN - m * m;
    if (var < 0.0) var = 0.0;
    g_m1[c] = (float)m;
    g_i1[c] = rsqrtf((float)var + BN_EPS);
}

// reduce per-block float partials -> g_m1/g_i1 at outOff
__global__ void reduce_part_kernel(const float* __restrict__ part, int nBy, int O,
                                   int statN, int outOff) {
    int c = blockIdx.x * 128 + threadIdx.x;
    if (c >= O) return;
    float a0 = 0.f, a1 = 0.f, a2 = 0.f, a3 = 0.f;
    float b0 = 0.f, b1 = 0.f, b2 = 0.f, b3 = 0.f;
    const float* ps = part;
    const float* pq = part + (long)nBy * O;
    int r = 0;
    for (; r + 4 <= nBy; r += 4) {
        a0 += ps[(long)(r + 0) * O + c]; b0 += pq[(long)(r + 0) * O + c];
        a1 += ps[(long)(r + 1) * O + c]; b1 += pq[(long)(r + 1) * O + c];
        a2 += ps[(long)(r + 2) * O + c]; b2 += pq[(long)(r + 2) * O + c];
        a3 += ps[(long)(r + 3) * O + c]; b3 += pq[(long)(r + 3) * O + c];
    }
    for (; r < nBy; r++) { a0 += ps[(long)r * O + c]; b0 += pq[(long)r * O + c]; }
    double s = (double)a0 + a1 + a2 + a3;
    double q = (double)b0 + b1 + b2 + b3;
    double m = s / statN;
    double var = q / statN - m * m;
    if (var < 0.0) var = 0.0;
    g_m1[outOff + c] = (float)m;
    g_i1[outOff + c] = rsqrtf((float)var + BN_EPS);
}

__global__ void bn_apply_kernel(float* __restrict__ X, long total, int C, int act) {
    long t = (long)blockIdx.x * blockDim.x + threadIdx.x;
    if (t >= total) return;
    int c = (int)(t % C);
    float y = (X[t] - g_m1[c]) * g_i1[c];
    X[t] = (act == 0) ? fmaxf(y, 0.f) : (y >= 0.f ? y : 0.2f * y);
}

__global__ void bn_small_kernel(float* __restrict__ X, int C, float slope) {
    int c = blockIdx.x * blockDim.x + threadIdx.x;
    if (c >= C) return;
    double s = 0.0, ss = 0.0;
    for (int r = 0; r < 8; r++) { double v = X[r * C + c]; s += v; ss += v * v; }
    double m = s / 8.0;
    double var = ss / 8.0 - m * m;
    if (var < 0.0) var = 0.0;
    float inv = rsqrtf((float)var + BN_EPS);
    for (int r = 0; r < 8; r++) {
        float y = (X[r * C + c] - (float)m) * inv;
        X[r * C + c] = y >= 0.f ? y : slope * y;
    }
}

// ----------------------------------------------------------------------------
// 128x128 tiled GEMM, TEMPLATED so non-BN / non-emit variants carry zero
// extra smem or epilogue code (R6 regression fix).
// ----------------------------------------------------------------------------
template <int USE_BN, int EMIT>
__global__ void gemm128_kernel(const float* __restrict__ A, const float* __restrict__ W,
                               const float* __restrict__ bias, float* __restrict__ C,
                               int R, int D, int O,
                               const float* __restrict__ bnM, const float* __restrict__ bnI) {
    __shared__ float As[16][132];
    __shared__ float Ws[16][132];
    __shared__ float sM[USE_BN ? 768 : 1];
    __shared__ float sI[USE_BN ? 768 : 1];
    int tid = threadIdx.x;
    if (USE_BN) {
        for (int c = tid; c < D; c += 256) { sM[c] = bnM[c]; sI[c] = bnI[c]; }
        __syncthreads();
    }
    long rowBase = (long)blockIdx.y * 128;
    int colBase = blockIdx.x * 128;
    int tr = tid >> 4, tc = tid & 15;
    int lrow = tid >> 2;
    int lkq = tid & 3;
    float acc[8][8];
    #pragma unroll
    for (int i = 0; i < 8; i++)
        #pragma unroll
        for (int j = 0; j < 8; j++) acc[i][j] = 0.f;

    for (int k0 = 0; k0 < D; k0 += 16) {
        #pragma unroll
        for (int half = 0; half < 2; half++) {
            int row = lrow + 64 * half;
            int kc = k0 + lkq * 4;
            float4 av = *(const float4*)(A + (rowBase + row) * D + kc);
            if (USE_BN) {
                av.x = fmaxf((av.x - sM[kc + 0]) * sI[kc + 0], 0.f);
                av.y = fmaxf((av.y - sM[kc + 1]) * sI[kc + 1], 0.f);
                av.z = fmaxf((av.z - sM[kc + 2]) * sI[kc + 2], 0.f);
                av.w = fmaxf((av.w - sM[kc + 3]) * sI[kc + 3], 0.f);
            }
            As[lkq * 4 + 0][row] = av.x;
            As[lkq * 4 + 1][row] = av.y;
            As[lkq * 4 + 2][row] = av.z;
            As[lkq * 4 + 3][row] = av.w;
            int wr = colBase + row;
            float4 wv = make_float4(0.f, 0.f, 0.f, 0.f);
            if (wr < O) wv = *(const float4*)(W + (long)wr * D + kc);
            Ws[lkq * 4 + 0][row] = wv.x;
            Ws[lkq * 4 + 1][row] = wv.y;
            Ws[lkq * 4 + 2][row] = wv.z;
            Ws[lkq * 4 + 3][row] = wv.w;
        }
        __syncthreads();
        #pragma unroll
        for (int kk = 0; kk < 16; kk++) {
            float a[8], w[8];
            *(float4*)(a + 0) = *(const float4*)&As[kk][tr * 8 + 0];
            *(float4*)(a + 4) = *(const float4*)&As[kk][tr * 8 + 4];
            *(float4*)(w + 0) = *(const float4*)&Ws[kk][tc * 8 + 0];
            *(float4*)(w + 4) = *(const float4*)&Ws[kk][tc * 8 + 4];
            #pragma unroll
            for (int i = 0; i < 8; i++)
                #pragma unroll
                for (int j = 0; j < 8; j++)
                    acc[i][j] += a[i] * w[j];
        }
        __syncthreads();
    }
    #pragma unroll
    for (int i = 0; i < 8; i++) {
        long row = rowBase + tr * 8 + i;
        int col0 = colBase + tc * 8;
        if (col0 >= O) continue;
        float b0 = 0, b1 = 0, b2 = 0, b3 = 0, b4 = 0, b5 = 0, b6 = 0, b7 = 0;
        if (bias) {
            b0 = bias[col0 + 0]; b1 = bias[col0 + 1]; b2 = bias[col0 + 2]; b3 = bias[col0 + 3];
            b4 = bias[col0 + 4]; b5 = bias[col0 + 5]; b6 = bias[col0 + 6]; b7 = bias[col0 + 7];
        }
        float4 v0 = make_float4(acc[i][0] + b0, acc[i][1] + b1, acc[i][2] + b2, acc[i][3] + b3);
        float4 v1 = make_float4(acc[i][4] + b4, acc[i][5] + b5, acc[i][6] + b6, acc[i][7] + b7);
        *(float4*)(C + row * O + col0) = v0;
        *(float4*)(C + row * O + col0 + 4) = v1;
    }

    if (EMIT) {
        #pragma unroll
        for (int j = 0; j < 8; j++) {
            float sm = 0.f;
            #pragma unroll
            for (int i = 0; i < 8; i++) sm += acc[i][j];
            As[tr][tc * 8 + j] = sm;
        }
        __syncthreads();
        if (tr == 0) {
            #pragma unroll
            for (int j = 0; j < 8; j++) {
                int col = colBase + tc * 8 + j;
                if (col >= O) continue;
                float tot = 0.f;
                for (int q = 0; q < 16; q++) tot += As[q][tc * 8 + j];
                g_part[(long)blockIdx.y * O + col] = tot;
            }
        }
        __syncthreads();
        #pragma unroll
        for (int j = 0; j < 8; j++) {
            float sm = 0.f;
            #pragma unroll
            for (int i = 0; i < 8; i++) sm += acc[i][j] * acc[i][j];
            As[tr][tc * 8 + j] = sm;
        }
        __syncthreads();
        if (tr == 0) {
            #pragma unroll
            for (int j = 0; j < 8; j++) {
                int col = colBase + tc * 8 + j;
                if (col >= O) continue;
                float tot = 0.f;
                for (int q = 0; q < 16; q++) tot += As[q][tc * 8 + j];
                g_part[(long)gridDim.y * O + (long)blockIdx.y * O + col] = tot;
            }
        }
    }
}

// ----------------------------------------------------------------------------
// Fused local-op GEMM2
// ----------------------------------------------------------------------------
__global__ void local_gemm2_kernel(const float* __restrict__ U, const float* __restrict__ V,
                                   const int* __restrict__ knn, const float* __restrict__ W,
                                   float* __restrict__ poolOut,
                                   int S, int N, int D, int O, int kshift,
                                   int OC, int off,
                                   const float* __restrict__ bn1M, const float* __restrict__ bn1I,
                                   float* __restrict__ part) {
    __shared__ float As[16][132];
    __shared__ float Ws[16][132];
    __shared__ float sRed[16][132];
    __shared__ float sM[256];
    __shared__ float sI[256];
    __shared__ int sP[128];
    __shared__ int sS[128];
    int tid = threadIdx.x;
    long rowBase = (long)blockIdx.y * 128;
    int colBase = blockIdx.x * 128;

    for (int c = tid; c < D; c += 256) { sM[c] = bn1M[c]; sI[c] = bn1I[c]; }
    if (tid < 128) {
        long grow = rowBase + tid;
        int s = (int)(grow >> kshift);
        int j = (int)(grow & ((1 << kshift) - 1));
        int b = s / S;
        sS[tid] = s;
        sP[tid] = b * N + knn[(long)s * 64 + j];
    }
    __syncthreads();

    int tr = tid >> 4, tc = tid & 15;
    int lrow = tid >> 2;
    int lkq = tid & 3;
    float acc[8][8];
    #pragma unroll
    for (int i = 0; i < 8; i++)
        #pragma unroll
        for (int j = 0; j < 8; j++) acc[i][j] = 0.f;

    for (int k0 = 0; k0 < D; k0 += 16) {
        #pragma unroll
        for (int half = 0; half < 2; half++) {
            int row = lrow + 64 * half;
            int kc = k0 + lkq * 4;
            float4 uv = *(const float4*)(U + (long)sP[row] * D + kc);
            float4 vv = *(const float4*)(V + (long)sS[row] * D + kc);
            As[lkq * 4 + 0][row] = fmaxf((uv.x + vv.x - sM[kc + 0]) * sI[kc + 0], 0.f);
            As[lkq * 4 + 1][row] = fmaxf((uv.y + vv.y - sM[kc + 1]) * sI[kc + 1], 0.f);
            As[lkq * 4 + 2][row] = fmaxf((uv.z + vv.z - sM[kc + 2]) * sI[kc + 2], 0.f);
            As[lkq * 4 + 3][row] = fmaxf((uv.w + vv.w - sM[kc + 3]) * sI[kc + 3], 0.f);
            float4 wv = *(const float4*)(W + (long)(colBase + row) * D + kc);
            Ws[lkq * 4 + 0][row] = wv.x;
            Ws[lkq * 4 + 1][row] = wv.y;
            Ws[lkq * 4 + 2][row] = wv.z;
            Ws[lkq * 4 + 3][row] = wv.w;
        }
        __syncthreads();
        #pragma unroll
        for (int kk = 0; kk < 16; kk++) {
            float a[8], w[8];
            *(float4*)(a + 0) = *(const float4*)&As[kk][tr * 8 + 0];
            *(float4*)(a + 4) = *(const float4*)&As[kk][tr * 8 + 4];
            *(float4*)(w + 0) = *(const float4*)&Ws[kk][tc * 8 + 0];
            *(float4*)(w + 4) = *(const float4*)&Ws[kk][tc * 8 + 4];
            #pragma unroll
            for (int i = 0; i < 8; i++)
                #pragma unroll
                for (int j = 0; j < 8; j++)
                    acc[i][j] += a[i] * w[j];
        }
        __syncthreads();
    }

    int g = (1 << kshift) >> 3;
    #pragma unroll
    for (int j = 0; j < 8; j++) {
        float m = acc[0][j];
        #pragma unroll
        for (int i = 1; i < 8; i++) m = fmaxf(m, acc[i][j]);
        sRed[tr][tc * 8 + j] = m;
    }
    __syncthreads();
    if ((tr & (g - 1)) == 0) {
        int s = sS[tr * 8];
        #pragma unroll
        for (int j = 0; j < 8; j++) {
            float m = sRed[tr][tc * 8 + j];
            for (int q = 1; q < g; q++) m = fmaxf(m, sRed[tr + q][tc * 8 + j]);
            poolOut[(long)s * OC + off + colBase + tc * 8 + j] = m;
        }
    }
    __syncthreads();
    #pragma unroll
    for (int j = 0; j < 8; j++) {
        float sm = 0.f;
        #pragma unroll
        for (int i = 0; i < 8; i++) sm += acc[i][j];
        sRed[tr][tc * 8 + j] = sm;
    }
    __syncthreads();
    if (tr == 0) {
        #pragma unroll
        for (int j = 0; j < 8; j++) {
            float tot = 0.f;
            for (int q = 0; q < 16; q++) tot += sRed[q][tc * 8 + j];
            part[(long)blockIdx.y * O + colBase + tc * 8 + j] = tot;
        }
    }
    __syncthreads();
    #pragma unroll
    for (int j = 0; j < 8; j++) {
        float sm = 0.f;
        #pragma unroll
        for (int i = 0; i < 8; i++) sm += acc[i][j] * acc[i][j];
        sRed[tr][tc * 8 + j] = sm;
    }
    __syncthreads();
    if (tr == 0) {
        #pragma unroll
        for (int j = 0; j < 8; j++) {
            float tot = 0.f;
            for (int q = 0; q < 16; q++) tot += sRed[q][tc * 8 + j];
            part[(long)gridDim.y * O + (long)blockIdx.y * O + colBase + tc * 8 + j] = tot;
        }
    }
}

// ----------------------------------------------------------------------------
// BN1 stats: one incremental pass over all 3 k-scales (prefix property).
// ----------------------------------------------------------------------------
__global__ void stats1_all_kernel(const float* __restrict__ U, const float* __restrict__ V,
                                  const int* __restrict__ knn, int S, int N, int C,
                                  int cpb, int nB, float* __restrict__ part) {
    int c = threadIdx.x;   // blockDim == C
    int blk = blockIdx.x;
    float s0 = 0.f, q0 = 0.f, s1 = 0.f, q1 = 0.f, s2 = 0.f, q2 = 0.f;
    for (int ss = 0; ss < cpb; ss++) {
        int s = blk * cpb + ss;
        int b = s / S;
        float v = V[(long)s * C + c];
        const int* kn = knn + (long)s * 64;
        for (int j = 0; j < 16; j++) {
            float x = U[((long)b * N + kn[j]) * C + c] + v;
            s0 += x; q0 += x * x;
        }
        for (int j = 16; j < 32; j++) {
            float x = U[((long)b * N + kn[j]) * C + c] + v;
            s1 += x; q1 += x * x;
        }
        for (int j = 32; j < 64; j++) {
            float x = U[((long)b * N + kn[j]) * C + c] + v;
            s2 += x; q2 += x * x;
        }
    }
    long base = (long)blk * C + c;
    long stride = (long)nB * C;
    part[0 * stride + base] = s0;
    part[1 * stride + base] = s1;
    part[2 * stride + base] = s2;
    part[3 * stride + base] = q0;
    part[4 * stride + base] = q1;
    part[5 * stride + base] = q2;
}

__global__ void stats1_fin_kernel(const float* __restrict__ part, int nB, int C, int S8) {
    int c = blockIdx.x * 128 + threadIdx.x;
    if (c >= C) return;
    long stride = (long)nB * C;
    float a0 = 0.f, a1 = 0.f, a2 = 0.f, b0 = 0.f, b1 = 0.f, b2 = 0.f;
    for (int r = 0; r < nB; r++) {
        long idx = (long)r * C + c;
        a0 += part[0 * stride + idx];
        a1 += part[1 * stride + idx];
        a2 += part[2 * stride + idx];
        b0 += part[3 * stride + idx];
        b1 += part[4 * stride + idx];
        b2 += part[5 * stride + idx];
    }
    double cs = a0, cq = b0;
    const int ks[3] = {16, 32, 64};
    double add_s[3] = {0.0, (double)a1, (double)a2};
    double add_q[3] = {0.0, (double)b1, (double)b2};
    for (int sc = 0; sc < 3; sc++) {
        cs += add_s[sc]; cq += add_q[sc];
        double n = (double)S8 * ks[sc];
        double m = cs / n;
        double var = cq / n - m * m;
        if (var < 0.0) var = 0.0;
        g_s1m[sc * 256 + c] = (float)m;
        g_s1i[sc * 256 + c] = rsqrtf((float)var + BN_EPS);
    }
}

__global__ void split_w1_kernel(const float* __restrict__ w1, float* __restrict__ wa,
                                float* __restrict__ wd, int O, int D, int total) {
    int t = blockIdx.x * 256 + threadIdx.x;
    if (t >= total) return;
    int d = t % D, o = t / D;
    float a = w1[(long)o * 2 * D + d];
    float b = w1[(long)o * 2 * D + D + d];
    wa[t] = a;
    wd[t] = b - a;
}

// ----------------------------------------------------------------------------
// Generic fallback GEMM (odd shapes)
// ----------------------------------------------------------------------------
__global__ void gemm_kernel(const float* __restrict__ A, const float* __restrict__ W,
                            const float* __restrict__ bias, float* __restrict__ C,
                            int R, int D, int O) {
    __shared__ float As[64][17];
    __shared__ float Ws[64][17];
    int tid = threadIdx.x;
    int tr = tid >> 4, tc = tid & 15;
    long rowBase = (long)blockIdx.y * 64;
    int colBase = blockIdx.x * 64;
    float acc[4][4] = {};
    for (int k0 = 0; k0 < D; k0 += 16) {
        #pragma unroll
        for (int e = tid; e < 1024; e += 256) {
            int rr = e >> 4, kk = e & 15;
            long ar = rowBase + rr; int ac = k0 + kk;
            As[rr][kk] = (ar < R && ac < D) ? A[ar * D + ac] : 0.f;
            int wr = colBase + rr;
            Ws[rr][kk] = (wr < O && ac < D) ? W[(long)wr * D + ac] : 0.f;
        }
        __syncthreads();
        #pragma unroll
        for (int kk = 0; kk < 16; kk++) {
            float a[4], w[4];
            #pragma unroll
            for (int i = 0; i < 4; i++) a[i] = As[tr + 16*i][kk];
            #pragma unroll
            for (int j = 0; j < 4; j++) w[j] = Ws[tc + 16*j][kk];
            #pragma unroll
            for (int i = 0; i < 4; i++)
                #pragma unroll
                for (int j = 0; j < 4; j++)
                    acc[i][j] += a[i] * w[j];
        }
        __syncthreads();
    }
    #pragma unroll
    for (int i = 0; i < 4; i++) {
        long row = rowBase + tr + 16*i;
        if (row >= R) continue;
        #pragma unroll
        for (int j = 0; j < 4; j++) {
            int col = colBase + tc + 16*j;
            if (col >= O) continue;
            float vv = acc[i][j];
            if (bias) vv += bias[col];
            C[row * O + col] = vv;
        }
    }
}

// ----------------------------------------------------------------------------
// Layout / elementwise helpers
// ----------------------------------------------------------------------------
__global__ void transpose_x_kernel(const float* __restrict__ x, float* __restrict__ xyz) {
    int t = blockIdx.x * 256 + threadIdx.x;
    if (t >= 8 * 2048 * 3) return;
    int c = t % 3; int n = (t / 3) % 2048; int b = t / (3 * 2048);
    xyz[t] = x[((long)b * 3 + c) * 2048 + n];
}

__global__ void gather_kernel(const float* __restrict__ src, const int* __restrict__ idx,
                              float* __restrict__ dst, int S, int N, int D, long total) {
    long t = (long)blockIdx.x * blockDim.x + threadIdx.x;
    if (t >= total) return;
    int c = (int)(t % D); long bs = t / D;
    int b = (int)(bs / S);
    dst[t] = src[((long)b * N + idx[bs]) * D + c];
}

__global__ void catf1_kernel(const float* __restrict__ f1, float* __restrict__ cat) {
    int t = blockIdx.x * 256 + threadIdx.x;
    int c = t & 255; int row = t >> 8;
    cat[(long)row * 1280 + 1024 + c] = f1[t];
}

__global__ void maxn_bn_kernel(const float* __restrict__ X, float* __restrict__ G) {
    int b = blockIdx.x; int c = blockIdx.y * 256 + threadIdx.x;
    float m = -FLT_MAX;
    for (int n = 0; n < 256; n++) m = fmaxf(m, X[((long)b * 256 + n) * 1024 + c]);
    float y = (m - g_m1[c]) * g_i1[c];
    G[b * 1024 + c] = y >= 0.f ? y : 0.2f * y;
}

// ----------------------------------------------------------------------------
// FPS / kNN with warp-shuffle reductions (tie order preserved)
// ----------------------------------------------------------------------------
__device__ __forceinline__ unsigned keymap(float f) {
    unsigned u = __float_as_uint(f);
    return (u & 0x80000000u) ? ~u : (u | 0x80000000u);
}

__device__ void fps_body(const float* __restrict__ xyz, int N, int npoint,
                         int* __restrict__ outIdx, int b,
                         float* sx, float* sy, float* sz, float* sd,
                         unsigned long long* warpBest, int* sFar) {
    int t = threadIdx.x;
    int nt = blockDim.x;
    int numWarps = nt >> 5;
    for (int n = t; n < N; n += nt) {
        sx[n] = xyz[((long)b * N + n) * 3 + 0];
        sy[n] = xyz[((long)b * N + n) * 3 + 1];
        sz[n] = xyz[((long)b * N + n) * 3 + 2];
        sd[n] = 1e10f;
    }
    __syncthreads();
    int far = 0;
    for (int it = 0; it < npoint; it++) {
        if (t == 0) outIdx[b * npoint + it] = far;
        float cx = sx[far], cy = sy[far], cz = sz[far];
        unsigned long long best = 0ull;
        for (int n = t; n < N; n += nt) {
            float dx = sx[n] - cx, dy = sy[n] - cy, dz = sz[n] - cz;
            float d = dx * dx + dy * dy + dz * dz;
            float dm = fminf(sd[n], d);
            sd[n] = dm;
            unsigned long long key = ((unsigned long long)keymap(dm) << 32) | (unsigned)(~n);
            if (key > best) best = key;
        }
        #pragma unroll
        for (int o = 16; o > 0; o >>= 1) {
            unsigned long long other = __shfl_xor_sync(0xffffffffu, best, o);
            if (other > best) best = other;
        }
        if ((t & 31) == 0) warpBest[t >> 5] = best;
        __syncthreads();
        if (t < 32) {
            unsigned long long v = (t < numWarps) ? warpBest[t] : 0ull;
            #pragma unroll
            for (int o = 16; o > 0; o >>= 1) {
                unsigned long long other = __shfl_xor_sync(0xffffffffu, v, o);
                if (other > v) v = other;
            }
            if (t == 0) *sFar = (int)(~((unsigned)(v & 0xffffffffu)));
        }
        __syncthreads();
        far = *sFar;
    }
}

__device__ void knn_body(const float* __restrict__ centers, const float* __restrict__ xyz,
                         int S, int N, int* __restrict__ knnOut, int bs,
                         float* sd, unsigned long long* warpBest) {
    int t = threadIdx.x;
    int nt = blockDim.x;
    int numWarps = nt >> 5;
    int b = bs / S;
    float cx = centers[(long)bs * 3 + 0];
    float cy = centers[(long)bs * 3 + 1];
    float cz = centers[(long)bs * 3 + 2];
    float cn = cx * cx + cy * cy + cz * cz;
    for (int n = t; n < N; n += nt) {
        float px = xyz[((long)b * N + n) * 3 + 0];
        float py = xyz[((long)b * N + n) * 3 + 1];
        float pz = xyz[((long)b * N + n) * 3 + 2];
        float pn = px * px + py * py + pz * pz;
        float dot = cx * px + cy * py + cz * pz;
        sd[n] = cn + pn - 2.f * dot;
    }
    __syncthreads();
    for (int j = 0; j < 64; j++) {
        unsigned long long best = 0xFFFFFFFFFFFFFFFFull;
        for (int n = t; n < N; n += nt) {
            unsigned long long key = ((unsigned long long)keymap(sd[n]) << 32) | (unsigned)n;
            if (key < best) best = key;
        }
        #pragma unroll
        for (int o = 16; o > 0; o >>= 1) {
            unsigned long long other = __shfl_xor_sync(0xffffffffu, best, o);
            if (other < best) best = other;
        }
        if ((t & 31) == 0) warpBest[t >> 5] = best;
        __syncthreads();
        if (t < 32) {
            unsigned long long v = (t < numWarps) ? warpBest[t] : 0xFFFFFFFFFFFFFFFFull;
            #pragma unroll
            for (int o = 16; o > 0; o >>= 1) {
                unsigned long long other = __shfl_xor_sync(0xffffffffu, v, o);
                if (other < v) v = other;
            }
            if (t == 0) {
                int sel = (int)(v & 0xffffffffu);
                knnOut[(long)bs * 64 + j] = sel;
                sd[sel] = FLT_MAX;
            }
        }
        __syncthreads();
    }
}

__global__ void fps_kernel(const float* xyz, int N, int npoint, int* outIdx) {
    __shared__ float buf[4 * 2048];
    __shared__ unsigned long long wb[32];
    __shared__ int sFar;
    fps_body(xyz, N, npoint, outIdx, blockIdx.x, buf, buf + N, buf + 2 * N, buf + 3 * N, wb, &sFar);
}

__global__ void knn_kernel(const float* centers, const float* xyz, int S, int N, int* knnOut) {
    __shared__ float buf[2048];
    __shared__ unsigned long long wb[32];
    knn_body(centers, xyz, S, N, knnOut, blockIdx.x, buf, wb);
}

__global__ void knn_fps_kernel(const float* centers, const float* xyz, int S, int N,
                               int* knnOut, int nKnn,
                               const float* xyz2, int N2, int np2, int* outIdx2) {
    __shared__ float buf[4 * 2048];
    __shared__ unsigned long long wb[32];
    __shared__ int sFar;
    if (blockIdx.x < nKnn) {
        knn_body(centers, xyz, S, N, knnOut, blockIdx.x, buf, wb);
    } else {
        int b = blockIdx.x - nKnn;
        fps_body(xyz2, N2, np2, outIdx2, b, buf, buf + N2, buf + 2 * N2, buf + 3 * N2, wb, &sFar);
    }
}

// ----------------------------------------------------------------------------
// Attention (reference reshape quirk preserved)
// ----------------------------------------------------------------------------
__global__ void gemmqv_kernel(const float* __restrict__ xx, const float* __restrict__ pos,
                              const float* __restrict__ wqk, const float* __restrict__ wv,
                              const float* __restrict__ bv,
                              float* __restrict__ qb, float* __restrict__ vb) {
    __shared__ float As[16][132];
    __shared__ float Ws[16][132];
    int tid = threadIdx.x;
    long rowBase = (long)blockIdx.y * 128;
    int colBase = blockIdx.x * 128;
    int tr = tid >> 4, tc = tid & 15;
    int lrow = tid >> 2;
    int lkq = tid & 3;
    const int D = 256;
    float acc[8][8];
    #pragma unroll
    for (int i = 0; i < 8; i++)
        #pragma unroll
        for (int j = 0; j < 8; j++) acc[i][j] = 0.f;

    for (int k0 = 0; k0 < D; k0 += 16) {
        #pragma unroll
        for (int half = 0; half < 2; half++) {
            int row = lrow + 64 * half;
            int kc = k0 + lkq * 4;
            float4 av = *(const float4*)(xx + (rowBase + row) * D + kc);
            float4 pv = *(const float4*)(pos + (rowBase + row) * D + kc);
            As[lkq * 4 + 0][row] = av.x + pv.x;
            As[lkq * 4 + 1][row] = av.y + pv.y;
            As[lkq * 4 + 2][row] = av.z + pv.z;
            As[lkq * 4 + 3][row] = av.w + pv.w;
            int ocol = colBase + row;
            const float* Wp = (ocol < 256) ? (wqk + (long)ocol * D) : (wv + (long)(ocol - 256) * D);
            float4 wvv = *(const float4*)(Wp + kc);
            Ws[lkq * 4 + 0][row] = wvv.x;
            Ws[lkq * 4 + 1][row] = wvv.y;
            Ws[lkq * 4 + 2][row] = wvv.z;
            Ws[lkq * 4 + 3][row] = wvv.w;
        }
        __syncthreads();
        #pragma unroll
        for (int kk = 0; kk < 16; kk++) {
            float a[8], w[8];
            *(float4*)(a + 0) = *(const float4*)&As[kk][tr * 8 + 0];
            *(float4*)(a + 4) = *(const float4*)&As[kk][tr * 8 + 4];
            *(float4*)(w + 0) = *(const float4*)&Ws[kk][tc * 8 + 0];
            *(float4*)(w + 4) = *(const float4*)&Ws[kk][tc * 8 + 4];
            #pragma unroll
            for (int i = 0; i < 8; i++)
                #pragma unroll
                for (int j = 0; j < 8; j++)
                    acc[i][j] += a[i] * w[j];
        }
        __syncthreads();
    }
    int col0 = colBase + tc * 8;
    #pragma unroll
    for (int i = 0; i < 8; i++) {
        long row = rowBase + tr * 8 + i;
        if (col0 < 256) {
            float4 v0 = make_float4(acc[i][0], acc[i][1], acc[i][2], acc[i][3]);
            float4 v1 = make_float4(acc[i][4], acc[i][5], acc[i][6], acc[i][7]);
            *(float4*)(qb + row * 256 + col0) = v0;
            *(float4*)(qb + row * 256 + col0 + 4) = v1;
        } else {
            int cc = col0 - 256;
            float4 v0 = make_float4(acc[i][0] + bv[cc + 0], acc[i][1] + bv[cc + 1],
                                    acc[i][2] + bv[cc + 2], acc[i][3] + bv[cc + 3]);
            float4 v1 = make_float4(acc[i][4] + bv[cc + 4], acc[i][5] + bv[cc + 5],
                                    acc[i][6] + bv[cc + 6], acc[i][7] + bv[cc + 7]);
            *(float4*)(vb + row * 256 + cc) = v0;
            *(float4*)(vb + row * 256 + cc + 4) = v1;
        }
    }
}

__global__ void gram_kernel(const float* __restrict__ Q, float* __restrict__ A) {
    int bh = blockIdx.z; int b = bh >> 2; int h = bh & 3;
    int i0 = blockIdx.y * 16, j0 = blockIdx.x * 16;
    __shared__ float Qi[16][65];
    __shared__ float Qj[16][65];
    int tid = threadIdx.x;
    for (int e = tid; e < 1024; e += 256) {
        int r = e >> 6, d = e & 63;
        int i = i0 + r;
        Qi[r][d] = Q[((long)b * 256 + h * 64 + (i >> 2)) * 256 + (i & 3) * 64 + d];
        Qj[r][d] = Q[((long)b * 256 + j0 + r) * 256 + h * 64 + d];
    }
    __syncthreads();
    int ti = tid >> 4, tj = tid & 15;
    float acc = 0.f;
    #pragma unroll
    for (int d = 0; d < 64; d++) acc += Qi[ti][d] * Qj[tj][d];
    A[((long)bh * 256 + (i0 + ti)) * 256 + (j0 + tj)] = acc;
}

__global__ void softmax_row_kernel(float* __restrict__ A) {
    __shared__ float red[256];
    long row = blockIdx.x;
    float* p = A + row * 256;
    int t = threadIdx.x;
    float v = p[t];
    red[t] = v; __syncthreads();
    for (int s = 128; s > 0; s >>= 1) { if (t < s) red[t] = fmaxf(red[t], red[t + s]); __syncthreads(); }
    float m = red[0]; __syncthreads();
    float e = expf(v - m);
    red[t] = e; __syncthreads();
    for (int s = 128; s > 0; s >>= 1) { if (t < s) red[t] += red[t + s]; __syncthreads(); }
    p[t] = e / red[0];
}

__global__ void colsm_xr_kernel(const float* __restrict__ attn, const float* __restrict__ V,
                                const float* __restrict__ xx, const float* __restrict__ pos,
                                float* __restrict__ xrb) {
    int b = blockIdx.x >> 8;
    int i = blockIdx.x & 255;
    int t = threadIdx.x;
    __shared__ float colv[4][256];
    __shared__ float4 r4[256];
    #pragma unroll
    for (int h = 0; h < 4; h++)
        colv[h][t] = attn[(((long)(b * 4 + h)) * 256 + t) * 256 + i];
    float4 vm = make_float4(colv[0][t], colv[1][t], colv[2][t], colv[3][t]);
    r4[t] = vm;
    __syncthreads();
    for (int s = 128; s > 0; s >>= 1) {
        if (t < s) {
            float4 o = r4[t + s];
            r4[t].x = fmaxf(r4[t].x, o.x); r4[t].y = fmaxf(r4[t].y, o.y);
            r4[t].z = fmaxf(r4[t].z, o.z); r4[t].w = fmaxf(r4[t].w, o.w);
        }
        __syncthreads();
    }
    float4 mx = r4[0];
    __syncthreads();
    float4 ev = make_float4(expf(vm.x - mx.x), expf(vm.y - mx.y),
                            expf(vm.z - mx.z), expf(vm.w - mx.w));
    r4[t] = ev;
    __syncthreads();
    for (int s = 128; s > 0; s >>= 1) {
        if (t < s) {
            float4 o = r4[t + s];
            r4[t].x += o.x; r4[t].y += o.y; r4[t].z += o.z; r4[t].w += o.w;
        }
        __syncthreads();
    }
    float4 sm = r4[0];
    __syncthreads();
    colv[0][t] = ev.x / sm.x;
    colv[1][t] = ev.y / sm.y;
    colv[2][t] = ev.z / sm.z;
    colv[3][t] = ev.w / sm.w;
    __syncthreads();
    int c = t; int h = c >> 6;
    const float* vp = V + ((long)b * 256) * 256 + c;
    float acc = 0.f;
    #pragma unroll 8
    for (int j = 0; j < 256; j++) acc += vp[(long)j * 256] * colv[h][j];
    long row = (long)b * 256 + i;
    xrb[row * 256 + c] = xx[row * 256 + c] + pos[row * 256 + c] - acc;
}

__global__ void addcat_bn_kernel(const float* __restrict__ qb, float* __restrict__ xx,
                                 const float* __restrict__ pos, float* __restrict__ cat,
                                 int layer) {
    int t = blockIdx.x * 256 + threadIdx.x;
    int c = t & 255; int row = t >> 8;
    float y = fmaxf((qb[t] - g_m1[c]) * g_i1[c], 0.f);
    float v = xx[t] + pos[t] + y;
    xx[t] = v;
    cat[(long)row * 1280 + layer * 256 + c] = v;
}

// ----------------------------------------------------------------------------
// Host orchestration
// ----------------------------------------------------------------------------
static void gemm_old(const float* A, const float* W, const float* bias, float* C,
                     int R, int D, int O) {
    dim3 grid(CEILDIV(O, 64), CEILDIV(R, 64));
    gemm_kernel<<<grid, 256>>>(A, W, bias, C, R, D, O);
}

static float* s_m1;
static float* s_i1;

static void gemm_big(const float* A, const float* W, const float* bias, float* C,
                     int R, int D, int O, int useStats, int emitStats) {
    dim3 grid(CEILDIV(O, 128), R / 128);
    if (useStats) {
        if (emitStats)
            gemm128_kernel<1, 1><<<grid, 256>>>(A, W, bias, C, R, D, O, s_m1, s_i1);
        else
            gemm128_kernel<1, 0><<<grid, 256>>>(A, W, bias, C, R, D, O, s_m1, s_i1);
    } else {
        if (emitStats)
            gemm128_kernel<0, 1><<<grid, 256>>>(A, W, bias, C, R, D, O, nullptr, nullptr);
        else
            gemm128_kernel<0, 0><<<grid, 256>>>(A, W, bias, C, R, D, O, nullptr, nullptr);
    }
}

extern "C" void kernel_launch(void* const* d_in, const int* in_sizes, int n_in,
                              void* d_out, int out_size) {
    const float* x       = (const float*)d_in[0];
    const float* conv1_w = (const float*)d_in[1];
    const float* conv2_w = (const float*)d_in[2];
    const float* g0_w1   = (const float*)d_in[3];
    const float* g0_w2   = (const float*)d_in[4];
    const float* g0_wc   = (const float*)d_in[5];
    const float* g1_w1   = (const float*)d_in[6];
    const float* g1_w2   = (const float*)d_in[7];
    const float* g1_wc   = (const float*)d_in[8];
    const float* pt_w    = (const float*)d_in[9];
    const float* pos_w   = (const float*)d_in[10];
    const float* pos_b   = (const float*)d_in[11];
    const float* sa_wqk  = (const float*)d_in[12];
    const float* sa_wv   = (const float*)d_in[13];
    const float* sa_bv   = (const float*)d_in[14];
    const float* sa_wt   = (const float*)d_in[15];
    const float* sa_bt   = (const float*)d_in[16];
    const float* fuse_w  = (const float*)d_in[17];
    const float* lin1_w  = (const float*)d_in[18];
    const float* lin2_w  = (const float*)d_in[19];
    const float* lin2_b  = (const float*)d_in[20];
    const float* lin3_w  = (const float*)d_in[21];
    const float* lin3_b  = (const float*)d_in[22];
    float* out = (float*)d_out;

    float *xyz, *h1, *points, *newxyz, *newxyz2, *newpts, *Ub, *Vb, *w1a, *w1d, *pool, *f0, *f1;
    float *pos, *xx, *qb, *vb, *xrb, *attn, *catb, *fuseb, *gmax, *l1, *l2, *part, *s1m, *s1i;
    int *fpsidx, *knn, *knn2;
    cudaGetSymbolAddress((void**)&xyz, g_xyz);
    cudaGetSymbolAddress((void**)&h1, g_h1);
    cudaGetSymbolAddress((void**)&points, g_points);
    cudaGetSymbolAddress((void**)&fpsidx, g_fpsidx);
    cudaGetSymbolAddress((void**)&newxyz, g_newxyz);
    cudaGetSymbolAddress((void**)&newxyz2, g_newxyz2);
    cudaGetSymbolAddress((void**)&newpts, g_newpts);
    cudaGetSymbolAddress((void**)&knn, g_knn);
    cudaGetSymbolAddress((void**)&knn2, g_knn2);
    cudaGetSymbolAddress((void**)&Ub, g_U);
    cudaGetSymbolAddress((void**)&Vb, g_V);
    cudaGetSymbolAddress((void**)&w1a, g_w1a);
    cudaGetSymbolAddress((void**)&w1d, g_w1d);
    cudaGetSymbolAddress((void**)&part, g_part);
    cudaGetSymbolAddress((void**)&pool, g_pool);
    cudaGetSymbolAddress((void**)&f0, g_f0);
    cudaGetSymbolAddress((void**)&f1, g_f1);
    cudaGetSymbolAddress((void**)&pos, g_pos);
    cudaGetSymbolAddress((void**)&xx, g_x);
    cudaGetSymbolAddress((void**)&qb, g_q);
    cudaGetSymbolAddress((void**)&vb, g_v);
    cudaGetSymbolAddress((void**)&xrb, g_xr);
    cudaGetSymbolAddress((void**)&attn, g_attn);
    cudaGetSymbolAddress((void**)&catb, g_cat);
    cudaGetSymbolAddress((void**)&fuseb, g_fuse);
    cudaGetSymbolAddress((void**)&gmax, g_gmax);
    cudaGetSymbolAddress((void**)&l1, g_l1);
    cudaGetSymbolAddress((void**)&l2, g_l2);
    cudaGetSymbolAddress((void**)&s_m1, g_m1);
    cudaGetSymbolAddress((void**)&s_i1, g_i1);
    cudaGetSymbolAddress((void**)&s1m, g_s1m);
    cudaGetSymbolAddress((void**)&s1i, g_s1i);

    // ---- Stage A ----
    transpose_x_kernel<<<CEILDIV(8*2048*3, 256), 256>>>(x, xyz);
    gemm_old(xyz, conv1_w, nullptr, h1, 16384, 3, 64);
    zero_stats_kernel<<<1, 1024>>>();
    stats_h1_kernel<<<512, 64>>>(h1, 16384, 64, 32);
    finalize1_kernel<<<1, 256>>>(64, 16384);
    gemm_big(h1, conv2_w, nullptr, points, 16384, 64, 64, 1, 1);
    reduce_part_kernel<<<1, 128>>>(part, 128, 64, 16384, 0);

    // ---- Stage B ----
    fps_kernel<<<8, 1024>>>(xyz, 2048, 512, fpsidx);
    gather_kernel<<<CEILDIV(8*512*3, 256), 256>>>(xyz, fpsidx, newxyz, 512, 2048, 3, 8L*512*3);
    gather_kernel<<<CEILDIV(8*512*64, 256), 256>>>(points, fpsidx, newpts, 512, 2048, 64, 8L*512*64);
    knn_fps_kernel<<<4096 + 8, 256>>>(newxyz, xyz, 512, 2048, knn, 4096,
                                      newxyz, 512, 256, fpsidx);
    gather_kernel<<<CEILDIV(8*256*3, 256), 256>>>(newxyz, fpsidx, newxyz2, 256, 512, 3, 8L*256*3);
    knn_kernel<<<2048, 256>>>(newxyz2, newxyz, 256, 512, knn2);

    // ---- Stage C ----
    {
        split_w1_kernel<<<CEILDIV(128*64, 256), 256>>>(g0_w1, w1a, w1d, 128, 64, 128*64);
        gemm_big(points, w1a, nullptr, Ub, 16384, 64, 128, 1, 0);
        gemm_big(newpts, w1d, nullptr, Vb, 4096, 64, 128, 1, 0);
        stats1_all_kernel<<<256, 128>>>(Ub, Vb, knn, 512, 2048, 128, 16, 256, part);
        stats1_fin_kernel<<<1, 128>>>(part, 256, 128, 8*512);
        const int kshift[3] = {4, 5, 6};
        long pOff[3] = {0, 2L*512*128, 2L*512*128 + 2L*1024*128};
        for (int si = 0; si < 3; si++) {
            int nBy = (8 * 512 * (1 << kshift[si])) / 128;
            dim3 grid(1, nBy);
            local_gemm2_kernel<<<grid, 256>>>(Ub, Vb, knn, g0_w2, pool,
                                              512, 2048, 128, 128, kshift[si], 384, si * 128,
                                              s1m + si * 256, s1i + si * 256, part + pOff[si]);
        }
        for (int si = 0; si < 3; si++) {
            int R = 8 * 512 * (1 << kshift[si]);
            reduce_part_kernel<<<1, 128>>>(part + pOff[si], R / 128, 128, R, si * 128);
        }
        gemm_big(pool, g0_wc, nullptr, f0, 4096, 384, 128, 1, 1);
        reduce_part_kernel<<<1, 128>>>(part, 32, 128, 4096, 0);
    }

    // ---- Stage D gather ----
    gather_kernel<<<CEILDIV(8*256*128, 256), 256>>>(f0, fpsidx, newpts, 256, 512, 128, 8L*256*128);

    // ---- Stage E ----
    {
        split_w1_kernel<<<CEILDIV(256*128, 256), 256>>>(g1_w1, w1a, w1d, 256, 128, 256*128);
        gemm_big(f0, w1a, nullptr, Ub, 4096, 128, 256, 1, 0);
        gemm_big(newpts, w1d, nullptr, Vb, 2048, 128, 256, 1, 0);
        stats1_all_kernel<<<128, 256>>>(Ub, Vb, knn2, 256, 512, 256, 16, 128, part);
        stats1_fin_kernel<<<2, 128>>>(part, 128, 256, 8*256);
        const int kshift[3] = {4, 5, 6};
        long pOff[3] = {0, 2L*256*256, 2L*256*256 + 2L*512*256};
        for (int si = 0; si < 3; si++) {
            int nBy = (8 * 256 * (1 << kshift[si])) / 128;
            dim3 grid(2, nBy);
            local_gemm2_kernel<<<grid, 256>>>(Ub, Vb, knn2, g1_w2, pool,
                                              256, 512, 256, 256, kshift[si], 768, si * 256,
                                              s1m + si * 256, s1i + si * 256, part + pOff[si]);
        }
        for (int si = 0; si < 3; si++) {
            int R = 8 * 256 * (1 << kshift[si]);
            reduce_part_kernel<<<2, 128>>>(part + pOff[si], R / 128, 256, R, si * 256);
        }
        gemm_big(pool, g1_wc, nullptr, f1, 2048, 768, 256, 1, 1);
        reduce_part_kernel<<<2, 128>>>(part, 16, 256, 2048, 0);
        bn_apply_kernel<<<2048, 256>>>(f1, 8L*256*256, 256, 0);
    }

    // ---- Stage F ----
    gemm_old(newxyz2, pos_w, pos_b, pos, 2048, 3, 256);
    gemm_big(f1, pt_w, nullptr, xx, 2048, 256, 256, 0, 1);
    reduce_part_kernel<<<2, 128>>>(part, 16, 256, 2048, 0);
    bn_apply_kernel<<<2048, 256>>>(xx, 8L*256*256, 256, 0);

    // ---- Stage G ----
    for (int i = 0; i < 4; i++) {
        gemmqv_kernel<<<dim3(4, 16), 256>>>(xx, pos,
                                            sa_wqk + (long)i * 256 * 256,
                                            sa_wv + (long)i * 256 * 256,
                                            sa_bv + i * 256, qb, vb);
        gram_kernel<<<dim3(16, 16, 32), 256>>>(qb, attn);
        softmax_row_kernel<<<8192, 256>>>(attn);
        colsm_xr_kernel<<<2048, 256>>>(attn, vb, xx, pos, xrb);
        gemm_big(xrb, sa_wt + (long)i * 256 * 256, sa_bt + i * 256, qb, 2048, 256, 256, 0, 1);
        reduce_part_kernel<<<2, 128>>>(part, 16, 256, 2048, 0);
        addcat_bn_kernel<<<2048, 256>>>(qb, xx, pos, catb, i);
    }
    catf1_kernel<<<2048, 256>>>(f1, catb);

    // ---- Stage H ----
    gemm_big(catb, fuse_w, nullptr, fuseb, 2048, 1280, 1024, 0, 1);
    reduce_part_kernel<<<8, 128>>>(part, 16, 1024, 2048, 0);
    maxn_bn_kernel<<<dim3(8, 4), 256>>>(fuseb, gmax);
    gemm_old(gmax, lin1_w, nullptr, l1, 8, 1024, 512);
    bn_small_kernel<<<2, 256>>>(l1, 512, 0.2f);
    gemm_old(l1, lin2_w, lin2_b, l2, 8, 512, 256);
    bn_small_kernel<<<1, 256>>>(l2, 256, 0.2f);
    gemm_old(l2, lin3_w, lin3_b, out, 8, 256, 40);
}

// round 10
// speedup vs baseline: 1.0550x; 1.0550x over previous
#include <cuda_runtime.h>
#include <math.h>
#include <float.h>

#define CEILDIV(a,b) (((a)+(b)-1)/(b))
#define BN_EPS 1e-5f
#define PART_OFF (2048*256)

// ----------------------------------------------------------------------------
// Scratch (device globals)
// ----------------------------------------------------------------------------
__device__ float g_xyz[8*2048*3];
__device__ float g_h1[8*2048*64];
__device__ float g_points[8*2048*64];
__device__ int   g_fpsidx[8*512];
__device__ float g_newxyz[8*512*3];
__device__ float g_newxyz2[8*256*3];
__device__ float g_newpts[8*512*64];        // stage2: 8*256*128
__device__ int   g_knn[8*512*64];           // stage-1 kNN lists
__device__ int   g_knn2[8*256*64];          // stage-2 kNN lists (separate buffers!)
__device__ float g_U[16384*128];            // stage E: 4096x256
__device__ float g_V[4096*128];             // stage E: 2048x256
__device__ float g_w1a[256*128];
__device__ float g_w1d[256*128];
__device__ float g_part[2*2048*256];        // per-block partial sums / sumsq
__device__ float g_pool[8*512*384];         // stage2: 8*256*768
__device__ float g_f0[8*512*128];
__device__ float g_f1[8*256*256];
__device__ float g_pos[8*256*256];
__device__ float g_x[8*256*256];
__device__ float g_q[8*256*256];
__device__ float g_v[8*256*256];
__device__ float g_xr[8*256*256];
__device__ float g_attn[8*4*256*256];
__device__ float g_cat[8*256*1280];
__device__ float g_fuse[8*256*1024];
__device__ float g_gmax[8*1024];
__device__ float g_l1[8*512];
__device__ float g_l2[8*256];
__device__ double g_sum[1024];
__device__ double g_sumsq[1024];
__device__ float g_m1[1024];
__device__ float g_i1[1024];
__device__ float g_m2[256];
__device__ float g_i2[256];

// ----------------------------------------------------------------------------
// BN stats plumbing
// ----------------------------------------------------------------------------
__global__ void zero_stats_kernel() {
    int t = threadIdx.x;
    g_sum[t] = 0.0; g_sumsq[t] = 0.0;
}

// R9: wide-grid stats with float inner accumulation and NO atomics.
// Writes per-block partials: part[blk*C + c] (sums), part[nB*C + blk*C + c] (sumsq).
__global__ void stats_part_kernel(const float* __restrict__ X, int R, int C, int rpb,
                                  int nB, float* __restrict__ part) {
    int blk = blockIdx.x;
    int r0 = blk * rpb;
    int r1 = r0 + rpb; if (r1 > R) r1 = R;
    int nch = (C + 255) / 256;
    float acc[4] = {0.f, 0.f, 0.f, 0.f};
    float accsq[4] = {0.f, 0.f, 0.f, 0.f};
    for (int r = r0; r < r1; r++) {
        const float* row = X + (long)r * C;
        #pragma unroll
        for (int k = 0; k < 4; k++) {
            if (k < nch) {
                int c = threadIdx.x + k * 256;
                if (c < C) { float v = row[c]; acc[k] += v; accsq[k] += v * v; }
            }
        }
    }
    #pragma unroll
    for (int k = 0; k < 4; k++) {
        if (k < nch) {
            int c = threadIdx.x + k * 256;
            if (c < C) {
                part[(long)blk * C + c] = acc[k];
                part[(long)nB * C + (long)blk * C + c] = accsq[k];
            }
        }
    }
}

// R9: reduce partials straight into g_m1/g_i1 (no doubles buffer, no finalize pass)
__global__ void reduce_m1_kernel(const float* __restrict__ part, int nB, int C, int statN) {
    int c = blockIdx.x * 128 + threadIdx.x;
    if (c >= C) return;
    float a0 = 0.f, a1 = 0.f, a2 = 0.f, a3 = 0.f;
    float b0 = 0.f, b1 = 0.f, b2 = 0.f, b3 = 0.f;
    const float* ps = part;
    const float* pq = part + (long)nB * C;
    int r = 0;
    for (; r + 4 <= nB; r += 4) {
        a0 += ps[(long)(r + 0) * C + c]; b0 += pq[(long)(r + 0) * C + c];
        a1 += ps[(long)(r + 1) * C + c]; b1 += pq[(long)(r + 1) * C + c];
        a2 += ps[(long)(r + 2) * C + c]; b2 += pq[(long)(r + 2) * C + c];
        a3 += ps[(long)(r + 3) * C + c]; b3 += pq[(long)(r + 3) * C + c];
    }
    for (; r < nB; r++) { a0 += ps[(long)r * C + c]; b0 += pq[(long)r * C + c]; }
    double s = (double)a0 + a1 + a2 + a3;
    double q = (double)b0 + b1 + b2 + b3;
    double m = s / statN;
    double var = q / statN - m * m;
    if (var < 0.0) var = 0.0;
    g_m1[c] = (float)m;
    g_i1[c] = rsqrtf((float)var + BN_EPS);
}

__global__ void finalize1_kernel(int C, int statN) {
    int c = blockIdx.x * 256 + threadIdx.x;
    if (c >= C) return;
    double m = g_sum[c] / statN;
    double var = g_sumsq[c] / statN - m * m;
    if (var < 0.0) var = 0.0;
    g_m1[c] = (float)m;
    g_i1[c] = rsqrtf((float)var + BN_EPS);
}

// act: 0 = relu, 1 = leaky(0.2)
__global__ void bn_apply_kernel(float* __restrict__ X, long total, int C, int act) {
    long t = (long)blockIdx.x * blockDim.x + threadIdx.x;
    if (t >= total) return;
    int c = (int)(t % C);
    float y = (X[t] - g_m1[c]) * g_i1[c];
    X[t] = (act == 0) ? fmaxf(y, 0.f) : (y >= 0.f ? y : 0.2f * y);
}

__global__ void bn_small_kernel(float* __restrict__ X, int C, float slope) {
    int c = blockIdx.x * blockDim.x + threadIdx.x;
    if (c >= C) return;
    double s = 0.0, ss = 0.0;
    for (int r = 0; r < 8; r++) { double v = X[r * C + c]; s += v; ss += v * v; }
    double m = s / 8.0;
    double var = ss / 8.0 - m * m;
    if (var < 0.0) var = 0.0;
    float inv = rsqrtf((float)var + BN_EPS);
    for (int r = 0; r < 8; r++) {
        float y = (X[r * C + c] - (float)m) * inv;
        X[r * C + c] = y >= 0.f ? y : slope * y;
    }
}

// reduce per-block partials -> g_m2/g_i2 (for BN2 of local op)
__global__ void reduce_part_kernel(int nBy, int O, int statN) {
    int c = blockIdx.x;
    int t = threadIdx.x;
    double a = 0.0, b = 0.0;
    for (int r = t; r < nBy; r += 256) {
        a += g_part[r * O + c];
        b += g_part[PART_OFF + r * O + c];
    }
    __shared__ double sa[256], sb[256];
    sa[t] = a; sb[t] = b;
    __syncthreads();
    for (int s = 128; s > 0; s >>= 1) {
        if (t < s) { sa[t] += sa[t + s]; sb[t] += sb[t + s]; }
        __syncthreads();
    }
    if (t == 0) {
        double m = sa[0] / statN;
        double var = sb[0] / statN - m * m;
        if (var < 0.0) var = 0.0;
        g_m2[c] = (float)m;
        g_i2[c] = rsqrtf((float)var + BN_EPS);
    }
}

// ----------------------------------------------------------------------------
// 128x128 tiled GEMM (optionally BN+relu on A via g_m1/g_i1; max BN'd D = 128)
// ----------------------------------------------------------------------------
__global__ void gemm128_kernel(const float* __restrict__ A, const float* __restrict__ W,
                               const float* __restrict__ bias, float* __restrict__ C,
                               int R, int D, int O, int useStats) {
    __shared__ float As[16][132];
    __shared__ float Ws[16][132];
    __shared__ float sM[256];
    __shared__ float sI[256];
    int tid = threadIdx.x;
    if (useStats) {
        for (int c = tid; c < D; c += 256) { sM[c] = g_m1[c]; sI[c] = g_i1[c]; }
        __syncthreads();
    }
    long rowBase = (long)blockIdx.y * 128;
    int colBase = blockIdx.x * 128;
    int tr = tid >> 4, tc = tid & 15;
    int lrow = tid >> 2;
    int lkq = tid & 3;
    float acc[8][8];
    #pragma unroll
    for (int i = 0; i < 8; i++)
        #pragma unroll
        for (int j = 0; j < 8; j++) acc[i][j] = 0.f;

    for (int k0 = 0; k0 < D; k0 += 16) {
        #pragma unroll
        for (int half = 0; half < 2; half++) {
            int row = lrow + 64 * half;
            int kc = k0 + lkq * 4;
            float4 av = *(const float4*)(A + (rowBase + row) * D + kc);
            if (useStats) {
                av.x = fmaxf((av.x - sM[kc + 0]) * sI[kc + 0], 0.f);
                av.y = fmaxf((av.y - sM[kc + 1]) * sI[kc + 1], 0.f);
                av.z = fmaxf((av.z - sM[kc + 2]) * sI[kc + 2], 0.f);
                av.w = fmaxf((av.w - sM[kc + 3]) * sI[kc + 3], 0.f);
            }
            As[lkq * 4 + 0][row] = av.x;
            As[lkq * 4 + 1][row] = av.y;
            As[lkq * 4 + 2][row] = av.z;
            As[lkq * 4 + 3][row] = av.w;
            int wr = colBase + row;
            float4 wv = make_float4(0.f, 0.f, 0.f, 0.f);
            if (wr < O) wv = *(const float4*)(W + (long)wr * D + kc);
            Ws[lkq * 4 + 0][row] = wv.x;
            Ws[lkq * 4 + 1][row] = wv.y;
            Ws[lkq * 4 + 2][row] = wv.z;
            Ws[lkq * 4 + 3][row] = wv.w;
        }
        __syncthreads();
        #pragma unroll
        for (int kk = 0; kk < 16; kk++) {
            float a[8], w[8];
            *(float4*)(a + 0) = *(const float4*)&As[kk][tr * 8 + 0];
            *(float4*)(a + 4) = *(const float4*)&As[kk][tr * 8 + 4];
            *(float4*)(w + 0) = *(const float4*)&Ws[kk][tc * 8 + 0];
            *(float4*)(w + 4) = *(const float4*)&Ws[kk][tc * 8 + 4];
            #pragma unroll
            for (int i = 0; i < 8; i++)
                #pragma unroll
                for (int j = 0; j < 8; j++)
                    acc[i][j] += a[i] * w[j];
        }
        __syncthreads();
    }
    #pragma unroll
    for (int i = 0; i < 8; i++) {
        long row = rowBase + tr * 8 + i;
        int col0 = colBase + tc * 8;
        if (col0 >= O) continue;
        float b0 = 0, b1 = 0, b2 = 0, b3 = 0, b4 = 0, b5 = 0, b6 = 0, b7 = 0;
        if (bias) {
            b0 = bias[col0 + 0]; b1 = bias[col0 + 1]; b2 = bias[col0 + 2]; b3 = bias[col0 + 3];
            b4 = bias[col0 + 4]; b5 = bias[col0 + 5]; b6 = bias[col0 + 6]; b7 = bias[col0 + 7];
        }
        float4 v0 = make_float4(acc[i][0] + b0, acc[i][1] + b1, acc[i][2] + b2, acc[i][3] + b3);
        float4 v1 = make_float4(acc[i][4] + b4, acc[i][5] + b5, acc[i][6] + b6, acc[i][7] + b7);
        *(float4*)(C + row * O + col0) = v0;
        *(float4*)(C + row * O + col0 + 4) = v1;
    }
}

// ----------------------------------------------------------------------------
// Fused local-op GEMM2 (A built on the fly, BN1 from g_m1/g_i1; epilogue:
// per-center raw max -> pool, per-block channel partials -> g_part)
// ----------------------------------------------------------------------------
__global__ void local_gemm2_kernel(const float* __restrict__ U, const float* __restrict__ V,
                                   const int* __restrict__ knn, const float* __restrict__ W,
                                   float* __restrict__ poolOut,
                                   int S, int N, int D, int O, int kshift,
                                   int OC, int off) {
    __shared__ float As[16][132];
    __shared__ float Ws[16][132];
    __shared__ float sRed[16][132];
    __shared__ float sM[256];
    __shared__ float sI[256];
    __shared__ int sP[128];
    __shared__ int sS[128];
    int tid = threadIdx.x;
    long rowBase = (long)blockIdx.y * 128;
    int colBase = blockIdx.x * 128;

    for (int c = tid; c < D; c += 256) { sM[c] = g_m1[c]; sI[c] = g_i1[c]; }
    if (tid < 128) {
        long grow = rowBase + tid;
        int s = (int)(grow >> kshift);
        int j = (int)(grow & ((1 << kshift) - 1));
        int b = s / S;
        sS[tid] = s;
        sP[tid] = b * N + knn[(long)s * 64 + j];
    }
    __syncthreads();

    int tr = tid >> 4, tc = tid & 15;
    int lrow = tid >> 2;
    int lkq = tid & 3;
    float acc[8][8];
    #pragma unroll
    for (int i = 0; i < 8; i++)
        #pragma unroll
        for (int j = 0; j < 8; j++) acc[i][j] = 0.f;

    for (int k0 = 0; k0 < D; k0 += 16) {
        #pragma unroll
        for (int half = 0; half < 2; half++) {
            int row = lrow + 64 * half;
            int kc = k0 + lkq * 4;
            float4 uv = *(const float4*)(U + (long)sP[row] * D + kc);
            float4 vv = *(const float4*)(V + (long)sS[row] * D + kc);
            As[lkq * 4 + 0][row] = fmaxf((uv.x + vv.x - sM[kc + 0]) * sI[kc + 0], 0.f);
            As[lkq * 4 + 1][row] = fmaxf((uv.y + vv.y - sM[kc + 1]) * sI[kc + 1], 0.f);
            As[lkq * 4 + 2][row] = fmaxf((uv.z + vv.z - sM[kc + 2]) * sI[kc + 2], 0.f);
            As[lkq * 4 + 3][row] = fmaxf((uv.w + vv.w - sM[kc + 3]) * sI[kc + 3], 0.f);
            float4 wv = *(const float4*)(W + (long)(colBase + row) * D + kc);
            Ws[lkq * 4 + 0][row] = wv.x;
            Ws[lkq * 4 + 1][row] = wv.y;
            Ws[lkq * 4 + 2][row] = wv.z;
            Ws[lkq * 4 + 3][row] = wv.w;
        }
        __syncthreads();
        #pragma unroll
        for (int kk = 0; kk < 16; kk++) {
            float a[8], w[8];
            *(float4*)(a + 0) = *(const float4*)&As[kk][tr * 8 + 0];
            *(float4*)(a + 4) = *(const float4*)&As[kk][tr * 8 + 4];
            *(float4*)(w + 0) = *(const float4*)&Ws[kk][tc * 8 + 0];
            *(float4*)(w + 4) = *(const float4*)&Ws[kk][tc * 8 + 4];
            #pragma unroll
            for (int i = 0; i < 8; i++)
                #pragma unroll
                for (int j = 0; j < 8; j++)
                    acc[i][j] += a[i] * w[j];
        }
        __syncthreads();
    }

    // epilogue 1: per-center raw max -> poolOut
    int g = (1 << kshift) >> 3;
    #pragma unroll
    for (int j = 0; j < 8; j++) {
        float m = acc[0][j];
        #pragma unroll
        for (int i = 1; i < 8; i++) m = fmaxf(m, acc[i][j]);
        sRed[tr][tc * 8 + j] = m;
    }
    __syncthreads();
    if ((tr & (g - 1)) == 0) {
        int s = sS[tr * 8];
        #pragma unroll
        for (int j = 0; j < 8; j++) {
            float m = sRed[tr][tc * 8 + j];
            for (int q = 1; q < g; q++) m = fmaxf(m, sRed[tr + q][tc * 8 + j]);
            poolOut[(long)s * OC + off + colBase + tc * 8 + j] = m;
        }
    }
    __syncthreads();
    // epilogue 2: per-block channel sums -> g_part
    #pragma unroll
    for (int j = 0; j < 8; j++) {
        float sm = 0.f;
        #pragma unroll
        for (int i = 0; i < 8; i++) sm += acc[i][j];
        sRed[tr][tc * 8 + j] = sm;
    }
    __syncthreads();
    if (tr == 0) {
        #pragma unroll
        for (int j = 0; j < 8; j++) {
            float tot = 0.f;
            for (int q = 0; q < 16; q++) tot += sRed[q][tc * 8 + j];
            g_part[(long)blockIdx.y * O + colBase + tc * 8 + j] = tot;
        }
    }
    __syncthreads();
    #pragma unroll
    for (int j = 0; j < 8; j++) {
        float sm = 0.f;
        #pragma unroll
        for (int i = 0; i < 8; i++) sm += acc[i][j] * acc[i][j];
        sRed[tr][tc * 8 + j] = sm;
    }
    __syncthreads();
    if (tr == 0) {
        #pragma unroll
        for (int j = 0; j < 8; j++) {
            float tot = 0.f;
            for (int q = 0; q < 16; q++) tot += sRed[q][tc * 8 + j];
            g_part[PART_OFF + (long)blockIdx.y * O + colBase + tc * 8 + j] = tot;
        }
    }
}

// BN1 stats over layer-1 values (U[idx]+V); cpb centers per block, C threads.
__global__ void stats1_kernel(const float* __restrict__ U, const float* __restrict__ V,
                              const int* __restrict__ knn, int S, int N, int C, int k, int cpb) {
    int c = threadIdx.x;
    int s0 = blockIdx.x * cpb;
    double acc = 0.0, accsq = 0.0;
    for (int ss = 0; ss < cpb; ss++) {
        int s = s0 + ss;
        int b = s / S;
        float v = V[(long)s * C + c];
        const int* kn = knn + (long)s * 64;
        for (int j = 0; j < k; j++) {
            float u = U[((long)b * N + kn[j]) * C + c];
            float x = u + v;
            acc += x;
            accsq += x * x;
        }
    }
    atomicAdd(&g_sum[c], acc);
    atomicAdd(&g_sumsq[c], accsq);
}

// pool[s, off+c] = relu(bn2(rawmax)) via g_m2/g_i2
__global__ void pool_finalize_kernel(float* __restrict__ pool, int OC, int off) {
    int s = blockIdx.x;
    int c = threadIdx.x;
    long p = (long)s * OC + off + c;
    pool[p] = fmaxf((pool[p] - g_m2[c]) * g_i2[c], 0.f);
}

__global__ void split_w1_kernel(const float* __restrict__ w1, float* __restrict__ wa,
                                float* __restrict__ wd, int O, int D, int total) {
    int t = blockIdx.x * 256 + threadIdx.x;
    if (t >= total) return;
    int d = t % D, o = t / D;
    float a = w1[(long)o * 2 * D + d];
    float b = w1[(long)o * 2 * D + D + d];
    wa[t] = a;
    wd[t] = b - a;
}

// ----------------------------------------------------------------------------
// Generic fallback GEMM (odd shapes)
// ----------------------------------------------------------------------------
__global__ void gemm_kernel(const float* __restrict__ A, const float* __restrict__ W,
                            const float* __restrict__ bias, float* __restrict__ C,
                            int R, int D, int O) {
    __shared__ float As[64][17];
    __shared__ float Ws[64][17];
    int tid = threadIdx.x;
    int tr = tid >> 4, tc = tid & 15;
    long rowBase = (long)blockIdx.y * 64;
    int colBase = blockIdx.x * 64;
    float acc[4][4] = {};
    for (int k0 = 0; k0 < D; k0 += 16) {
        #pragma unroll
        for (int e = tid; e < 1024; e += 256) {
            int rr = e >> 4, kk = e & 15;
            long ar = rowBase + rr; int ac = k0 + kk;
            As[rr][kk] = (ar < R && ac < D) ? A[ar * D + ac] : 0.f;
            int wr = colBase + rr;
            Ws[rr][kk] = (wr < O && ac < D) ? W[(long)wr * D + ac] : 0.f;
        }
        __syncthreads();
        #pragma unroll
        for (int kk = 0; kk < 16; kk++) {
            float a[4], w[4];
            #pragma unroll
            for (int i = 0; i < 4; i++) a[i] = As[tr + 16*i][kk];
            #pragma unroll
            for (int j = 0; j < 4; j++) w[j] = Ws[tc + 16*j][kk];
            #pragma unroll
            for (int i = 0; i < 4; i++)
                #pragma unroll
                for (int j = 0; j < 4; j++)
                    acc[i][j] += a[i] * w[j];
        }
        __syncthreads();
    }
    #pragma unroll
    for (int i = 0; i < 4; i++) {
        long row = rowBase + tr + 16*i;
        if (row >= R) continue;
        #pragma unroll
        for (int j = 0; j < 4; j++) {
            int col = colBase + tc + 16*j;
            if (col >= O) continue;
            float vv = acc[i][j];
            if (bias) vv += bias[col];
            C[row * O + col] = vv;
        }
    }
}

// ----------------------------------------------------------------------------
// Layout / elementwise helpers
// ----------------------------------------------------------------------------
__global__ void transpose_x_kernel(const float* __restrict__ x, float* __restrict__ xyz) {
    int t = blockIdx.x * 256 + threadIdx.x;
    if (t >= 8 * 2048 * 3) return;
    int c = t % 3; int n = (t / 3) % 2048; int b = t / (3 * 2048);
    xyz[t] = x[((long)b * 3 + c) * 2048 + n];
}

__global__ void gather_kernel(const float* __restrict__ src, const int* __restrict__ idx,
                              float* __restrict__ dst, int S, int N, int D, long total) {
    long t = (long)blockIdx.x * blockDim.x + threadIdx.x;
    if (t >= total) return;
    int c = (int)(t % D); long bs = t / D;
    int b = (int)(bs / S);
    dst[t] = src[((long)b * N + idx[bs]) * D + c];
}

__global__ void catf1_kernel(const float* __restrict__ f1, float* __restrict__ cat) {
    int t = blockIdx.x * 256 + threadIdx.x;
    int c = t & 255; int row = t >> 8;
    cat[(long)row * 1280 + 1024 + c] = f1[t];
}

__global__ void maxn_kernel(const float* __restrict__ X, float* __restrict__ G) {
    int b = blockIdx.x; int c = blockIdx.y * 256 + threadIdx.x;
    float m = -FLT_MAX;
    for (int n = 0; n < 256; n++) m = fmaxf(m, X[((long)b * 256 + n) * 1024 + c]);
    G[b * 1024 + c] = m;
}

// ----------------------------------------------------------------------------
// FPS / kNN with warp-shuffle reductions (tie order preserved)
// ----------------------------------------------------------------------------
__device__ __forceinline__ unsigned keymap(float f) {
    unsigned u = __float_as_uint(f);
    return (u & 0x80000000u) ? ~u : (u | 0x80000000u);
}

__device__ void fps_body(const float* __restrict__ xyz, int N, int npoint,
                         int* __restrict__ outIdx, int b,
                         float* sx, float* sy, float* sz, float* sd,
                         unsigned long long* warpBest, int* sFar) {
    int t = threadIdx.x;
    int nt = blockDim.x;
    int numWarps = nt >> 5;
    for (int n = t; n < N; n += nt) {
        sx[n] = xyz[((long)b * N + n) * 3 + 0];
        sy[n] = xyz[((long)b * N + n) * 3 + 1];
        sz[n] = xyz[((long)b * N + n) * 3 + 2];
        sd[n] = 1e10f;
    }
    __syncthreads();
    int far = 0;
    for (int it = 0; it < npoint; it++) {
        if (t == 0) outIdx[b * npoint + it] = far;
        float cx = sx[far], cy = sy[far], cz = sz[far];
        unsigned long long best = 0ull;
        for (int n = t; n < N; n += nt) {
            float dx = sx[n] - cx, dy = sy[n] - cy, dz = sz[n] - cz;
            float d = dx * dx + dy * dy + dz * dz;
            float dm = fminf(sd[n], d);
            sd[n] = dm;
            unsigned long long key = ((unsigned long long)keymap(dm) << 32) | (unsigned)(~n);
            if (key > best) best = key;
        }
        #pragma unroll
        for (int o = 16; o > 0; o >>= 1) {
            unsigned long long other = __shfl_xor_sync(0xffffffffu, best, o);
            if (other > best) best = other;
        }
        if ((t & 31) == 0) warpBest[t >> 5] = best;
        __syncthreads();
        if (t < 32) {
            unsigned long long v = (t < numWarps) ? warpBest[t] : 0ull;
            #pragma unroll
            for (int o = 16; o > 0; o >>= 1) {
                unsigned long long other = __shfl_xor_sync(0xffffffffu, v, o);
                if (other > v) v = other;
            }
            if (t == 0) *sFar = (int)(~((unsigned)(v & 0xffffffffu)));
        }
        __syncthreads();
        far = *sFar;
    }
}

__device__ void knn_body(const float* __restrict__ centers, const float* __restrict__ xyz,
                         int S, int N, int* __restrict__ knnOut, int bs,
                         float* sd, unsigned long long* warpBest) {
    int t = threadIdx.x;
    int nt = blockDim.x;
    int numWarps = nt >> 5;
    int b = bs / S;
    float cx = centers[(long)bs * 3 + 0];
    float cy = centers[(long)bs * 3 + 1];
    float cz = centers[(long)bs * 3 + 2];
    float cn = cx * cx + cy * cy + cz * cz;
    for (int n = t; n < N; n += nt) {
        float px = xyz[((long)b * N + n) * 3 + 0];
        float py = xyz[((long)b * N + n) * 3 + 1];
        float pz = xyz[((long)b * N + n) * 3 + 2];
        float pn = px * px + py * py + pz * pz;
        float dot = cx * px + cy * py + cz * pz;
        sd[n] = cn + pn - 2.f * dot;
    }
    __syncthreads();
    for (int j = 0; j < 64; j++) {
        unsigned long long best = 0xFFFFFFFFFFFFFFFFull;
        for (int n = t; n < N; n += nt) {
            unsigned long long key = ((unsigned long long)keymap(sd[n]) << 32) | (unsigned)n;
            if (key < best) best = key;
        }
        #pragma unroll
        for (int o = 16; o > 0; o >>= 1) {
            unsigned long long other = __shfl_xor_sync(0xffffffffu, best, o);
            if (other < best) best = other;
        }
        if ((t & 31) == 0) warpBest[t >> 5] = best;
        __syncthreads();
        if (t < 32) {
            unsigned long long v = (t < numWarps) ? warpBest[t] : 0xFFFFFFFFFFFFFFFFull;
            #pragma unroll
            for (int o = 16; o > 0; o >>= 1) {
                unsigned long long other = __shfl_xor_sync(0xffffffffu, v, o);
                if (other < v) v = other;
            }
            if (t == 0) {
                int sel = (int)(v & 0xffffffffu);
                knnOut[(long)bs * 64 + j] = sel;
                sd[sel] = FLT_MAX;
            }
        }
        __syncthreads();
    }
}

__global__ void fps_kernel(const float* xyz, int N, int npoint, int* outIdx) {
    __shared__ float buf[4 * 2048];
    __shared__ unsigned long long wb[32];
    __shared__ int sFar;
    fps_body(xyz, N, npoint, outIdx, blockIdx.x, buf, buf + N, buf + 2 * N, buf + 3 * N, wb, &sFar);
}

__global__ void knn_kernel(const float* centers, const float* xyz, int S, int N, int* knnOut) {
    __shared__ float buf[2048];
    __shared__ unsigned long long wb[32];
    knn_body(centers, xyz, S, N, knnOut, blockIdx.x, buf, wb);
}

__global__ void knn_fps_kernel(const float* centers, const float* xyz, int S, int N,
                               int* knnOut, int nKnn,
                               const float* xyz2, int N2, int np2, int* outIdx2) {
    __shared__ float buf[4 * 2048];
    __shared__ unsigned long long wb[32];
    __shared__ int sFar;
    if (blockIdx.x < nKnn) {
        knn_body(centers, xyz, S, N, knnOut, blockIdx.x, buf, wb);
    } else {
        int b = blockIdx.x - nKnn;
        fps_body(xyz2, N2, np2, outIdx2, b, buf, buf + N2, buf + 2 * N2, buf + 3 * N2, wb, &sFar);
    }
}

// ----------------------------------------------------------------------------
// Attention (reference reshape quirk preserved)
// ----------------------------------------------------------------------------
__global__ void gemmqv_kernel(const float* __restrict__ xx, const float* __restrict__ pos,
                              const float* __restrict__ wqk, const float* __restrict__ wv,
                              const float* __restrict__ bv,
                              float* __restrict__ qb, float* __restrict__ vb) {
    __shared__ float As[16][132];
    __shared__ float Ws[16][132];
    int tid = threadIdx.x;
    long rowBase = (long)blockIdx.y * 128;
    int colBase = blockIdx.x * 128;
    int tr = tid >> 4, tc = tid & 15;
    int lrow = tid >> 2;
    int lkq = tid & 3;
    const int D = 256;
    float acc[8][8];
    #pragma unroll
    for (int i = 0; i < 8; i++)
        #pragma unroll
        for (int j = 0; j < 8; j++) acc[i][j] = 0.f;

    for (int k0 = 0; k0 < D; k0 += 16) {
        #pragma unroll
        for (int half = 0; half < 2; half++) {
            int row = lrow + 64 * half;
            int kc = k0 + lkq * 4;
            float4 av = *(const float4*)(xx + (rowBase + row) * D + kc);
            float4 pv = *(const float4*)(pos + (rowBase + row) * D + kc);
            As[lkq * 4 + 0][row] = av.x + pv.x;
            As[lkq * 4 + 1][row] = av.y + pv.y;
            As[lkq * 4 + 2][row] = av.z + pv.z;
            As[lkq * 4 + 3][row] = av.w + pv.w;
            int ocol = colBase + row;
            const float* Wp = (ocol < 256) ? (wqk + (long)ocol * D) : (wv + (long)(ocol - 256) * D);
            float4 wvv = *(const float4*)(Wp + kc);
            Ws[lkq * 4 + 0][row] = wvv.x;
            Ws[lkq * 4 + 1][row] = wvv.y;
            Ws[lkq * 4 + 2][row] = wvv.z;
            Ws[lkq * 4 + 3][row] = wvv.w;
        }
        __syncthreads();
        #pragma unroll
        for (int kk = 0; kk < 16; kk++) {
            float a[8], w[8];
            *(float4*)(a + 0) = *(const float4*)&As[kk][tr * 8 + 0];
            *(float4*)(a + 4) = *(const float4*)&As[kk][tr * 8 + 4];
            *(float4*)(w + 0) = *(const float4*)&Ws[kk][tc * 8 + 0];
            *(float4*)(w + 4) = *(const float4*)&Ws[kk][tc * 8 + 4];
            #pragma unroll
            for (int i = 0; i < 8; i++)
                #pragma unroll
                for (int j = 0; j < 8; j++)
                    acc[i][j] += a[i] * w[j];
        }
        __syncthreads();
    }
    int col0 = colBase + tc * 8;
    #pragma unroll
    for (int i = 0; i < 8; i++) {
        long row = rowBase + tr * 8 + i;
        if (col0 < 256) {
            float4 v0 = make_float4(acc[i][0], acc[i][1], acc[i][2], acc[i][3]);
            float4 v1 = make_float4(acc[i][4], acc[i][5], acc[i][6], acc[i][7]);
            *(float4*)(qb + row * 256 + col0) = v0;
            *(float4*)(qb + row * 256 + col0 + 4) = v1;
        } else {
            int cc = col0 - 256;
            float4 v0 = make_float4(acc[i][0] + bv[cc + 0], acc[i][1] + bv[cc + 1],
                                    acc[i][2] + bv[cc + 2], acc[i][3] + bv[cc + 3]);
            float4 v1 = make_float4(acc[i][4] + bv[cc + 4], acc[i][5] + bv[cc + 5],
                                    acc[i][6] + bv[cc + 6], acc[i][7] + bv[cc + 7]);
            *(float4*)(vb + row * 256 + cc) = v0;
            *(float4*)(vb + row * 256 + cc + 4) = v1;
        }
    }
}

__global__ void gram_kernel(const float* __restrict__ Q, float* __restrict__ A) {
    int bh = blockIdx.z; int b = bh >> 2; int h = bh & 3;
    int i0 = blockIdx.y * 16, j0 = blockIdx.x * 16;
    __shared__ float Qi[16][65];
    __shared__ float Qj[16][65];
    int tid = threadIdx.x;
    for (int e = tid; e < 1024; e += 256) {
        int r = e >> 6, d = e & 63;
        int i = i0 + r;
        Qi[r][d] = Q[((long)b * 256 + h * 64 + (i >> 2)) * 256 + (i & 3) * 64 + d];
        Qj[r][d] = Q[((long)b * 256 + j0 + r) * 256 + h * 64 + d];
    }
    __syncthreads();
    int ti = tid >> 4, tj = tid & 15;
    float acc = 0.f;
    #pragma unroll
    for (int d = 0; d < 64; d++) acc += Qi[ti][d] * Qj[tj][d];
    A[((long)bh * 256 + (i0 + ti)) * 256 + (j0 + tj)] = acc;
}

__global__ void softmax_row_kernel(float* __restrict__ A) {
    __shared__ float red[256];
    long row = blockIdx.x;
    float* p = A + row * 256;
    int t = threadIdx.x;
    float v = p[t];
    red[t] = v; __syncthreads();
    for (int s = 128; s > 0; s >>= 1) { if (t < s) red[t] = fmaxf(red[t], red[t + s]); __syncthreads(); }
    float m = red[0]; __syncthreads();
    float e = expf(v - m);
    red[t] = e; __syncthreads();
    for (int s = 128; s > 0; s >>= 1) { if (t < s) red[t] += red[t + s]; __syncthreads(); }
    p[t] = e / red[0];
}

__global__ void colsm_xr_kernel(const float* __restrict__ attn, const float* __restrict__ V,
                                const float* __restrict__ xx, const float* __restrict__ pos,
                                float* __restrict__ xrb) {
    int b = blockIdx.x >> 8;
    int i = blockIdx.x & 255;
    int t = threadIdx.x;
    __shared__ float colv[4][256];
    __shared__ float4 r4[256];
    #pragma unroll
    for (int h = 0; h < 4; h++)
        colv[h][t] = attn[(((long)(b * 4 + h)) * 256 + t) * 256 + i];
    float4 vm = make_float4(colv[0][t], colv[1][t], colv[2][t], colv[3][t]);
    r4[t] = vm;
    __syncthreads();
    for (int s = 128; s > 0; s >>= 1) {
        if (t < s) {
            float4 o = r4[t + s];
            r4[t].x = fmaxf(r4[t].x, o.x); r4[t].y = fmaxf(r4[t].y, o.y);
            r4[t].z = fmaxf(r4[t].z, o.z); r4[t].w = fmaxf(r4[t].w, o.w);
        }
        __syncthreads();
    }
    float4 mx = r4[0];
    __syncthreads();
    float4 ev = make_float4(expf(vm.x - mx.x), expf(vm.y - mx.y),
                            expf(vm.z - mx.z), expf(vm.w - mx.w));
    r4[t] = ev;
    __syncthreads();
    for (int s = 128; s > 0; s >>= 1) {
        if (t < s) {
            float4 o = r4[t + s];
            r4[t].x += o.x; r4[t].y += o.y; r4[t].z += o.z; r4[t].w += o.w;
        }
        __syncthreads();
    }
    float4 sm = r4[0];
    __syncthreads();
    colv[0][t] = ev.x / sm.x;
    colv[1][t] = ev.y / sm.y;
    colv[2][t] = ev.z / sm.z;
    colv[3][t] = ev.w / sm.w;
    __syncthreads();
    int c = t; int h = c >> 6;
    const float* vp = V + ((long)b * 256) * 256 + c;
    float acc = 0.f;
    #pragma unroll 8
    for (int j = 0; j < 256; j++) acc += vp[(long)j * 256] * colv[h][j];
    long row = (long)b * 256 + i;
    xrb[row * 256 + c] = xx[row * 256 + c] + pos[row * 256 + c] - acc;
}

__global__ void addcat_bn_kernel(const float* __restrict__ qb, float* __restrict__ xx,
                                 const float* __restrict__ pos, float* __restrict__ cat,
                                 int layer) {
    int t = blockIdx.x * 256 + threadIdx.x;
    int c = t & 255; int row = t >> 8;
    float y = fmaxf((qb[t] - g_m1[c]) * g_i1[c], 0.f);
    float v = xx[t] + pos[t] + y;
    xx[t] = v;
    cat[(long)row * 1280 + layer * 256 + c] = v;
}

// ----------------------------------------------------------------------------
// Host orchestration
// ----------------------------------------------------------------------------
static void gemm_old(const float* A, const float* W, const float* bias, float* C,
                     int R, int D, int O) {
    dim3 grid(CEILDIV(O, 64), CEILDIV(R, 64));
    gemm_kernel<<<grid, 256>>>(A, W, bias, C, R, D, O);
}

static void gemm_big(const float* A, const float* W, const float* bias, float* C,
                     int R, int D, int O, int useStats) {
    dim3 grid(CEILDIV(O, 128), R / 128);
    gemm128_kernel<<<grid, 256>>>(A, W, bias, C, R, D, O, useStats);
}

static float* s_part;

// R9: no atomics, no zero/finalize — 2 launches, wide grid, float accumulation
static void computeStats(const float* X, int R, int C) {
    int rpb = R / 512;
    if (rpb < 8) rpb = 8;
    int nB = R / rpb;
    stats_part_kernel<<<nB, 256>>>(X, R, C, rpb, nB, s_part);
    reduce_m1_kernel<<<CEILDIV(C, 128), 128>>>(s_part, nB, C, R);
}

static void bn(float* X, int R, int C, int act) {
    computeStats(X, R, C);
    long total = (long)R * C;
    bn_apply_kernel<<<(int)CEILDIV(total, 256), 256>>>(X, total, C, act);
}

extern "C" void kernel_launch(void* const* d_in, const int* in_sizes, int n_in,
                              void* d_out, int out_size) {
    const float* x       = (const float*)d_in[0];
    const float* conv1_w = (const float*)d_in[1];
    const float* conv2_w = (const float*)d_in[2];
    const float* g0_w1   = (const float*)d_in[3];
    const float* g0_w2   = (const float*)d_in[4];
    const float* g0_wc   = (const float*)d_in[5];
    const float* g1_w1   = (const float*)d_in[6];
    const float* g1_w2   = (const float*)d_in[7];
    const float* g1_wc   = (const float*)d_in[8];
    const float* pt_w    = (const float*)d_in[9];
    const float* pos_w   = (const float*)d_in[10];
    const float* pos_b   = (const float*)d_in[11];
    const float* sa_wqk  = (const float*)d_in[12];
    const float* sa_wv   = (const float*)d_in[13];
    const float* sa_bv   = (const float*)d_in[14];
    const float* sa_wt   = (const float*)d_in[15];
    const float* sa_bt   = (const float*)d_in[16];
    const float* fuse_w  = (const float*)d_in[17];
    const float* lin1_w  = (const float*)d_in[18];
    const float* lin2_w  = (const float*)d_in[19];
    const float* lin2_b  = (const float*)d_in[20];
    const float* lin3_w  = (const float*)d_in[21];
    const float* lin3_b  = (const float*)d_in[22];
    float* out = (float*)d_out;

    float *xyz, *h1, *points, *newxyz, *newxyz2, *newpts, *Ub, *Vb, *w1a, *w1d, *pool, *f0, *f1;
    float *pos, *xx, *qb, *vb, *xrb, *attn, *catb, *fuseb, *gmax, *l1, *l2;
    int *fpsidx, *knn, *knn2;
    cudaGetSymbolAddress((void**)&xyz, g_xyz);
    cudaGetSymbolAddress((void**)&h1, g_h1);
    cudaGetSymbolAddress((void**)&points, g_points);
    cudaGetSymbolAddress((void**)&fpsidx, g_fpsidx);
    cudaGetSymbolAddress((void**)&newxyz, g_newxyz);
    cudaGetSymbolAddress((void**)&newxyz2, g_newxyz2);
    cudaGetSymbolAddress((void**)&newpts, g_newpts);
    cudaGetSymbolAddress((void**)&knn, g_knn);
    cudaGetSymbolAddress((void**)&knn2, g_knn2);
    cudaGetSymbolAddress((void**)&Ub, g_U);
    cudaGetSymbolAddress((void**)&Vb, g_V);
    cudaGetSymbolAddress((void**)&w1a, g_w1a);
    cudaGetSymbolAddress((void**)&w1d, g_w1d);
    cudaGetSymbolAddress((void**)&s_part, g_part);
    cudaGetSymbolAddress((void**)&pool, g_pool);
    cudaGetSymbolAddress((void**)&f0, g_f0);
    cudaGetSymbolAddress((void**)&f1, g_f1);
    cudaGetSymbolAddress((void**)&pos, g_pos);
    cudaGetSymbolAddress((void**)&xx, g_x);
    cudaGetSymbolAddress((void**)&qb, g_q);
    cudaGetSymbolAddress((void**)&vb, g_v);
    cudaGetSymbolAddress((void**)&xrb, g_xr);
    cudaGetSymbolAddress((void**)&attn, g_attn);
    cudaGetSymbolAddress((void**)&catb, g_cat);
    cudaGetSymbolAddress((void**)&fuseb, g_fuse);
    cudaGetSymbolAddress((void**)&gmax, g_gmax);
    cudaGetSymbolAddress((void**)&l1, g_l1);
    cudaGetSymbolAddress((void**)&l2, g_l2);

    // ---- Stage A ----
    transpose_x_kernel<<<CEILDIV(8*2048*3, 256), 256>>>(x, xyz);
    gemm_old(xyz, conv1_w, nullptr, h1, 16384, 3, 64);
    computeStats(h1, 16384, 64);
    gemm_big(h1, conv2_w, nullptr, points, 16384, 64, 64, 1);
    bn(points, 16384, 64, 0);

    // ---- Stage B: FPS(512) + gathers; kNN1 co-launched with FPS2; kNN2 separate buf ----
    fps_kernel<<<8, 1024>>>(xyz, 2048, 512, fpsidx);
    gather_kernel<<<CEILDIV(8*512*3, 256), 256>>>(xyz, fpsidx, newxyz, 512, 2048, 3, 8L*512*3);
    gather_kernel<<<CEILDIV(8*512*64, 256), 256>>>(points, fpsidx, newpts, 512, 2048, 64, 8L*512*64);
    knn_fps_kernel<<<4096 + 8, 256>>>(newxyz, xyz, 512, 2048, knn, 4096,
                                      newxyz, 512, 256, fpsidx);
    gather_kernel<<<CEILDIV(8*256*3, 256), 256>>>(newxyz, fpsidx, newxyz2, 256, 512, 3, 8L*256*3);
    knn_kernel<<<2048, 256>>>(newxyz2, newxyz, 256, 512, knn2);

    // ---- Stage C: local_op 0 via U/V ----
    {
        split_w1_kernel<<<CEILDIV(128*64, 256), 256>>>(g0_w1, w1a, w1d, 128, 64, 128*64);
        gemm_big(points, w1a, nullptr, Ub, 16384, 64, 128, 0);
        gemm_big(newpts, w1d, nullptr, Vb, 4096, 64, 128, 0);
        const int ks[3] = {16, 32, 64};
        const int kshift[3] = {4, 5, 6};
        for (int si = 0; si < 3; si++) {
            int k = ks[si];
            int R = 8 * 512 * k;
            zero_stats_kernel<<<1, 1024>>>();
            stats1_kernel<<<256, 128>>>(Ub, Vb, knn, 512, 2048, 128, k, 16);
            finalize1_kernel<<<1, 256>>>(128, R);
            int nBy = R / 128;
            dim3 grid(1, nBy);
            local_gemm2_kernel<<<grid, 256>>>(Ub, Vb, knn, g0_w2, pool,
                                              512, 2048, 128, 128, kshift[si], 384, si * 128);
            reduce_part_kernel<<<128, 256>>>(nBy, 128, R);
            pool_finalize_kernel<<<4096, 128>>>(pool, 384, si * 128);
        }
        gemm_big(pool, g0_wc, nullptr, f0, 4096, 384, 128, 0);
        bn(f0, 4096, 128, 0);
    }

    // ---- Stage D gather for stage E ----
    gather_kernel<<<CEILDIV(8*256*128, 256), 256>>>(f0, fpsidx, newpts, 256, 512, 128, 8L*256*128);

    // ---- Stage E: local_op 1 via U/V ----
    {
        split_w1_kernel<<<CEILDIV(256*128, 256), 256>>>(g1_w1, w1a, w1d, 256, 128, 256*128);
        gemm_big(f0, w1a, nullptr, Ub, 4096, 128, 256, 0);
        gemm_big(newpts, w1d, nullptr, Vb, 2048, 128, 256, 0);
        const int ks[3] = {16, 32, 64};
        const int kshift[3] = {4, 5, 6};
        for (int si = 0; si < 3; si++) {
            int k = ks[si];
            int R = 8 * 256 * k;
            zero_stats_kernel<<<1, 1024>>>();
            stats1_kernel<<<128, 256>>>(Ub, Vb, knn2, 256, 512, 256, k, 16);
            finalize1_kernel<<<1, 256>>>(256, R);
            int nBy = R / 128;
            dim3 grid(2, nBy);
            local_gemm2_kernel<<<grid, 256>>>(Ub, Vb, knn2, g1_w2, pool,
                                              256, 512, 256, 256, kshift[si], 768, si * 256);
            reduce_part_kernel<<<256, 256>>>(nBy, 256, R);
            pool_finalize_kernel<<<2048, 256>>>(pool, 768, si * 256);
        }
        gemm_big(pool, g1_wc, nullptr, f1, 2048, 768, 256, 0);
        bn(f1, 2048, 256, 0);
    }

    // ---- Stage F ----
    gemm_old(newxyz2, pos_w, pos_b, pos, 2048, 3, 256);
    gemm_big(f1, pt_w, nullptr, xx, 2048, 256, 256, 0);
    bn(xx, 2048, 256, 0);

    // ---- Stage G: 4 offset self-attention layers ----
    for (int i = 0; i < 4; i++) {
        gemmqv_kernel<<<dim3(4, 16), 256>>>(xx, pos,
                                            sa_wqk + (long)i * 256 * 256,
                                            sa_wv + (long)i * 256 * 256,
                                            sa_bv + i * 256, qb, vb);
        gram_kernel<<<dim3(16, 16, 32), 256>>>(qb, attn);
        softmax_row_kernel<<<8192, 256>>>(attn);
        colsm_xr_kernel<<<2048, 256>>>(attn, vb, xx, pos, xrb);
        gemm_big(xrb, sa_wt + (long)i * 256 * 256, sa_bt + i * 256, qb, 2048, 256, 256, 0);
        computeStats(qb, 2048, 256);
        addcat_bn_kernel<<<2048, 256>>>(qb, xx, pos, catb, i);
    }
    catf1_kernel<<<2048, 256>>>(f1, catb);

    // ---- Stage H ----
    gemm_big(catb, fuse_w, nullptr, fuseb, 2048, 1280, 1024, 0);
    bn(fuseb, 2048, 1024, 1);
    maxn_kernel<<<dim3(8, 4), 256>>>(fuseb, gmax);
    gemm_old(gmax, lin1_w, nullptr, l1, 8, 1024, 512);
    bn_small_kernel<<<2, 256>>>(l1, 512, 0.2f);
    gemm_old(l1, lin2_w, lin2_b, l2, 8, 512, 256);
    bn_small_kernel<<<1, 256>>>(l2, 256, 0.2f);
    gemm_old(l2, lin3_w, lin3_b, out, 8, 256, 40);
}

// round 12
// speedup vs baseline: 1.1093x; 1.0515x over previous
#include <cuda_runtime.h>
#include <math.h>
#include <float.h>

#define CEILDIV(a,b) (((a)+(b)-1)/(b))
#define BN_EPS 1e-5f
#define PART_OFF (2048*256)

// ----------------------------------------------------------------------------
// Scratch (device globals)
// ----------------------------------------------------------------------------
__device__ float g_xyz[8*2048*3];
__device__ float g_h1[8*2048*64];
__device__ float g_points[8*2048*64];
__device__ int   g_fpsidx[8*512];
__device__ float g_newxyz[8*512*3];
__device__ float g_newxyz2[8*256*3];
__device__ float g_newpts[8*512*64];        // stage2: 8*256*128
__device__ int   g_knn[8*512*64];           // stage-1 kNN lists
__device__ int   g_knn2[8*256*64];          // stage-2 kNN lists (separate buffers!)
__device__ float g_U[16384*128];            // stage E: 4096x256
__device__ float g_V[4096*128];             // stage E: 2048x256
__device__ float g_w1a[256*128];
__device__ float g_w1d[256*128];
__device__ float g_part[2*2048*256];        // per-block partial sums / sumsq
__device__ float g_pool[8*512*384];         // stage2: 8*256*768
__device__ float g_f0[8*512*128];
__device__ float g_f1[8*256*256];
__device__ float g_pos[8*256*256];
__device__ float g_x[8*256*256];
__device__ float g_q[8*256*256];
__device__ float g_v[8*256*256];
__device__ float g_xr[8*256*256];
__device__ float g_attn[8*4*256*256];
__device__ float g_cat[8*256*1280];
__device__ float g_fuse[8*256*1024];
__device__ float g_gmax[8*1024];
__device__ float g_l1[8*512];
__device__ float g_l2[8*256];
__device__ double g_sum[1024];
__device__ double g_sumsq[1024];
__device__ float g_m1[1024];
__device__ float g_i1[1024];
__device__ float g_m2[256];
__device__ float g_i2[256];

// ----------------------------------------------------------------------------
// BN stats plumbing
// ----------------------------------------------------------------------------
__global__ void zero_stats_kernel() {
    int t = threadIdx.x;
    g_sum[t] = 0.0; g_sumsq[t] = 0.0;
}

// wide-grid stats with float inner accumulation, NO atomics.
// part[blk*C + c] (sums), part[nB*C + blk*C + c] (sumsq).
__global__ void stats_part_kernel(const float* __restrict__ X, int R, int C, int rpb,
                                  int nB, float* __restrict__ part) {
    int blk = blockIdx.x;
    int r0 = blk * rpb;
    int r1 = r0 + rpb; if (r1 > R) r1 = R;
    int nch = (C + 255) / 256;
    float acc[4] = {0.f, 0.f, 0.f, 0.f};
    float accsq[4] = {0.f, 0.f, 0.f, 0.f};
    for (int r = r0; r < r1; r++) {
        const float* row = X + (long)r * C;
        #pragma unroll
        for (int k = 0; k < 4; k++) {
            if (k < nch) {
                int c = threadIdx.x + k * 256;
                if (c < C) { float v = row[c]; acc[k] += v; accsq[k] += v * v; }
            }
        }
    }
    #pragma unroll
    for (int k = 0; k < 4; k++) {
        if (k < nch) {
            int c = threadIdx.x + k * 256;
            if (c < C) {
                part[(long)blk * C + c] = acc[k];
                part[(long)nB * C + (long)blk * C + c] = accsq[k];
            }
        }
    }
}

// R11 FIX: block-per-channel parallel reduction of partials -> g_m1/g_i1.
// grid = C blocks, 256 threads; R10's version was grid<=2 and serialized (72us).
__global__ void reduce_m1_kernel(const float* __restrict__ part, int nB, int C, int statN) {
    int c = blockIdx.x;
    int t = threadIdx.x;
    float a = 0.f, b = 0.f;
    for (int r = t; r < nB; r += 256) {
        a += part[(long)r * C + c];
        b += part[(long)nB * C + (long)r * C + c];
    }
    __shared__ float sa[256], sb[256];
    sa[t] = a; sb[t] = b;
    __syncthreads();
    for (int s = 128; s > 0; s >>= 1) {
        if (t < s) { sa[t] += sa[t + s]; sb[t] += sb[t + s]; }
        __syncthreads();
    }
    if (t == 0) {
        double m = (double)sa[0] / statN;
        double var = (double)sb[0] / statN - m * m;
        if (var < 0.0) var = 0.0;
        g_m1[c] = (float)m;
        g_i1[c] = rsqrtf((float)var + BN_EPS);
    }
}

__global__ void finalize1_kernel(int C, int statN) {
    int c = blockIdx.x * 256 + threadIdx.x;
    if (c >= C) return;
    double m = g_sum[c] / statN;
    double var = g_sumsq[c] / statN - m * m;
    if (var < 0.0) var = 0.0;
    g_m1[c] = (float)m;
    g_i1[c] = rsqrtf((float)var + BN_EPS);
}

// act: 0 = relu, 1 = leaky(0.2)
__global__ void bn_apply_kernel(float* __restrict__ X, long total, int C, int act) {
    long t = (long)blockIdx.x * blockDim.x + threadIdx.x;
    if (t >= total) return;
    int c = (int)(t % C);
    float y = (X[t] - g_m1[c]) * g_i1[c];
    X[t] = (act == 0) ? fmaxf(y, 0.f) : (y >= 0.f ? y : 0.2f * y);
}

__global__ void bn_small_kernel(float* __restrict__ X, int C, float slope) {
    int c = blockIdx.x * blockDim.x + threadIdx.x;
    if (c >= C) return;
    double s = 0.0, ss = 0.0;
    for (int r = 0; r < 8; r++) { double v = X[r * C + c]; s += v; ss += v * v; }
    double m = s / 8.0;
    double var = ss / 8.0 - m * m;
    if (var < 0.0) var = 0.0;
    float inv = rsqrtf((float)var + BN_EPS);
    for (int r = 0; r < 8; r++) {
        float y = (X[r * C + c] - (float)m) * inv;
        X[r * C + c] = y >= 0.f ? y : slope * y;
    }
}

// reduce per-block partials -> g_m2/g_i2 (for BN2 of local op)
__global__ void reduce_part_kernel(int nBy, int O, int statN) {
    int c = blockIdx.x;
    int t = threadIdx.x;
    double a = 0.0, b = 0.0;
    for (int r = t; r < nBy; r += 256) {
        a += g_part[r * O + c];
        b += g_part[PART_OFF + r * O + c];
    }
    __shared__ double sa[256], sb[256];
    sa[t] = a; sb[t] = b;
    __syncthreads();
    for (int s = 128; s > 0; s >>= 1) {
        if (t < s) { sa[t] += sa[t + s]; sb[t] += sb[t + s]; }
        __syncthreads();
    }
    if (t == 0) {
        double m = sa[0] / statN;
        double var = sb[0] / statN - m * m;
        if (var < 0.0) var = 0.0;
        g_m2[c] = (float)m;
        g_i2[c] = rsqrtf((float)var + BN_EPS);
    }
}

// ----------------------------------------------------------------------------
// 128x128 tiled GEMM (optionally BN+relu on A via g_m1/g_i1; max BN'd D = 128)
// ----------------------------------------------------------------------------
__global__ void gemm128_kernel(const float* __restrict__ A, const float* __restrict__ W,
                               const float* __restrict__ bias, float* __restrict__ C,
                               int R, int D, int O, int useStats) {
    __shared__ float As[16][132];
    __shared__ float Ws[16][132];
    __shared__ float sM[256];
    __shared__ float sI[256];
    int tid = threadIdx.x;
    if (useStats) {
        for (int c = tid; c < D; c += 256) { sM[c] = g_m1[c]; sI[c] = g_i1[c]; }
        __syncthreads();
    }
    long rowBase = (long)blockIdx.y * 128;
    int colBase = blockIdx.x * 128;
    int tr = tid >> 4, tc = tid & 15;
    int lrow = tid >> 2;
    int lkq = tid & 3;
    float acc[8][8];
    #pragma unroll
    for (int i = 0; i < 8; i++)
        #pragma unroll
        for (int j = 0; j < 8; j++) acc[i][j] = 0.f;

    for (int k0 = 0; k0 < D; k0 += 16) {
        #pragma unroll
        for (int half = 0; half < 2; half++) {
            int row = lrow + 64 * half;
            int kc = k0 + lkq * 4;
            float4 av = *(const float4*)(A + (rowBase + row) * D + kc);
            if (useStats) {
                av.x = fmaxf((av.x - sM[kc + 0]) * sI[kc + 0], 0.f);
                av.y = fmaxf((av.y - sM[kc + 1]) * sI[kc + 1], 0.f);
                av.z = fmaxf((av.z - sM[kc + 2]) * sI[kc + 2], 0.f);
                av.w = fmaxf((av.w - sM[kc + 3]) * sI[kc + 3], 0.f);
            }
            As[lkq * 4 + 0][row] = av.x;
            As[lkq * 4 + 1][row] = av.y;
            As[lkq * 4 + 2][row] = av.z;
            As[lkq * 4 + 3][row] = av.w;
            int wr = colBase + row;
            float4 wv = make_float4(0.f, 0.f, 0.f, 0.f);
            if (wr < O) wv = *(const float4*)(W + (long)wr * D + kc);
            Ws[lkq * 4 + 0][row] = wv.x;
            Ws[lkq * 4 + 1][row] = wv.y;
            Ws[lkq * 4 + 2][row] = wv.z;
            Ws[lkq * 4 + 3][row] = wv.w;
        }
        __syncthreads();
        #pragma unroll
        for (int kk = 0; kk < 16; kk++) {
            float a[8], w[8];
            *(float4*)(a + 0) = *(const float4*)&As[kk][tr * 8 + 0];
            *(float4*)(a + 4) = *(const float4*)&As[kk][tr * 8 + 4];
            *(float4*)(w + 0) = *(const float4*)&Ws[kk][tc * 8 + 0];
            *(float4*)(w + 4) = *(const float4*)&Ws[kk][tc * 8 + 4];
            #pragma unroll
            for (int i = 0; i < 8; i++)
                #pragma unroll
                for (int j = 0; j < 8; j++)
                    acc[i][j] += a[i] * w[j];
        }
        __syncthreads();
    }
    #pragma unroll
    for (int i = 0; i < 8; i++) {
        long row = rowBase + tr * 8 + i;
        int col0 = colBase + tc * 8;
        if (col0 >= O) continue;
        float b0 = 0, b1 = 0, b2 = 0, b3 = 0, b4 = 0, b5 = 0, b6 = 0, b7 = 0;
        if (bias) {
            b0 = bias[col0 + 0]; b1 = bias[col0 + 1]; b2 = bias[col0 + 2]; b3 = bias[col0 + 3];
            b4 = bias[col0 + 4]; b5 = bias[col0 + 5]; b6 = bias[col0 + 6]; b7 = bias[col0 + 7];
        }
        float4 v0 = make_float4(acc[i][0] + b0, acc[i][1] + b1, acc[i][2] + b2, acc[i][3] + b3);
        float4 v1 = make_float4(acc[i][4] + b4, acc[i][5] + b5, acc[i][6] + b6, acc[i][7] + b7);
        *(float4*)(C + row * O + col0) = v0;
        *(float4*)(C + row * O + col0 + 4) = v1;
    }
}

// ----------------------------------------------------------------------------
// Fused local-op GEMM2 (A built on the fly, BN1 from g_m1/g_i1; epilogue:
// per-center raw max -> pool, per-block channel partials -> g_part)
// ----------------------------------------------------------------------------
__global__ void local_gemm2_kernel(const float* __restrict__ U, const float* __restrict__ V,
                                   const int* __restrict__ knn, const float* __restrict__ W,
                                   float* __restrict__ poolOut,
                                   int S, int N, int D, int O, int kshift,
                                   int OC, int off) {
    __shared__ float As[16][132];
    __shared__ float Ws[16][132];
    __shared__ float sRed[16][132];
    __shared__ float sM[256];
    __shared__ float sI[256];
    __shared__ int sP[128];
    __shared__ int sS[128];
    int tid = threadIdx.x;
    long rowBase = (long)blockIdx.y * 128;
    int colBase = blockIdx.x * 128;

    for (int c = tid; c < D; c += 256) { sM[c] = g_m1[c]; sI[c] = g_i1[c]; }
    if (tid < 128) {
        long grow = rowBase + tid;
        int s = (int)(grow >> kshift);
        int j = (int)(grow & ((1 << kshift) - 1));
        int b = s / S;
        sS[tid] = s;
        sP[tid] = b * N + knn[(long)s * 64 + j];
    }
    __syncthreads();

    int tr = tid >> 4, tc = tid & 15;
    int lrow = tid >> 2;
    int lkq = tid & 3;
    float acc[8][8];
    #pragma unroll
    for (int i = 0; i < 8; i++)
        #pragma unroll
        for (int j = 0; j < 8; j++) acc[i][j] = 0.f;

    for (int k0 = 0; k0 < D; k0 += 16) {
        #pragma unroll
        for (int half = 0; half < 2; half++) {
            int row = lrow + 64 * half;
            int kc = k0 + lkq * 4;
            float4 uv = *(const float4*)(U + (long)sP[row] * D + kc);
            float4 vv = *(const float4*)(V + (long)sS[row] * D + kc);
            As[lkq * 4 + 0][row] = fmaxf((uv.x + vv.x - sM[kc + 0]) * sI[kc + 0], 0.f);
            As[lkq * 4 + 1][row] = fmaxf((uv.y + vv.y - sM[kc + 1]) * sI[kc + 1], 0.f);
            As[lkq * 4 + 2][row] = fmaxf((uv.z + vv.z - sM[kc + 2]) * sI[kc + 2], 0.f);
            As[lkq * 4 + 3][row] = fmaxf((uv.w + vv.w - sM[kc + 3]) * sI[kc + 3], 0.f);
            float4 wv = *(const float4*)(W + (long)(colBase + row) * D + kc);
            Ws[lkq * 4 + 0][row] = wv.x;
            Ws[lkq * 4 + 1][row] = wv.y;
            Ws[lkq * 4 + 2][row] = wv.z;
            Ws[lkq * 4 + 3][row] = wv.w;
        }
        __syncthreads();
        #pragma unroll
        for (int kk = 0; kk < 16; kk++) {
            float a[8], w[8];
            *(float4*)(a + 0) = *(const float4*)&As[kk][tr * 8 + 0];
            *(float4*)(a + 4) = *(const float4*)&As[kk][tr * 8 + 4];
            *(float4*)(w + 0) = *(const float4*)&Ws[kk][tc * 8 + 0];
            *(float4*)(w + 4) = *(const float4*)&Ws[kk][tc * 8 + 4];
            #pragma unroll
            for (int i = 0; i < 8; i++)
                #pragma unroll
                for (int j = 0; j < 8; j++)
                    acc[i][j] += a[i] * w[j];
        }
        __syncthreads();
    }

    // epilogue 1: per-center raw max -> poolOut
    int g = (1 << kshift) >> 3;
    #pragma unroll
    for (int j = 0; j < 8; j++) {
        float m = acc[0][j];
        #pragma unroll
        for (int i = 1; i < 8; i++) m = fmaxf(m, acc[i][j]);
        sRed[tr][tc * 8 + j] = m;
    }
    __syncthreads();
    if ((tr & (g - 1)) == 0) {
        int s = sS[tr * 8];
        #pragma unroll
        for (int j = 0; j < 8; j++) {
            float m = sRed[tr][tc * 8 + j];
            for (int q = 1; q < g; q++) m = fmaxf(m, sRed[tr + q][tc * 8 + j]);
            poolOut[(long)s * OC + off + colBase + tc * 8 + j] = m;
        }
    }
    __syncthreads();
    // epilogue 2: per-block channel sums -> g_part
    #pragma unroll
    for (int j = 0; j < 8; j++) {
        float sm = 0.f;
        #pragma unroll
        for (int i = 0; i < 8; i++) sm += acc[i][j];
        sRed[tr][tc * 8 + j] = sm;
    }
    __syncthreads();
    if (tr == 0) {
        #pragma unroll
        for (int j = 0; j < 8; j++) {
            float tot = 0.f;
            for (int q = 0; q < 16; q++) tot += sRed[q][tc * 8 + j];
            g_part[(long)blockIdx.y * O + colBase + tc * 8 + j] = tot;
        }
    }
    __syncthreads();
    #pragma unroll
    for (int j = 0; j < 8; j++) {
        float sm = 0.f;
        #pragma unroll
        for (int i = 0; i < 8; i++) sm += acc[i][j] * acc[i][j];
        sRed[tr][tc * 8 + j] = sm;
    }
    __syncthreads();
    if (tr == 0) {
        #pragma unroll
        for (int j = 0; j < 8; j++) {
            float tot = 0.f;
            for (int q = 0; q < 16; q++) tot += sRed[q][tc * 8 + j];
            g_part[PART_OFF + (long)blockIdx.y * O + colBase + tc * 8 + j] = tot;
        }
    }
}

// BN1 stats over layer-1 values (U[idx]+V); cpb centers per block, C threads.
__global__ void stats1_kernel(const float* __restrict__ U, const float* __restrict__ V,
                              const int* __restrict__ knn, int S, int N, int C, int k, int cpb) {
    int c = threadIdx.x;
    int s0 = blockIdx.x * cpb;
    double acc = 0.0, accsq = 0.0;
    for (int ss = 0; ss < cpb; ss++) {
        int s = s0 + ss;
        int b = s / S;
        float v = V[(long)s * C + c];
        const int* kn = knn + (long)s * 64;
        for (int j = 0; j < k; j++) {
            float u = U[((long)b * N + kn[j]) * C + c];
            float x = u + v;
            acc += x;
            accsq += x * x;
        }
    }
    atomicAdd(&g_sum[c], acc);
    atomicAdd(&g_sumsq[c], accsq);
}

// pool[s, off+c] = relu(bn2(rawmax)) via g_m2/g_i2
__global__ void pool_finalize_kernel(float* __restrict__ pool, int OC, int off) {
    int s = blockIdx.x;
    int c = threadIdx.x;
    long p = (long)s * OC + off + c;
    pool[p] = fmaxf((pool[p] - g_m2[c]) * g_i2[c], 0.f);
}

__global__ void split_w1_kernel(const float* __restrict__ w1, float* __restrict__ wa,
                                float* __restrict__ wd, int O, int D, int total) {
    int t = blockIdx.x * 256 + threadIdx.x;
    if (t >= total) return;
    int d = t % D, o = t / D;
    float a = w1[(long)o * 2 * D + d];
    float b = w1[(long)o * 2 * D + D + d];
    wa[t] = a;
    wd[t] = b - a;
}

// ----------------------------------------------------------------------------
// Generic fallback GEMM (odd shapes)
// ----------------------------------------------------------------------------
__global__ void gemm_kernel(const float* __restrict__ A, const float* __restrict__ W,
                            const float* __restrict__ bias, float* __restrict__ C,
                            int R, int D, int O) {
    __shared__ float As[64][17];
    __shared__ float Ws[64][17];
    int tid = threadIdx.x;
    int tr = tid >> 4, tc = tid & 15;
    long rowBase = (long)blockIdx.y * 64;
    int colBase = blockIdx.x * 64;
    float acc[4][4] = {};
    for (int k0 = 0; k0 < D; k0 += 16) {
        #pragma unroll
        for (int e = tid; e < 1024; e += 256) {
            int rr = e >> 4, kk = e & 15;
            long ar = rowBase + rr; int ac = k0 + kk;
            As[rr][kk] = (ar < R && ac < D) ? A[ar * D + ac] : 0.f;
            int wr = colBase + rr;
            Ws[rr][kk] = (wr < O && ac < D) ? W[(long)wr * D + ac] : 0.f;
        }
        __syncthreads();
        #pragma unroll
        for (int kk = 0; kk < 16; kk++) {
            float a[4], w[4];
            #pragma unroll
            for (int i = 0; i < 4; i++) a[i] = As[tr + 16*i][kk];
            #pragma unroll
            for (int j = 0; j < 4; j++) w[j] = Ws[tc + 16*j][kk];
            #pragma unroll
            for (int i = 0; i < 4; i++)
                #pragma unroll
                for (int j = 0; j < 4; j++)
                    acc[i][j] += a[i] * w[j];
        }
        __syncthreads();
    }
    #pragma unroll
    for (int i = 0; i < 4; i++) {
        long row = rowBase + tr + 16*i;
        if (row >= R) continue;
        #pragma unroll
        for (int j = 0; j < 4; j++) {
            int col = colBase + tc + 16*j;
            if (col >= O) continue;
            float vv = acc[i][j];
            if (bias) vv += bias[col];
            C[row * O + col] = vv;
        }
    }
}

// ----------------------------------------------------------------------------
// Layout / elementwise helpers
// ----------------------------------------------------------------------------
__global__ void transpose_x_kernel(const float* __restrict__ x, float* __restrict__ xyz) {
    int t = blockIdx.x * 256 + threadIdx.x;
    if (t >= 8 * 2048 * 3) return;
    int c = t % 3; int n = (t / 3) % 2048; int b = t / (3 * 2048);
    xyz[t] = x[((long)b * 3 + c) * 2048 + n];
}

__global__ void gather_kernel(const float* __restrict__ src, const int* __restrict__ idx,
                              float* __restrict__ dst, int S, int N, int D, long total) {
    long t = (long)blockIdx.x * blockDim.x + threadIdx.x;
    if (t >= total) return;
    int c = (int)(t % D); long bs = t / D;
    int b = (int)(bs / S);
    dst[t] = src[((long)b * N + idx[bs]) * D + c];
}

__global__ void catf1_kernel(const float* __restrict__ f1, float* __restrict__ cat) {
    int t = blockIdx.x * 256 + threadIdx.x;
    int c = t & 255; int row = t >> 8;
    cat[(long)row * 1280 + 1024 + c] = f1[t];
}

__global__ void maxn_kernel(const float* __restrict__ X, float* __restrict__ G) {
    int b = blockIdx.x; int c = blockIdx.y * 256 + threadIdx.x;
    float m = -FLT_MAX;
    for (int n = 0; n < 256; n++) m = fmaxf(m, X[((long)b * 256 + n) * 1024 + c]);
    G[b * 1024 + c] = m;
}

// ----------------------------------------------------------------------------
// FPS / kNN with warp-shuffle reductions (tie order preserved)
// ----------------------------------------------------------------------------
__device__ __forceinline__ unsigned keymap(float f) {
    unsigned u = __float_as_uint(f);
    return (u & 0x80000000u) ? ~u : (u | 0x80000000u);
}

__device__ void fps_body(const float* __restrict__ xyz, int N, int npoint,
                         int* __restrict__ outIdx, int b,
                         float* sx, float* sy, float* sz, float* sd,
                         unsigned long long* warpBest, int* sFar) {
    int t = threadIdx.x;
    int nt = blockDim.x;
    int numWarps = nt >> 5;
    for (int n = t; n < N; n += nt) {
        sx[n] = xyz[((long)b * N + n) * 3 + 0];
        sy[n] = xyz[((long)b * N + n) * 3 + 1];
        sz[n] = xyz[((long)b * N + n) * 3 + 2];
        sd[n] = 1e10f;
    }
    __syncthreads();
    int far = 0;
    for (int it = 0; it < npoint; it++) {
        if (t == 0) outIdx[b * npoint + it] = far;
        float cx = sx[far], cy = sy[far], cz = sz[far];
        unsigned long long best = 0ull;
        for (int n = t; n < N; n += nt) {
            float dx = sx[n] - cx, dy = sy[n] - cy, dz = sz[n] - cz;
            float d = dx * dx + dy * dy + dz * dz;
            float dm = fminf(sd[n], d);
            sd[n] = dm;
            unsigned long long key = ((unsigned long long)keymap(dm) << 32) | (unsigned)(~n);
            if (key > best) best = key;
        }
        #pragma unroll
        for (int o = 16; o > 0; o >>= 1) {
            unsigned long long other = __shfl_xor_sync(0xffffffffu, best, o);
            if (other > best) best = other;
        }
        if ((t & 31) == 0) warpBest[t >> 5] = best;
        __syncthreads();
        if (t < 32) {
            unsigned long long v = (t < numWarps) ? warpBest[t] : 0ull;
            #pragma unroll
            for (int o = 16; o > 0; o >>= 1) {
                unsigned long long other = __shfl_xor_sync(0xffffffffu, v, o);
                if (other > v) v = other;
            }
            if (t == 0) *sFar = (int)(~((unsigned)(v & 0xffffffffu)));
        }
        __syncthreads();
        far = *sFar;
    }
}

__device__ void knn_body(const float* __restrict__ centers, const float* __restrict__ xyz,
                         int S, int N, int* __restrict__ knnOut, int bs,
                         float* sd, unsigned long long* warpBest) {
    int t = threadIdx.x;
    int nt = blockDim.x;
    int numWarps = nt >> 5;
    int b = bs / S;
    float cx = centers[(long)bs * 3 + 0];
    float cy = centers[(long)bs * 3 + 1];
    float cz = centers[(long)bs * 3 + 2];
    float cn = cx * cx + cy * cy + cz * cz;
    for (int n = t; n < N; n += nt) {
        float px = xyz[((long)b * N + n) * 3 + 0];
        float py = xyz[((long)b * N + n) * 3 + 1];
        float pz = xyz[((long)b * N + n) * 3 + 2];
        float pn = px * px + py * py + pz * pz;
        float dot = cx * px + cy * py + cz * pz;
        sd[n] = cn + pn - 2.f * dot;
    }
    __syncthreads();
    for (int j = 0; j < 64; j++) {
        unsigned long long best = 0xFFFFFFFFFFFFFFFFull;
        for (int n = t; n < N; n += nt) {
            unsigned long long key = ((unsigned long long)keymap(sd[n]) << 32) | (unsigned)n;
            if (key < best) best = key;
        }
        #pragma unroll
        for (int o = 16; o > 0; o >>= 1) {
            unsigned long long other = __shfl_xor_sync(0xffffffffu, best, o);
            if (other < best) best = other;
        }
        if ((t & 31) == 0) warpBest[t >> 5] = best;
        __syncthreads();
        if (t < 32) {
            unsigned long long v = (t < numWarps) ? warpBest[t] : 0xFFFFFFFFFFFFFFFFull;
            #pragma unroll
            for (int o = 16; o > 0; o >>= 1) {
                unsigned long long other = __shfl_xor_sync(0xffffffffu, v, o);
                if (other < v) v = other;
            }
            if (t == 0) {
                int sel = (int)(v & 0xffffffffu);
                knnOut[(long)bs * 64 + j] = sel;
                sd[sel] = FLT_MAX;
            }
        }
        __syncthreads();
    }
}

__global__ void fps_kernel(const float* xyz, int N, int npoint, int* outIdx) {
    __shared__ float buf[4 * 2048];
    __shared__ unsigned long long wb[32];
    __shared__ int sFar;
    fps_body(xyz, N, npoint, outIdx, blockIdx.x, buf, buf + N, buf + 2 * N, buf + 3 * N, wb, &sFar);
}

__global__ void knn_kernel(const float* centers, const float* xyz, int S, int N, int* knnOut) {
    __shared__ float buf[2048];
    __shared__ unsigned long long wb[32];
    knn_body(centers, xyz, S, N, knnOut, blockIdx.x, buf, wb);
}

__global__ void knn_fps_kernel(const float* centers, const float* xyz, int S, int N,
                               int* knnOut, int nKnn,
                               const float* xyz2, int N2, int np2, int* outIdx2) {
    __shared__ float buf[4 * 2048];
    __shared__ unsigned long long wb[32];
    __shared__ int sFar;
    if (blockIdx.x < nKnn) {
        knn_body(centers, xyz, S, N, knnOut, blockIdx.x, buf, wb);
    } else {
        int b = blockIdx.x - nKnn;
        fps_body(xyz2, N2, np2, outIdx2, b, buf, buf + N2, buf + 2 * N2, buf + 3 * N2, wb, &sFar);
    }
}

// ----------------------------------------------------------------------------
// Attention (reference reshape quirk preserved)
// ----------------------------------------------------------------------------
__global__ void gemmqv_kernel(const float* __restrict__ xx, const float* __restrict__ pos,
                              const float* __restrict__ wqk, const float* __restrict__ wv,
                              const float* __restrict__ bv,
                              float* __restrict__ qb, float* __restrict__ vb) {
    __shared__ float As[16][132];
    __shared__ float Ws[16][132];
    int tid = threadIdx.x;
    long rowBase = (long)blockIdx.y * 128;
    int colBase = blockIdx.x * 128;
    int tr = tid >> 4, tc = tid & 15;
    int lrow = tid >> 2;
    int lkq = tid & 3;
    const int D = 256;
    float acc[8][8];
    #pragma unroll
    for (int i = 0; i < 8; i++)
        #pragma unroll
        for (int j = 0; j < 8; j++) acc[i][j] = 0.f;

    for (int k0 = 0; k0 < D; k0 += 16) {
        #pragma unroll
        for (int half = 0; half < 2; half++) {
            int row = lrow + 64 * half;
            int kc = k0 + lkq * 4;
            float4 av = *(const float4*)(xx + (rowBase + row) * D + kc);
            float4 pv = *(const float4*)(pos + (rowBase + row) * D + kc);
            As[lkq * 4 + 0][row] = av.x + pv.x;
            As[lkq * 4 + 1][row] = av.y + pv.y;
            As[lkq * 4 + 2][row] = av.z + pv.z;
            As[lkq * 4 + 3][row] = av.w + pv.w;
            int ocol = colBase + row;
            const float* Wp = (ocol < 256) ? (wqk + (long)ocol * D) : (wv + (long)(ocol - 256) * D);
            float4 wvv = *(const float4*)(Wp + kc);
            Ws[lkq * 4 + 0][row] = wvv.x;
            Ws[lkq * 4 + 1][row] = wvv.y;
            Ws[lkq * 4 + 2][row] = wvv.z;
            Ws[lkq * 4 + 3][row] = wvv.w;
        }
        __syncthreads();
        #pragma unroll
        for (int kk = 0; kk < 16; kk++) {
            float a[8], w[8];
            *(float4*)(a + 0) = *(const float4*)&As[kk][tr * 8 + 0];
            *(float4*)(a + 4) = *(const float4*)&As[kk][tr * 8 + 4];
            *(float4*)(w + 0) = *(const float4*)&Ws[kk][tc * 8 + 0];
            *(float4*)(w + 4) = *(const float4*)&Ws[kk][tc * 8 + 4];
            #pragma unroll
            for (int i = 0; i < 8; i++)
                #pragma unroll
                for (int j = 0; j < 8; j++)
                    acc[i][j] += a[i] * w[j];
        }
        __syncthreads();
    }
    int col0 = colBase + tc * 8;
    #pragma unroll
    for (int i = 0; i < 8; i++) {
        long row = rowBase + tr * 8 + i;
        if (col0 < 256) {
            float4 v0 = make_float4(acc[i][0], acc[i][1], acc[i][2], acc[i][3]);
            float4 v1 = make_float4(acc[i][4], acc[i][5], acc[i][6], acc[i][7]);
            *(float4*)(qb + row * 256 + col0) = v0;
            *(float4*)(qb + row * 256 + col0 + 4) = v1;
        } else {
            int cc = col0 - 256;
            float4 v0 = make_float4(acc[i][0] + bv[cc + 0], acc[i][1] + bv[cc + 1],
                                    acc[i][2] + bv[cc + 2], acc[i][3] + bv[cc + 3]);
            float4 v1 = make_float4(acc[i][4] + bv[cc + 4], acc[i][5] + bv[cc + 5],
                                    acc[i][6] + bv[cc + 6], acc[i][7] + bv[cc + 7]);
            *(float4*)(vb + row * 256 + cc) = v0;
            *(float4*)(vb + row * 256 + cc + 4) = v1;
        }
    }
}

__global__ void gram_kernel(const float* __restrict__ Q, float* __restrict__ A) {
    int bh = blockIdx.z; int b = bh >> 2; int h = bh & 3;
    int i0 = blockIdx.y * 16, j0 = blockIdx.x * 16;
    __shared__ float Qi[16][65];
    __shared__ float Qj[16][65];
    int tid = threadIdx.x;
    for (int e = tid; e < 1024; e += 256) {
        int r = e >> 6, d = e & 63;
        int i = i0 + r;
        Qi[r][d] = Q[((long)b * 256 + h * 64 + (i >> 2)) * 256 + (i & 3) * 64 + d];
        Qj[r][d] = Q[((long)b * 256 + j0 + r) * 256 + h * 64 + d];
    }
    __syncthreads();
    int ti = tid >> 4, tj = tid & 15;
    float acc = 0.f;
    #pragma unroll
    for (int d = 0; d < 64; d++) acc += Qi[ti][d] * Qj[tj][d];
    A[((long)bh * 256 + (i0 + ti)) * 256 + (j0 + tj)] = acc;
}

__global__ void softmax_row_kernel(float* __restrict__ A) {
    __shared__ float red[256];
    long row = blockIdx.x;
    float* p = A + row * 256;
    int t = threadIdx.x;
    float v = p[t];
    red[t] = v; __syncthreads();
    for (int s = 128; s > 0; s >>= 1) { if (t < s) red[t] = fmaxf(red[t], red[t + s]); __syncthreads(); }
    float m = red[0]; __syncthreads();
    float e = expf(v - m);
    red[t] = e; __syncthreads();
    for (int s = 128; s > 0; s >>= 1) { if (t < s) red[t] += red[t + s]; __syncthreads(); }
    p[t] = e / red[0];
}

__global__ void colsm_xr_kernel(const float* __restrict__ attn, const float* __restrict__ V,
                                const float* __restrict__ xx, const float* __restrict__ pos,
                                float* __restrict__ xrb) {
    int b = blockIdx.x >> 8;
    int i = blockIdx.x & 255;
    int t = threadIdx.x;
    __shared__ float colv[4][256];
    __shared__ float4 r4[256];
    #pragma unroll
    for (int h = 0; h < 4; h++)
        colv[h][t] = attn[(((long)(b * 4 + h)) * 256 + t) * 256 + i];
    float4 vm = make_float4(colv[0][t], colv[1][t], colv[2][t], colv[3][t]);
    r4[t] = vm;
    __syncthreads();
    for (int s = 128; s > 0; s >>= 1) {
        if (t < s) {
            float4 o = r4[t + s];
            r4[t].x = fmaxf(r4[t].x, o.x); r4[t].y = fmaxf(r4[t].y, o.y);
            r4[t].z = fmaxf(r4[t].z, o.z); r4[t].w = fmaxf(r4[t].w, o.w);
        }
        __syncthreads();
    }
    float4 mx = r4[0];
    __syncthreads();
    float4 ev = make_float4(expf(vm.x - mx.x), expf(vm.y - mx.y),
                            expf(vm.z - mx.z), expf(vm.w - mx.w));
    r4[t] = ev;
    __syncthreads();
    for (int s = 128; s > 0; s >>= 1) {
        if (t < s) {
            float4 o = r4[t + s];
            r4[t].x += o.x; r4[t].y += o.y; r4[t].z += o.z; r4[t].w += o.w;
        }
        __syncthreads();
    }
    float4 sm = r4[0];
    __syncthreads();
    colv[0][t] = ev.x / sm.x;
    colv[1][t] = ev.y / sm.y;
    colv[2][t] = ev.z / sm.z;
    colv[3][t] = ev.w / sm.w;
    __syncthreads();
    int c = t; int h = c >> 6;
    const float* vp = V + ((long)b * 256) * 256 + c;
    float acc = 0.f;
    #pragma unroll 8
    for (int j = 0; j < 256; j++) acc += vp[(long)j * 256] * colv[h][j];
    long row = (long)b * 256 + i;
    xrb[row * 256 + c] = xx[row * 256 + c] + pos[row * 256 + c] - acc;
}

__global__ void addcat_bn_kernel(const float* __restrict__ qb, float* __restrict__ xx,
                                 const float* __restrict__ pos, float* __restrict__ cat,
                                 int layer) {
    int t = blockIdx.x * 256 + threadIdx.x;
    int c = t & 255; int row = t >> 8;
    float y = fmaxf((qb[t] - g_m1[c]) * g_i1[c], 0.f);
    float v = xx[t] + pos[t] + y;
    xx[t] = v;
    cat[(long)row * 1280 + layer * 256 + c] = v;
}

// ----------------------------------------------------------------------------
// Host orchestration
// ----------------------------------------------------------------------------
static void gemm_old(const float* A, const float* W, const float* bias, float* C,
                     int R, int D, int O) {
    dim3 grid(CEILDIV(O, 64), CEILDIV(R, 64));
    gemm_kernel<<<grid, 256>>>(A, W, bias, C, R, D, O);
}

static void gemm_big(const float* A, const float* W, const float* bias, float* C,
                     int R, int D, int O, int useStats) {
    dim3 grid(CEILDIV(O, 128), R / 128);
    gemm128_kernel<<<grid, 256>>>(A, W, bias, C, R, D, O, useStats);
}

static float* s_part;

// R11: wide stats_part + block-per-channel parallel reduce
static void computeStats(const float* X, int R, int C) {
    int rpb = R / 512;
    if (rpb < 8) rpb = 8;
    int nB = R / rpb;
    stats_part_kernel<<<nB, 256>>>(X, R, C, rpb, nB, s_part);
    reduce_m1_kernel<<<C, 256>>>(s_part, nB, C, R);
}

static void bn(float* X, int R, int C, int act) {
    computeStats(X, R, C);
    long total = (long)R * C;
    bn_apply_kernel<<<(int)CEILDIV(total, 256), 256>>>(X, total, C, act);
}

extern "C" void kernel_launch(void* const* d_in, const int* in_sizes, int n_in,
                              void* d_out, int out_size) {
    const float* x       = (const float*)d_in[0];
    const float* conv1_w = (const float*)d_in[1];
    const float* conv2_w = (const float*)d_in[2];
    const float* g0_w1   = (const float*)d_in[3];
    const float* g0_w2   = (const float*)d_in[4];
    const float* g0_wc   = (const float*)d_in[5];
    const float* g1_w1   = (const float*)d_in[6];
    const float* g1_w2   = (const float*)d_in[7];
    const float* g1_wc   = (const float*)d_in[8];
    const float* pt_w    = (const float*)d_in[9];
    const float* pos_w   = (const float*)d_in[10];
    const float* pos_b   = (const float*)d_in[11];
    const float* sa_wqk  = (const float*)d_in[12];
    const float* sa_wv   = (const float*)d_in[13];
    const float* sa_bv   = (const float*)d_in[14];
    const float* sa_wt   = (const float*)d_in[15];
    const float* sa_bt   = (const float*)d_in[16];
    const float* fuse_w  = (const float*)d_in[17];
    const float* lin1_w  = (const float*)d_in[18];
    const float* lin2_w  = (const float*)d_in[19];
    const float* lin2_b  = (const float*)d_in[20];
    const float* lin3_w  = (const float*)d_in[21];
    const float* lin3_b  = (const float*)d_in[22];
    float* out = (float*)d_out;

    float *xyz, *h1, *points, *newxyz, *newxyz2, *newpts, *Ub, *Vb, *w1a, *w1d, *pool, *f0, *f1;
    float *pos, *xx, *qb, *vb, *xrb, *attn, *catb, *fuseb, *gmax, *l1, *l2;
    int *fpsidx, *knn, *knn2;
    cudaGetSymbolAddress((void**)&xyz, g_xyz);
    cudaGetSymbolAddress((void**)&h1, g_h1);
    cudaGetSymbolAddress((void**)&points, g_points);
    cudaGetSymbolAddress((void**)&fpsidx, g_fpsidx);
    cudaGetSymbolAddress((void**)&newxyz, g_newxyz);
    cudaGetSymbolAddress((void**)&newxyz2, g_newxyz2);
    cudaGetSymbolAddress((void**)&newpts, g_newpts);
    cudaGetSymbolAddress((void**)&knn, g_knn);
    cudaGetSymbolAddress((void**)&knn2, g_knn2);
    cudaGetSymbolAddress((void**)&Ub, g_U);
    cudaGetSymbolAddress((void**)&Vb, g_V);
    cudaGetSymbolAddress((void**)&w1a, g_w1a);
    cudaGetSymbolAddress((void**)&w1d, g_w1d);
    cudaGetSymbolAddress((void**)&s_part, g_part);
    cudaGetSymbolAddress((void**)&pool, g_pool);
    cudaGetSymbolAddress((void**)&f0, g_f0);
    cudaGetSymbolAddress((void**)&f1, g_f1);
    cudaGetSymbolAddress((void**)&pos, g_pos);
    cudaGetSymbolAddress((void**)&xx, g_x);
    cudaGetSymbolAddress((void**)&qb, g_q);
    cudaGetSymbolAddress((void**)&vb, g_v);
    cudaGetSymbolAddress((void**)&xrb, g_xr);
    cudaGetSymbolAddress((void**)&attn, g_attn);
    cudaGetSymbolAddress((void**)&catb, g_cat);
    cudaGetSymbolAddress((void**)&fuseb, g_fuse);
    cudaGetSymbolAddress((void**)&gmax, g_gmax);
    cudaGetSymbolAddress((void**)&l1, g_l1);
    cudaGetSymbolAddress((void**)&l2, g_l2);

    // ---- Stage A ----
    transpose_x_kernel<<<CEILDIV(8*2048*3, 256), 256>>>(x, xyz);
    gemm_old(xyz, conv1_w, nullptr, h1, 16384, 3, 64);
    computeStats(h1, 16384, 64);
    gemm_big(h1, conv2_w, nullptr, points, 16384, 64, 64, 1);
    bn(points, 16384, 64, 0);

    // ---- Stage B: FPS(512) + gathers; kNN1 co-launched with FPS2; kNN2 separate buf ----
    fps_kernel<<<8, 1024>>>(xyz, 2048, 512, fpsidx);
    gather_kernel<<<CEILDIV(8*512*3, 256), 256>>>(xyz, fpsidx, newxyz, 512, 2048, 3, 8L*512*3);
    gather_kernel<<<CEILDIV(8*512*64, 256), 256>>>(points, fpsidx, newpts, 512, 2048, 64, 8L*512*64);
    knn_fps_kernel<<<4096 + 8, 256>>>(newxyz, xyz, 512, 2048, knn, 4096,
                                      newxyz, 512, 256, fpsidx);
    gather_kernel<<<CEILDIV(8*256*3, 256), 256>>>(newxyz, fpsidx, newxyz2, 256, 512, 3, 8L*256*3);
    knn_kernel<<<2048, 256>>>(newxyz2, newxyz, 256, 512, knn2);

    // ---- Stage C: local_op 0 via U/V ----
    {
        split_w1_kernel<<<CEILDIV(128*64, 256), 256>>>(g0_w1, w1a, w1d, 128, 64, 128*64);
        gemm_big(points, w1a, nullptr, Ub, 16384, 64, 128, 0);
        gemm_big(newpts, w1d, nullptr, Vb, 4096, 64, 128, 0);
        const int ks[3] = {16, 32, 64};
        const int kshift[3] = {4, 5, 6};
        for (int si = 0; si < 3; si++) {
            int k = ks[si];
            int R = 8 * 512 * k;
            zero_stats_kernel<<<1, 1024>>>();
            stats1_kernel<<<256, 128>>>(Ub, Vb, knn, 512, 2048, 128, k, 16);
            finalize1_kernel<<<1, 256>>>(128, R);
            int nBy = R / 128;
            dim3 grid(1, nBy);
            local_gemm2_kernel<<<grid, 256>>>(Ub, Vb, knn, g0_w2, pool,
                                              512, 2048, 128, 128, kshift[si], 384, si * 128);
            reduce_part_kernel<<<128, 256>>>(nBy, 128, R);
            pool_finalize_kernel<<<4096, 128>>>(pool, 384, si * 128);
        }
        gemm_big(pool, g0_wc, nullptr, f0, 4096, 384, 128, 0);
        bn(f0, 4096, 128, 0);
    }

    // ---- Stage D gather for stage E ----
    gather_kernel<<<CEILDIV(8*256*128, 256), 256>>>(f0, fpsidx, newpts, 256, 512, 128, 8L*256*128);

    // ---- Stage E: local_op 1 via U/V ----
    {
        split_w1_kernel<<<CEILDIV(256*128, 256), 256>>>(g1_w1, w1a, w1d, 256, 128, 256*128);
        gemm_big(f0, w1a, nullptr, Ub, 4096, 128, 256, 0);
        gemm_big(newpts, w1d, nullptr, Vb, 2048, 128, 256, 0);
        const int ks[3] = {16, 32, 64};
        const int kshift[3] = {4, 5, 6};
        for (int si = 0; si < 3; si++) {
            int k = ks[si];
            int R = 8 * 256 * k;
            zero_stats_kernel<<<1, 1024>>>();
            stats1_kernel<<<128, 256>>>(Ub, Vb, knn2, 256, 512, 256, k, 16);
            finalize1_kernel<<<1, 256>>>(256, R);
            int nBy = R / 128;
            dim3 grid(2, nBy);
            local_gemm2_kernel<<<grid, 256>>>(Ub, Vb, knn2, g1_w2, pool,
                                              256, 512, 256, 256, kshift[si], 768, si * 256);
            reduce_part_kernel<<<256, 256>>>(nBy, 256, R);
            pool_finalize_kernel<<<2048, 256>>>(pool, 768, si * 256);
        }
        gemm_big(pool, g1_wc, nullptr, f1, 2048, 768, 256, 0);
        bn(f1, 2048, 256, 0);
    }

    // ---- Stage F ----
    gemm_old(newxyz2, pos_w, pos_b, pos, 2048, 3, 256);
    gemm_big(f1, pt_w, nullptr, xx, 2048, 256, 256, 0);
    bn(xx, 2048, 256, 0);

    // ---- Stage G: 4 offset self-attention layers ----
    for (int i = 0; i < 4; i++) {
        gemmqv_kernel<<<dim3(4, 16), 256>>>(xx, pos,
                                            sa_wqk + (long)i * 256 * 256,
                                            sa_wv + (long)i * 256 * 256,
                                            sa_bv + i * 256, qb, vb);
        gram_kernel<<<dim3(16, 16, 32), 256>>>(qb, attn);
        softmax_row_kernel<<<8192, 256>>>(attn);
        colsm_xr_kernel<<<2048, 256>>>(attn, vb, xx, pos, xrb);
        gemm_big(xrb, sa_wt + (long)i * 256 * 256, sa_bt + i * 256, qb, 2048, 256, 256, 0);
        computeStats(qb, 2048, 256);
        addcat_bn_kernel<<<2048, 256>>>(qb, xx, pos, catb, i);
    }
    catf1_kernel<<<2048, 256>>>(f1, catb);

    // ---- Stage H ----
    gemm_big(catb, fuse_w, nullptr, fuseb, 2048, 1280, 1024, 0);
    bn(fuseb, 2048, 1024, 1);
    maxn_kernel<<<dim3(8, 4), 256>>>(fuseb, gmax);
    gemm_old(gmax, lin1_w, nullptr, l1, 8, 1024, 512);
    bn_small_kernel<<<2, 256>>>(l1, 512, 0.2f);
    gemm_old(l1, lin2_w, lin2_b, l2, 8, 512, 256);
    bn_small_kernel<<<1, 256>>>(l2, 256, 0.2f);
    gemm_old(l2, lin3_w, lin3_b, out, 8, 256, 40);
}

// round 13
// speedup vs baseline: 1.1146x; 1.0048x over previous
#include <cuda_runtime.h>
#include <math.h>
#include <float.h>

#define CEILDIV(a,b) (((a)+(b)-1)/(b))
#define BN_EPS 1e-5f
#define PART_OFF (2048*256)

// ----------------------------------------------------------------------------
// Scratch (device globals)
// ----------------------------------------------------------------------------
__device__ float g_xyz[8*2048*3];
__device__ float g_h1[8*2048*64];
__device__ float g_points[8*2048*64];
__device__ int   g_fpsidx[8*512];
__device__ float g_newxyz[8*512*3];
__device__ float g_newxyz2[8*256*3];
__device__ float g_newpts[8*512*64];        // stage2: 8*256*128
__device__ int   g_knn[8*512*64];           // stage-1 kNN lists
__device__ int   g_knn2[8*256*64];          // stage-2 kNN lists (separate buffers!)
__device__ float g_U[16384*128];            // stage E: 4096x256
__device__ float g_V[4096*128];             // stage E: 2048x256
__device__ float g_w1a[256*128];
__device__ float g_w1d[256*128];
__device__ float g_part[2*2048*256];        // per-block partial sums / sumsq
__device__ float g_pool[8*512*384];         // stage2: 8*256*768
__device__ float g_f0[8*512*128];
__device__ float g_f1[8*256*256];
__device__ float g_pos[8*256*256];
__device__ float g_x[8*256*256];
__device__ float g_q[8*256*256];
__device__ float g_v[8*256*256];
__device__ float g_xr[8*256*256];
__device__ float g_attn[8*4*256*256];
__device__ float g_cat[8*256*1280];
__device__ float g_fuse[8*256*1024];
__device__ float g_gmax[8*1024];
__device__ float g_l1[8*512];
__device__ float g_l2[8*256];
__device__ float g_m1[1024];
__device__ float g_i1[1024];
__device__ float g_m2[256];
__device__ float g_i2[256];
__device__ float g_s1m[3*256];
__device__ float g_s1i[3*256];

// ----------------------------------------------------------------------------
// BN stats plumbing (R12-record versions)
// ----------------------------------------------------------------------------
// wide-grid stats with float inner accumulation, NO atomics.
__global__ void stats_part_kernel(const float* __restrict__ X, int R, int C, int rpb,
                                  int nB, float* __restrict__ part) {
    int blk = blockIdx.x;
    int r0 = blk * rpb;
    int r1 = r0 + rpb; if (r1 > R) r1 = R;
    int nch = (C + 255) / 256;
    float acc[4] = {0.f, 0.f, 0.f, 0.f};
    float accsq[4] = {0.f, 0.f, 0.f, 0.f};
    for (int r = r0; r < r1; r++) {
        const float* row = X + (long)r * C;
        #pragma unroll
        for (int k = 0; k < 4; k++) {
            if (k < nch) {
                int c = threadIdx.x + k * 256;
                if (c < C) { float v = row[c]; acc[k] += v; accsq[k] += v * v; }
            }
        }
    }
    #pragma unroll
    for (int k = 0; k < 4; k++) {
        if (k < nch) {
            int c = threadIdx.x + k * 256;
            if (c < C) {
                part[(long)blk * C + c] = acc[k];
                part[(long)nB * C + (long)blk * C + c] = accsq[k];
            }
        }
    }
}

// block-per-channel parallel reduction of partials -> g_m1/g_i1 (R12 fix, 5.9us)
__global__ void reduce_m1_kernel(const float* __restrict__ part, int nB, int C, int statN) {
    int c = blockIdx.x;
    int t = threadIdx.x;
    float a = 0.f, b = 0.f;
    for (int r = t; r < nB; r += 256) {
        a += part[(long)r * C + c];
        b += part[(long)nB * C + (long)r * C + c];
    }
    __shared__ float sa[256], sb[256];
    sa[t] = a; sb[t] = b;
    __syncthreads();
    for (int s = 128; s > 0; s >>= 1) {
        if (t < s) { sa[t] += sa[t + s]; sb[t] += sb[t + s]; }
        __syncthreads();
    }
    if (t == 0) {
        double m = (double)sa[0] / statN;
        double var = (double)sb[0] / statN - m * m;
        if (var < 0.0) var = 0.0;
        g_m1[c] = (float)m;
        g_i1[c] = rsqrtf((float)var + BN_EPS);
    }
}

// act: 0 = relu, 1 = leaky(0.2)
__global__ void bn_apply_kernel(float* __restrict__ X, long total, int C, int act) {
    long t = (long)blockIdx.x * blockDim.x + threadIdx.x;
    if (t >= total) return;
    int c = (int)(t % C);
    float y = (X[t] - g_m1[c]) * g_i1[c];
    X[t] = (act == 0) ? fmaxf(y, 0.f) : (y >= 0.f ? y : 0.2f * y);
}

__global__ void bn_small_kernel(float* __restrict__ X, int C, float slope) {
    int c = blockIdx.x * blockDim.x + threadIdx.x;
    if (c >= C) return;
    double s = 0.0, ss = 0.0;
    for (int r = 0; r < 8; r++) { double v = X[r * C + c]; s += v; ss += v * v; }
    double m = s / 8.0;
    double var = ss / 8.0 - m * m;
    if (var < 0.0) var = 0.0;
    float inv = rsqrtf((float)var + BN_EPS);
    for (int r = 0; r < 8; r++) {
        float y = (X[r * C + c] - (float)m) * inv;
        X[r * C + c] = y >= 0.f ? y : slope * y;
    }
}

// reduce local_gemm2 per-block partials -> g_m2/g_i2 (for BN2 of local op)
__global__ void reduce_part_kernel(int nBy, int O, int statN) {
    int c = blockIdx.x;
    int t = threadIdx.x;
    double a = 0.0, b = 0.0;
    for (int r = t; r < nBy; r += 256) {
        a += g_part[r * O + c];
        b += g_part[PART_OFF + r * O + c];
    }
    __shared__ double sa[256], sb[256];
    sa[t] = a; sb[t] = b;
    __syncthreads();
    for (int s = 128; s > 0; s >>= 1) {
        if (t < s) { sa[t] += sa[t + s]; sb[t] += sb[t + s]; }
        __syncthreads();
    }
    if (t == 0) {
        double m = sa[0] / statN;
        double var = sb[0] / statN - m * m;
        if (var < 0.0) var = 0.0;
        g_m2[c] = (float)m;
        g_i2[c] = rsqrtf((float)var + BN_EPS);
    }
}

// ----------------------------------------------------------------------------
// R13: BN1 stats — ONE incremental pass over all 3 k-scales (prefix property).
// Per-block float partials for j-ranges [0,16),[16,32),[32,64).
// part layout: sums at [scale*nB*C], sumsq at [(3+scale)*nB*C]. (R6-verified.)
// ----------------------------------------------------------------------------
__global__ void stats1_all_kernel(const float* __restrict__ U, const float* __restrict__ V,
                                  const int* __restrict__ knn, int S, int N, int C,
                                  int cpb, int nB, float* __restrict__ part) {
    int c = threadIdx.x;   // blockDim == C
    int blk = blockIdx.x;
    float s0 = 0.f, q0 = 0.f, s1 = 0.f, q1 = 0.f, s2 = 0.f, q2 = 0.f;
    for (int ss = 0; ss < cpb; ss++) {
        int s = blk * cpb + ss;
        int b = s / S;
        float v = V[(long)s * C + c];
        const int* kn = knn + (long)s * 64;
        for (int j = 0; j < 16; j++) {
            float x = U[((long)b * N + kn[j]) * C + c] + v;
            s0 += x; q0 += x * x;
        }
        for (int j = 16; j < 32; j++) {
            float x = U[((long)b * N + kn[j]) * C + c] + v;
            s1 += x; q1 += x * x;
        }
        for (int j = 32; j < 64; j++) {
            float x = U[((long)b * N + kn[j]) * C + c] + v;
            s2 += x; q2 += x * x;
        }
    }
    long base = (long)blk * C + c;
    long stride = (long)nB * C;
    part[0 * stride + base] = s0;
    part[1 * stride + base] = s1;
    part[2 * stride + base] = s2;
    part[3 * stride + base] = q0;
    part[4 * stride + base] = q1;
    part[5 * stride + base] = q2;
}

__global__ void stats1_fin_kernel(const float* __restrict__ part, int nB, int C, int S8) {
    int c = blockIdx.x * 128 + threadIdx.x;
    if (c >= C) return;
    long stride = (long)nB * C;
    float a0 = 0.f, a1 = 0.f, a2 = 0.f, b0 = 0.f, b1 = 0.f, b2 = 0.f;
    for (int r = 0; r < nB; r++) {
        long idx = (long)r * C + c;
        a0 += part[0 * stride + idx];
        a1 += part[1 * stride + idx];
        a2 += part[2 * stride + idx];
        b0 += part[3 * stride + idx];
        b1 += part[4 * stride + idx];
        b2 += part[5 * stride + idx];
    }
    double cs = a0, cq = b0;
    const int ks[3] = {16, 32, 64};
    double add_s[3] = {0.0, (double)a1, (double)a2};
    double add_q[3] = {0.0, (double)b1, (double)b2};
    for (int sc = 0; sc < 3; sc++) {
        cs += add_s[sc]; cq += add_q[sc];
        double n = (double)S8 * ks[sc];
        double m = cs / n;
        double var = cq / n - m * m;
        if (var < 0.0) var = 0.0;
        g_s1m[sc * 256 + c] = (float)m;
        g_s1i[sc * 256 + c] = rsqrtf((float)var + BN_EPS);
    }
}

// ----------------------------------------------------------------------------
// 128x128 tiled GEMM (optionally BN+relu on A via g_m1/g_i1; max BN'd D = 128)
// ----------------------------------------------------------------------------
__global__ void gemm128_kernel(const float* __restrict__ A, const float* __restrict__ W,
                               const float* __restrict__ bias, float* __restrict__ C,
                               int R, int D, int O, int useStats) {
    __shared__ float As[16][132];
    __shared__ float Ws[16][132];
    __shared__ float sM[256];
    __shared__ float sI[256];
    int tid = threadIdx.x;
    if (useStats) {
        for (int c = tid; c < D; c += 256) { sM[c] = g_m1[c]; sI[c] = g_i1[c]; }
        __syncthreads();
    }
    long rowBase = (long)blockIdx.y * 128;
    int colBase = blockIdx.x * 128;
    int tr = tid >> 4, tc = tid & 15;
    int lrow = tid >> 2;
    int lkq = tid & 3;
    float acc[8][8];
    #pragma unroll
    for (int i = 0; i < 8; i++)
        #pragma unroll
        for (int j = 0; j < 8; j++) acc[i][j] = 0.f;

    for (int k0 = 0; k0 < D; k0 += 16) {
        #pragma unroll
        for (int half = 0; half < 2; half++) {
            int row = lrow + 64 * half;
            int kc = k0 + lkq * 4;
            float4 av = *(const float4*)(A + (rowBase + row) * D + kc);
            if (useStats) {
                av.x = fmaxf((av.x - sM[kc + 0]) * sI[kc + 0], 0.f);
                av.y = fmaxf((av.y - sM[kc + 1]) * sI[kc + 1], 0.f);
                av.z = fmaxf((av.z - sM[kc + 2]) * sI[kc + 2], 0.f);
                av.w = fmaxf((av.w - sM[kc + 3]) * sI[kc + 3], 0.f);
            }
            As[lkq * 4 + 0][row] = av.x;
            As[lkq * 4 + 1][row] = av.y;
            As[lkq * 4 + 2][row] = av.z;
            As[lkq * 4 + 3][row] = av.w;
            int wr = colBase + row;
            float4 wv = make_float4(0.f, 0.f, 0.f, 0.f);
            if (wr < O) wv = *(const float4*)(W + (long)wr * D + kc);
            Ws[lkq * 4 + 0][row] = wv.x;
            Ws[lkq * 4 + 1][row] = wv.y;
            Ws[lkq * 4 + 2][row] = wv.z;
            Ws[lkq * 4 + 3][row] = wv.w;
        }
        __syncthreads();
        #pragma unroll
        for (int kk = 0; kk < 16; kk++) {
            float a[8], w[8];
            *(float4*)(a + 0) = *(const float4*)&As[kk][tr * 8 + 0];
            *(float4*)(a + 4) = *(const float4*)&As[kk][tr * 8 + 4];
            *(float4*)(w + 0) = *(const float4*)&Ws[kk][tc * 8 + 0];
            *(float4*)(w + 4) = *(const float4*)&Ws[kk][tc * 8 + 4];
            #pragma unroll
            for (int i = 0; i < 8; i++)
                #pragma unroll
                for (int j = 0; j < 8; j++)
                    acc[i][j] += a[i] * w[j];
        }
        __syncthreads();
    }
    #pragma unroll
    for (int i = 0; i < 8; i++) {
        long row = rowBase + tr * 8 + i;
        int col0 = colBase + tc * 8;
        if (col0 >= O) continue;
        float b0 = 0, b1 = 0, b2 = 0, b3 = 0, b4 = 0, b5 = 0, b6 = 0, b7 = 0;
        if (bias) {
            b0 = bias[col0 + 0]; b1 = bias[col0 + 1]; b2 = bias[col0 + 2]; b3 = bias[col0 + 3];
            b4 = bias[col0 + 4]; b5 = bias[col0 + 5]; b6 = bias[col0 + 6]; b7 = bias[col0 + 7];
        }
        float4 v0 = make_float4(acc[i][0] + b0, acc[i][1] + b1, acc[i][2] + b2, acc[i][3] + b3);
        float4 v1 = make_float4(acc[i][4] + b4, acc[i][5] + b5, acc[i][6] + b6, acc[i][7] + b7);
        *(float4*)(C + row * O + col0) = v0;
        *(float4*)(C + row * O + col0 + 4) = v1;
    }
}

// ----------------------------------------------------------------------------
// Fused local-op GEMM2 (A built on the fly; BN1 params passed explicitly;
// epilogue: per-center raw max -> pool, per-block channel partials -> g_part)
// ----------------------------------------------------------------------------
__global__ void local_gemm2_kernel(const float* __restrict__ U, const float* __restrict__ V,
                                   const int* __restrict__ knn, const float* __restrict__ W,
                                   float* __restrict__ poolOut,
                                   int S, int N, int D, int O, int kshift,
                                   int OC, int off,
                                   const float* __restrict__ bn1M,
                                   const float* __restrict__ bn1I) {
    __shared__ float As[16][132];
    __shared__ float Ws[16][132];
    __shared__ float sRed[16][132];
    __shared__ float sM[256];
    __shared__ float sI[256];
    __shared__ int sP[128];
    __shared__ int sS[128];
    int tid = threadIdx.x;
    long rowBase = (long)blockIdx.y * 128;
    int colBase = blockIdx.x * 128;

    for (int c = tid; c < D; c += 256) { sM[c] = bn1M[c]; sI[c] = bn1I[c]; }
    if (tid < 128) {
        long grow = rowBase + tid;
        int s = (int)(grow >> kshift);
        int j = (int)(grow & ((1 << kshift) - 1));
        int b = s / S;
        sS[tid] = s;
        sP[tid] = b * N + knn[(long)s * 64 + j];
    }
    __syncthreads();

    int tr = tid >> 4, tc = tid & 15;
    int lrow = tid >> 2;
    int lkq = tid & 3;
    float acc[8][8];
    #pragma unroll
    for (int i = 0; i < 8; i++)
        #pragma unroll
        for (int j = 0; j < 8; j++) acc[i][j] = 0.f;

    for (int k0 = 0; k0 < D; k0 += 16) {
        #pragma unroll
        for (int half = 0; half < 2; half++) {
            int row = lrow + 64 * half;
            int kc = k0 + lkq * 4;
            float4 uv = *(const float4*)(U + (long)sP[row] * D + kc);
            float4 vv = *(const float4*)(V + (long)sS[row] * D + kc);
            As[lkq * 4 + 0][row] = fmaxf((uv.x + vv.x - sM[kc + 0]) * sI[kc + 0], 0.f);
            As[lkq * 4 + 1][row] = fmaxf((uv.y + vv.y - sM[kc + 1]) * sI[kc + 1], 0.f);
            As[lkq * 4 + 2][row] = fmaxf((uv.z + vv.z - sM[kc + 2]) * sI[kc + 2], 0.f);
            As[lkq * 4 + 3][row] = fmaxf((uv.w + vv.w - sM[kc + 3]) * sI[kc + 3], 0.f);
            float4 wv = *(const float4*)(W + (long)(colBase + row) * D + kc);
            Ws[lkq * 4 + 0][row] = wv.x;
            Ws[lkq * 4 + 1][row] = wv.y;
            Ws[lkq * 4 + 2][row] = wv.z;
            Ws[lkq * 4 + 3][row] = wv.w;
        }
        __syncthreads();
        #pragma unroll
        for (int kk = 0; kk < 16; kk++) {
            float a[8], w[8];
            *(float4*)(a + 0) = *(const float4*)&As[kk][tr * 8 + 0];
            *(float4*)(a + 4) = *(const float4*)&As[kk][tr * 8 + 4];
            *(float4*)(w + 0) = *(const float4*)&Ws[kk][tc * 8 + 0];
            *(float4*)(w + 4) = *(const float4*)&Ws[kk][tc * 8 + 4];
            #pragma unroll
            for (int i = 0; i < 8; i++)
                #pragma unroll
                for (int j = 0; j < 8; j++)
                    acc[i][j] += a[i] * w[j];
        }
        __syncthreads();
    }

    // epilogue 1: per-center raw max -> poolOut
    int g = (1 << kshift) >> 3;
    #pragma unroll
    for (int j = 0; j < 8; j++) {
        float m = acc[0][j];
        #pragma unroll
        for (int i = 1; i < 8; i++) m = fmaxf(m, acc[i][j]);
        sRed[tr][tc * 8 + j] = m;
    }
    __syncthreads();
    if ((tr & (g - 1)) == 0) {
        int s = sS[tr * 8];
        #pragma unroll
        for (int j = 0; j < 8; j++) {
            float m = sRed[tr][tc * 8 + j];
            for (int q = 1; q < g; q++) m = fmaxf(m, sRed[tr + q][tc * 8 + j]);
            poolOut[(long)s * OC + off + colBase + tc * 8 + j] = m;
        }
    }
    __syncthreads();
    // epilogue 2: per-block channel sums -> g_part
    #pragma unroll
    for (int j = 0; j < 8; j++) {
        float sm = 0.f;
        #pragma unroll
        for (int i = 0; i < 8; i++) sm += acc[i][j];
        sRed[tr][tc * 8 + j] = sm;
    }
    __syncthreads();
    if (tr == 0) {
        #pragma unroll
        for (int j = 0; j < 8; j++) {
            float tot = 0.f;
            for (int q = 0; q < 16; q++) tot += sRed[q][tc * 8 + j];
            g_part[(long)blockIdx.y * O + colBase + tc * 8 + j] = tot;
        }
    }
    __syncthreads();
    #pragma unroll
    for (int j = 0; j < 8; j++) {
        float sm = 0.f;
        #pragma unroll
        for (int i = 0; i < 8; i++) sm += acc[i][j] * acc[i][j];
        sRed[tr][tc * 8 + j] = sm;
    }
    __syncthreads();
    if (tr == 0) {
        #pragma unroll
        for (int j = 0; j < 8; j++) {
            float tot = 0.f;
            for (int q = 0; q < 16; q++) tot += sRed[q][tc * 8 + j];
            g_part[PART_OFF + (long)blockIdx.y * O + colBase + tc * 8 + j] = tot;
        }
    }
}

// pool[s, off+c] = relu(bn2(rawmax)) via g_m2/g_i2
__global__ void pool_finalize_kernel(float* __restrict__ pool, int OC, int off) {
    int s = blockIdx.x;
    int c = threadIdx.x;
    long p = (long)s * OC + off + c;
    pool[p] = fmaxf((pool[p] - g_m2[c]) * g_i2[c], 0.f);
}

__global__ void split_w1_kernel(const float* __restrict__ w1, float* __restrict__ wa,
                                float* __restrict__ wd, int O, int D, int total) {
    int t = blockIdx.x * 256 + threadIdx.x;
    if (t >= total) return;
    int d = t % D, o = t / D;
    float a = w1[(long)o * 2 * D + d];
    float b = w1[(long)o * 2 * D + D + d];
    wa[t] = a;
    wd[t] = b - a;
}

// ----------------------------------------------------------------------------
// Generic fallback GEMM (odd shapes)
// ----------------------------------------------------------------------------
__global__ void gemm_kernel(const float* __restrict__ A, const float* __restrict__ W,
                            const float* __restrict__ bias, float* __restrict__ C,
                            int R, int D, int O) {
    __shared__ float As[64][17];
    __shared__ float Ws[64][17];
    int tid = threadIdx.x;
    int tr = tid >> 4, tc = tid & 15;
    long rowBase = (long)blockIdx.y * 64;
    int colBase = blockIdx.x * 64;
    float acc[4][4] = {};
    for (int k0 = 0; k0 < D; k0 += 16) {
        #pragma unroll
        for (int e = tid; e < 1024; e += 256) {
            int rr = e >> 4, kk = e & 15;
            long ar = rowBase + rr; int ac = k0 + kk;
            As[rr][kk] = (ar < R && ac < D) ? A[ar * D + ac] : 0.f;
            int wr = colBase + rr;
            Ws[rr][kk] = (wr < O && ac < D) ? W[(long)wr * D + ac] : 0.f;
        }
        __syncthreads();
        #pragma unroll
        for (int kk = 0; kk < 16; kk++) {
            float a[4], w[4];
            #pragma unroll
            for (int i = 0; i < 4; i++) a[i] = As[tr + 16*i][kk];
            #pragma unroll
            for (int j = 0; j < 4; j++) w[j] = Ws[tc + 16*j][kk];
            #pragma unroll
            for (int i = 0; i < 4; i++)
                #pragma unroll
                for (int j = 0; j < 4; j++)
                    acc[i][j] += a[i] * w[j];
        }
        __syncthreads();
    }
    #pragma unroll
    for (int i = 0; i < 4; i++) {
        long row = rowBase + tr + 16*i;
        if (row >= R) continue;
        #pragma unroll
        for (int j = 0; j < 4; j++) {
            int col = colBase + tc + 16*j;
            if (col >= O) continue;
            float vv = acc[i][j];
            if (bias) vv += bias[col];
            C[row * O + col] = vv;
        }
    }
}

// ----------------------------------------------------------------------------
// Layout / elementwise helpers
// ----------------------------------------------------------------------------
__global__ void transpose_x_kernel(const float* __restrict__ x, float* __restrict__ xyz) {
    int t = blockIdx.x * 256 + threadIdx.x;
    if (t >= 8 * 2048 * 3) return;
    int c = t % 3; int n = (t / 3) % 2048; int b = t / (3 * 2048);
    xyz[t] = x[((long)b * 3 + c) * 2048 + n];
}

__global__ void gather_kernel(const float* __restrict__ src, const int* __restrict__ idx,
                              float* __restrict__ dst, int S, int N, int D, long total) {
    long t = (long)blockIdx.x * blockDim.x + threadIdx.x;
    if (t >= total) return;
    int c = (int)(t % D); long bs = t / D;
    int b = (int)(bs / S);
    dst[t] = src[((long)b * N + idx[bs]) * D + c];
}

__global__ void catf1_kernel(const float* __restrict__ f1, float* __restrict__ cat) {
    int t = blockIdx.x * 256 + threadIdx.x;
    int c = t & 255; int row = t >> 8;
    cat[(long)row * 1280 + 1024 + c] = f1[t];
}

__global__ void maxn_kernel(const float* __restrict__ X, float* __restrict__ G) {
    int b = blockIdx.x; int c = blockIdx.y * 256 + threadIdx.x;
    float m = -FLT_MAX;
    for (int n = 0; n < 256; n++) m = fmaxf(m, X[((long)b * 256 + n) * 1024 + c]);
    G[b * 1024 + c] = m;
}

// ----------------------------------------------------------------------------
// FPS / kNN with warp-shuffle reductions (tie order preserved)
// ----------------------------------------------------------------------------
__device__ __forceinline__ unsigned keymap(float f) {
    unsigned u = __float_as_uint(f);
    return (u & 0x80000000u) ? ~u : (u | 0x80000000u);
}

__device__ void fps_body(const float* __restrict__ xyz, int N, int npoint,
                         int* __restrict__ outIdx, int b,
                         float* sx, float* sy, float* sz, float* sd,
                         unsigned long long* warpBest, int* sFar) {
    int t = threadIdx.x;
    int nt = blockDim.x;
    int numWarps = nt >> 5;
    for (int n = t; n < N; n += nt) {
        sx[n] = xyz[((long)b * N + n) * 3 + 0];
        sy[n] = xyz[((long)b * N + n) * 3 + 1];
        sz[n] = xyz[((long)b * N + n) * 3 + 2];
        sd[n] = 1e10f;
    }
    __syncthreads();
    int far = 0;
    for (int it = 0; it < npoint; it++) {
        if (t == 0) outIdx[b * npoint + it] = far;
        float cx = sx[far], cy = sy[far], cz = sz[far];
        unsigned long long best = 0ull;
        for (int n = t; n < N; n += nt) {
            float dx = sx[n] - cx, dy = sy[n] - cy, dz = sz[n] - cz;
            float d = dx * dx + dy * dy + dz * dz;
            float dm = fminf(sd[n], d);
            sd[n] = dm;
            unsigned long long key = ((unsigned long long)keymap(dm) << 32) | (unsigned)(~n);
            if (key > best) best = key;
        }
        #pragma unroll
        for (int o = 16; o > 0; o >>= 1) {
            unsigned long long other = __shfl_xor_sync(0xffffffffu, best, o);
            if (other > best) best = other;
        }
        if ((t & 31) == 0) warpBest[t >> 5] = best;
        __syncthreads();
        if (t < 32) {
            unsigned long long v = (t < numWarps) ? warpBest[t] : 0ull;
            #pragma unroll
            for (int o = 16; o > 0; o >>= 1) {
                unsigned long long other = __shfl_xor_sync(0xffffffffu, v, o);
                if (other > v) v = other;
            }
            if (t == 0) *sFar = (int)(~((unsigned)(v & 0xffffffffu)));
        }
        __syncthreads();
        far = *sFar;
    }
}

__device__ void knn_body(const float* __restrict__ centers, const float* __restrict__ xyz,
                         int S, int N, int* __restrict__ knnOut, int bs,
                         float* sd, unsigned long long* warpBest) {
    int t = threadIdx.x;
    int nt = blockDim.x;
    int numWarps = nt >> 5;
    int b = bs / S;
    float cx = centers[(long)bs * 3 + 0];
    float cy = centers[(long)bs * 3 + 1];
    float cz = centers[(long)bs * 3 + 2];
    float cn = cx * cx + cy * cy + cz * cz;
    for (int n = t; n < N; n += nt) {
        float px = xyz[((long)b * N + n) * 3 + 0];
        float py = xyz[((long)b * N + n) * 3 + 1];
        float pz = xyz[((long)b * N + n) * 3 + 2];
        float pn = px * px + py * py + pz * pz;
        float dot = cx * px + cy * py + cz * pz;
        sd[n] = cn + pn - 2.f * dot;
    }
    __syncthreads();
    for (int j = 0; j < 64; j++) {
        unsigned long long best = 0xFFFFFFFFFFFFFFFFull;
        for (int n = t; n < N; n += nt) {
            unsigned long long key = ((unsigned long long)keymap(sd[n]) << 32) | (unsigned)n;
            if (key < best) best = key;
        }
        #pragma unroll
        for (int o = 16; o > 0; o >>= 1) {
            unsigned long long other = __shfl_xor_sync(0xffffffffu, best, o);
            if (other < best) best = other;
        }
        if ((t & 31) == 0) warpBest[t >> 5] = best;
        __syncthreads();
        if (t < 32) {
            unsigned long long v = (t < numWarps) ? warpBest[t] : 0xFFFFFFFFFFFFFFFFull;
            #pragma unroll
            for (int o = 16; o > 0; o >>= 1) {
                unsigned long long other = __shfl_xor_sync(0xffffffffu, v, o);
                if (other < v) v = other;
            }
            if (t == 0) {
                int sel = (int)(v & 0xffffffffu);
                knnOut[(long)bs * 64 + j] = sel;
                sd[sel] = FLT_MAX;
            }
        }
        __syncthreads();
    }
}

__global__ void fps_kernel(const float* xyz, int N, int npoint, int* outIdx) {
    __shared__ float buf[4 * 2048];
    __shared__ unsigned long long wb[32];
    __shared__ int sFar;
    fps_body(xyz, N, npoint, outIdx, blockIdx.x, buf, buf + N, buf + 2 * N, buf + 3 * N, wb, &sFar);
}

__global__ void knn_kernel(const float* centers, const float* xyz, int S, int N, int* knnOut) {
    __shared__ float buf[2048];
    __shared__ unsigned long long wb[32];
    knn_body(centers, xyz, S, N, knnOut, blockIdx.x, buf, wb);
}

__global__ void knn_fps_kernel(const float* centers, const float* xyz, int S, int N,
                               int* knnOut, int nKnn,
                               const float* xyz2, int N2, int np2, int* outIdx2) {
    __shared__ float buf[4 * 2048];
    __shared__ unsigned long long wb[32];
    __shared__ int sFar;
    if (blockIdx.x < nKnn) {
        knn_body(centers, xyz, S, N, knnOut, blockIdx.x, buf, wb);
    } else {
        int b = blockIdx.x - nKnn;
        fps_body(xyz2, N2, np2, outIdx2, b, buf, buf + N2, buf + 2 * N2, buf + 3 * N2, wb, &sFar);
    }
}

// ----------------------------------------------------------------------------
// Attention (reference reshape quirk preserved)
// ----------------------------------------------------------------------------
__global__ void gemmqv_kernel(const float* __restrict__ xx, const float* __restrict__ pos,
                              const float* __restrict__ wqk, const float* __restrict__ wv,
                              const float* __restrict__ bv,
                              float* __restrict__ qb, float* __restrict__ vb) {
    __shared__ float As[16][132];
    __shared__ float Ws[16][132];
    int tid = threadIdx.x;
    long rowBase = (long)blockIdx.y * 128;
    int colBase = blockIdx.x * 128;
    int tr = tid >> 4, tc = tid & 15;
    int lrow = tid >> 2;
    int lkq = tid & 3;
    const int D = 256;
    float acc[8][8];
    #pragma unroll
    for (int i = 0; i < 8; i++)
        #pragma unroll
        for (int j = 0; j < 8; j++) acc[i][j] = 0.f;

    for (int k0 = 0; k0 < D; k0 += 16) {
        #pragma unroll
        for (int half = 0; half < 2; half++) {
            int row = lrow + 64 * half;
            int kc = k0 + lkq * 4;
            float4 av = *(const float4*)(xx + (rowBase + row) * D + kc);
            float4 pv = *(const float4*)(pos + (rowBase + row) * D + kc);
            As[lkq * 4 + 0][row] = av.x + pv.x;
            As[lkq * 4 + 1][row] = av.y + pv.y;
            As[lkq * 4 + 2][row] = av.z + pv.z;
            As[lkq * 4 + 3][row] = av.w + pv.w;
            int ocol = colBase + row;
            const float* Wp = (ocol < 256) ? (wqk + (long)ocol * D) : (wv + (long)(ocol - 256) * D);
            float4 wvv = *(const float4*)(Wp + kc);
            Ws[lkq * 4 + 0][row] = wvv.x;
            Ws[lkq * 4 + 1][row] = wvv.y;
            Ws[lkq * 4 + 2][row] = wvv.z;
            Ws[lkq * 4 + 3][row] = wvv.w;
        }
        __syncthreads();
        #pragma unroll
        for (int kk = 0; kk < 16; kk++) {
            float a[8], w[8];
            *(float4*)(a + 0) = *(const float4*)&As[kk][tr * 8 + 0];
            *(float4*)(a + 4) = *(const float4*)&As[kk][tr * 8 + 4];
            *(float4*)(w + 0) = *(const float4*)&Ws[kk][tc * 8 + 0];
            *(float4*)(w + 4) = *(const float4*)&Ws[kk][tc * 8 + 4];
            #pragma unroll
            for (int i = 0; i < 8; i++)
                #pragma unroll
                for (int j = 0; j < 8; j++)
                    acc[i][j] += a[i] * w[j];
        }
        __syncthreads();
    }
    int col0 = colBase + tc * 8;
    #pragma unroll
    for (int i = 0; i < 8; i++) {
        long row = rowBase + tr * 8 + i;
        if (col0 < 256) {
            float4 v0 = make_float4(acc[i][0], acc[i][1], acc[i][2], acc[i][3]);
            float4 v1 = make_float4(acc[i][4], acc[i][5], acc[i][6], acc[i][7]);
            *(float4*)(qb + row * 256 + col0) = v0;
            *(float4*)(qb + row * 256 + col0 + 4) = v1;
        } else {
            int cc = col0 - 256;
            float4 v0 = make_float4(acc[i][0] + bv[cc + 0], acc[i][1] + bv[cc + 1],
                                    acc[i][2] + bv[cc + 2], acc[i][3] + bv[cc + 3]);
            float4 v1 = make_float4(acc[i][4] + bv[cc + 4], acc[i][5] + bv[cc + 5],
                                    acc[i][6] + bv[cc + 6], acc[i][7] + bv[cc + 7]);
            *(float4*)(vb + row * 256 + cc) = v0;
            *(float4*)(vb + row * 256 + cc + 4) = v1;
        }
    }
}

__global__ void gram_kernel(const float* __restrict__ Q, float* __restrict__ A) {
    int bh = blockIdx.z; int b = bh >> 2; int h = bh & 3;
    int i0 = blockIdx.y * 16, j0 = blockIdx.x * 16;
    __shared__ float Qi[16][65];
    __shared__ float Qj[16][65];
    int tid = threadIdx.x;
    for (int e = tid; e < 1024; e += 256) {
        int r = e >> 6, d = e & 63;
        int i = i0 + r;
        Qi[r][d] = Q[((long)b * 256 + h * 64 + (i >> 2)) * 256 + (i & 3) * 64 + d];
        Qj[r][d] = Q[((long)b * 256 + j0 + r) * 256 + h * 64 + d];
    }
    __syncthreads();
    int ti = tid >> 4, tj = tid & 15;
    float acc = 0.f;
    #pragma unroll
    for (int d = 0; d < 64; d++) acc += Qi[ti][d] * Qj[tj][d];
    A[((long)bh * 256 + (i0 + ti)) * 256 + (j0 + tj)] = acc;
}

__global__ void softmax_row_kernel(float* __restrict__ A) {
    __shared__ float red[256];
    long row = blockIdx.x;
    float* p = A + row * 256;
    int t = threadIdx.x;
    float v = p[t];
    red[t] = v; __syncthreads();
    for (int s = 128; s > 0; s >>= 1) { if (t < s) red[t] = fmaxf(red[t], red[t + s]); __syncthreads(); }
    float m = red[0]; __syncthreads();
    float e = expf(v - m);
    red[t] = e; __syncthreads();
    for (int s = 128; s > 0; s >>= 1) { if (t < s) red[t] += red[t + s]; __syncthreads(); }
    p[t] = e / red[0];
}

__global__ void colsm_xr_kernel(const float* __restrict__ attn, const float* __restrict__ V,
                                const float* __restrict__ xx, const float* __restrict__ pos,
                                float* __restrict__ xrb) {
    int b = blockIdx.x >> 8;
    int i = blockIdx.x & 255;
    int t = threadIdx.x;
    __shared__ float colv[4][256];
    __shared__ float4 r4[256];
    #pragma unroll
    for (int h = 0; h < 4; h++)
        colv[h][t] = attn[(((long)(b * 4 + h)) * 256 + t) * 256 + i];
    float4 vm = make_float4(colv[0][t], colv[1][t], colv[2][t], colv[3][t]);
    r4[t] = vm;
    __syncthreads();
    for (int s = 128; s > 0; s >>= 1) {
        if (t < s) {
            float4 o = r4[t + s];
            r4[t].x = fmaxf(r4[t].x, o.x); r4[t].y = fmaxf(r4[t].y, o.y);
            r4[t].z = fmaxf(r4[t].z, o.z); r4[t].w = fmaxf(r4[t].w, o.w);
        }
        __syncthreads();
    }
    float4 mx = r4[0];
    __syncthreads();
    float4 ev = make_float4(expf(vm.x - mx.x), expf(vm.y - mx.y),
                            expf(vm.z - mx.z), expf(vm.w - mx.w));
    r4[t] = ev;
    __syncthreads();
    for (int s = 128; s > 0; s >>= 1) {
        if (t < s) {
            float4 o = r4[t + s];
            r4[t].x += o.x; r4[t].y += o.y; r4[t].z += o.z; r4[t].w += o.w;
        }
        __syncthreads();
    }
    float4 sm = r4[0];
    __syncthreads();
    colv[0][t] = ev.x / sm.x;
    colv[1][t] = ev.y / sm.y;
    colv[2][t] = ev.z / sm.z;
    colv[3][t] = ev.w / sm.w;
    __syncthreads();
    int c = t; int h = c >> 6;
    const float* vp = V + ((long)b * 256) * 256 + c;
    float acc = 0.f;
    #pragma unroll 8
    for (int j = 0; j < 256; j++) acc += vp[(long)j * 256] * colv[h][j];
    long row = (long)b * 256 + i;
    xrb[row * 256 + c] = xx[row * 256 + c] + pos[row * 256 + c] - acc;
}

__global__ void addcat_bn_kernel(const float* __restrict__ qb, float* __restrict__ xx,
                                 const float* __restrict__ pos, float* __restrict__ cat,
                                 int layer) {
    int t = blockIdx.x * 256 + threadIdx.x;
    int c = t & 255; int row = t >> 8;
    float y = fmaxf((qb[t] - g_m1[c]) * g_i1[c], 0.f);
    float v = xx[t] + pos[t] + y;
    xx[t] = v;
    cat[(long)row * 1280 + layer * 256 + c] = v;
}

// ----------------------------------------------------------------------------
// Host orchestration
// ----------------------------------------------------------------------------
static void gemm_old(const float* A, const float* W, const float* bias, float* C,
                     int R, int D, int O) {
    dim3 grid(CEILDIV(O, 64), CEILDIV(R, 64));
    gemm_kernel<<<grid, 256>>>(A, W, bias, C, R, D, O);
}

static void gemm_big(const float* A, const float* W, const float* bias, float* C,
                     int R, int D, int O, int useStats) {
    dim3 grid(CEILDIV(O, 128), R / 128);
    gemm128_kernel<<<grid, 256>>>(A, W, bias, C, R, D, O, useStats);
}

static float* s_part;

static void computeStats(const float* X, int R, int C) {
    int rpb = R / 512;
    if (rpb < 8) rpb = 8;
    int nB = R / rpb;
    stats_part_kernel<<<nB, 256>>>(X, R, C, rpb, nB, s_part);
    reduce_m1_kernel<<<C, 256>>>(s_part, nB, C, R);
}

static void bn(float* X, int R, int C, int act) {
    computeStats(X, R, C);
    long total = (long)R * C;
    bn_apply_kernel<<<(int)CEILDIV(total, 256), 256>>>(X, total, C, act);
}

extern "C" void kernel_launch(void* const* d_in, const int* in_sizes, int n_in,
                              void* d_out, int out_size) {
    const float* x       = (const float*)d_in[0];
    const float* conv1_w = (const float*)d_in[1];
    const float* conv2_w = (const float*)d_in[2];
    const float* g0_w1   = (const float*)d_in[3];
    const float* g0_w2   = (const float*)d_in[4];
    const float* g0_wc   = (const float*)d_in[5];
    const float* g1_w1   = (const float*)d_in[6];
    const float* g1_w2   = (const float*)d_in[7];
    const float* g1_wc   = (const float*)d_in[8];
    const float* pt_w    = (const float*)d_in[9];
    const float* pos_w   = (const float*)d_in[10];
    const float* pos_b   = (const float*)d_in[11];
    const float* sa_wqk  = (const float*)d_in[12];
    const float* sa_wv   = (const float*)d_in[13];
    const float* sa_bv   = (const float*)d_in[14];
    const float* sa_wt   = (const float*)d_in[15];
    const float* sa_bt   = (const float*)d_in[16];
    const float* fuse_w  = (const float*)d_in[17];
    const float* lin1_w  = (const float*)d_in[18];
    const float* lin2_w  = (const float*)d_in[19];
    const float* lin2_b  = (const float*)d_in[20];
    const float* lin3_w  = (const float*)d_in[21];
    const float* lin3_b  = (const float*)d_in[22];
    float* out = (float*)d_out;

    float *xyz, *h1, *points, *newxyz, *newxyz2, *newpts, *Ub, *Vb, *w1a, *w1d, *pool, *f0, *f1;
    float *pos, *xx, *qb, *vb, *xrb, *attn, *catb, *fuseb, *gmax, *l1, *l2, *s1m, *s1i;
    int *fpsidx, *knn, *knn2;
    cudaGetSymbolAddress((void**)&xyz, g_xyz);
    cudaGetSymbolAddress((void**)&h1, g_h1);
    cudaGetSymbolAddress((void**)&points, g_points);
    cudaGetSymbolAddress((void**)&fpsidx, g_fpsidx);
    cudaGetSymbolAddress((void**)&newxyz, g_newxyz);
    cudaGetSymbolAddress((void**)&newxyz2, g_newxyz2);
    cudaGetSymbolAddress((void**)&newpts, g_newpts);
    cudaGetSymbolAddress((void**)&knn, g_knn);
    cudaGetSymbolAddress((void**)&knn2, g_knn2);
    cudaGetSymbolAddress((void**)&Ub, g_U);
    cudaGetSymbolAddress((void**)&Vb, g_V);
    cudaGetSymbolAddress((void**)&w1a, g_w1a);
    cudaGetSymbolAddress((void**)&w1d, g_w1d);
    cudaGetSymbolAddress((void**)&s_part, g_part);
    cudaGetSymbolAddress((void**)&pool, g_pool);
    cudaGetSymbolAddress((void**)&f0, g_f0);
    cudaGetSymbolAddress((void**)&f1, g_f1);
    cudaGetSymbolAddress((void**)&pos, g_pos);
    cudaGetSymbolAddress((void**)&xx, g_x);
    cudaGetSymbolAddress((void**)&qb, g_q);
    cudaGetSymbolAddress((void**)&vb, g_v);
    cudaGetSymbolAddress((void**)&xrb, g_xr);
    cudaGetSymbolAddress((void**)&attn, g_attn);
    cudaGetSymbolAddress((void**)&catb, g_cat);
    cudaGetSymbolAddress((void**)&fuseb, g_fuse);
    cudaGetSymbolAddress((void**)&gmax, g_gmax);
    cudaGetSymbolAddress((void**)&l1, g_l1);
    cudaGetSymbolAddress((void**)&l2, g_l2);
    cudaGetSymbolAddress((void**)&s1m, g_s1m);
    cudaGetSymbolAddress((void**)&s1i, g_s1i);

    // ---- Stage A ----
    transpose_x_kernel<<<CEILDIV(8*2048*3, 256), 256>>>(x, xyz);
    gemm_old(xyz, conv1_w, nullptr, h1, 16384, 3, 64);
    computeStats(h1, 16384, 64);
    gemm_big(h1, conv2_w, nullptr, points, 16384, 64, 64, 1);
    bn(points, 16384, 64, 0);

    // ---- Stage B: FPS(512) + gathers; kNN1 co-launched with FPS2; kNN2 separate buf ----
    fps_kernel<<<8, 1024>>>(xyz, 2048, 512, fpsidx);
    gather_kernel<<<CEILDIV(8*512*3, 256), 256>>>(xyz, fpsidx, newxyz, 512, 2048, 3, 8L*512*3);
    gather_kernel<<<CEILDIV(8*512*64, 256), 256>>>(points, fpsidx, newpts, 512, 2048, 64, 8L*512*64);
    knn_fps_kernel<<<4096 + 8, 256>>>(newxyz, xyz, 512, 2048, knn, 4096,
                                      newxyz, 512, 256, fpsidx);
    gather_kernel<<<CEILDIV(8*256*3, 256), 256>>>(newxyz, fpsidx, newxyz2, 256, 512, 3, 8L*256*3);
    knn_kernel<<<2048, 256>>>(newxyz2, newxyz, 256, 512, knn2);

    // ---- Stage C: local_op 0 via U/V (R13: one-pass BN1 stats for all scales) ----
    {
        split_w1_kernel<<<CEILDIV(128*64, 256), 256>>>(g0_w1, w1a, w1d, 128, 64, 128*64);
        gemm_big(points, w1a, nullptr, Ub, 16384, 64, 128, 0);
        gemm_big(newpts, w1d, nullptr, Vb, 4096, 64, 128, 0);
        stats1_all_kernel<<<256, 128>>>(Ub, Vb, knn, 512, 2048, 128, 16, 256, s_part);
        stats1_fin_kernel<<<1, 128>>>(s_part, 256, 128, 8*512);
        const int kshift[3] = {4, 5, 6};
        for (int si = 0; si < 3; si++) {
            int R = 8 * 512 * (1 << kshift[si]);
            int nBy = R / 128;
            dim3 grid(1, nBy);
            local_gemm2_kernel<<<grid, 256>>>(Ub, Vb, knn, g0_w2, pool,
                                              512, 2048, 128, 128, kshift[si], 384, si * 128,
                                              s1m + si * 256, s1i + si * 256);
            reduce_part_kernel<<<128, 256>>>(nBy, 128, R);
            pool_finalize_kernel<<<4096, 128>>>(pool, 384, si * 128);
        }
        gemm_big(pool, g0_wc, nullptr, f0, 4096, 384, 128, 0);
        bn(f0, 4096, 128, 0);
    }

    // ---- Stage D gather for stage E ----
    gather_kernel<<<CEILDIV(8*256*128, 256), 256>>>(f0, fpsidx, newpts, 256, 512, 128, 8L*256*128);

    // ---- Stage E: local_op 1 via U/V ----
    {
        split_w1_kernel<<<CEILDIV(256*128, 256), 256>>>(g1_w1, w1a, w1d, 256, 128, 256*128);
        gemm_big(f0, w1a, nullptr, Ub, 4096, 128, 256, 0);
        gemm_big(newpts, w1d, nullptr, Vb, 2048, 128, 256, 0);
        stats1_all_kernel<<<128, 256>>>(Ub, Vb, knn2, 256, 512, 256, 16, 128, s_part);
        stats1_fin_kernel<<<2, 128>>>(s_part, 128, 256, 8*256);
        const int kshift[3] = {4, 5, 6};
        for (int si = 0; si < 3; si++) {
            int R = 8 * 256 * (1 << kshift[si]);
            int nBy = R / 128;
            dim3 grid(2, nBy);
            local_gemm2_kernel<<<grid, 256>>>(Ub, Vb, knn2, g1_w2, pool,
                                              256, 512, 256, 256, kshift[si], 768, si * 256,
                                              s1m + si * 256, s1i + si * 256);
            reduce_part_kernel<<<256, 256>>>(nBy, 256, R);
            pool_finalize_kernel<<<2048, 256>>>(pool, 768, si * 256);
        }
        gemm_big(pool, g1_wc, nullptr, f1, 2048, 768, 256, 0);
        bn(f1, 2048, 256, 0);
    }

    // ---- Stage F ----
    gemm_old(newxyz2, pos_w, pos_b, pos, 2048, 3, 256);
    gemm_big(f1, pt_w, nullptr, xx, 2048, 256, 256, 0);
    bn(xx, 2048, 256, 0);

    // ---- Stage G: 4 offset self-attention layers ----
    for (int i = 0; i < 4; i++) {
        gemmqv_kernel<<<dim3(4, 16), 256>>>(xx, pos,
                                            sa_wqk + (long)i * 256 * 256,
                                            sa_wv + (long)i * 256 * 256,
                                            sa_bv + i * 256, qb, vb);
        gram_kernel<<<dim3(16, 16, 32), 256>>>(qb, attn);
        softmax_row_kernel<<<8192, 256>>>(attn);
        colsm_xr_kernel<<<2048, 256>>>(attn, vb, xx, pos, xrb);
        gemm_big(xrb, sa_wt + (long)i * 256 * 256, sa_bt + i * 256, qb, 2048, 256, 256, 0);
        computeStats(qb, 2048, 256);
        addcat_bn_kernel<<<2048, 256>>>(qb, xx, pos, catb, i);
    }
    catf1_kernel<<<2048, 256>>>(f1, catb);

    // ---- Stage H ----
    gemm_big(catb, fuse_w, nullptr, fuseb, 2048, 1280, 1024, 0);
    bn(fuseb, 2048, 1024, 1);
    maxn_kernel<<<dim3(8, 4), 256>>>(fuseb, gmax);
    gemm_old(gmax, lin1_w, nullptr, l1, 8, 1024, 512);
    bn_small_kernel<<<2, 256>>>(l1, 512, 0.2f);
    gemm_old(l1, lin2_w, lin2_b, l2, 8, 512, 256);
    bn_small_kernel<<<1, 256>>>(l2, 256, 0.2f);
    gemm_old(l2, lin3_w, lin3_b, out, 8, 256, 40);
}

// round 14
// speedup vs baseline: 1.1290x; 1.0129x over previous
#include <cuda_runtime.h>
#include <math.h>
#include <float.h>

#define CEILDIV(a,b) (((a)+(b)-1)/(b))
#define BN_EPS 1e-5f
#define PART_OFF (2048*256)

// ----------------------------------------------------------------------------
// Scratch (device globals)
// ----------------------------------------------------------------------------
__device__ float g_xyz[8*2048*3];
__device__ float g_h1[8*2048*64];
__device__ float g_points[8*2048*64];
__device__ int   g_fpsidx[8*512];
__device__ float g_newxyz[8*512*3];
__device__ float g_newxyz2[8*256*3];
__device__ float g_newpts[8*512*64];        // stage2: 8*256*128
__device__ int   g_knn[8*512*64];
__device__ int   g_knn2[8*256*64];
__device__ float g_U[16384*128];            // stage E: 4096x256
__device__ float g_V[4096*128];             // stage E: 2048x256
__device__ float g_w1a[256*128];
__device__ float g_w1d[256*128];
__device__ float g_part[2*2048*256];
__device__ float g_pool[8*512*384];         // stage2: 8*256*768
__device__ float g_f0[8*512*128];
__device__ float g_f1[8*256*256];
__device__ float g_pos[8*256*256];
__device__ float g_x[8*256*256];
__device__ float g_q[8*256*256];
__device__ float g_v[8*256*256];
__device__ float g_xr[8*256*256];
__device__ float g_attn[8*4*256*256];
__device__ float g_cat[8*256*1280];
__device__ float g_fuse[8*256*1024];
__device__ float g_gmax[8*1024];
__device__ float g_l1[8*512];
__device__ float g_l2[8*256];
__device__ float g_m1[1024];
__device__ float g_i1[1024];
__device__ float g_m2[256];
__device__ float g_i2[256];
__device__ float g_s1m[3*256];
__device__ float g_s1i[3*256];

// ----------------------------------------------------------------------------
// BN stats plumbing (R12/R13-record versions)
// ----------------------------------------------------------------------------
__global__ void stats_part_kernel(const float* __restrict__ X, int R, int C, int rpb,
                                  int nB, float* __restrict__ part) {
    int blk = blockIdx.x;
    int r0 = blk * rpb;
    int r1 = r0 + rpb; if (r1 > R) r1 = R;
    int nch = (C + 255) / 256;
    float acc[4] = {0.f, 0.f, 0.f, 0.f};
    float accsq[4] = {0.f, 0.f, 0.f, 0.f};
    for (int r = r0; r < r1; r++) {
        const float* row = X + (long)r * C;
        #pragma unroll
        for (int k = 0; k < 4; k++) {
            if (k < nch) {
                int c = threadIdx.x + k * 256;
                if (c < C) { float v = row[c]; acc[k] += v; accsq[k] += v * v; }
            }
        }
    }
    #pragma unroll
    for (int k = 0; k < 4; k++) {
        if (k < nch) {
            int c = threadIdx.x + k * 256;
            if (c < C) {
                part[(long)blk * C + c] = acc[k];
                part[(long)nB * C + (long)blk * C + c] = accsq[k];
            }
        }
    }
}

__global__ void reduce_m1_kernel(const float* __restrict__ part, int nB, int C, int statN) {
    int c = blockIdx.x;
    int t = threadIdx.x;
    float a = 0.f, b = 0.f;
    for (int r = t; r < nB; r += 256) {
        a += part[(long)r * C + c];
        b += part[(long)nB * C + (long)r * C + c];
    }
    __shared__ float sa[256], sb[256];
    sa[t] = a; sb[t] = b;
    __syncthreads();
    for (int s = 128; s > 0; s >>= 1) {
        if (t < s) { sa[t] += sa[t + s]; sb[t] += sb[t + s]; }
        __syncthreads();
    }
    if (t == 0) {
        double m = (double)sa[0] / statN;
        double var = (double)sb[0] / statN - m * m;
        if (var < 0.0) var = 0.0;
        g_m1[c] = (float)m;
        g_i1[c] = rsqrtf((float)var + BN_EPS);
    }
}

__global__ void bn_apply_kernel(float* __restrict__ X, long total, int C, int act) {
    long t = (long)blockIdx.x * blockDim.x + threadIdx.x;
    if (t >= total) return;
    int c = (int)(t % C);
    float y = (X[t] - g_m1[c]) * g_i1[c];
    X[t] = (act == 0) ? fmaxf(y, 0.f) : (y >= 0.f ? y : 0.2f * y);
}

__global__ void bn_small_kernel(float* __restrict__ X, int C, float slope) {
    int c = blockIdx.x * blockDim.x + threadIdx.x;
    if (c >= C) return;
    double s = 0.0, ss = 0.0;
    for (int r = 0; r < 8; r++) { double v = X[r * C + c]; s += v; ss += v * v; }
    double m = s / 8.0;
    double var = ss / 8.0 - m * m;
    if (var < 0.0) var = 0.0;
    float inv = rsqrtf((float)var + BN_EPS);
    for (int r = 0; r < 8; r++) {
        float y = (X[r * C + c] - (float)m) * inv;
        X[r * C + c] = y >= 0.f ? y : slope * y;
    }
}

__global__ void reduce_part_kernel(int nBy, int O, int statN) {
    int c = blockIdx.x;
    int t = threadIdx.x;
    double a = 0.0, b = 0.0;
    for (int r = t; r < nBy; r += 256) {
        a += g_part[r * O + c];
        b += g_part[PART_OFF + r * O + c];
    }
    __shared__ double sa[256], sb[256];
    sa[t] = a; sb[t] = b;
    __syncthreads();
    for (int s = 128; s > 0; s >>= 1) {
        if (t < s) { sa[t] += sa[t + s]; sb[t] += sb[t + s]; }
        __syncthreads();
    }
    if (t == 0) {
        double m = sa[0] / statN;
        double var = sb[0] / statN - m * m;
        if (var < 0.0) var = 0.0;
        g_m2[c] = (float)m;
        g_i2[c] = rsqrtf((float)var + BN_EPS);
    }
}

// ----------------------------------------------------------------------------
// BN1 stats — one incremental pass over all 3 k-scales (R13 version)
// ----------------------------------------------------------------------------
__global__ void stats1_all_kernel(const float* __restrict__ U, const float* __restrict__ V,
                                  const int* __restrict__ knn, int S, int N, int C,
                                  int cpb, int nB, float* __restrict__ part) {
    int c = threadIdx.x;   // blockDim == C
    int blk = blockIdx.x;
    float s0 = 0.f, q0 = 0.f, s1 = 0.f, q1 = 0.f, s2 = 0.f, q2 = 0.f;
    for (int ss = 0; ss < cpb; ss++) {
        int s = blk * cpb + ss;
        int b = s / S;
        float v = V[(long)s * C + c];
        const int* kn = knn + (long)s * 64;
        for (int j = 0; j < 16; j++) {
            float x = U[((long)b * N + kn[j]) * C + c] + v;
            s0 += x; q0 += x * x;
        }
        for (int j = 16; j < 32; j++) {
            float x = U[((long)b * N + kn[j]) * C + c] + v;
            s1 += x; q1 += x * x;
        }
        for (int j = 32; j < 64; j++) {
            float x = U[((long)b * N + kn[j]) * C + c] + v;
            s2 += x; q2 += x * x;
        }
    }
    long base = (long)blk * C + c;
    long stride = (long)nB * C;
    part[0 * stride + base] = s0;
    part[1 * stride + base] = s1;
    part[2 * stride + base] = s2;
    part[3 * stride + base] = q0;
    part[4 * stride + base] = q1;
    part[5 * stride + base] = q2;
}

__global__ void stats1_fin_kernel(const float* __restrict__ part, int nB, int C, int S8) {
    int c = blockIdx.x * 128 + threadIdx.x;
    if (c >= C) return;
    long stride = (long)nB * C;
    float a0 = 0.f, a1 = 0.f, a2 = 0.f, b0 = 0.f, b1 = 0.f, b2 = 0.f;
    for (int r = 0; r < nB; r++) {
        long idx = (long)r * C + c;
        a0 += part[0 * stride + idx];
        a1 += part[1 * stride + idx];
        a2 += part[2 * stride + idx];
        b0 += part[3 * stride + idx];
        b1 += part[4 * stride + idx];
        b2 += part[5 * stride + idx];
    }
    double cs = a0, cq = b0;
    const int ks[3] = {16, 32, 64};
    double add_s[3] = {0.0, (double)a1, (double)a2};
    double add_q[3] = {0.0, (double)b1, (double)b2};
    for (int sc = 0; sc < 3; sc++) {
        cs += add_s[sc]; cq += add_q[sc];
        double n = (double)S8 * ks[sc];
        double m = cs / n;
        double var = cq / n - m * m;
        if (var < 0.0) var = 0.0;
        g_s1m[sc * 256 + c] = (float)m;
        g_s1i[sc * 256 + c] = rsqrtf((float)var + BN_EPS);
    }
}

// ----------------------------------------------------------------------------
// R14: 128x128 GEMM with double-buffered k-tiles (single sync per tile,
// global loads overlapped with FMA). __launch_bounds__ pins 2 blocks/SM.
// ----------------------------------------------------------------------------
__global__ __launch_bounds__(256, 2)
void gemm128_kernel(const float* __restrict__ A, const float* __restrict__ W,
                    const float* __restrict__ bias, float* __restrict__ C,
                    int R, int D, int O, int useStats) {
    __shared__ float As[2][16][132];
    __shared__ float Ws[2][16][132];
    __shared__ float sM[256];
    __shared__ float sI[256];
    int tid = threadIdx.x;
    if (useStats) {
        for (int c = tid; c < D; c += 256) { sM[c] = g_m1[c]; sI[c] = g_i1[c]; }
        __syncthreads();
    }
    long rowBase = (long)blockIdx.y * 128;
    int colBase = blockIdx.x * 128;
    int tr = tid >> 4, tc = tid & 15;
    int lrow = tid >> 2;
    int kq = (tid & 3) * 4;
    float acc[8][8];
    #pragma unroll
    for (int i = 0; i < 8; i++)
        #pragma unroll
        for (int j = 0; j < 8; j++) acc[i][j] = 0.f;

    int nT = D >> 4;
    // preload tile 0
    #pragma unroll
    for (int half = 0; half < 2; half++) {
        int row = lrow + 64 * half;
        float4 av = *(const float4*)(A + (rowBase + row) * D + kq);
        if (useStats) {
            av.x = fmaxf((av.x - sM[kq + 0]) * sI[kq + 0], 0.f);
            av.y = fmaxf((av.y - sM[kq + 1]) * sI[kq + 1], 0.f);
            av.z = fmaxf((av.z - sM[kq + 2]) * sI[kq + 2], 0.f);
            av.w = fmaxf((av.w - sM[kq + 3]) * sI[kq + 3], 0.f);
        }
        As[0][kq + 0][row] = av.x;
        As[0][kq + 1][row] = av.y;
        As[0][kq + 2][row] = av.z;
        As[0][kq + 3][row] = av.w;
        int wr = colBase + row;
        float4 wv = make_float4(0.f, 0.f, 0.f, 0.f);
        if (wr < O) wv = *(const float4*)(W + (long)wr * D + kq);
        Ws[0][kq + 0][row] = wv.x;
        Ws[0][kq + 1][row] = wv.y;
        Ws[0][kq + 2][row] = wv.z;
        Ws[0][kq + 3][row] = wv.w;
    }
    __syncthreads();

    int cur = 0;
    for (int t = 0; t < nT; t++) {
        float4 sa[2], sw[2];
        bool has = (t + 1) < nT;
        if (has) {
            int kc = (t + 1) * 16 + kq;
            #pragma unroll
            for (int half = 0; half < 2; half++) {
                int row = lrow + 64 * half;
                float4 av = *(const float4*)(A + (rowBase + row) * D + kc);
                if (useStats) {
                    av.x = fmaxf((av.x - sM[kc + 0]) * sI[kc + 0], 0.f);
                    av.y = fmaxf((av.y - sM[kc + 1]) * sI[kc + 1], 0.f);
                    av.z = fmaxf((av.z - sM[kc + 2]) * sI[kc + 2], 0.f);
                    av.w = fmaxf((av.w - sM[kc + 3]) * sI[kc + 3], 0.f);
                }
                sa[half] = av;
                int wr = colBase + row;
                float4 wv = make_float4(0.f, 0.f, 0.f, 0.f);
                if (wr < O) wv = *(const float4*)(W + (long)wr * D + kc);
                sw[half] = wv;
            }
        }
        #pragma unroll
        for (int kk = 0; kk < 16; kk++) {
            float a[8], w[8];
            *(float4*)(a + 0) = *(const float4*)&As[cur][kk][tr * 8 + 0];
            *(float4*)(a + 4) = *(const float4*)&As[cur][kk][tr * 8 + 4];
            *(float4*)(w + 0) = *(const float4*)&Ws[cur][kk][tc * 8 + 0];
            *(float4*)(w + 4) = *(const float4*)&Ws[cur][kk][tc * 8 + 4];
            #pragma unroll
            for (int i = 0; i < 8; i++)
                #pragma unroll
                for (int j = 0; j < 8; j++)
                    acc[i][j] += a[i] * w[j];
        }
        if (has) {
            int nxt = cur ^ 1;
            #pragma unroll
            for (int half = 0; half < 2; half++) {
                int row = lrow + 64 * half;
                As[nxt][kq + 0][row] = sa[half].x;
                As[nxt][kq + 1][row] = sa[half].y;
                As[nxt][kq + 2][row] = sa[half].z;
                As[nxt][kq + 3][row] = sa[half].w;
                Ws[nxt][kq + 0][row] = sw[half].x;
                Ws[nxt][kq + 1][row] = sw[half].y;
                Ws[nxt][kq + 2][row] = sw[half].z;
                Ws[nxt][kq + 3][row] = sw[half].w;
            }
        }
        __syncthreads();
        cur ^= 1;
    }
    #pragma unroll
    for (int i = 0; i < 8; i++) {
        long row = rowBase + tr * 8 + i;
        int col0 = colBase + tc * 8;
        if (col0 >= O) continue;
        float b0 = 0, b1 = 0, b2 = 0, b3 = 0, b4 = 0, b5 = 0, b6 = 0, b7 = 0;
        if (bias) {
            b0 = bias[col0 + 0]; b1 = bias[col0 + 1]; b2 = bias[col0 + 2]; b3 = bias[col0 + 3];
            b4 = bias[col0 + 4]; b5 = bias[col0 + 5]; b6 = bias[col0 + 6]; b7 = bias[col0 + 7];
        }
        float4 v0 = make_float4(acc[i][0] + b0, acc[i][1] + b1, acc[i][2] + b2, acc[i][3] + b3);
        float4 v1 = make_float4(acc[i][4] + b4, acc[i][5] + b5, acc[i][6] + b6, acc[i][7] + b7);
        *(float4*)(C + row * O + col0) = v0;
        *(float4*)(C + row * O + col0 + 4) = v1;
    }
}

// ----------------------------------------------------------------------------
// R14: fused local-op GEMM2, double-buffered (same pipeline as gemm128).
// Epilogue (pool max + BN2 partials) unchanged from R13.
// ----------------------------------------------------------------------------
__global__ __launch_bounds__(256, 2)
void local_gemm2_kernel(const float* __restrict__ U, const float* __restrict__ V,
                        const int* __restrict__ knn, const float* __restrict__ W,
                        float* __restrict__ poolOut,
                        int S, int N, int D, int O, int kshift,
                        int OC, int off,
                        const float* __restrict__ bn1M,
                        const float* __restrict__ bn1I) {
    __shared__ float As[2][16][132];
    __shared__ float Ws[2][16][132];
    __shared__ float sRed[16][132];
    __shared__ float sM[256];
    __shared__ float sI[256];
    __shared__ int sP[128];
    __shared__ int sS[128];
    int tid = threadIdx.x;
    long rowBase = (long)blockIdx.y * 128;
    int colBase = blockIdx.x * 128;

    for (int c = tid; c < D; c += 256) { sM[c] = bn1M[c]; sI[c] = bn1I[c]; }
    if (tid < 128) {
        long grow = rowBase + tid;
        int s = (int)(grow >> kshift);
        int j = (int)(grow & ((1 << kshift) - 1));
        int b = s / S;
        sS[tid] = s;
        sP[tid] = b * N + knn[(long)s * 64 + j];
    }
    __syncthreads();

    int tr = tid >> 4, tc = tid & 15;
    int lrow = tid >> 2;
    int kq = (tid & 3) * 4;
    float acc[8][8];
    #pragma unroll
    for (int i = 0; i < 8; i++)
        #pragma unroll
        for (int j = 0; j < 8; j++) acc[i][j] = 0.f;

    int nT = D >> 4;
    int p0 = sP[lrow], p1 = sP[lrow + 64];
    int s0i = sS[lrow], s1i = sS[lrow + 64];
    // preload tile 0
    {
        #pragma unroll
        for (int half = 0; half < 2; half++) {
            int row = lrow + 64 * half;
            int pi = half ? p1 : p0;
            int si = half ? s1i : s0i;
            float4 uv = *(const float4*)(U + (long)pi * D + kq);
            float4 vv = *(const float4*)(V + (long)si * D + kq);
            As[0][kq + 0][row] = fmaxf((uv.x + vv.x - sM[kq + 0]) * sI[kq + 0], 0.f);
            As[0][kq + 1][row] = fmaxf((uv.y + vv.y - sM[kq + 1]) * sI[kq + 1], 0.f);
            As[0][kq + 2][row] = fmaxf((uv.z + vv.z - sM[kq + 2]) * sI[kq + 2], 0.f);
            As[0][kq + 3][row] = fmaxf((uv.w + vv.w - sM[kq + 3]) * sI[kq + 3], 0.f);
            float4 wv = *(const float4*)(W + (long)(colBase + row) * D + kq);
            Ws[0][kq + 0][row] = wv.x;
            Ws[0][kq + 1][row] = wv.y;
            Ws[0][kq + 2][row] = wv.z;
            Ws[0][kq + 3][row] = wv.w;
        }
    }
    __syncthreads();

    int cur = 0;
    for (int t = 0; t < nT; t++) {
        float4 sa[2], sw[2];
        bool has = (t + 1) < nT;
        if (has) {
            int kc = (t + 1) * 16 + kq;
            #pragma unroll
            for (int half = 0; half < 2; half++) {
                int row = lrow + 64 * half;
                int pi = half ? p1 : p0;
                int si = half ? s1i : s0i;
                float4 uv = *(const float4*)(U + (long)pi * D + kc);
                float4 vv = *(const float4*)(V + (long)si * D + kc);
                float4 av;
                av.x = fmaxf((uv.x + vv.x - sM[kc + 0]) * sI[kc + 0], 0.f);
                av.y = fmaxf((uv.y + vv.y - sM[kc + 1]) * sI[kc + 1], 0.f);
                av.z = fmaxf((uv.z + vv.z - sM[kc + 2]) * sI[kc + 2], 0.f);
                av.w = fmaxf((uv.w + vv.w - sM[kc + 3]) * sI[kc + 3], 0.f);
                sa[half] = av;
                sw[half] = *(const float4*)(W + (long)(colBase + row) * D + kc);
            }
        }
        #pragma unroll
        for (int kk = 0; kk < 16; kk++) {
            float a[8], w[8];
            *(float4*)(a + 0) = *(const float4*)&As[cur][kk][tr * 8 + 0];
            *(float4*)(a + 4) = *(const float4*)&As[cur][kk][tr * 8 + 4];
            *(float4*)(w + 0) = *(const float4*)&Ws[cur][kk][tc * 8 + 0];
            *(float4*)(w + 4) = *(const float4*)&Ws[cur][kk][tc * 8 + 4];
            #pragma unroll
            for (int i = 0; i < 8; i++)
                #pragma unroll
                for (int j = 0; j < 8; j++)
                    acc[i][j] += a[i] * w[j];
        }
        if (has) {
            int nxt = cur ^ 1;
            #pragma unroll
            for (int half = 0; half < 2; half++) {
                int row = lrow + 64 * half;
                As[nxt][kq + 0][row] = sa[half].x;
                As[nxt][kq + 1][row] = sa[half].y;
                As[nxt][kq + 2][row] = sa[half].z;
                As[nxt][kq + 3][row] = sa[half].w;
                Ws[nxt][kq + 0][row] = sw[half].x;
                Ws[nxt][kq + 1][row] = sw[half].y;
                Ws[nxt][kq + 2][row] = sw[half].z;
                Ws[nxt][kq + 3][row] = sw[half].w;
            }
        }
        __syncthreads();
        cur ^= 1;
    }

    // epilogue 1: per-center raw max -> poolOut
    int g = (1 << kshift) >> 3;
    #pragma unroll
    for (int j = 0; j < 8; j++) {
        float m = acc[0][j];
        #pragma unroll
        for (int i = 1; i < 8; i++) m = fmaxf(m, acc[i][j]);
        sRed[tr][tc * 8 + j] = m;
    }
    __syncthreads();
    if ((tr & (g - 1)) == 0) {
        int s = sS[tr * 8];
        #pragma unroll
        for (int j = 0; j < 8; j++) {
            float m = sRed[tr][tc * 8 + j];
            for (int q = 1; q < g; q++) m = fmaxf(m, sRed[tr + q][tc * 8 + j]);
            poolOut[(long)s * OC + off + colBase + tc * 8 + j] = m;
        }
    }
    __syncthreads();
    // epilogue 2: per-block channel sums -> g_part
    #pragma unroll
    for (int j = 0; j < 8; j++) {
        float sm = 0.f;
        #pragma unroll
        for (int i = 0; i < 8; i++) sm += acc[i][j];
        sRed[tr][tc * 8 + j] = sm;
    }
    __syncthreads();
    if (tr == 0) {
        #pragma unroll
        for (int j = 0; j < 8; j++) {
            float tot = 0.f;
            for (int q = 0; q < 16; q++) tot += sRed[q][tc * 8 + j];
            g_part[(long)blockIdx.y * O + colBase + tc * 8 + j] = tot;
        }
    }
    __syncthreads();
    #pragma unroll
    for (int j = 0; j < 8; j++) {
        float sm = 0.f;
        #pragma unroll
        for (int i = 0; i < 8; i++) sm += acc[i][j] * acc[i][j];
        sRed[tr][tc * 8 + j] = sm;
    }
    __syncthreads();
    if (tr == 0) {
        #pragma unroll
        for (int j = 0; j < 8; j++) {
            float tot = 0.f;
            for (int q = 0; q < 16; q++) tot += sRed[q][tc * 8 + j];
            g_part[PART_OFF + (long)blockIdx.y * O + colBase + tc * 8 + j] = tot;
        }
    }
}

// pool[s, off+c] = relu(bn2(rawmax)) via g_m2/g_i2
__global__ void pool_finalize_kernel(float* __restrict__ pool, int OC, int off) {
    int s = blockIdx.x;
    int c = threadIdx.x;
    long p = (long)s * OC + off + c;
    pool[p] = fmaxf((pool[p] - g_m2[c]) * g_i2[c], 0.f);
}

__global__ void split_w1_kernel(const float* __restrict__ w1, float* __restrict__ wa,
                                float* __restrict__ wd, int O, int D, int total) {
    int t = blockIdx.x * 256 + threadIdx.x;
    if (t >= total) return;
    int d = t % D, o = t / D;
    float a = w1[(long)o * 2 * D + d];
    float b = w1[(long)o * 2 * D + D + d];
    wa[t] = a;
    wd[t] = b - a;
}

// ----------------------------------------------------------------------------
// Generic fallback GEMM (odd shapes)
// ----------------------------------------------------------------------------
__global__ void gemm_kernel(const float* __restrict__ A, const float* __restrict__ W,
                            const float* __restrict__ bias, float* __restrict__ C,
                            int R, int D, int O) {
    __shared__ float As[64][17];
    __shared__ float Ws[64][17];
    int tid = threadIdx.x;
    int tr = tid >> 4, tc = tid & 15;
    long rowBase = (long)blockIdx.y * 64;
    int colBase = blockIdx.x * 64;
    float acc[4][4] = {};
    for (int k0 = 0; k0 < D; k0 += 16) {
        #pragma unroll
        for (int e = tid; e < 1024; e += 256) {
            int rr = e >> 4, kk = e & 15;
            long ar = rowBase + rr; int ac = k0 + kk;
            As[rr][kk] = (ar < R && ac < D) ? A[ar * D + ac] : 0.f;
            int wr = colBase + rr;
            Ws[rr][kk] = (wr < O && ac < D) ? W[(long)wr * D + ac] : 0.f;
        }
        __syncthreads();
        #pragma unroll
        for (int kk = 0; kk < 16; kk++) {
            float a[4], w[4];
            #pragma unroll
            for (int i = 0; i < 4; i++) a[i] = As[tr + 16*i][kk];
            #pragma unroll
            for (int j = 0; j < 4; j++) w[j] = Ws[tc + 16*j][kk];
            #pragma unroll
            for (int i = 0; i < 4; i++)
                #pragma unroll
                for (int j = 0; j < 4; j++)
                    acc[i][j] += a[i] * w[j];
        }
        __syncthreads();
    }
    #pragma unroll
    for (int i = 0; i < 4; i++) {
        long row = rowBase + tr + 16*i;
        if (row >= R) continue;
        #pragma unroll
        for (int j = 0; j < 4; j++) {
            int col = colBase + tc + 16*j;
            if (col >= O) continue;
            float vv = acc[i][j];
            if (bias) vv += bias[col];
            C[row * O + col] = vv;
        }
    }
}

// ----------------------------------------------------------------------------
// Layout / elementwise helpers
// ----------------------------------------------------------------------------
__global__ void transpose_x_kernel(const float* __restrict__ x, float* __restrict__ xyz) {
    int t = blockIdx.x * 256 + threadIdx.x;
    if (t >= 8 * 2048 * 3) return;
    int c = t % 3; int n = (t / 3) % 2048; int b = t / (3 * 2048);
    xyz[t] = x[((long)b * 3 + c) * 2048 + n];
}

__global__ void gather_kernel(const float* __restrict__ src, const int* __restrict__ idx,
                              float* __restrict__ dst, int S, int N, int D, long total) {
    long t = (long)blockIdx.x * blockDim.x + threadIdx.x;
    if (t >= total) return;
    int c = (int)(t % D); long bs = t / D;
    int b = (int)(bs / S);
    dst[t] = src[((long)b * N + idx[bs]) * D + c];
}

__global__ void catf1_kernel(const float* __restrict__ f1, float* __restrict__ cat) {
    int t = blockIdx.x * 256 + threadIdx.x;
    int c = t & 255; int row = t >> 8;
    cat[(long)row * 1280 + 1024 + c] = f1[t];
}

__global__ void maxn_kernel(const float* __restrict__ X, float* __restrict__ G) {
    int b = blockIdx.x; int c = blockIdx.y * 256 + threadIdx.x;
    float m = -FLT_MAX;
    for (int n = 0; n < 256; n++) m = fmaxf(m, X[((long)b * 256 + n) * 1024 + c]);
    G[b * 1024 + c] = m;
}

// ----------------------------------------------------------------------------
// FPS / kNN with warp-shuffle reductions (tie order preserved)
// ----------------------------------------------------------------------------
__device__ __forceinline__ unsigned keymap(float f) {
    unsigned u = __float_as_uint(f);
    return (u & 0x80000000u) ? ~u : (u | 0x80000000u);
}

__device__ void fps_body(const float* __restrict__ xyz, int N, int npoint,
                         int* __restrict__ outIdx, int b,
                         float* sx, float* sy, float* sz, float* sd,
                         unsigned long long* warpBest, int* sFar) {
    int t = threadIdx.x;
    int nt = blockDim.x;
    int numWarps = nt >> 5;
    for (int n = t; n < N; n += nt) {
        sx[n] = xyz[((long)b * N + n) * 3 + 0];
        sy[n] = xyz[((long)b * N + n) * 3 + 1];
        sz[n] = xyz[((long)b * N + n) * 3 + 2];
        sd[n] = 1e10f;
    }
    __syncthreads();
    int far = 0;
    for (int it = 0; it < npoint; it++) {
        if (t == 0) outIdx[b * npoint + it] = far;
        float cx = sx[far], cy = sy[far], cz = sz[far];
        unsigned long long best = 0ull;
        for (int n = t; n < N; n += nt) {
            float dx = sx[n] - cx, dy = sy[n] - cy, dz = sz[n] - cz;
            float d = dx * dx + dy * dy + dz * dz;
            float dm = fminf(sd[n], d);
            sd[n] = dm;
            unsigned long long key = ((unsigned long long)keymap(dm) << 32) | (unsigned)(~n);
            if (key > best) best = key;
        }
        #pragma unroll
        for (int o = 16; o > 0; o >>= 1) {
            unsigned long long other = __shfl_xor_sync(0xffffffffu, best, o);
            if (other > best) best = other;
        }
        if ((t & 31) == 0) warpBest[t >> 5] = best;
        __syncthreads();
        if (t < 32) {
            unsigned long long v = (t < numWarps) ? warpBest[t] : 0ull;
            #pragma unroll
            for (int o = 16; o > 0; o >>= 1) {
                unsigned long long other = __shfl_xor_sync(0xffffffffu, v, o);
                if (other > v) v = other;
            }
            if (t == 0) *sFar = (int)(~((unsigned)(v & 0xffffffffu)));
        }
        __syncthreads();
        far = *sFar;
    }
}

__device__ void knn_body(const float* __restrict__ centers, const float* __restrict__ xyz,
                         int S, int N, int* __restrict__ knnOut, int bs,
                         float* sd, unsigned long long* warpBest) {
    int t = threadIdx.x;
    int nt = blockDim.x;
    int numWarps = nt >> 5;
    int b = bs / S;
    float cx = centers[(long)bs * 3 + 0];
    float cy = centers[(long)bs * 3 + 1];
    float cz = centers[(long)bs * 3 + 2];
    float cn = cx * cx + cy * cy + cz * cz;
    for (int n = t; n < N; n += nt) {
        float px = xyz[((long)b * N + n) * 3 + 0];
        float py = xyz[((long)b * N + n) * 3 + 1];
        float pz = xyz[((long)b * N + n) * 3 + 2];
        float pn = px * px + py * py + pz * pz;
        float dot = cx * px + cy * py + cz * pz;
        sd[n] = cn + pn - 2.f * dot;
    }
    __syncthreads();
    for (int j = 0; j < 64; j++) {
        unsigned long long best = 0xFFFFFFFFFFFFFFFFull;
        for (int n = t; n < N; n += nt) {
            unsigned long long key = ((unsigned long long)keymap(sd[n]) << 32) | (unsigned)n;
            if (key < best) best = key;
        }
        #pragma unroll
        for (int o = 16; o > 0; o >>= 1) {
            unsigned long long other = __shfl_xor_sync(0xffffffffu, best, o);
            if (other < best) best = other;
        }
        if ((t & 31) == 0) warpBest[t >> 5] = best;
        __syncthreads();
        if (t < 32) {
            unsigned long long v = (t < numWarps) ? warpBest[t] : 0xFFFFFFFFFFFFFFFFull;
            #pragma unroll
            for (int o = 16; o > 0; o >>= 1) {
                unsigned long long other = __shfl_xor_sync(0xffffffffu, v, o);
                if (other < v) v = other;
            }
            if (t == 0) {
                int sel = (int)(v & 0xffffffffu);
                knnOut[(long)bs * 64 + j] = sel;
                sd[sel] = FLT_MAX;
            }
        }
        __syncthreads();
    }
}

__global__ void fps_kernel(const float* xyz, int N, int npoint, int* outIdx) {
    __shared__ float buf[4 * 2048];
    __shared__ unsigned long long wb[32];
    __shared__ int sFar;
    fps_body(xyz, N, npoint, outIdx, blockIdx.x, buf, buf + N, buf + 2 * N, buf + 3 * N, wb, &sFar);
}

__global__ void knn_kernel(const float* centers, const float* xyz, int S, int N, int* knnOut) {
    __shared__ float buf[2048];
    __shared__ unsigned long long wb[32];
    knn_body(centers, xyz, S, N, knnOut, blockIdx.x, buf, wb);
}

__global__ void knn_fps_kernel(const float* centers, const float* xyz, int S, int N,
                               int* knnOut, int nKnn,
                               const float* xyz2, int N2, int np2, int* outIdx2) {
    __shared__ float buf[4 * 2048];
    __shared__ unsigned long long wb[32];
    __shared__ int sFar;
    if (blockIdx.x < nKnn) {
        knn_body(centers, xyz, S, N, knnOut, blockIdx.x, buf, wb);
    } else {
        int b = blockIdx.x - nKnn;
        fps_body(xyz2, N2, np2, outIdx2, b, buf, buf + N2, buf + 2 * N2, buf + 3 * N2, wb, &sFar);
    }
}

// ----------------------------------------------------------------------------
// Attention (reference reshape quirk preserved)
// ----------------------------------------------------------------------------
__global__ void gemmqv_kernel(const float* __restrict__ xx, const float* __restrict__ pos,
                              const float* __restrict__ wqk, const float* __restrict__ wv,
                              const float* __restrict__ bv,
                              float* __restrict__ qb, float* __restrict__ vb) {
    __shared__ float As[16][132];
    __shared__ float Ws[16][132];
    int tid = threadIdx.x;
    long rowBase = (long)blockIdx.y * 128;
    int colBase = blockIdx.x * 128;
    int tr = tid >> 4, tc = tid & 15;
    int lrow = tid >> 2;
    int lkq = tid & 3;
    const int D = 256;
    float acc[8][8];
    #pragma unroll
    for (int i = 0; i < 8; i++)
        #pragma unroll
        for (int j = 0; j < 8; j++) acc[i][j] = 0.f;

    for (int k0 = 0; k0 < D; k0 += 16) {
        #pragma unroll
        for (int half = 0; half < 2; half++) {
            int row = lrow + 64 * half;
            int kc = k0 + lkq * 4;
            float4 av = *(const float4*)(xx + (rowBase + row) * D + kc);
            float4 pv = *(const float4*)(pos + (rowBase + row) * D + kc);
            As[lkq * 4 + 0][row] = av.x + pv.x;
            As[lkq * 4 + 1][row] = av.y + pv.y;
            As[lkq * 4 + 2][row] = av.z + pv.z;
            As[lkq * 4 + 3][row] = av.w + pv.w;
            int ocol = colBase + row;
            const float* Wp = (ocol < 256) ? (wqk + (long)ocol * D) : (wv + (long)(ocol - 256) * D);
            float4 wvv = *(const float4*)(Wp + kc);
            Ws[lkq * 4 + 0][row] = wvv.x;
            Ws[lkq * 4 + 1][row] = wvv.y;
            Ws[lkq * 4 + 2][row] = wvv.z;
            Ws[lkq * 4 + 3][row] = wvv.w;
        }
        __syncthreads();
        #pragma unroll
        for (int kk = 0; kk < 16; kk++) {
            float a[8], w[8];
            *(float4*)(a + 0) = *(const float4*)&As[kk][tr * 8 + 0];
            *(float4*)(a + 4) = *(const float4*)&As[kk][tr * 8 + 4];
            *(float4*)(w + 0) = *(const float4*)&Ws[kk][tc * 8 + 0];
            *(float4*)(w + 4) = *(const float4*)&Ws[kk][tc * 8 + 4];
            #pragma unroll
            for (int i = 0; i < 8; i++)
                #pragma unroll
                for (int j = 0; j < 8; j++)
                    acc[i][j] += a[i] * w[j];
        }
        __syncthreads();
    }
    int col0 = colBase + tc * 8;
    #pragma unroll
    for (int i = 0; i < 8; i++) {
        long row = rowBase + tr * 8 + i;
        if (col0 < 256) {
            float4 v0 = make_float4(acc[i][0], acc[i][1], acc[i][2], acc[i][3]);
            float4 v1 = make_float4(acc[i][4], acc[i][5], acc[i][6], acc[i][7]);
            *(float4*)(qb + row * 256 + col0) = v0;
            *(float4*)(qb + row * 256 + col0 + 4) = v1;
        } else {
            int cc = col0 - 256;
            float4 v0 = make_float4(acc[i][0] + bv[cc + 0], acc[i][1] + bv[cc + 1],
                                    acc[i][2] + bv[cc + 2], acc[i][3] + bv[cc + 3]);
            float4 v1 = make_float4(acc[i][4] + bv[cc + 4], acc[i][5] + bv[cc + 5],
                                    acc[i][6] + bv[cc + 6], acc[i][7] + bv[cc + 7]);
            *(float4*)(vb + row * 256 + cc) = v0;
            *(float4*)(vb + row * 256 + cc + 4) = v1;
        }
    }
}

__global__ void gram_kernel(const float* __restrict__ Q, float* __restrict__ A) {
    int bh = blockIdx.z; int b = bh >> 2; int h = bh & 3;
    int i0 = blockIdx.y * 16, j0 = blockIdx.x * 16;
    __shared__ float Qi[16][65];
    __shared__ float Qj[16][65];
    int tid = threadIdx.x;
    for (int e = tid; e < 1024; e += 256) {
        int r = e >> 6, d = e & 63;
        int i = i0 + r;
        Qi[r][d] = Q[((long)b * 256 + h * 64 + (i >> 2)) * 256 + (i & 3) * 64 + d];
        Qj[r][d] = Q[((long)b * 256 + j0 + r) * 256 + h * 64 + d];
    }
    __syncthreads();
    int ti = tid >> 4, tj = tid & 15;
    float acc = 0.f;
    #pragma unroll
    for (int d = 0; d < 64; d++) acc += Qi[ti][d] * Qj[tj][d];
    A[((long)bh * 256 + (i0 + ti)) * 256 + (j0 + tj)] = acc;
}

__global__ void softmax_row_kernel(float* __restrict__ A) {
    __shared__ float red[256];
    long row = blockIdx.x;
    float* p = A + row * 256;
    int t = threadIdx.x;
    float v = p[t];
    red[t] = v; __syncthreads();
    for (int s = 128; s > 0; s >>= 1) { if (t < s) red[t] = fmaxf(red[t], red[t + s]); __syncthreads(); }
    float m = red[0]; __syncthreads();
    float e = expf(v - m);
    red[t] = e; __syncthreads();
    for (int s = 128; s > 0; s >>= 1) { if (t < s) red[t] += red[t + s]; __syncthreads(); }
    p[t] = e / red[0];
}

__global__ void colsm_xr_kernel(const float* __restrict__ attn, const float* __restrict__ V,
                                const float* __restrict__ xx, const float* __restrict__ pos,
                                float* __restrict__ xrb) {
    int b = blockIdx.x >> 8;
    int i = blockIdx.x & 255;
    int t = threadIdx.x;
    __shared__ float colv[4][256];
    __shared__ float4 r4[256];
    #pragma unroll
    for (int h = 0; h < 4; h++)
        colv[h][t] = attn[(((long)(b * 4 + h)) * 256 + t) * 256 + i];
    float4 vm = make_float4(colv[0][t], colv[1][t], colv[2][t], colv[3][t]);
    r4[t] = vm;
    __syncthreads();
    for (int s = 128; s > 0; s >>= 1) {
        if (t < s) {
            float4 o = r4[t + s];
            r4[t].x = fmaxf(r4[t].x, o.x); r4[t].y = fmaxf(r4[t].y, o.y);
            r4[t].z = fmaxf(r4[t].z, o.z); r4[t].w = fmaxf(r4[t].w, o.w);
        }
        __syncthreads();
    }
    float4 mx = r4[0];
    __syncthreads();
    float4 ev = make_float4(expf(vm.x - mx.x), expf(vm.y - mx.y),
                            expf(vm.z - mx.z), expf(vm.w - mx.w));
    r4[t] = ev;
    __syncthreads();
    for (int s = 128; s > 0; s >>= 1) {
        if (t < s) {
            float4 o = r4[t + s];
            r4[t].x += o.x; r4[t].y += o.y; r4[t].z += o.z; r4[t].w += o.w;
        }
        __syncthreads();
    }
    float4 sm = r4[0];
    __syncthreads();
    colv[0][t] = ev.x / sm.x;
    colv[1][t] = ev.y / sm.y;
    colv[2][t] = ev.z / sm.z;
    colv[3][t] = ev.w / sm.w;
    __syncthreads();
    int c = t; int h = c >> 6;
    const float* vp = V + ((long)b * 256) * 256 + c;
    float acc = 0.f;
    #pragma unroll 8
    for (int j = 0; j < 256; j++) acc += vp[(long)j * 256] * colv[h][j];
    long row = (long)b * 256 + i;
    xrb[row * 256 + c] = xx[row * 256 + c] + pos[row * 256 + c] - acc;
}

__global__ void addcat_bn_kernel(const float* __restrict__ qb, float* __restrict__ xx,
                                 const float* __restrict__ pos, float* __restrict__ cat,
                                 int layer) {
    int t = blockIdx.x * 256 + threadIdx.x;
    int c = t & 255; int row = t >> 8;
    float y = fmaxf((qb[t] - g_m1[c]) * g_i1[c], 0.f);
    float v = xx[t] + pos[t] + y;
    xx[t] = v;
    cat[(long)row * 1280 + layer * 256 + c] = v;
}

// ----------------------------------------------------------------------------
// Host orchestration
// ----------------------------------------------------------------------------
static void gemm_old(const float* A, const float* W, const float* bias, float* C,
                     int R, int D, int O) {
    dim3 grid(CEILDIV(O, 64), CEILDIV(R, 64));
    gemm_kernel<<<grid, 256>>>(A, W, bias, C, R, D, O);
}

static void gemm_big(const float* A, const float* W, const float* bias, float* C,
                     int R, int D, int O, int useStats) {
    dim3 grid(CEILDIV(O, 128), R / 128);
    gemm128_kernel<<<grid, 256>>>(A, W, bias, C, R, D, O, useStats);
}

static float* s_part;

static void computeStats(const float* X, int R, int C) {
    int rpb = R / 512;
    if (rpb < 8) rpb = 8;
    int nB = R / rpb;
    stats_part_kernel<<<nB, 256>>>(X, R, C, rpb, nB, s_part);
    reduce_m1_kernel<<<C, 256>>>(s_part, nB, C, R);
}

static void bn(float* X, int R, int C, int act) {
    computeStats(X, R, C);
    long total = (long)R * C;
    bn_apply_kernel<<<(int)CEILDIV(total, 256), 256>>>(X, total, C, act);
}

extern "C" void kernel_launch(void* const* d_in, const int* in_sizes, int n_in,
                              void* d_out, int out_size) {
    const float* x       = (const float*)d_in[0];
    const float* conv1_w = (const float*)d_in[1];
    const float* conv2_w = (const float*)d_in[2];
    const float* g0_w1   = (const float*)d_in[3];
    const float* g0_w2   = (const float*)d_in[4];
    const float* g0_wc   = (const float*)d_in[5];
    const float* g1_w1   = (const float*)d_in[6];
    const float* g1_w2   = (const float*)d_in[7];
    const float* g1_wc   = (const float*)d_in[8];
    const float* pt_w    = (const float*)d_in[9];
    const float* pos_w   = (const float*)d_in[10];
    const float* pos_b   = (const float*)d_in[11];
    const float* sa_wqk  = (const float*)d_in[12];
    const float* sa_wv   = (const float*)d_in[13];
    const float* sa_bv   = (const float*)d_in[14];
    const float* sa_wt   = (const float*)d_in[15];
    const float* sa_bt   = (const float*)d_in[16];
    const float* fuse_w  = (const float*)d_in[17];
    const float* lin1_w  = (const float*)d_in[18];
    const float* lin2_w  = (const float*)d_in[19];
    const float* lin2_b  = (const float*)d_in[20];
    const float* lin3_w  = (const float*)d_in[21];
    const float* lin3_b  = (const float*)d_in[22];
    float* out = (float*)d_out;

    float *xyz, *h1, *points, *newxyz, *newxyz2, *newpts, *Ub, *Vb, *w1a, *w1d, *pool, *f0, *f1;
    float *pos, *xx, *qb, *vb, *xrb, *attn, *catb, *fuseb, *gmax, *l1, *l2, *s1m, *s1i;
    int *fpsidx, *knn, *knn2;
    cudaGetSymbolAddress((void**)&xyz, g_xyz);
    cudaGetSymbolAddress((void**)&h1, g_h1);
    cudaGetSymbolAddress((void**)&points, g_points);
    cudaGetSymbolAddress((void**)&fpsidx, g_fpsidx);
    cudaGetSymbolAddress((void**)&newxyz, g_newxyz);
    cudaGetSymbolAddress((void**)&newxyz2, g_newxyz2);
    cudaGetSymbolAddress((void**)&newpts, g_newpts);
    cudaGetSymbolAddress((void**)&knn, g_knn);
    cudaGetSymbolAddress((void**)&knn2, g_knn2);
    cudaGetSymbolAddress((void**)&Ub, g_U);
    cudaGetSymbolAddress((void**)&Vb, g_V);
    cudaGetSymbolAddress((void**)&w1a, g_w1a);
    cudaGetSymbolAddress((void**)&w1d, g_w1d);
    cudaGetSymbolAddress((void**)&s_part, g_part);
    cudaGetSymbolAddress((void**)&pool, g_pool);
    cudaGetSymbolAddress((void**)&f0, g_f0);
    cudaGetSymbolAddress((void**)&f1, g_f1);
    cudaGetSymbolAddress((void**)&pos, g_pos);
    cudaGetSymbolAddress((void**)&xx, g_x);
    cudaGetSymbolAddress((void**)&qb, g_q);
    cudaGetSymbolAddress((void**)&vb, g_v);
    cudaGetSymbolAddress((void**)&xrb, g_xr);
    cudaGetSymbolAddress((void**)&attn, g_attn);
    cudaGetSymbolAddress((void**)&catb, g_cat);
    cudaGetSymbolAddress((void**)&fuseb, g_fuse);
    cudaGetSymbolAddress((void**)&gmax, g_gmax);
    cudaGetSymbolAddress((void**)&l1, g_l1);
    cudaGetSymbolAddress((void**)&l2, g_l2);
    cudaGetSymbolAddress((void**)&s1m, g_s1m);
    cudaGetSymbolAddress((void**)&s1i, g_s1i);

    // ---- Stage A ----
    transpose_x_kernel<<<CEILDIV(8*2048*3, 256), 256>>>(x, xyz);
    gemm_old(xyz, conv1_w, nullptr, h1, 16384, 3, 64);
    computeStats(h1, 16384, 64);
    gemm_big(h1, conv2_w, nullptr, points, 16384, 64, 64, 1);
    bn(points, 16384, 64, 0);

    // ---- Stage B ----
    fps_kernel<<<8, 1024>>>(xyz, 2048, 512, fpsidx);
    gather_kernel<<<CEILDIV(8*512*3, 256), 256>>>(xyz, fpsidx, newxyz, 512, 2048, 3, 8L*512*3);
    gather_kernel<<<CEILDIV(8*512*64, 256), 256>>>(points, fpsidx, newpts, 512, 2048, 64, 8L*512*64);
    knn_fps_kernel<<<4096 + 8, 256>>>(newxyz, xyz, 512, 2048, knn, 4096,
                                      newxyz, 512, 256, fpsidx);
    gather_kernel<<<CEILDIV(8*256*3, 256), 256>>>(newxyz, fpsidx, newxyz2, 256, 512, 3, 8L*256*3);
    knn_kernel<<<2048, 256>>>(newxyz2, newxyz, 256, 512, knn2);

    // ---- Stage C ----
    {
        split_w1_kernel<<<CEILDIV(128*64, 256), 256>>>(g0_w1, w1a, w1d, 128, 64, 128*64);
        gemm_big(points, w1a, nullptr, Ub, 16384, 64, 128, 0);
        gemm_big(newpts, w1d, nullptr, Vb, 4096, 64, 128, 0);
        stats1_all_kernel<<<256, 128>>>(Ub, Vb, knn, 512, 2048, 128, 16, 256, s_part);
        stats1_fin_kernel<<<1, 128>>>(s_part, 256, 128, 8*512);
        const int kshift[3] = {4, 5, 6};
        for (int si = 0; si < 3; si++) {
            int R = 8 * 512 * (1 << kshift[si]);
            int nBy = R / 128;
            dim3 grid(1, nBy);
            local_gemm2_kernel<<<grid, 256>>>(Ub, Vb, knn, g0_w2, pool,
                                              512, 2048, 128, 128, kshift[si], 384, si * 128,
                                              s1m + si * 256, s1i + si * 256);
            reduce_part_kernel<<<128, 256>>>(nBy, 128, R);
            pool_finalize_kernel<<<4096, 128>>>(pool, 384, si * 128);
        }
        gemm_big(pool, g0_wc, nullptr, f0, 4096, 384, 128, 0);
        bn(f0, 4096, 128, 0);
    }

    // ---- Stage D gather ----
    gather_kernel<<<CEILDIV(8*256*128, 256), 256>>>(f0, fpsidx, newpts, 256, 512, 128, 8L*256*128);

    // ---- Stage E ----
    {
        split_w1_kernel<<<CEILDIV(256*128, 256), 256>>>(g1_w1, w1a, w1d, 256, 128, 256*128);
        gemm_big(f0, w1a, nullptr, Ub, 4096, 128, 256, 0);
        gemm_big(newpts, w1d, nullptr, Vb, 2048, 128, 256, 0);
        stats1_all_kernel<<<128, 256>>>(Ub, Vb, knn2, 256, 512, 256, 16, 128, s_part);
        stats1_fin_kernel<<<2, 128>>>(s_part, 128, 256, 8*256);
        const int kshift[3] = {4, 5, 6};
        for (int si = 0; si < 3; si++) {
            int R = 8 * 256 * (1 << kshift[si]);
            int nBy = R / 128;
            dim3 grid(2, nBy);
            local_gemm2_kernel<<<grid, 256>>>(Ub, Vb, knn2, g1_w2, pool,
                                              256, 512, 256, 256, kshift[si], 768, si * 256,
                                              s1m + si * 256, s1i + si * 256);
            reduce_part_kernel<<<256, 256>>>(nBy, 256, R);
            pool_finalize_kernel<<<2048, 256>>>(pool, 768, si * 256);
        }
        gemm_big(pool, g1_wc, nullptr, f1, 2048, 768, 256, 0);
        bn(f1, 2048, 256, 0);
    }

    // ---- Stage F ----
    gemm_old(newxyz2, pos_w, pos_b, pos, 2048, 3, 256);
    gemm_big(f1, pt_w, nullptr, xx, 2048, 256, 256, 0);
    bn(xx, 2048, 256, 0);

    // ---- Stage G ----
    for (int i = 0; i < 4; i++) {
        gemmqv_kernel<<<dim3(4, 16), 256>>>(xx, pos,
                                            sa_wqk + (long)i * 256 * 256,
                                            sa_wv + (long)i * 256 * 256,
                                            sa_bv + i * 256, qb, vb);
        gram_kernel<<<dim3(16, 16, 32), 256>>>(qb, attn);
        softmax_row_kernel<<<8192, 256>>>(attn);
        colsm_xr_kernel<<<2048, 256>>>(attn, vb, xx, pos, xrb);
        gemm_big(xrb, sa_wt + (long)i * 256 * 256, sa_bt + i * 256, qb, 2048, 256, 256, 0);
        computeStats(qb, 2048, 256);
        addcat_bn_kernel<<<2048, 256>>>(qb, xx, pos, catb, i);
    }
    catf1_kernel<<<2048, 256>>>(f1, catb);

    // ---- Stage H ----
    gemm_big(catb, fuse_w, nullptr, fuseb, 2048, 1280, 1024, 0);
    bn(fuseb, 2048, 1024, 1);
    maxn_kernel<<<dim3(8, 4), 256>>>(fuseb, gmax);
    gemm_old(gmax, lin1_w, nullptr, l1, 8, 1024, 512);
    bn_small_kernel<<<2, 256>>>(l1, 512, 0.2f);
    gemm_old(l1, lin2_w, lin2_b, l2, 8, 512, 256);
    bn_small_kernel<<<1, 256>>>(l2, 256, 0.2f);
    gemm_old(l2, lin3_w, lin3_b, out, 8, 256, 40);
}

// round 15
// speedup vs baseline: 1.1690x; 1.0354x over previous
#include <cuda_runtime.h>
#include <math.h>
#include <float.h>

#define CEILDIV(a,b) (((a)+(b)-1)/(b))
#define BN_EPS 1e-5f
#define PART_OFF (2048*256)

// ----------------------------------------------------------------------------
// Scratch (device globals)
// ----------------------------------------------------------------------------
__device__ float g_xyz[8*2048*3];
__device__ float g_h1[8*2048*64];
__device__ float g_points[8*2048*64];
__device__ int   g_fpsidx[8*512];
__device__ float g_newxyz[8*512*3];
__device__ float g_newxyz2[8*256*3];
__device__ float g_newpts[8*512*64];        // stage2: 8*256*128
__device__ int   g_knn[8*512*64];
__device__ int   g_knn2[8*256*64];
__device__ float g_U[16384*128];            // stage E: 4096x256
__device__ float g_V[4096*128];             // stage E: 2048x256
__device__ float g_w1a[256*128];
__device__ float g_w1d[256*128];
__device__ float g_part[2*2048*256];
__device__ float g_pool[8*512*384];         // stage2: 8*256*768
__device__ float g_f0[8*512*128];
__device__ float g_f1[8*256*256];
__device__ float g_pos[8*256*256];
__device__ float g_x[8*256*256];
__device__ float g_q[8*256*256];
__device__ float g_v[8*256*256];
__device__ float g_xr[8*256*256];
__device__ float g_attn[8*4*256*256];
__device__ float g_cat[8*256*1280];
__device__ float g_fuse[8*256*1024];
__device__ float g_gmax[8*1024];
__device__ float g_l1[8*512];
__device__ float g_l2[8*256];
__device__ float g_m1[1024];
__device__ float g_i1[1024];
__device__ float g_m2[256];
__device__ float g_i2[256];
__device__ float g_s1m[3*256];
__device__ float g_s1i[3*256];

// ----------------------------------------------------------------------------
// BN stats plumbing (R12/R13-record versions)
// ----------------------------------------------------------------------------
__global__ void stats_part_kernel(const float* __restrict__ X, int R, int C, int rpb,
                                  int nB, float* __restrict__ part) {
    int blk = blockIdx.x;
    int r0 = blk * rpb;
    int r1 = r0 + rpb; if (r1 > R) r1 = R;
    int nch = (C + 255) / 256;
    float acc[4] = {0.f, 0.f, 0.f, 0.f};
    float accsq[4] = {0.f, 0.f, 0.f, 0.f};
    for (int r = r0; r < r1; r++) {
        const float* row = X + (long)r * C;
        #pragma unroll
        for (int k = 0; k < 4; k++) {
            if (k < nch) {
                int c = threadIdx.x + k * 256;
                if (c < C) { float v = row[c]; acc[k] += v; accsq[k] += v * v; }
            }
        }
    }
    #pragma unroll
    for (int k = 0; k < 4; k++) {
        if (k < nch) {
            int c = threadIdx.x + k * 256;
            if (c < C) {
                part[(long)blk * C + c] = acc[k];
                part[(long)nB * C + (long)blk * C + c] = accsq[k];
            }
        }
    }
}

__global__ void reduce_m1_kernel(const float* __restrict__ part, int nB, int C, int statN) {
    int c = blockIdx.x;
    int t = threadIdx.x;
    float a = 0.f, b = 0.f;
    for (int r = t; r < nB; r += 256) {
        a += part[(long)r * C + c];
        b += part[(long)nB * C + (long)r * C + c];
    }
    __shared__ float sa[256], sb[256];
    sa[t] = a; sb[t] = b;
    __syncthreads();
    for (int s = 128; s > 0; s >>= 1) {
        if (t < s) { sa[t] += sa[t + s]; sb[t] += sb[t + s]; }
        __syncthreads();
    }
    if (t == 0) {
        double m = (double)sa[0] / statN;
        double var = (double)sb[0] / statN - m * m;
        if (var < 0.0) var = 0.0;
        g_m1[c] = (float)m;
        g_i1[c] = rsqrtf((float)var + BN_EPS);
    }
}

__global__ void bn_apply_kernel(float* __restrict__ X, long total, int C, int act) {
    long t = (long)blockIdx.x * blockDim.x + threadIdx.x;
    if (t >= total) return;
    int c = (int)(t % C);
    float y = (X[t] - g_m1[c]) * g_i1[c];
    X[t] = (act == 0) ? fmaxf(y, 0.f) : (y >= 0.f ? y : 0.2f * y);
}

__global__ void bn_small_kernel(float* __restrict__ X, int C, float slope) {
    int c = blockIdx.x * blockDim.x + threadIdx.x;
    if (c >= C) return;
    double s = 0.0, ss = 0.0;
    for (int r = 0; r < 8; r++) { double v = X[r * C + c]; s += v; ss += v * v; }
    double m = s / 8.0;
    double var = ss / 8.0 - m * m;
    if (var < 0.0) var = 0.0;
    float inv = rsqrtf((float)var + BN_EPS);
    for (int r = 0; r < 8; r++) {
        float y = (X[r * C + c] - (float)m) * inv;
        X[r * C + c] = y >= 0.f ? y : slope * y;
    }
}

__global__ void reduce_part_kernel(int nBy, int O, int statN) {
    int c = blockIdx.x;
    int t = threadIdx.x;
    double a = 0.0, b = 0.0;
    for (int r = t; r < nBy; r += 256) {
        a += g_part[r * O + c];
        b += g_part[PART_OFF + r * O + c];
    }
    __shared__ double sa[256], sb[256];
    sa[t] = a; sb[t] = b;
    __syncthreads();
    for (int s = 128; s > 0; s >>= 1) {
        if (t < s) { sa[t] += sa[t + s]; sb[t] += sb[t + s]; }
        __syncthreads();
    }
    if (t == 0) {
        double m = sa[0] / statN;
        double var = sb[0] / statN - m * m;
        if (var < 0.0) var = 0.0;
        g_m2[c] = (float)m;
        g_i2[c] = rsqrtf((float)var + BN_EPS);
    }
}

// ----------------------------------------------------------------------------
// BN1 stats — one incremental pass over all 3 k-scales (R13 version)
// ----------------------------------------------------------------------------
__global__ void stats1_all_kernel(const float* __restrict__ U, const float* __restrict__ V,
                                  const int* __restrict__ knn, int S, int N, int C,
                                  int cpb, int nB, float* __restrict__ part) {
    int c = threadIdx.x;   // blockDim == C
    int blk = blockIdx.x;
    float s0 = 0.f, q0 = 0.f, s1 = 0.f, q1 = 0.f, s2 = 0.f, q2 = 0.f;
    for (int ss = 0; ss < cpb; ss++) {
        int s = blk * cpb + ss;
        int b = s / S;
        float v = V[(long)s * C + c];
        const int* kn = knn + (long)s * 64;
        for (int j = 0; j < 16; j++) {
            float x = U[((long)b * N + kn[j]) * C + c] + v;
            s0 += x; q0 += x * x;
        }
        for (int j = 16; j < 32; j++) {
            float x = U[((long)b * N + kn[j]) * C + c] + v;
            s1 += x; q1 += x * x;
        }
        for (int j = 32; j < 64; j++) {
            float x = U[((long)b * N + kn[j]) * C + c] + v;
            s2 += x; q2 += x * x;
        }
    }
    long base = (long)blk * C + c;
    long stride = (long)nB * C;
    part[0 * stride + base] = s0;
    part[1 * stride + base] = s1;
    part[2 * stride + base] = s2;
    part[3 * stride + base] = q0;
    part[4 * stride + base] = q1;
    part[5 * stride + base] = q2;
}

__global__ void stats1_fin_kernel(const float* __restrict__ part, int nB, int C, int S8) {
    int c = blockIdx.x * 128 + threadIdx.x;
    if (c >= C) return;
    long stride = (long)nB * C;
    float a0 = 0.f, a1 = 0.f, a2 = 0.f, b0 = 0.f, b1 = 0.f, b2 = 0.f;
    for (int r = 0; r < nB; r++) {
        long idx = (long)r * C + c;
        a0 += part[0 * stride + idx];
        a1 += part[1 * stride + idx];
        a2 += part[2 * stride + idx];
        b0 += part[3 * stride + idx];
        b1 += part[4 * stride + idx];
        b2 += part[5 * stride + idx];
    }
    double cs = a0, cq = b0;
    const int ks[3] = {16, 32, 64};
    double add_s[3] = {0.0, (double)a1, (double)a2};
    double add_q[3] = {0.0, (double)b1, (double)b2};
    for (int sc = 0; sc < 3; sc++) {
        cs += add_s[sc]; cq += add_q[sc];
        double n = (double)S8 * ks[sc];
        double m = cs / n;
        double var = cq / n - m * m;
        if (var < 0.0) var = 0.0;
        g_s1m[sc * 256 + c] = (float)m;
        g_s1i[sc * 256 + c] = rsqrtf((float)var + BN_EPS);
    }
}

// ----------------------------------------------------------------------------
// R14: 128x128 GEMM with double-buffered k-tiles
// ----------------------------------------------------------------------------
__global__ __launch_bounds__(256, 2)
void gemm128_kernel(const float* __restrict__ A, const float* __restrict__ W,
                    const float* __restrict__ bias, float* __restrict__ C,
                    int R, int D, int O, int useStats) {
    __shared__ float As[2][16][132];
    __shared__ float Ws[2][16][132];
    __shared__ float sM[256];
    __shared__ float sI[256];
    int tid = threadIdx.x;
    if (useStats) {
        for (int c = tid; c < D; c += 256) { sM[c] = g_m1[c]; sI[c] = g_i1[c]; }
        __syncthreads();
    }
    long rowBase = (long)blockIdx.y * 128;
    int colBase = blockIdx.x * 128;
    int tr = tid >> 4, tc = tid & 15;
    int lrow = tid >> 2;
    int kq = (tid & 3) * 4;
    float acc[8][8];
    #pragma unroll
    for (int i = 0; i < 8; i++)
        #pragma unroll
        for (int j = 0; j < 8; j++) acc[i][j] = 0.f;

    int nT = D >> 4;
    #pragma unroll
    for (int half = 0; half < 2; half++) {
        int row = lrow + 64 * half;
        float4 av = *(const float4*)(A + (rowBase + row) * D + kq);
        if (useStats) {
            av.x = fmaxf((av.x - sM[kq + 0]) * sI[kq + 0], 0.f);
            av.y = fmaxf((av.y - sM[kq + 1]) * sI[kq + 1], 0.f);
            av.z = fmaxf((av.z - sM[kq + 2]) * sI[kq + 2], 0.f);
            av.w = fmaxf((av.w - sM[kq + 3]) * sI[kq + 3], 0.f);
        }
        As[0][kq + 0][row] = av.x;
        As[0][kq + 1][row] = av.y;
        As[0][kq + 2][row] = av.z;
        As[0][kq + 3][row] = av.w;
        int wr = colBase + row;
        float4 wv = make_float4(0.f, 0.f, 0.f, 0.f);
        if (wr < O) wv = *(const float4*)(W + (long)wr * D + kq);
        Ws[0][kq + 0][row] = wv.x;
        Ws[0][kq + 1][row] = wv.y;
        Ws[0][kq + 2][row] = wv.z;
        Ws[0][kq + 3][row] = wv.w;
    }
    __syncthreads();

    int cur = 0;
    for (int t = 0; t < nT; t++) {
        float4 sa[2], sw[2];
        bool has = (t + 1) < nT;
        if (has) {
            int kc = (t + 1) * 16 + kq;
            #pragma unroll
            for (int half = 0; half < 2; half++) {
                int row = lrow + 64 * half;
                float4 av = *(const float4*)(A + (rowBase + row) * D + kc);
                if (useStats) {
                    av.x = fmaxf((av.x - sM[kc + 0]) * sI[kc + 0], 0.f);
                    av.y = fmaxf((av.y - sM[kc + 1]) * sI[kc + 1], 0.f);
                    av.z = fmaxf((av.z - sM[kc + 2]) * sI[kc + 2], 0.f);
                    av.w = fmaxf((av.w - sM[kc + 3]) * sI[kc + 3], 0.f);
                }
                sa[half] = av;
                int wr = colBase + row;
                float4 wv = make_float4(0.f, 0.f, 0.f, 0.f);
                if (wr < O) wv = *(const float4*)(W + (long)wr * D + kc);
                sw[half] = wv;
            }
        }
        #pragma unroll
        for (int kk = 0; kk < 16; kk++) {
            float a[8], w[8];
            *(float4*)(a + 0) = *(const float4*)&As[cur][kk][tr * 8 + 0];
            *(float4*)(a + 4) = *(const float4*)&As[cur][kk][tr * 8 + 4];
            *(float4*)(w + 0) = *(const float4*)&Ws[cur][kk][tc * 8 + 0];
            *(float4*)(w + 4) = *(const float4*)&Ws[cur][kk][tc * 8 + 4];
            #pragma unroll
            for (int i = 0; i < 8; i++)
                #pragma unroll
                for (int j = 0; j < 8; j++)
                    acc[i][j] += a[i] * w[j];
        }
        if (has) {
            int nxt = cur ^ 1;
            #pragma unroll
            for (int half = 0; half < 2; half++) {
                int row = lrow + 64 * half;
                As[nxt][kq + 0][row] = sa[half].x;
                As[nxt][kq + 1][row] = sa[half].y;
                As[nxt][kq + 2][row] = sa[half].z;
                As[nxt][kq + 3][row] = sa[half].w;
                Ws[nxt][kq + 0][row] = sw[half].x;
                Ws[nxt][kq + 1][row] = sw[half].y;
                Ws[nxt][kq + 2][row] = sw[half].z;
                Ws[nxt][kq + 3][row] = sw[half].w;
            }
        }
        __syncthreads();
        cur ^= 1;
    }
    #pragma unroll
    for (int i = 0; i < 8; i++) {
        long row = rowBase + tr * 8 + i;
        int col0 = colBase + tc * 8;
        if (col0 >= O) continue;
        float b0 = 0, b1 = 0, b2 = 0, b3 = 0, b4 = 0, b5 = 0, b6 = 0, b7 = 0;
        if (bias) {
            b0 = bias[col0 + 0]; b1 = bias[col0 + 1]; b2 = bias[col0 + 2]; b3 = bias[col0 + 3];
            b4 = bias[col0 + 4]; b5 = bias[col0 + 5]; b6 = bias[col0 + 6]; b7 = bias[col0 + 7];
        }
        float4 v0 = make_float4(acc[i][0] + b0, acc[i][1] + b1, acc[i][2] + b2, acc[i][3] + b3);
        float4 v1 = make_float4(acc[i][4] + b4, acc[i][5] + b5, acc[i][6] + b6, acc[i][7] + b7);
        *(float4*)(C + row * O + col0) = v0;
        *(float4*)(C + row * O + col0 + 4) = v1;
    }
}

// ----------------------------------------------------------------------------
// R14: fused local-op GEMM2, double-buffered
// ----------------------------------------------------------------------------
__global__ __launch_bounds__(256, 2)
void local_gemm2_kernel(const float* __restrict__ U, const float* __restrict__ V,
                        const int* __restrict__ knn, const float* __restrict__ W,
                        float* __restrict__ poolOut,
                        int S, int N, int D, int O, int kshift,
                        int OC, int off,
                        const float* __restrict__ bn1M,
                        const float* __restrict__ bn1I) {
    __shared__ float As[2][16][132];
    __shared__ float Ws[2][16][132];
    __shared__ float sRed[16][132];
    __shared__ float sM[256];
    __shared__ float sI[256];
    __shared__ int sP[128];
    __shared__ int sS[128];
    int tid = threadIdx.x;
    long rowBase = (long)blockIdx.y * 128;
    int colBase = blockIdx.x * 128;

    for (int c = tid; c < D; c += 256) { sM[c] = bn1M[c]; sI[c] = bn1I[c]; }
    if (tid < 128) {
        long grow = rowBase + tid;
        int s = (int)(grow >> kshift);
        int j = (int)(grow & ((1 << kshift) - 1));
        int b = s / S;
        sS[tid] = s;
        sP[tid] = b * N + knn[(long)s * 64 + j];
    }
    __syncthreads();

    int tr = tid >> 4, tc = tid & 15;
    int lrow = tid >> 2;
    int kq = (tid & 3) * 4;
    float acc[8][8];
    #pragma unroll
    for (int i = 0; i < 8; i++)
        #pragma unroll
        for (int j = 0; j < 8; j++) acc[i][j] = 0.f;

    int nT = D >> 4;
    int p0 = sP[lrow], p1 = sP[lrow + 64];
    int s0i = sS[lrow], s1i = sS[lrow + 64];
    {
        #pragma unroll
        for (int half = 0; half < 2; half++) {
            int row = lrow + 64 * half;
            int pi = half ? p1 : p0;
            int si = half ? s1i : s0i;
            float4 uv = *(const float4*)(U + (long)pi * D + kq);
            float4 vv = *(const float4*)(V + (long)si * D + kq);
            As[0][kq + 0][row] = fmaxf((uv.x + vv.x - sM[kq + 0]) * sI[kq + 0], 0.f);
            As[0][kq + 1][row] = fmaxf((uv.y + vv.y - sM[kq + 1]) * sI[kq + 1], 0.f);
            As[0][kq + 2][row] = fmaxf((uv.z + vv.z - sM[kq + 2]) * sI[kq + 2], 0.f);
            As[0][kq + 3][row] = fmaxf((uv.w + vv.w - sM[kq + 3]) * sI[kq + 3], 0.f);
            float4 wv = *(const float4*)(W + (long)(colBase + row) * D + kq);
            Ws[0][kq + 0][row] = wv.x;
            Ws[0][kq + 1][row] = wv.y;
            Ws[0][kq + 2][row] = wv.z;
            Ws[0][kq + 3][row] = wv.w;
        }
    }
    __syncthreads();

    int cur = 0;
    for (int t = 0; t < nT; t++) {
        float4 sa[2], sw[2];
        bool has = (t + 1) < nT;
        if (has) {
            int kc = (t + 1) * 16 + kq;
            #pragma unroll
            for (int half = 0; half < 2; half++) {
                int row = lrow + 64 * half;
                int pi = half ? p1 : p0;
                int si = half ? s1i : s0i;
                float4 uv = *(const float4*)(U + (long)pi * D + kc);
                float4 vv = *(const float4*)(V + (long)si * D + kc);
                float4 av;
                av.x = fmaxf((uv.x + vv.x - sM[kc + 0]) * sI[kc + 0], 0.f);
                av.y = fmaxf((uv.y + vv.y - sM[kc + 1]) * sI[kc + 1], 0.f);
                av.z = fmaxf((uv.z + vv.z - sM[kc + 2]) * sI[kc + 2], 0.f);
                av.w = fmaxf((uv.w + vv.w - sM[kc + 3]) * sI[kc + 3], 0.f);
                sa[half] = av;
                sw[half] = *(const float4*)(W + (long)(colBase + row) * D + kc);
            }
        }
        #pragma unroll
        for (int kk = 0; kk < 16; kk++) {
            float a[8], w[8];
            *(float4*)(a + 0) = *(const float4*)&As[cur][kk][tr * 8 + 0];
            *(float4*)(a + 4) = *(const float4*)&As[cur][kk][tr * 8 + 4];
            *(float4*)(w + 0) = *(const float4*)&Ws[cur][kk][tc * 8 + 0];
            *(float4*)(w + 4) = *(const float4*)&Ws[cur][kk][tc * 8 + 4];
            #pragma unroll
            for (int i = 0; i < 8; i++)
                #pragma unroll
                for (int j = 0; j < 8; j++)
                    acc[i][j] += a[i] * w[j];
        }
        if (has) {
            int nxt = cur ^ 1;
            #pragma unroll
            for (int half = 0; half < 2; half++) {
                int row = lrow + 64 * half;
                As[nxt][kq + 0][row] = sa[half].x;
                As[nxt][kq + 1][row] = sa[half].y;
                As[nxt][kq + 2][row] = sa[half].z;
                As[nxt][kq + 3][row] = sa[half].w;
                Ws[nxt][kq + 0][row] = sw[half].x;
                Ws[nxt][kq + 1][row] = sw[half].y;
                Ws[nxt][kq + 2][row] = sw[half].z;
                Ws[nxt][kq + 3][row] = sw[half].w;
            }
        }
        __syncthreads();
        cur ^= 1;
    }

    int g = (1 << kshift) >> 3;
    #pragma unroll
    for (int j = 0; j < 8; j++) {
        float m = acc[0][j];
        #pragma unroll
        for (int i = 1; i < 8; i++) m = fmaxf(m, acc[i][j]);
        sRed[tr][tc * 8 + j] = m;
    }
    __syncthreads();
    if ((tr & (g - 1)) == 0) {
        int s = sS[tr * 8];
        #pragma unroll
        for (int j = 0; j < 8; j++) {
            float m = sRed[tr][tc * 8 + j];
            for (int q = 1; q < g; q++) m = fmaxf(m, sRed[tr + q][tc * 8 + j]);
            poolOut[(long)s * OC + off + colBase + tc * 8 + j] = m;
        }
    }
    __syncthreads();
    #pragma unroll
    for (int j = 0; j < 8; j++) {
        float sm = 0.f;
        #pragma unroll
        for (int i = 0; i < 8; i++) sm += acc[i][j];
        sRed[tr][tc * 8 + j] = sm;
    }
    __syncthreads();
    if (tr == 0) {
        #pragma unroll
        for (int j = 0; j < 8; j++) {
            float tot = 0.f;
            for (int q = 0; q < 16; q++) tot += sRed[q][tc * 8 + j];
            g_part[(long)blockIdx.y * O + colBase + tc * 8 + j] = tot;
        }
    }
    __syncthreads();
    #pragma unroll
    for (int j = 0; j < 8; j++) {
        float sm = 0.f;
        #pragma unroll
        for (int i = 0; i < 8; i++) sm += acc[i][j] * acc[i][j];
        sRed[tr][tc * 8 + j] = sm;
    }
    __syncthreads();
    if (tr == 0) {
        #pragma unroll
        for (int j = 0; j < 8; j++) {
            float tot = 0.f;
            for (int q = 0; q < 16; q++) tot += sRed[q][tc * 8 + j];
            g_part[PART_OFF + (long)blockIdx.y * O + colBase + tc * 8 + j] = tot;
        }
    }
}

__global__ void pool_finalize_kernel(float* __restrict__ pool, int OC, int off) {
    int s = blockIdx.x;
    int c = threadIdx.x;
    long p = (long)s * OC + off + c;
    pool[p] = fmaxf((pool[p] - g_m2[c]) * g_i2[c], 0.f);
}

__global__ void split_w1_kernel(const float* __restrict__ w1, float* __restrict__ wa,
                                float* __restrict__ wd, int O, int D, int total) {
    int t = blockIdx.x * 256 + threadIdx.x;
    if (t >= total) return;
    int d = t % D, o = t / D;
    float a = w1[(long)o * 2 * D + d];
    float b = w1[(long)o * 2 * D + D + d];
    wa[t] = a;
    wd[t] = b - a;
}

// ----------------------------------------------------------------------------
// Generic fallback GEMM (odd shapes)
// ----------------------------------------------------------------------------
__global__ void gemm_kernel(const float* __restrict__ A, const float* __restrict__ W,
                            const float* __restrict__ bias, float* __restrict__ C,
                            int R, int D, int O) {
    __shared__ float As[64][17];
    __shared__ float Ws[64][17];
    int tid = threadIdx.x;
    int tr = tid >> 4, tc = tid & 15;
    long rowBase = (long)blockIdx.y * 64;
    int colBase = blockIdx.x * 64;
    float acc[4][4] = {};
    for (int k0 = 0; k0 < D; k0 += 16) {
        #pragma unroll
        for (int e = tid; e < 1024; e += 256) {
            int rr = e >> 4, kk = e & 15;
            long ar = rowBase + rr; int ac = k0 + kk;
            As[rr][kk] = (ar < R && ac < D) ? A[ar * D + ac] : 0.f;
            int wr = colBase + rr;
            Ws[rr][kk] = (wr < O && ac < D) ? W[(long)wr * D + ac] : 0.f;
        }
        __syncthreads();
        #pragma unroll
        for (int kk = 0; kk < 16; kk++) {
            float a[4], w[4];
            #pragma unroll
            for (int i = 0; i < 4; i++) a[i] = As[tr + 16*i][kk];
            #pragma unroll
            for (int j = 0; j < 4; j++) w[j] = Ws[tc + 16*j][kk];
            #pragma unroll
            for (int i = 0; i < 4; i++)
                #pragma unroll
                for (int j = 0; j < 4; j++)
                    acc[i][j] += a[i] * w[j];
        }
        __syncthreads();
    }
    #pragma unroll
    for (int i = 0; i < 4; i++) {
        long row = rowBase + tr + 16*i;
        if (row >= R) continue;
        #pragma unroll
        for (int j = 0; j < 4; j++) {
            int col = colBase + tc + 16*j;
            if (col >= O) continue;
            float vv = acc[i][j];
            if (bias) vv += bias[col];
            C[row * O + col] = vv;
        }
    }
}

// ----------------------------------------------------------------------------
// Layout / elementwise helpers
// ----------------------------------------------------------------------------
__global__ void transpose_x_kernel(const float* __restrict__ x, float* __restrict__ xyz) {
    int t = blockIdx.x * 256 + threadIdx.x;
    if (t >= 8 * 2048 * 3) return;
    int c = t % 3; int n = (t / 3) % 2048; int b = t / (3 * 2048);
    xyz[t] = x[((long)b * 3 + c) * 2048 + n];
}

__global__ void gather_kernel(const float* __restrict__ src, const int* __restrict__ idx,
                              float* __restrict__ dst, int S, int N, int D, long total) {
    long t = (long)blockIdx.x * blockDim.x + threadIdx.x;
    if (t >= total) return;
    int c = (int)(t % D); long bs = t / D;
    int b = (int)(bs / S);
    dst[t] = src[((long)b * N + idx[bs]) * D + c];
}

__global__ void catf1_kernel(const float* __restrict__ f1, float* __restrict__ cat) {
    int t = blockIdx.x * 256 + threadIdx.x;
    int c = t & 255; int row = t >> 8;
    cat[(long)row * 1280 + 1024 + c] = f1[t];
}

__global__ void maxn_kernel(const float* __restrict__ X, float* __restrict__ G) {
    int b = blockIdx.x; int c = blockIdx.y * 256 + threadIdx.x;
    float m = -FLT_MAX;
    for (int n = 0; n < 256; n++) m = fmaxf(m, X[((long)b * 256 + n) * 1024 + c]);
    G[b * 1024 + c] = m;
}

// ----------------------------------------------------------------------------
// FPS / kNN with warp-shuffle reductions (tie order preserved)
// ----------------------------------------------------------------------------
__device__ __forceinline__ unsigned keymap(float f) {
    unsigned u = __float_as_uint(f);
    return (u & 0x80000000u) ? ~u : (u | 0x80000000u);
}

__device__ void fps_body(const float* __restrict__ xyz, int N, int npoint,
                         int* __restrict__ outIdx, int b,
                         float* sx, float* sy, float* sz, float* sd,
                         unsigned long long* warpBest, int* sFar) {
    int t = threadIdx.x;
    int nt = blockDim.x;
    int numWarps = nt >> 5;
    for (int n = t; n < N; n += nt) {
        sx[n] = xyz[((long)b * N + n) * 3 + 0];
        sy[n] = xyz[((long)b * N + n) * 3 + 1];
        sz[n] = xyz[((long)b * N + n) * 3 + 2];
        sd[n] = 1e10f;
    }
    __syncthreads();
    int far = 0;
    for (int it = 0; it < npoint; it++) {
        if (t == 0) outIdx[b * npoint + it] = far;
        float cx = sx[far], cy = sy[far], cz = sz[far];
        unsigned long long best = 0ull;
        for (int n = t; n < N; n += nt) {
            float dx = sx[n] - cx, dy = sy[n] - cy, dz = sz[n] - cz;
            float d = dx * dx + dy * dy + dz * dz;
            float dm = fminf(sd[n], d);
            sd[n] = dm;
            unsigned long long key = ((unsigned long long)keymap(dm) << 32) | (unsigned)(~n);
            if (key > best) best = key;
        }
        #pragma unroll
        for (int o = 16; o > 0; o >>= 1) {
            unsigned long long other = __shfl_xor_sync(0xffffffffu, best, o);
            if (other > best) best = other;
        }
        if ((t & 31) == 0) warpBest[t >> 5] = best;
        __syncthreads();
        if (t < 32) {
            unsigned long long v = (t < numWarps) ? warpBest[t] : 0ull;
            #pragma unroll
            for (int o = 16; o > 0; o >>= 1) {
                unsigned long long other = __shfl_xor_sync(0xffffffffu, v, o);
                if (other > v) v = other;
            }
            if (t == 0) *sFar = (int)(~((unsigned)(v & 0xffffffffu)));
        }
        __syncthreads();
        far = *sFar;
    }
}

__device__ void knn_body(const float* __restrict__ centers, const float* __restrict__ xyz,
                         int S, int N, int* __restrict__ knnOut, int bs,
                         float* sd, unsigned long long* warpBest) {
    int t = threadIdx.x;
    int nt = blockDim.x;
    int numWarps = nt >> 5;
    int b = bs / S;
    float cx = centers[(long)bs * 3 + 0];
    float cy = centers[(long)bs * 3 + 1];
    float cz = centers[(long)bs * 3 + 2];
    float cn = cx * cx + cy * cy + cz * cz;
    for (int n = t; n < N; n += nt) {
        float px = xyz[((long)b * N + n) * 3 + 0];
        float py = xyz[((long)b * N + n) * 3 + 1];
        float pz = xyz[((long)b * N + n) * 3 + 2];
        float pn = px * px + py * py + pz * pz;
        float dot = cx * px + cy * py + cz * pz;
        sd[n] = cn + pn - 2.f * dot;
    }
    __syncthreads();
    for (int j = 0; j < 64; j++) {
        unsigned long long best = 0xFFFFFFFFFFFFFFFFull;
        for (int n = t; n < N; n += nt) {
            unsigned long long key = ((unsigned long long)keymap(sd[n]) << 32) | (unsigned)n;
            if (key < best) best = key;
        }
        #pragma unroll
        for (int o = 16; o > 0; o >>= 1) {
            unsigned long long other = __shfl_xor_sync(0xffffffffu, best, o);
            if (other < best) best = other;
        }
        if ((t & 31) == 0) warpBest[t >> 5] = best;
        __syncthreads();
        if (t < 32) {
            unsigned long long v = (t < numWarps) ? warpBest[t] : 0xFFFFFFFFFFFFFFFFull;
            #pragma unroll
            for (int o = 16; o > 0; o >>= 1) {
                unsigned long long other = __shfl_xor_sync(0xffffffffu, v, o);
                if (other < v) v = other;
            }
            if (t == 0) {
                int sel = (int)(v & 0xffffffffu);
                knnOut[(long)bs * 64 + j] = sel;
                sd[sel] = FLT_MAX;
            }
        }
        __syncthreads();
    }
}

__global__ void fps_kernel(const float* xyz, int N, int npoint, int* outIdx) {
    __shared__ float buf[4 * 2048];
    __shared__ unsigned long long wb[32];
    __shared__ int sFar;
    fps_body(xyz, N, npoint, outIdx, blockIdx.x, buf, buf + N, buf + 2 * N, buf + 3 * N, wb, &sFar);
}

__global__ void knn_kernel(const float* centers, const float* xyz, int S, int N, int* knnOut) {
    __shared__ float buf[2048];
    __shared__ unsigned long long wb[32];
    knn_body(centers, xyz, S, N, knnOut, blockIdx.x, buf, wb);
}

__global__ void knn_fps_kernel(const float* centers, const float* xyz, int S, int N,
                               int* knnOut, int nKnn,
                               const float* xyz2, int N2, int np2, int* outIdx2) {
    __shared__ float buf[4 * 2048];
    __shared__ unsigned long long wb[32];
    __shared__ int sFar;
    if (blockIdx.x < nKnn) {
        knn_body(centers, xyz, S, N, knnOut, blockIdx.x, buf, wb);
    } else {
        int b = blockIdx.x - nKnn;
        fps_body(xyz2, N2, np2, outIdx2, b, buf, buf + N2, buf + 2 * N2, buf + 3 * N2, wb, &sFar);
    }
}

// ----------------------------------------------------------------------------
// Attention (reference reshape quirk preserved)
// ----------------------------------------------------------------------------
__global__ void gemmqv_kernel(const float* __restrict__ xx, const float* __restrict__ pos,
                              const float* __restrict__ wqk, const float* __restrict__ wv,
                              const float* __restrict__ bv,
                              float* __restrict__ qb, float* __restrict__ vb) {
    __shared__ float As[16][132];
    __shared__ float Ws[16][132];
    int tid = threadIdx.x;
    long rowBase = (long)blockIdx.y * 128;
    int colBase = blockIdx.x * 128;
    int tr = tid >> 4, tc = tid & 15;
    int lrow = tid >> 2;
    int lkq = tid & 3;
    const int D = 256;
    float acc[8][8];
    #pragma unroll
    for (int i = 0; i < 8; i++)
        #pragma unroll
        for (int j = 0; j < 8; j++) acc[i][j] = 0.f;

    for (int k0 = 0; k0 < D; k0 += 16) {
        #pragma unroll
        for (int half = 0; half < 2; half++) {
            int row = lrow + 64 * half;
            int kc = k0 + lkq * 4;
            float4 av = *(const float4*)(xx + (rowBase + row) * D + kc);
            float4 pv = *(const float4*)(pos + (rowBase + row) * D + kc);
            As[lkq * 4 + 0][row] = av.x + pv.x;
            As[lkq * 4 + 1][row] = av.y + pv.y;
            As[lkq * 4 + 2][row] = av.z + pv.z;
            As[lkq * 4 + 3][row] = av.w + pv.w;
            int ocol = colBase + row;
            const float* Wp = (ocol < 256) ? (wqk + (long)ocol * D) : (wv + (long)(ocol - 256) * D);
            float4 wvv = *(const float4*)(Wp + kc);
            Ws[lkq * 4 + 0][row] = wvv.x;
            Ws[lkq * 4 + 1][row] = wvv.y;
            Ws[lkq * 4 + 2][row] = wvv.z;
            Ws[lkq * 4 + 3][row] = wvv.w;
        }
        __syncthreads();
        #pragma unroll
        for (int kk = 0; kk < 16; kk++) {
            float a[8], w[8];
            *(float4*)(a + 0) = *(const float4*)&As[kk][tr * 8 + 0];
            *(float4*)(a + 4) = *(const float4*)&As[kk][tr * 8 + 4];
            *(float4*)(w + 0) = *(const float4*)&Ws[kk][tc * 8 + 0];
            *(float4*)(w + 4) = *(const float4*)&Ws[kk][tc * 8 + 4];
            #pragma unroll
            for (int i = 0; i < 8; i++)
                #pragma unroll
                for (int j = 0; j < 8; j++)
                    acc[i][j] += a[i] * w[j];
        }
        __syncthreads();
    }
    int col0 = colBase + tc * 8;
    #pragma unroll
    for (int i = 0; i < 8; i++) {
        long row = rowBase + tr * 8 + i;
        if (col0 < 256) {
            float4 v0 = make_float4(acc[i][0], acc[i][1], acc[i][2], acc[i][3]);
            float4 v1 = make_float4(acc[i][4], acc[i][5], acc[i][6], acc[i][7]);
            *(float4*)(qb + row * 256 + col0) = v0;
            *(float4*)(qb + row * 256 + col0 + 4) = v1;
        } else {
            int cc = col0 - 256;
            float4 v0 = make_float4(acc[i][0] + bv[cc + 0], acc[i][1] + bv[cc + 1],
                                    acc[i][2] + bv[cc + 2], acc[i][3] + bv[cc + 3]);
            float4 v1 = make_float4(acc[i][4] + bv[cc + 4], acc[i][5] + bv[cc + 5],
                                    acc[i][6] + bv[cc + 6], acc[i][7] + bv[cc + 7]);
            *(float4*)(vb + row * 256 + cc) = v0;
            *(float4*)(vb + row * 256 + cc + 4) = v1;
        }
    }
}

// R15: 64x64-tile gram. A[bh][i][j] = sum_d q(i,d) * k(j,d); q uses the
// reference's position-split reshape, k the channel-split (as in old gram).
__global__ void gram64_kernel(const float* __restrict__ Q, float* __restrict__ A) {
    int bh = blockIdx.z; int b = bh >> 2; int h = bh & 3;
    int i0 = blockIdx.y * 64, j0 = blockIdx.x * 64;
    __shared__ float Qi[64][68];   // [d][r] transposed
    __shared__ float Qj[64][68];
    int tid = threadIdx.x;
    #pragma unroll
    for (int it = 0; it < 4; it++) {
        int idx = tid + it * 256;          // 0..1023
        int r = idx >> 4;                  // 0..63
        int dq = (idx & 15) * 4;           // 0..60
        int i = i0 + r;
        float4 qi = *(const float4*)(Q + ((long)b * 256 + h * 64 + (i >> 2)) * 256 + (i & 3) * 64 + dq);
        Qi[dq + 0][r] = qi.x;
        Qi[dq + 1][r] = qi.y;
        Qi[dq + 2][r] = qi.z;
        Qi[dq + 3][r] = qi.w;
        float4 qj = *(const float4*)(Q + ((long)b * 256 + j0 + r) * 256 + h * 64 + dq);
        Qj[dq + 0][r] = qj.x;
        Qj[dq + 1][r] = qj.y;
        Qj[dq + 2][r] = qj.z;
        Qj[dq + 3][r] = qj.w;
    }
    __syncthreads();
    int tr = tid >> 4, tc = tid & 15;
    float acc[4][4] = {};
    #pragma unroll
    for (int d = 0; d < 64; d++) {
        float4 a4 = *(const float4*)&Qi[d][tr * 4];
        float4 b4 = *(const float4*)&Qj[d][tc * 4];
        float a[4] = {a4.x, a4.y, a4.z, a4.w};
        float w[4] = {b4.x, b4.y, b4.z, b4.w};
        #pragma unroll
        for (int ii = 0; ii < 4; ii++)
            #pragma unroll
            for (int jj = 0; jj < 4; jj++)
                acc[ii][jj] += a[ii] * w[jj];
    }
    #pragma unroll
    for (int ii = 0; ii < 4; ii++) {
        long row = (long)bh * 256 + i0 + tr * 4 + ii;
        #pragma unroll
        for (int jj = 0; jj < 4; jj++)
            A[row * 256 + j0 + tc * 4 + jj] = acc[ii][jj];
    }
}

__global__ void softmax_row_kernel(float* __restrict__ A) {
    __shared__ float red[256];
    long row = blockIdx.x;
    float* p = A + row * 256;
    int t = threadIdx.x;
    float v = p[t];
    red[t] = v; __syncthreads();
    for (int s = 128; s > 0; s >>= 1) { if (t < s) red[t] = fmaxf(red[t], red[t + s]); __syncthreads(); }
    float m = red[0]; __syncthreads();
    float e = expf(v - m);
    red[t] = e; __syncthreads();
    for (int s = 128; s > 0; s >>= 1) { if (t < s) red[t] += red[t + s]; __syncthreads(); }
    p[t] = e / red[0];
}

// R15: column softmax over rows r (axis -2) per column, coalesced.
// grid (4 col-chunks, 32 bh); 256 threads: jl=t>>6 strides rows, il=t&63 column.
__global__ void colsm_kernel(float* __restrict__ A) {
    int bh = blockIdx.y;
    int i0 = blockIdx.x * 64;
    int t = threadIdx.x;
    int jl = t >> 6, il = t & 63;
    __shared__ float red[4][64];
    __shared__ float smax[64], ssum[64];
    long base = (long)bh * 256 * 256 + i0 + il;
    float mx = -FLT_MAX;
    for (int r = jl; r < 256; r += 4)
        mx = fmaxf(mx, A[base + (long)r * 256]);
    red[jl][il] = mx;
    __syncthreads();
    if (jl == 0)
        smax[il] = fmaxf(fmaxf(red[0][il], red[1][il]), fmaxf(red[2][il], red[3][il]));
    __syncthreads();
    float sm = 0.f;
    for (int r = jl; r < 256; r += 4)
        sm += expf(A[base + (long)r * 256] - smax[il]);
    red[jl][il] = sm;
    __syncthreads();
    if (jl == 0)
        ssum[il] = red[0][il] + red[1][il] + red[2][il] + red[3][il];
    __syncthreads();
    for (int r = jl; r < 256; r += 4) {
        long idx = base + (long)r * 256;
        A[idx] = expf(A[idx] - smax[il]) / ssum[il];
    }
}

// R15: XR as tiled GEMM: XR[b,i,h*64+c] = sum_r A2[bh][r][i] * V[b][r][h*64+c];
// epilogue fuses xrb = xx + pos - XR. grid (4 i-tiles, 32 bh), 256 threads.
__global__ void xr_gemm_kernel(const float* __restrict__ A2, const float* __restrict__ Vb,
                               const float* __restrict__ xx, const float* __restrict__ pos,
                               float* __restrict__ xrb) {
    int bh = blockIdx.y; int b = bh >> 2; int h = bh & 3;
    int i0 = blockIdx.x * 64;
    __shared__ float As[16][68];
    __shared__ float Vs[16][68];
    int tid = threadIdx.x;
    int rk = tid >> 4;            // 0..15 (j-row within tile)
    int cq = (tid & 15) * 4;      // float4 col
    int tr = tid >> 4, tc = tid & 15;
    float acc[4][4] = {};
    for (int j0 = 0; j0 < 256; j0 += 16) {
        float4 a4 = *(const float4*)(A2 + ((long)bh * 256 + j0 + rk) * 256 + i0 + cq);
        As[rk][cq + 0] = a4.x;
        As[rk][cq + 1] = a4.y;
        As[rk][cq + 2] = a4.z;
        As[rk][cq + 3] = a4.w;
        float4 v4 = *(const float4*)(Vb + ((long)b * 256 + j0 + rk) * 256 + h * 64 + cq);
        Vs[rk][cq + 0] = v4.x;
        Vs[rk][cq + 1] = v4.y;
        Vs[rk][cq + 2] = v4.z;
        Vs[rk][cq + 3] = v4.w;
        __syncthreads();
        #pragma unroll
        for (int jk = 0; jk < 16; jk++) {
            float4 aa = *(const float4*)&As[jk][tr * 4];
            float4 vv = *(const float4*)&Vs[jk][tc * 4];
            float a[4] = {aa.x, aa.y, aa.z, aa.w};
            float w[4] = {vv.x, vv.y, vv.z, vv.w};
            #pragma unroll
            for (int ii = 0; ii < 4; ii++)
                #pragma unroll
                for (int cc = 0; cc < 4; cc++)
                    acc[ii][cc] += a[ii] * w[cc];
        }
        __syncthreads();
    }
    #pragma unroll
    for (int ii = 0; ii < 4; ii++) {
        long row = (long)b * 256 + i0 + tr * 4 + ii;
        #pragma unroll
        for (int cc = 0; cc < 4; cc++) {
            long idx = row * 256 + h * 64 + tc * 4 + cc;
            xrb[idx] = xx[idx] + pos[idx] - acc[ii][cc];
        }
    }
}

__global__ void addcat_bn_kernel(const float* __restrict__ qb, float* __restrict__ xx,
                                 const float* __restrict__ pos, float* __restrict__ cat,
                                 int layer) {
    int t = blockIdx.x * 256 + threadIdx.x;
    int c = t & 255; int row = t >> 8;
    float y = fmaxf((qb[t] - g_m1[c]) * g_i1[c], 0.f);
    float v = xx[t] + pos[t] + y;
    xx[t] = v;
    cat[(long)row * 1280 + layer * 256 + c] = v;
}

// ----------------------------------------------------------------------------
// Host orchestration
// ----------------------------------------------------------------------------
static void gemm_old(const float* A, const float* W, const float* bias, float* C,
                     int R, int D, int O) {
    dim3 grid(CEILDIV(O, 64), CEILDIV(R, 64));
    gemm_kernel<<<grid, 256>>>(A, W, bias, C, R, D, O);
}

static void gemm_big(const float* A, const float* W, const float* bias, float* C,
                     int R, int D, int O, int useStats) {
    dim3 grid(CEILDIV(O, 128), R / 128);
    gemm128_kernel<<<grid, 256>>>(A, W, bias, C, R, D, O, useStats);
}

static float* s_part;

static void computeStats(const float* X, int R, int C) {
    int rpb = R / 512;
    if (rpb < 8) rpb = 8;
    int nB = R / rpb;
    stats_part_kernel<<<nB, 256>>>(X, R, C, rpb, nB, s_part);
    reduce_m1_kernel<<<C, 256>>>(s_part, nB, C, R);
}

static void bn(float* X, int R, int C, int act) {
    computeStats(X, R, C);
    long total = (long)R * C;
    bn_apply_kernel<<<(int)CEILDIV(total, 256), 256>>>(X, total, C, act);
}

extern "C" void kernel_launch(void* const* d_in, const int* in_sizes, int n_in,
                              void* d_out, int out_size) {
    const float* x       = (const float*)d_in[0];
    const float* conv1_w = (const float*)d_in[1];
    const float* conv2_w = (const float*)d_in[2];
    const float* g0_w1   = (const float*)d_in[3];
    const float* g0_w2   = (const float*)d_in[4];
    const float* g0_wc   = (const float*)d_in[5];
    const float* g1_w1   = (const float*)d_in[6];
    const float* g1_w2   = (const float*)d_in[7];
    const float* g1_wc   = (const float*)d_in[8];
    const float* pt_w    = (const float*)d_in[9];
    const float* pos_w   = (const float*)d_in[10];
    const float* pos_b   = (const float*)d_in[11];
    const float* sa_wqk  = (const float*)d_in[12];
    const float* sa_wv   = (const float*)d_in[13];
    const float* sa_bv   = (const float*)d_in[14];
    const float* sa_wt   = (const float*)d_in[15];
    const float* sa_bt   = (const float*)d_in[16];
    const float* fuse_w  = (const float*)d_in[17];
    const float* lin1_w  = (const float*)d_in[18];
    const float* lin2_w  = (const float*)d_in[19];
    const float* lin2_b  = (const float*)d_in[20];
    const float* lin3_w  = (const float*)d_in[21];
    const float* lin3_b  = (const float*)d_in[22];
    float* out = (float*)d_out;

    float *xyz, *h1, *points, *newxyz, *newxyz2, *newpts, *Ub, *Vb, *w1a, *w1d, *pool, *f0, *f1;
    float *pos, *xx, *qb, *vb, *xrb, *attn, *catb, *fuseb, *gmax, *l1, *l2, *s1m, *s1i;
    int *fpsidx, *knn, *knn2;
    cudaGetSymbolAddress((void**)&xyz, g_xyz);
    cudaGetSymbolAddress((void**)&h1, g_h1);
    cudaGetSymbolAddress((void**)&points, g_points);
    cudaGetSymbolAddress((void**)&fpsidx, g_fpsidx);
    cudaGetSymbolAddress((void**)&newxyz, g_newxyz);
    cudaGetSymbolAddress((void**)&newxyz2, g_newxyz2);
    cudaGetSymbolAddress((void**)&newpts, g_newpts);
    cudaGetSymbolAddress((void**)&knn, g_knn);
    cudaGetSymbolAddress((void**)&knn2, g_knn2);
    cudaGetSymbolAddress((void**)&Ub, g_U);
    cudaGetSymbolAddress((void**)&Vb, g_V);
    cudaGetSymbolAddress((void**)&w1a, g_w1a);
    cudaGetSymbolAddress((void**)&w1d, g_w1d);
    cudaGetSymbolAddress((void**)&s_part, g_part);
    cudaGetSymbolAddress((void**)&pool, g_pool);
    cudaGetSymbolAddress((void**)&f0, g_f0);
    cudaGetSymbolAddress((void**)&f1, g_f1);
    cudaGetSymbolAddress((void**)&pos, g_pos);
    cudaGetSymbolAddress((void**)&xx, g_x);
    cudaGetSymbolAddress((void**)&qb, g_q);
    cudaGetSymbolAddress((void**)&vb, g_v);
    cudaGetSymbolAddress((void**)&xrb, g_xr);
    cudaGetSymbolAddress((void**)&attn, g_attn);
    cudaGetSymbolAddress((void**)&catb, g_cat);
    cudaGetSymbolAddress((void**)&fuseb, g_fuse);
    cudaGetSymbolAddress((void**)&gmax, g_gmax);
    cudaGetSymbolAddress((void**)&l1, g_l1);
    cudaGetSymbolAddress((void**)&l2, g_l2);
    cudaGetSymbolAddress((void**)&s1m, g_s1m);
    cudaGetSymbolAddress((void**)&s1i, g_s1i);

    // ---- Stage A ----
    transpose_x_kernel<<<CEILDIV(8*2048*3, 256), 256>>>(x, xyz);
    gemm_old(xyz, conv1_w, nullptr, h1, 16384, 3, 64);
    computeStats(h1, 16384, 64);
    gemm_big(h1, conv2_w, nullptr, points, 16384, 64, 64, 1);
    bn(points, 16384, 64, 0);

    // ---- Stage B ----
    fps_kernel<<<8, 1024>>>(xyz, 2048, 512, fpsidx);
    gather_kernel<<<CEILDIV(8*512*3, 256), 256>>>(xyz, fpsidx, newxyz, 512, 2048, 3, 8L*512*3);
    gather_kernel<<<CEILDIV(8*512*64, 256), 256>>>(points, fpsidx, newpts, 512, 2048, 64, 8L*512*64);
    knn_fps_kernel<<<4096 + 8, 256>>>(newxyz, xyz, 512, 2048, knn, 4096,
                                      newxyz, 512, 256, fpsidx);
    gather_kernel<<<CEILDIV(8*256*3, 256), 256>>>(newxyz, fpsidx, newxyz2, 256, 512, 3, 8L*256*3);
    knn_kernel<<<2048, 256>>>(newxyz2, newxyz, 256, 512, knn2);

    // ---- Stage C ----
    {
        split_w1_kernel<<<CEILDIV(128*64, 256), 256>>>(g0_w1, w1a, w1d, 128, 64, 128*64);
        gemm_big(points, w1a, nullptr, Ub, 16384, 64, 128, 0);
        gemm_big(newpts, w1d, nullptr, Vb, 4096, 64, 128, 0);
        stats1_all_kernel<<<256, 128>>>(Ub, Vb, knn, 512, 2048, 128, 16, 256, s_part);
        stats1_fin_kernel<<<1, 128>>>(s_part, 256, 128, 8*512);
        const int kshift[3] = {4, 5, 6};
        for (int si = 0; si < 3; si++) {
            int R = 8 * 512 * (1 << kshift[si]);
            int nBy = R / 128;
            dim3 grid(1, nBy);
            local_gemm2_kernel<<<grid, 256>>>(Ub, Vb, knn, g0_w2, pool,
                                              512, 2048, 128, 128, kshift[si], 384, si * 128,
                                              s1m + si * 256, s1i + si * 256);
            reduce_part_kernel<<<128, 256>>>(nBy, 128, R);
            pool_finalize_kernel<<<4096, 128>>>(pool, 384, si * 128);
        }
        gemm_big(pool, g0_wc, nullptr, f0, 4096, 384, 128, 0);
        bn(f0, 4096, 128, 0);
    }

    // ---- Stage D gather ----
    gather_kernel<<<CEILDIV(8*256*128, 256), 256>>>(f0, fpsidx, newpts, 256, 512, 128, 8L*256*128);

    // ---- Stage E ----
    {
        split_w1_kernel<<<CEILDIV(256*128, 256), 256>>>(g1_w1, w1a, w1d, 256, 128, 256*128);
        gemm_big(f0, w1a, nullptr, Ub, 4096, 128, 256, 0);
        gemm_big(newpts, w1d, nullptr, Vb, 2048, 128, 256, 0);
        stats1_all_kernel<<<128, 256>>>(Ub, Vb, knn2, 256, 512, 256, 16, 128, s_part);
        stats1_fin_kernel<<<2, 128>>>(s_part, 128, 256, 8*256);
        const int kshift[3] = {4, 5, 6};
        for (int si = 0; si < 3; si++) {
            int R = 8 * 256 * (1 << kshift[si]);
            int nBy = R / 128;
            dim3 grid(2, nBy);
            local_gemm2_kernel<<<grid, 256>>>(Ub, Vb, knn2, g1_w2, pool,
                                              256, 512, 256, 256, kshift[si], 768, si * 256,
                                              s1m + si * 256, s1i + si * 256);
            reduce_part_kernel<<<256, 256>>>(nBy, 256, R);
            pool_finalize_kernel<<<2048, 256>>>(pool, 768, si * 256);
        }
        gemm_big(pool, g1_wc, nullptr, f1, 2048, 768, 256, 0);
        bn(f1, 2048, 256, 0);
    }

    // ---- Stage F ----
    gemm_old(newxyz2, pos_w, pos_b, pos, 2048, 3, 256);
    gemm_big(f1, pt_w, nullptr, xx, 2048, 256, 256, 0);
    bn(xx, 2048, 256, 0);

    // ---- Stage G: 4 offset self-attention layers (R15 attention middle) ----
    for (int i = 0; i < 4; i++) {
        gemmqv_kernel<<<dim3(4, 16), 256>>>(xx, pos,
                                            sa_wqk + (long)i * 256 * 256,
                                            sa_wv + (long)i * 256 * 256,
                                            sa_bv + i * 256, qb, vb);
        gram64_kernel<<<dim3(4, 4, 32), 256>>>(qb, attn);
        softmax_row_kernel<<<8192, 256>>>(attn);
        colsm_kernel<<<dim3(4, 32), 256>>>(attn);
        xr_gemm_kernel<<<dim3(4, 32), 256>>>(attn, vb, xx, pos, xrb);
        gemm_big(xrb, sa_wt + (long)i * 256 * 256, sa_bt + i * 256, qb, 2048, 256, 256, 0);
        computeStats(qb, 2048, 256);
        addcat_bn_kernel<<<2048, 256>>>(qb, xx, pos, catb, i);
    }
    catf1_kernel<<<2048, 256>>>(f1, catb);

    // ---- Stage H ----
    gemm_big(catb, fuse_w, nullptr, fuseb, 2048, 1280, 1024, 0);
    bn(fuseb, 2048, 1024, 1);
    maxn_kernel<<<dim3(8, 4), 256>>>(fuseb, gmax);
    gemm_old(gmax, lin1_w, nullptr, l1, 8, 1024, 512);
    bn_small_kernel<<<2, 256>>>(l1, 512, 0.2f);
    gemm_old(l1, lin2_w, lin2_b, l2, 8, 512, 256);
    bn_small_kernel<<<1, 256>>>(l2, 256, 0.2f);
    gemm_old(l2, lin3_w, lin3_b, out, 8, 256, 40);
}

// round 16
// speedup vs baseline: 1.2106x; 1.0357x over previous
#include <cuda_runtime.h>
#include <math.h>
#include <float.h>

#define CEILDIV(a,b) (((a)+(b)-1)/(b))
#define BN_EPS 1e-5f

// ----------------------------------------------------------------------------
// Scratch (device globals)
// ----------------------------------------------------------------------------
__device__ float g_xyz[8*2048*3];
__device__ float g_h1[8*2048*64];
__device__ float g_points[8*2048*64];
__device__ int   g_fpsidx[8*512];
__device__ float g_newxyz[8*512*3];
__device__ float g_newxyz2[8*256*3];
__device__ float g_newpts[8*512*64];        // stage2: 8*256*128
__device__ int   g_knn[8*512*64];
__device__ int   g_knn2[8*256*64];
__device__ float g_U[16384*128];            // stage E: 4096x256
__device__ float g_V[4096*128];             // stage E: 2048x256
__device__ float g_w1a[256*128];
__device__ float g_w1d[256*128];
__device__ float g_part[2*2048*256];        // per-scale partial regions (disjoint)
__device__ float g_pool[8*512*384];         // stage2: 8*256*768
__device__ float g_f0[8*512*128];
__device__ float g_f1[8*256*256];
__device__ float g_pos[8*256*256];
__device__ float g_x[8*256*256];
__device__ float g_q[8*256*256];
__device__ float g_v[8*256*256];
__device__ float g_xr[8*256*256];
__device__ float g_attn[8*4*256*256];
__device__ float g_cat[8*256*1280];
__device__ float g_fuse[8*256*1024];
__device__ float g_gmax[8*1024];
__device__ float g_l1[8*512];
__device__ float g_l2[8*256];
__device__ float g_m1[1024];
__device__ float g_i1[1024];
__device__ float g_m2[3*256];
__device__ float g_i2[3*256];
__device__ float g_s1m[3*256];
__device__ float g_s1i[3*256];

// ----------------------------------------------------------------------------
// BN stats plumbing (R12/R13-record versions)
// ----------------------------------------------------------------------------
__global__ void stats_part_kernel(const float* __restrict__ X, int R, int C, int rpb,
                                  int nB, float* __restrict__ part) {
    int blk = blockIdx.x;
    int r0 = blk * rpb;
    int r1 = r0 + rpb; if (r1 > R) r1 = R;
    int nch = (C + 255) / 256;
    float acc[4] = {0.f, 0.f, 0.f, 0.f};
    float accsq[4] = {0.f, 0.f, 0.f, 0.f};
    for (int r = r0; r < r1; r++) {
        const float* row = X + (long)r * C;
        #pragma unroll
        for (int k = 0; k < 4; k++) {
            if (k < nch) {
                int c = threadIdx.x + k * 256;
                if (c < C) { float v = row[c]; acc[k] += v; accsq[k] += v * v; }
            }
        }
    }
    #pragma unroll
    for (int k = 0; k < 4; k++) {
        if (k < nch) {
            int c = threadIdx.x + k * 256;
            if (c < C) {
                part[(long)blk * C + c] = acc[k];
                part[(long)nB * C + (long)blk * C + c] = accsq[k];
            }
        }
    }
}

__global__ void reduce_m1_kernel(const float* __restrict__ part, int nB, int C, int statN) {
    int c = blockIdx.x;
    int t = threadIdx.x;
    float a = 0.f, b = 0.f;
    for (int r = t; r < nB; r += 256) {
        a += part[(long)r * C + c];
        b += part[(long)nB * C + (long)r * C + c];
    }
    __shared__ float sa[256], sb[256];
    sa[t] = a; sb[t] = b;
    __syncthreads();
    for (int s = 128; s > 0; s >>= 1) {
        if (t < s) { sa[t] += sa[t + s]; sb[t] += sb[t + s]; }
        __syncthreads();
    }
    if (t == 0) {
        double m = (double)sa[0] / statN;
        double var = (double)sb[0] / statN - m * m;
        if (var < 0.0) var = 0.0;
        g_m1[c] = (float)m;
        g_i1[c] = rsqrtf((float)var + BN_EPS);
    }
}

__global__ void bn_apply_kernel(float* __restrict__ X, long total, int C, int act) {
    long t = (long)blockIdx.x * blockDim.x + threadIdx.x;
    if (t >= total) return;
    int c = (int)(t % C);
    float y = (X[t] - g_m1[c]) * g_i1[c];
    X[t] = (act == 0) ? fmaxf(y, 0.f) : (y >= 0.f ? y : 0.2f * y);
}

__global__ void bn_small_kernel(float* __restrict__ X, int C, float slope) {
    int c = blockIdx.x * blockDim.x + threadIdx.x;
    if (c >= C) return;
    double s = 0.0, ss = 0.0;
    for (int r = 0; r < 8; r++) { double v = X[r * C + c]; s += v; ss += v * v; }
    double m = s / 8.0;
    double var = ss / 8.0 - m * m;
    if (var < 0.0) var = 0.0;
    float inv = rsqrtf((float)var + BN_EPS);
    for (int r = 0; r < 8; r++) {
        float y = (X[r * C + c] - (float)m) * inv;
        X[r * C + c] = y >= 0.f ? y : slope * y;
    }
}

// R16: combined BN2 reduce for all 3 scales. grid (O, 3).
// scale si partial region base: si==0 ? 0 : si==1 ? 2*n16*O : 2*(n16+n32)*O.
__global__ void reduce_m2_all_kernel(int n16, int n32, int n64, int O) {
    int si = blockIdx.y;
    int c = blockIdx.x;
    int t = threadIdx.x;
    int nBy = (si == 0) ? n16 : (si == 1) ? n32 : n64;
    long base = (si == 0) ? 0L : (si == 1) ? 2L * n16 * O : 2L * (n16 + n32) * O;
    const float* ps = g_part + base;
    const float* pq = ps + (long)nBy * O;
    float a = 0.f, b = 0.f;
    for (int r = t; r < nBy; r += 256) {
        a += ps[(long)r * O + c];
        b += pq[(long)r * O + c];
    }
    __shared__ float sa[256], sb[256];
    sa[t] = a; sb[t] = b;
    __syncthreads();
    for (int s = 128; s > 0; s >>= 1) {
        if (t < s) { sa[t] += sa[t + s]; sb[t] += sb[t + s]; }
        __syncthreads();
    }
    if (t == 0) {
        long statN = (long)nBy * 128;   // rows = blocks * 128
        double m = (double)sa[0] / statN;
        double var = (double)sb[0] / statN - m * m;
        if (var < 0.0) var = 0.0;
        g_m2[si * 256 + c] = (float)m;
        g_i2[si * 256 + c] = rsqrtf((float)var + BN_EPS);
    }
}

// R16: combined pool finalize: grid (S8, 3), blockDim = O.
__global__ void pool_fin_all_kernel(float* __restrict__ pool, int OC, int O) {
    int s = blockIdx.x;
    int si = blockIdx.y;
    int c = threadIdx.x;
    long p = (long)s * OC + si * O + c;
    pool[p] = fmaxf((pool[p] - g_m2[si * 256 + c]) * g_i2[si * 256 + c], 0.f);
}

// ----------------------------------------------------------------------------
// BN1 stats — one incremental pass over all 3 k-scales (R13 version)
// ----------------------------------------------------------------------------
__global__ void stats1_all_kernel(const float* __restrict__ U, const float* __restrict__ V,
                                  const int* __restrict__ knn, int S, int N, int C,
                                  int cpb, int nB, float* __restrict__ part) {
    int c = threadIdx.x;   // blockDim == C
    int blk = blockIdx.x;
    float s0 = 0.f, q0 = 0.f, s1 = 0.f, q1 = 0.f, s2 = 0.f, q2 = 0.f;
    for (int ss = 0; ss < cpb; ss++) {
        int s = blk * cpb + ss;
        int b = s / S;
        float v = V[(long)s * C + c];
        const int* kn = knn + (long)s * 64;
        for (int j = 0; j < 16; j++) {
            float x = U[((long)b * N + kn[j]) * C + c] + v;
            s0 += x; q0 += x * x;
        }
        for (int j = 16; j < 32; j++) {
            float x = U[((long)b * N + kn[j]) * C + c] + v;
            s1 += x; q1 += x * x;
        }
        for (int j = 32; j < 64; j++) {
            float x = U[((long)b * N + kn[j]) * C + c] + v;
            s2 += x; q2 += x * x;
        }
    }
    long base = (long)blk * C + c;
    long stride = (long)nB * C;
    part[0 * stride + base] = s0;
    part[1 * stride + base] = s1;
    part[2 * stride + base] = s2;
    part[3 * stride + base] = q0;
    part[4 * stride + base] = q1;
    part[5 * stride + base] = q2;
}

__global__ void stats1_fin_kernel(const float* __restrict__ part, int nB, int C, int S8) {
    int c = blockIdx.x * 128 + threadIdx.x;
    if (c >= C) return;
    long stride = (long)nB * C;
    float a0 = 0.f, a1 = 0.f, a2 = 0.f, b0 = 0.f, b1 = 0.f, b2 = 0.f;
    for (int r = 0; r < nB; r++) {
        long idx = (long)r * C + c;
        a0 += part[0 * stride + idx];
        a1 += part[1 * stride + idx];
        a2 += part[2 * stride + idx];
        b0 += part[3 * stride + idx];
        b1 += part[4 * stride + idx];
        b2 += part[5 * stride + idx];
    }
    double cs = a0, cq = b0;
    const int ks[3] = {16, 32, 64};
    double add_s[3] = {0.0, (double)a1, (double)a2};
    double add_q[3] = {0.0, (double)b1, (double)b2};
    for (int sc = 0; sc < 3; sc++) {
        cs += add_s[sc]; cq += add_q[sc];
        double n = (double)S8 * ks[sc];
        double m = cs / n;
        double var = cq / n - m * m;
        if (var < 0.0) var = 0.0;
        g_s1m[sc * 256 + c] = (float)m;
        g_s1i[sc * 256 + c] = rsqrtf((float)var + BN_EPS);
    }
}

// ----------------------------------------------------------------------------
// R14: 128x128 GEMM with double-buffered k-tiles
// ----------------------------------------------------------------------------
__global__ __launch_bounds__(256, 2)
void gemm128_kernel(const float* __restrict__ A, const float* __restrict__ W,
                    const float* __restrict__ bias, float* __restrict__ C,
                    int R, int D, int O, int useStats) {
    __shared__ float As[2][16][132];
    __shared__ float Ws[2][16][132];
    __shared__ float sM[256];
    __shared__ float sI[256];
    int tid = threadIdx.x;
    if (useStats) {
        for (int c = tid; c < D; c += 256) { sM[c] = g_m1[c]; sI[c] = g_i1[c]; }
        __syncthreads();
    }
    long rowBase = (long)blockIdx.y * 128;
    int colBase = blockIdx.x * 128;
    int tr = tid >> 4, tc = tid & 15;
    int lrow = tid >> 2;
    int kq = (tid & 3) * 4;
    float acc[8][8];
    #pragma unroll
    for (int i = 0; i < 8; i++)
        #pragma unroll
        for (int j = 0; j < 8; j++) acc[i][j] = 0.f;

    int nT = D >> 4;
    #pragma unroll
    for (int half = 0; half < 2; half++) {
        int row = lrow + 64 * half;
        float4 av = *(const float4*)(A + (rowBase + row) * D + kq);
        if (useStats) {
            av.x = fmaxf((av.x - sM[kq + 0]) * sI[kq + 0], 0.f);
            av.y = fmaxf((av.y - sM[kq + 1]) * sI[kq + 1], 0.f);
            av.z = fmaxf((av.z - sM[kq + 2]) * sI[kq + 2], 0.f);
            av.w = fmaxf((av.w - sM[kq + 3]) * sI[kq + 3], 0.f);
        }
        As[0][kq + 0][row] = av.x;
        As[0][kq + 1][row] = av.y;
        As[0][kq + 2][row] = av.z;
        As[0][kq + 3][row] = av.w;
        int wr = colBase + row;
        float4 wv = make_float4(0.f, 0.f, 0.f, 0.f);
        if (wr < O) wv = *(const float4*)(W + (long)wr * D + kq);
        Ws[0][kq + 0][row] = wv.x;
        Ws[0][kq + 1][row] = wv.y;
        Ws[0][kq + 2][row] = wv.z;
        Ws[0][kq + 3][row] = wv.w;
    }
    __syncthreads();

    int cur = 0;
    for (int t = 0; t < nT; t++) {
        float4 sa[2], sw[2];
        bool has = (t + 1) < nT;
        if (has) {
            int kc = (t + 1) * 16 + kq;
            #pragma unroll
            for (int half = 0; half < 2; half++) {
                int row = lrow + 64 * half;
                float4 av = *(const float4*)(A + (rowBase + row) * D + kc);
                if (useStats) {
                    av.x = fmaxf((av.x - sM[kc + 0]) * sI[kc + 0], 0.f);
                    av.y = fmaxf((av.y - sM[kc + 1]) * sI[kc + 1], 0.f);
                    av.z = fmaxf((av.z - sM[kc + 2]) * sI[kc + 2], 0.f);
                    av.w = fmaxf((av.w - sM[kc + 3]) * sI[kc + 3], 0.f);
                }
                sa[half] = av;
                int wr = colBase + row;
                float4 wv = make_float4(0.f, 0.f, 0.f, 0.f);
                if (wr < O) wv = *(const float4*)(W + (long)wr * D + kc);
                sw[half] = wv;
            }
        }
        #pragma unroll
        for (int kk = 0; kk < 16; kk++) {
            float a[8], w[8];
            *(float4*)(a + 0) = *(const float4*)&As[cur][kk][tr * 8 + 0];
            *(float4*)(a + 4) = *(const float4*)&As[cur][kk][tr * 8 + 4];
            *(float4*)(w + 0) = *(const float4*)&Ws[cur][kk][tc * 8 + 0];
            *(float4*)(w + 4) = *(const float4*)&Ws[cur][kk][tc * 8 + 4];
            #pragma unroll
            for (int i = 0; i < 8; i++)
                #pragma unroll
                for (int j = 0; j < 8; j++)
                    acc[i][j] += a[i] * w[j];
        }
        if (has) {
            int nxt = cur ^ 1;
            #pragma unroll
            for (int half = 0; half < 2; half++) {
                int row = lrow + 64 * half;
                As[nxt][kq + 0][row] = sa[half].x;
                As[nxt][kq + 1][row] = sa[half].y;
                As[nxt][kq + 2][row] = sa[half].z;
                As[nxt][kq + 3][row] = sa[half].w;
                Ws[nxt][kq + 0][row] = sw[half].x;
                Ws[nxt][kq + 1][row] = sw[half].y;
                Ws[nxt][kq + 2][row] = sw[half].z;
                Ws[nxt][kq + 3][row] = sw[half].w;
            }
        }
        __syncthreads();
        cur ^= 1;
    }
    #pragma unroll
    for (int i = 0; i < 8; i++) {
        long row = rowBase + tr * 8 + i;
        int col0 = colBase + tc * 8;
        if (col0 >= O) continue;
        float b0 = 0, b1 = 0, b2 = 0, b3 = 0, b4 = 0, b5 = 0, b6 = 0, b7 = 0;
        if (bias) {
            b0 = bias[col0 + 0]; b1 = bias[col0 + 1]; b2 = bias[col0 + 2]; b3 = bias[col0 + 3];
            b4 = bias[col0 + 4]; b5 = bias[col0 + 5]; b6 = bias[col0 + 6]; b7 = bias[col0 + 7];
        }
        float4 v0 = make_float4(acc[i][0] + b0, acc[i][1] + b1, acc[i][2] + b2, acc[i][3] + b3);
        float4 v1 = make_float4(acc[i][4] + b4, acc[i][5] + b5, acc[i][6] + b6, acc[i][7] + b7);
        *(float4*)(C + row * O + col0) = v0;
        *(float4*)(C + row * O + col0 + 4) = v1;
    }
}

// ----------------------------------------------------------------------------
// R16: fused local-op GEMM2, ALL THREE k-scales in one launch.
// Block y decodes scale si (kshift = 4+si), its pool offset (si*O), its BN1
// params (g_s1m + si*256) and its disjoint partial region within g_part.
// ----------------------------------------------------------------------------
__global__ __launch_bounds__(256, 2)
void local_gemm2_kernel(const float* __restrict__ U, const float* __restrict__ V,
                        const int* __restrict__ knn, const float* __restrict__ W,
                        float* __restrict__ poolOut,
                        int S, int N, int D, int O,
                        int n16, int n32, int OC) {
    __shared__ float As[2][16][132];
    __shared__ float Ws[2][16][132];
    __shared__ float sRed[16][132];
    __shared__ float sM[256];
    __shared__ float sI[256];
    __shared__ int sP[128];
    __shared__ int sS[128];
    int tid = threadIdx.x;
    int by = blockIdx.y;
    int si, localY;
    if (by < n16)            { si = 0; localY = by; }
    else if (by < n16 + n32) { si = 1; localY = by - n16; }
    else                     { si = 2; localY = by - n16 - n32; }
    int kshift = 4 + si;
    int nBy = (si == 0) ? n16 : (si == 1) ? n32 : (gridDim.y - n16 - n32);
    long partBase = (si == 0) ? 0L : (si == 1) ? 2L * n16 * O : 2L * (n16 + n32) * O;
    float* part = g_part + partBase;
    const float* bn1M = g_s1m + si * 256;
    const float* bn1I = g_s1i + si * 256;
    int off = si * O;
    long rowBase = (long)localY * 128;
    int colBase = blockIdx.x * 128;

    for (int c = tid; c < D; c += 256) { sM[c] = bn1M[c]; sI[c] = bn1I[c]; }
    if (tid < 128) {
        long grow = rowBase + tid;
        int s = (int)(grow >> kshift);
        int j = (int)(grow & ((1 << kshift) - 1));
        int b = s / S;
        sS[tid] = s;
        sP[tid] = b * N + knn[(long)s * 64 + j];
    }
    __syncthreads();

    int tr = tid >> 4, tc = tid & 15;
    int lrow = tid >> 2;
    int kq = (tid & 3) * 4;
    float acc[8][8];
    #pragma unroll
    for (int i = 0; i < 8; i++)
        #pragma unroll
        for (int j = 0; j < 8; j++) acc[i][j] = 0.f;

    int nT = D >> 4;
    int p0 = sP[lrow], p1 = sP[lrow + 64];
    int s0i = sS[lrow], s1i = sS[lrow + 64];
    {
        #pragma unroll
        for (int half = 0; half < 2; half++) {
            int row = lrow + 64 * half;
            int pi = half ? p1 : p0;
            int sidx = half ? s1i : s0i;
            float4 uv = *(const float4*)(U + (long)pi * D + kq);
            float4 vv = *(const float4*)(V + (long)sidx * D + kq);
            As[0][kq + 0][row] = fmaxf((uv.x + vv.x - sM[kq + 0]) * sI[kq + 0], 0.f);
            As[0][kq + 1][row] = fmaxf((uv.y + vv.y - sM[kq + 1]) * sI[kq + 1], 0.f);
            As[0][kq + 2][row] = fmaxf((uv.z + vv.z - sM[kq + 2]) * sI[kq + 2], 0.f);
            As[0][kq + 3][row] = fmaxf((uv.w + vv.w - sM[kq + 3]) * sI[kq + 3], 0.f);
            float4 wv = *(const float4*)(W + (long)(colBase + row) * D + kq);
            Ws[0][kq + 0][row] = wv.x;
            Ws[0][kq + 1][row] = wv.y;
            Ws[0][kq + 2][row] = wv.z;
            Ws[0][kq + 3][row] = wv.w;
        }
    }
    __syncthreads();

    int cur = 0;
    for (int t = 0; t < nT; t++) {
        float4 sa[2], sw[2];
        bool has = (t + 1) < nT;
        if (has) {
            int kc = (t + 1) * 16 + kq;
            #pragma unroll
            for (int half = 0; half < 2; half++) {
                int row = lrow + 64 * half;
                int pi = half ? p1 : p0;
                int sidx = half ? s1i : s0i;
                float4 uv = *(const float4*)(U + (long)pi * D + kc);
                float4 vv = *(const float4*)(V + (long)sidx * D + kc);
                float4 av;
                av.x = fmaxf((uv.x + vv.x - sM[kc + 0]) * sI[kc + 0], 0.f);
                av.y = fmaxf((uv.y + vv.y - sM[kc + 1]) * sI[kc + 1], 0.f);
                av.z = fmaxf((uv.z + vv.z - sM[kc + 2]) * sI[kc + 2], 0.f);
                av.w = fmaxf((uv.w + vv.w - sM[kc + 3]) * sI[kc + 3], 0.f);
                sa[half] = av;
                sw[half] = *(const float4*)(W + (long)(colBase + row) * D + kc);
            }
        }
        #pragma unroll
        for (int kk = 0; kk < 16; kk++) {
            float a[8], w[8];
            *(float4*)(a + 0) = *(const float4*)&As[cur][kk][tr * 8 + 0];
            *(float4*)(a + 4) = *(const float4*)&As[cur][kk][tr * 8 + 4];
            *(float4*)(w + 0) = *(const float4*)&Ws[cur][kk][tc * 8 + 0];
            *(float4*)(w + 4) = *(const float4*)&Ws[cur][kk][tc * 8 + 4];
            #pragma unroll
            for (int i = 0; i < 8; i++)
                #pragma unroll
                for (int j = 0; j < 8; j++)
                    acc[i][j] += a[i] * w[j];
        }
        if (has) {
            int nxt = cur ^ 1;
            #pragma unroll
            for (int half = 0; half < 2; half++) {
                int row = lrow + 64 * half;
                As[nxt][kq + 0][row] = sa[half].x;
                As[nxt][kq + 1][row] = sa[half].y;
                As[nxt][kq + 2][row] = sa[half].z;
                As[nxt][kq + 3][row] = sa[half].w;
                Ws[nxt][kq + 0][row] = sw[half].x;
                Ws[nxt][kq + 1][row] = sw[half].y;
                Ws[nxt][kq + 2][row] = sw[half].z;
                Ws[nxt][kq + 3][row] = sw[half].w;
            }
        }
        __syncthreads();
        cur ^= 1;
    }

    // epilogue 1: per-center raw max -> poolOut
    int g = (1 << kshift) >> 3;
    #pragma unroll
    for (int j = 0; j < 8; j++) {
        float m = acc[0][j];
        #pragma unroll
        for (int i = 1; i < 8; i++) m = fmaxf(m, acc[i][j]);
        sRed[tr][tc * 8 + j] = m;
    }
    __syncthreads();
    if ((tr & (g - 1)) == 0) {
        int s = sS[tr * 8];
        #pragma unroll
        for (int j = 0; j < 8; j++) {
            float m = sRed[tr][tc * 8 + j];
            for (int q = 1; q < g; q++) m = fmaxf(m, sRed[tr + q][tc * 8 + j]);
            poolOut[(long)s * OC + off + colBase + tc * 8 + j] = m;
        }
    }
    __syncthreads();
    // epilogue 2: per-block channel sums -> this scale's partial region
    #pragma unroll
    for (int j = 0; j < 8; j++) {
        float sm = 0.f;
        #pragma unroll
        for (int i = 0; i < 8; i++) sm += acc[i][j];
        sRed[tr][tc * 8 + j] = sm;
    }
    __syncthreads();
    if (tr == 0) {
        #pragma unroll
        for (int j = 0; j < 8; j++) {
            float tot = 0.f;
            for (int q = 0; q < 16; q++) tot += sRed[q][tc * 8 + j];
            part[(long)localY * O + colBase + tc * 8 + j] = tot;
        }
    }
    __syncthreads();
    #pragma unroll
    for (int j = 0; j < 8; j++) {
        float sm = 0.f;
        #pragma unroll
        for (int i = 0; i < 8; i++) sm += acc[i][j] * acc[i][j];
        sRed[tr][tc * 8 + j] = sm;
    }
    __syncthreads();
    if (tr == 0) {
        #pragma unroll
        for (int j = 0; j < 8; j++) {
            float tot = 0.f;
            for (int q = 0; q < 16; q++) tot += sRed[q][tc * 8 + j];
            part[((long)nBy + localY) * O + colBase + tc * 8 + j] = tot;
        }
    }
}

__global__ void split_w1_kernel(const float* __restrict__ w1, float* __restrict__ wa,
                                float* __restrict__ wd, int O, int D, int total) {
    int t = blockIdx.x * 256 + threadIdx.x;
    if (t >= total) return;
    int d = t % D, o = t / D;
    float a = w1[(long)o * 2 * D + d];
    float b = w1[(long)o * 2 * D + D + d];
    wa[t] = a;
    wd[t] = b - a;
}

// ----------------------------------------------------------------------------
// Generic fallback GEMM (odd shapes)
// ----------------------------------------------------------------------------
__global__ void gemm_kernel(const float* __restrict__ A, const float* __restrict__ W,
                            const float* __restrict__ bias, float* __restrict__ C,
                            int R, int D, int O) {
    __shared__ float As[64][17];
    __shared__ float Ws[64][17];
    int tid = threadIdx.x;
    int tr = tid >> 4, tc = tid & 15;
    long rowBase = (long)blockIdx.y * 64;
    int colBase = blockIdx.x * 64;
    float acc[4][4] = {};
    for (int k0 = 0; k0 < D; k0 += 16) {
        #pragma unroll
        for (int e = tid; e < 1024; e += 256) {
            int rr = e >> 4, kk = e & 15;
            long ar = rowBase + rr; int ac = k0 + kk;
            As[rr][kk] = (ar < R && ac < D) ? A[ar * D + ac] : 0.f;
            int wr = colBase + rr;
            Ws[rr][kk] = (wr < O && ac < D) ? W[(long)wr * D + ac] : 0.f;
        }
        __syncthreads();
        #pragma unroll
        for (int kk = 0; kk < 16; kk++) {
            float a[4], w[4];
            #pragma unroll
            for (int i = 0; i < 4; i++) a[i] = As[tr + 16*i][kk];
            #pragma unroll
            for (int j = 0; j < 4; j++) w[j] = Ws[tc + 16*j][kk];
            #pragma unroll
            for (int i = 0; i < 4; i++)
                #pragma unroll
                for (int j = 0; j < 4; j++)
                    acc[i][j] += a[i] * w[j];
        }
        __syncthreads();
    }
    #pragma unroll
    for (int i = 0; i < 4; i++) {
        long row = rowBase + tr + 16*i;
        if (row >= R) continue;
        #pragma unroll
        for (int j = 0; j < 4; j++) {
            int col = colBase + tc + 16*j;
            if (col >= O) continue;
            float vv = acc[i][j];
            if (bias) vv += bias[col];
            C[row * O + col] = vv;
        }
    }
}

// ----------------------------------------------------------------------------
// Layout / elementwise helpers
// ----------------------------------------------------------------------------
__global__ void transpose_x_kernel(const float* __restrict__ x, float* __restrict__ xyz) {
    int t = blockIdx.x * 256 + threadIdx.x;
    if (t >= 8 * 2048 * 3) return;
    int c = t % 3; int n = (t / 3) % 2048; int b = t / (3 * 2048);
    xyz[t] = x[((long)b * 3 + c) * 2048 + n];
}

__global__ void gather_kernel(const float* __restrict__ src, const int* __restrict__ idx,
                              float* __restrict__ dst, int S, int N, int D, long total) {
    long t = (long)blockIdx.x * blockDim.x + threadIdx.x;
    if (t >= total) return;
    int c = (int)(t % D); long bs = t / D;
    int b = (int)(bs / S);
    dst[t] = src[((long)b * N + idx[bs]) * D + c];
}

__global__ void catf1_kernel(const float* __restrict__ f1, float* __restrict__ cat) {
    int t = blockIdx.x * 256 + threadIdx.x;
    int c = t & 255; int row = t >> 8;
    cat[(long)row * 1280 + 1024 + c] = f1[t];
}

__global__ void maxn_kernel(const float* __restrict__ X, float* __restrict__ G) {
    int b = blockIdx.x; int c = blockIdx.y * 256 + threadIdx.x;
    float m = -FLT_MAX;
    for (int n = 0; n < 256; n++) m = fmaxf(m, X[((long)b * 256 + n) * 1024 + c]);
    G[b * 1024 + c] = m;
}

// ----------------------------------------------------------------------------
// FPS / kNN with warp-shuffle reductions (tie order preserved)
// ----------------------------------------------------------------------------
__device__ __forceinline__ unsigned keymap(float f) {
    unsigned u = __float_as_uint(f);
    return (u & 0x80000000u) ? ~u : (u | 0x80000000u);
}

__device__ void fps_body(const float* __restrict__ xyz, int N, int npoint,
                         int* __restrict__ outIdx, int b,
                         float* sx, float* sy, float* sz, float* sd,
                         unsigned long long* warpBest, int* sFar) {
    int t = threadIdx.x;
    int nt = blockDim.x;
    int numWarps = nt >> 5;
    for (int n = t; n < N; n += nt) {
        sx[n] = xyz[((long)b * N + n) * 3 + 0];
        sy[n] = xyz[((long)b * N + n) * 3 + 1];
        sz[n] = xyz[((long)b * N + n) * 3 + 2];
        sd[n] = 1e10f;
    }
    __syncthreads();
    int far = 0;
    for (int it = 0; it < npoint; it++) {
        if (t == 0) outIdx[b * npoint + it] = far;
        float cx = sx[far], cy = sy[far], cz = sz[far];
        unsigned long long best = 0ull;
        for (int n = t; n < N; n += nt) {
            float dx = sx[n] - cx, dy = sy[n] - cy, dz = sz[n] - cz;
            float d = dx * dx + dy * dy + dz * dz;
            float dm = fminf(sd[n], d);
            sd[n] = dm;
            unsigned long long key = ((unsigned long long)keymap(dm) << 32) | (unsigned)(~n);
            if (key > best) best = key;
        }
        #pragma unroll
        for (int o = 16; o > 0; o >>= 1) {
            unsigned long long other = __shfl_xor_sync(0xffffffffu, best, o);
            if (other > best) best = other;
        }
        if ((t & 31) == 0) warpBest[t >> 5] = best;
        __syncthreads();
        if (t < 32) {
            unsigned long long v = (t < numWarps) ? warpBest[t] : 0ull;
            #pragma unroll
            for (int o = 16; o > 0; o >>= 1) {
                unsigned long long other = __shfl_xor_sync(0xffffffffu, v, o);
                if (other > v) v = other;
            }
            if (t == 0) *sFar = (int)(~((unsigned)(v & 0xffffffffu)));
        }
        __syncthreads();
        far = *sFar;
    }
}

__device__ void knn_body(const float* __restrict__ centers, const float* __restrict__ xyz,
                         int S, int N, int* __restrict__ knnOut, int bs,
                         float* sd, unsigned long long* warpBest) {
    int t = threadIdx.x;
    int nt = blockDim.x;
    int numWarps = nt >> 5;
    int b = bs / S;
    float cx = centers[(long)bs * 3 + 0];
    float cy = centers[(long)bs * 3 + 1];
    float cz = centers[(long)bs * 3 + 2];
    float cn = cx * cx + cy * cy + cz * cz;
    for (int n = t; n < N; n += nt) {
        float px = xyz[((long)b * N + n) * 3 + 0];
        float py = xyz[((long)b * N + n) * 3 + 1];
        float pz = xyz[((long)b * N + n) * 3 + 2];
        float pn = px * px + py * py + pz * pz;
        float dot = cx * px + cy * py + cz * pz;
        sd[n] = cn + pn - 2.f * dot;
    }
    __syncthreads();
    for (int j = 0; j < 64; j++) {
        unsigned long long best = 0xFFFFFFFFFFFFFFFFull;
        for (int n = t; n < N; n += nt) {
            unsigned long long key = ((unsigned long long)keymap(sd[n]) << 32) | (unsigned)n;
            if (key < best) best = key;
        }
        #pragma unroll
        for (int o = 16; o > 0; o >>= 1) {
            unsigned long long other = __shfl_xor_sync(0xffffffffu, best, o);
            if (other < best) best = other;
        }
        if ((t & 31) == 0) warpBest[t >> 5] = best;
        __syncthreads();
        if (t < 32) {
            unsigned long long v = (t < numWarps) ? warpBest[t] : 0xFFFFFFFFFFFFFFFFull;
            #pragma unroll
            for (int o = 16; o > 0; o >>= 1) {
                unsigned long long other = __shfl_xor_sync(0xffffffffu, v, o);
                if (other < v) v = other;
            }
            if (t == 0) {
                int sel = (int)(v & 0xffffffffu);
                knnOut[(long)bs * 64 + j] = sel;
                sd[sel] = FLT_MAX;
            }
        }
        __syncthreads();
    }
}

__global__ void fps_kernel(const float* xyz, int N, int npoint, int* outIdx) {
    __shared__ float buf[4 * 2048];
    __shared__ unsigned long long wb[32];
    __shared__ int sFar;
    fps_body(xyz, N, npoint, outIdx, blockIdx.x, buf, buf + N, buf + 2 * N, buf + 3 * N, wb, &sFar);
}

__global__ void knn_kernel(const float* centers, const float* xyz, int S, int N, int* knnOut) {
    __shared__ float buf[2048];
    __shared__ unsigned long long wb[32];
    knn_body(centers, xyz, S, N, knnOut, blockIdx.x, buf, wb);
}

__global__ void knn_fps_kernel(const float* centers, const float* xyz, int S, int N,
                               int* knnOut, int nKnn,
                               const float* xyz2, int N2, int np2, int* outIdx2) {
    __shared__ float buf[4 * 2048];
    __shared__ unsigned long long wb[32];
    __shared__ int sFar;
    if (blockIdx.x < nKnn) {
        knn_body(centers, xyz, S, N, knnOut, blockIdx.x, buf, wb);
    } else {
        int b = blockIdx.x - nKnn;
        fps_body(xyz2, N2, np2, outIdx2, b, buf, buf + N2, buf + 2 * N2, buf + 3 * N2, wb, &sFar);
    }
}

// ----------------------------------------------------------------------------
// Attention (reference reshape quirk preserved)
// ----------------------------------------------------------------------------
__global__ void gemmqv_kernel(const float* __restrict__ xx, const float* __restrict__ pos,
                              const float* __restrict__ wqk, const float* __restrict__ wv,
                              const float* __restrict__ bv,
                              float* __restrict__ qb, float* __restrict__ vb) {
    __shared__ float As[16][132];
    __shared__ float Ws[16][132];
    int tid = threadIdx.x;
    long rowBase = (long)blockIdx.y * 128;
    int colBase = blockIdx.x * 128;
    int tr = tid >> 4, tc = tid & 15;
    int lrow = tid >> 2;
    int lkq = tid & 3;
    const int D = 256;
    float acc[8][8];
    #pragma unroll
    for (int i = 0; i < 8; i++)
        #pragma unroll
        for (int j = 0; j < 8; j++) acc[i][j] = 0.f;

    for (int k0 = 0; k0 < D; k0 += 16) {
        #pragma unroll
        for (int half = 0; half < 2; half++) {
            int row = lrow + 64 * half;
            int kc = k0 + lkq * 4;
            float4 av = *(const float4*)(xx + (rowBase + row) * D + kc);
            float4 pv = *(const float4*)(pos + (rowBase + row) * D + kc);
            As[lkq * 4 + 0][row] = av.x + pv.x;
            As[lkq * 4 + 1][row] = av.y + pv.y;
            As[lkq * 4 + 2][row] = av.z + pv.z;
            As[lkq * 4 + 3][row] = av.w + pv.w;
            int ocol = colBase + row;
            const float* Wp = (ocol < 256) ? (wqk + (long)ocol * D) : (wv + (long)(ocol - 256) * D);
            float4 wvv = *(const float4*)(Wp + kc);
            Ws[lkq * 4 + 0][row] = wvv.x;
            Ws[lkq * 4 + 1][row] = wvv.y;
            Ws[lkq * 4 + 2][row] = wvv.z;
            Ws[lkq * 4 + 3][row] = wvv.w;
        }
        __syncthreads();
        #pragma unroll
        for (int kk = 0; kk < 16; kk++) {
            float a[8], w[8];
            *(float4*)(a + 0) = *(const float4*)&As[kk][tr * 8 + 0];
            *(float4*)(a + 4) = *(const float4*)&As[kk][tr * 8 + 4];
            *(float4*)(w + 0) = *(const float4*)&Ws[kk][tc * 8 + 0];
            *(float4*)(w + 4) = *(const float4*)&Ws[kk][tc * 8 + 4];
            #pragma unroll
            for (int i = 0; i < 8; i++)
                #pragma unroll
                for (int j = 0; j < 8; j++)
                    acc[i][j] += a[i] * w[j];
        }
        __syncthreads();
    }
    int col0 = colBase + tc * 8;
    #pragma unroll
    for (int i = 0; i < 8; i++) {
        long row = rowBase + tr * 8 + i;
        if (col0 < 256) {
            float4 v0 = make_float4(acc[i][0], acc[i][1], acc[i][2], acc[i][3]);
            float4 v1 = make_float4(acc[i][4], acc[i][5], acc[i][6], acc[i][7]);
            *(float4*)(qb + row * 256 + col0) = v0;
            *(float4*)(qb + row * 256 + col0 + 4) = v1;
        } else {
            int cc = col0 - 256;
            float4 v0 = make_float4(acc[i][0] + bv[cc + 0], acc[i][1] + bv[cc + 1],
                                    acc[i][2] + bv[cc + 2], acc[i][3] + bv[cc + 3]);
            float4 v1 = make_float4(acc[i][4] + bv[cc + 4], acc[i][5] + bv[cc + 5],
                                    acc[i][6] + bv[cc + 6], acc[i][7] + bv[cc + 7]);
            *(float4*)(vb + row * 256 + cc) = v0;
            *(float4*)(vb + row * 256 + cc + 4) = v1;
        }
    }
}

// R15: 64x64-tile gram (reference reshape quirk preserved)
__global__ void gram64_kernel(const float* __restrict__ Q, float* __restrict__ A) {
    int bh = blockIdx.z; int b = bh >> 2; int h = bh & 3;
    int i0 = blockIdx.y * 64, j0 = blockIdx.x * 64;
    __shared__ float Qi[64][68];
    __shared__ float Qj[64][68];
    int tid = threadIdx.x;
    #pragma unroll
    for (int it = 0; it < 4; it++) {
        int idx = tid + it * 256;
        int r = idx >> 4;
        int dq = (idx & 15) * 4;
        int i = i0 + r;
        float4 qi = *(const float4*)(Q + ((long)b * 256 + h * 64 + (i >> 2)) * 256 + (i & 3) * 64 + dq);
        Qi[dq + 0][r] = qi.x;
        Qi[dq + 1][r] = qi.y;
        Qi[dq + 2][r] = qi.z;
        Qi[dq + 3][r] = qi.w;
        float4 qj = *(const float4*)(Q + ((long)b * 256 + j0 + r) * 256 + h * 64 + dq);
        Qj[dq + 0][r] = qj.x;
        Qj[dq + 1][r] = qj.y;
        Qj[dq + 2][r] = qj.z;
        Qj[dq + 3][r] = qj.w;
    }
    __syncthreads();
    int tr = tid >> 4, tc = tid & 15;
    float acc[4][4] = {};
    #pragma unroll
    for (int d = 0; d < 64; d++) {
        float4 a4 = *(const float4*)&Qi[d][tr * 4];
        float4 b4 = *(const float4*)&Qj[d][tc * 4];
        float a[4] = {a4.x, a4.y, a4.z, a4.w};
        float w[4] = {b4.x, b4.y, b4.z, b4.w};
        #pragma unroll
        for (int ii = 0; ii < 4; ii++)
            #pragma unroll
            for (int jj = 0; jj < 4; jj++)
                acc[ii][jj] += a[ii] * w[jj];
    }
    #pragma unroll
    for (int ii = 0; ii < 4; ii++) {
        long row = (long)bh * 256 + i0 + tr * 4 + ii;
        #pragma unroll
        for (int jj = 0; jj < 4; jj++)
            A[row * 256 + j0 + tc * 4 + jj] = acc[ii][jj];
    }
}

__global__ void softmax_row_kernel(float* __restrict__ A) {
    __shared__ float red[256];
    long row = blockIdx.x;
    float* p = A + row * 256;
    int t = threadIdx.x;
    float v = p[t];
    red[t] = v; __syncthreads();
    for (int s = 128; s > 0; s >>= 1) { if (t < s) red[t] = fmaxf(red[t], red[t + s]); __syncthreads(); }
    float m = red[0]; __syncthreads();
    float e = expf(v - m);
    red[t] = e; __syncthreads();
    for (int s = 128; s > 0; s >>= 1) { if (t < s) red[t] += red[t + s]; __syncthreads(); }
    p[t] = e / red[0];
}

// R15: coalesced column softmax (axis -2)
__global__ void colsm_kernel(float* __restrict__ A) {
    int bh = blockIdx.y;
    int i0 = blockIdx.x * 64;
    int t = threadIdx.x;
    int jl = t >> 6, il = t & 63;
    __shared__ float red[4][64];
    __shared__ float smax[64], ssum[64];
    long base = (long)bh * 256 * 256 + i0 + il;
    float mx = -FLT_MAX;
    for (int r = jl; r < 256; r += 4)
        mx = fmaxf(mx, A[base + (long)r * 256]);
    red[jl][il] = mx;
    __syncthreads();
    if (jl == 0)
        smax[il] = fmaxf(fmaxf(red[0][il], red[1][il]), fmaxf(red[2][il], red[3][il]));
    __syncthreads();
    float sm = 0.f;
    for (int r = jl; r < 256; r += 4)
        sm += expf(A[base + (long)r * 256] - smax[il]);
    red[jl][il] = sm;
    __syncthreads();
    if (jl == 0)
        ssum[il] = red[0][il] + red[1][il] + red[2][il] + red[3][il];
    __syncthreads();
    for (int r = jl; r < 256; r += 4) {
        long idx = base + (long)r * 256;
        A[idx] = expf(A[idx] - smax[il]) / ssum[il];
    }
}

// R15: XR as tiled GEMM with fused xrb = xx + pos - XR epilogue
__global__ void xr_gemm_kernel(const float* __restrict__ A2, const float* __restrict__ Vb,
                               const float* __restrict__ xx, const float* __restrict__ pos,
                               float* __restrict__ xrb) {
    int bh = blockIdx.y; int b = bh >> 2; int h = bh & 3;
    int i0 = blockIdx.x * 64;
    __shared__ float As[16][68];
    __shared__ float Vs[16][68];
    int tid = threadIdx.x;
    int rk = tid >> 4;
    int cq = (tid & 15) * 4;
    int tr = tid >> 4, tc = tid & 15;
    float acc[4][4] = {};
    for (int j0 = 0; j0 < 256; j0 += 16) {
        float4 a4 = *(const float4*)(A2 + ((long)bh * 256 + j0 + rk) * 256 + i0 + cq);
        As[rk][cq + 0] = a4.x;
        As[rk][cq + 1] = a4.y;
        As[rk][cq + 2] = a4.z;
        As[rk][cq + 3] = a4.w;
        float4 v4 = *(const float4*)(Vb + ((long)b * 256 + j0 + rk) * 256 + h * 64 + cq);
        Vs[rk][cq + 0] = v4.x;
        Vs[rk][cq + 1] = v4.y;
        Vs[rk][cq + 2] = v4.z;
        Vs[rk][cq + 3] = v4.w;
        __syncthreads();
        #pragma unroll
        for (int jk = 0; jk < 16; jk++) {
            float4 aa = *(const float4*)&As[jk][tr * 4];
            float4 vv = *(const float4*)&Vs[jk][tc * 4];
            float a[4] = {aa.x, aa.y, aa.z, aa.w};
            float w[4] = {vv.x, vv.y, vv.z, vv.w};
            #pragma unroll
            for (int ii = 0; ii < 4; ii++)
                #pragma unroll
                for (int cc = 0; cc < 4; cc++)
                    acc[ii][cc] += a[ii] * w[cc];
        }
        __syncthreads();
    }
    #pragma unroll
    for (int ii = 0; ii < 4; ii++) {
        long row = (long)b * 256 + i0 + tr * 4 + ii;
        #pragma unroll
        for (int cc = 0; cc < 4; cc++) {
            long idx = row * 256 + h * 64 + tc * 4 + cc;
            xrb[idx] = xx[idx] + pos[idx] - acc[ii][cc];
        }
    }
}

__global__ void addcat_bn_kernel(const float* __restrict__ qb, float* __restrict__ xx,
                                 const float* __restrict__ pos, float* __restrict__ cat,
                                 int layer) {
    int t = blockIdx.x * 256 + threadIdx.x;
    int c = t & 255; int row = t >> 8;
    float y = fmaxf((qb[t] - g_m1[c]) * g_i1[c], 0.f);
    float v = xx[t] + pos[t] + y;
    xx[t] = v;
    cat[(long)row * 1280 + layer * 256 + c] = v;
}

// ----------------------------------------------------------------------------
// Host orchestration
// ----------------------------------------------------------------------------
static void gemm_old(const float* A, const float* W, const float* bias, float* C,
                     int R, int D, int O) {
    dim3 grid(CEILDIV(O, 64), CEILDIV(R, 64));
    gemm_kernel<<<grid, 256>>>(A, W, bias, C, R, D, O);
}

static void gemm_big(const float* A, const float* W, const float* bias, float* C,
                     int R, int D, int O, int useStats) {
    dim3 grid(CEILDIV(O, 128), R / 128);
    gemm128_kernel<<<grid, 256>>>(A, W, bias, C, R, D, O, useStats);
}

static float* s_part;

static void computeStats(const float* X, int R, int C) {
    int rpb = R / 512;
    if (rpb < 8) rpb = 8;
    int nB = R / rpb;
    stats_part_kernel<<<nB, 256>>>(X, R, C, rpb, nB, s_part);
    reduce_m1_kernel<<<C, 256>>>(s_part, nB, C, R);
}

static void bn(float* X, int R, int C, int act) {
    computeStats(X, R, C);
    long total = (long)R * C;
    bn_apply_kernel<<<(int)CEILDIV(total, 256), 256>>>(X, total, C, act);
}

extern "C" void kernel_launch(void* const* d_in, const int* in_sizes, int n_in,
                              void* d_out, int out_size) {
    const float* x       = (const float*)d_in[0];
    const float* conv1_w = (const float*)d_in[1];
    const float* conv2_w = (const float*)d_in[2];
    const float* g0_w1   = (const float*)d_in[3];
    const float* g0_w2   = (const float*)d_in[4];
    const float* g0_wc   = (const float*)d_in[5];
    const float* g1_w1   = (const float*)d_in[6];
    const float* g1_w2   = (const float*)d_in[7];
    const float* g1_wc   = (const float*)d_in[8];
    const float* pt_w    = (const float*)d_in[9];
    const float* pos_w   = (const float*)d_in[10];
    const float* pos_b   = (const float*)d_in[11];
    const float* sa_wqk  = (const float*)d_in[12];
    const float* sa_wv   = (const float*)d_in[13];
    const float* sa_bv   = (const float*)d_in[14];
    const float* sa_wt   = (const float*)d_in[15];
    const float* sa_bt   = (const float*)d_in[16];
    const float* fuse_w  = (const float*)d_in[17];
    const float* lin1_w  = (const float*)d_in[18];
    const float* lin2_w  = (const float*)d_in[19];
    const float* lin2_b  = (const float*)d_in[20];
    const float* lin3_w  = (const float*)d_in[21];
    const float* lin3_b  = (const float*)d_in[22];
    float* out = (float*)d_out;

    float *xyz, *h1, *points, *newxyz, *newxyz2, *newpts, *Ub, *Vb, *w1a, *w1d, *pool, *f0, *f1;
    float *pos, *xx, *qb, *vb, *xrb, *attn, *catb, *fuseb, *gmax, *l1, *l2;
    int *fpsidx, *knn, *knn2;
    cudaGetSymbolAddress((void**)&xyz, g_xyz);
    cudaGetSymbolAddress((void**)&h1, g_h1);
    cudaGetSymbolAddress((void**)&points, g_points);
    cudaGetSymbolAddress((void**)&fpsidx, g_fpsidx);
    cudaGetSymbolAddress((void**)&newxyz, g_newxyz);
    cudaGetSymbolAddress((void**)&newxyz2, g_newxyz2);
    cudaGetSymbolAddress((void**)&newpts, g_newpts);
    cudaGetSymbolAddress((void**)&knn, g_knn);
    cudaGetSymbolAddress((void**)&knn2, g_knn2);
    cudaGetSymbolAddress((void**)&Ub, g_U);
    cudaGetSymbolAddress((void**)&Vb, g_V);
    cudaGetSymbolAddress((void**)&w1a, g_w1a);
    cudaGetSymbolAddress((void**)&w1d, g_w1d);
    cudaGetSymbolAddress((void**)&s_part, g_part);
    cudaGetSymbolAddress((void**)&pool, g_pool);
    cudaGetSymbolAddress((void**)&f0, g_f0);
    cudaGetSymbolAddress((void**)&f1, g_f1);
    cudaGetSymbolAddress((void**)&pos, g_pos);
    cudaGetSymbolAddress((void**)&xx, g_x);
    cudaGetSymbolAddress((void**)&qb, g_q);
    cudaGetSymbolAddress((void**)&vb, g_v);
    cudaGetSymbolAddress((void**)&xrb, g_xr);
    cudaGetSymbolAddress((void**)&attn, g_attn);
    cudaGetSymbolAddress((void**)&catb, g_cat);
    cudaGetSymbolAddress((void**)&fuseb, g_fuse);
    cudaGetSymbolAddress((void**)&gmax, g_gmax);
    cudaGetSymbolAddress((void**)&l1, g_l1);
    cudaGetSymbolAddress((void**)&l2, g_l2);

    // ---- Stage A ----
    transpose_x_kernel<<<CEILDIV(8*2048*3, 256), 256>>>(x, xyz);
    gemm_old(xyz, conv1_w, nullptr, h1, 16384, 3, 64);
    computeStats(h1, 16384, 64);
    gemm_big(h1, conv2_w, nullptr, points, 16384, 64, 64, 1);
    bn(points, 16384, 64, 0);

    // ---- Stage B ----
    fps_kernel<<<8, 1024>>>(xyz, 2048, 512, fpsidx);
    gather_kernel<<<CEILDIV(8*512*3, 256), 256>>>(xyz, fpsidx, newxyz, 512, 2048, 3, 8L*512*3);
    gather_kernel<<<CEILDIV(8*512*64, 256), 256>>>(points, fpsidx, newpts, 512, 2048, 64, 8L*512*64);
    knn_fps_kernel<<<4096 + 8, 256>>>(newxyz, xyz, 512, 2048, knn, 4096,
                                      newxyz, 512, 256, fpsidx);
    gather_kernel<<<CEILDIV(8*256*3, 256), 256>>>(newxyz, fpsidx, newxyz2, 256, 512, 3, 8L*256*3);
    knn_kernel<<<2048, 256>>>(newxyz2, newxyz, 256, 512, knn2);

    // ---- Stage C: local_op 0 (R16: all 3 scales fused in one launch) ----
    {
        split_w1_kernel<<<CEILDIV(128*64, 256), 256>>>(g0_w1, w1a, w1d, 128, 64, 128*64);
        gemm_big(points, w1a, nullptr, Ub, 16384, 64, 128, 0);
        gemm_big(newpts, w1d, nullptr, Vb, 4096, 64, 128, 0);
        stats1_all_kernel<<<256, 128>>>(Ub, Vb, knn, 512, 2048, 128, 16, 256, s_part);
        stats1_fin_kernel<<<1, 128>>>(s_part, 256, 128, 8*512);
        int n16 = 8*512*16/128, n32 = 8*512*32/128, n64 = 8*512*64/128;   // 512,1024,2048
        dim3 grid(1, n16 + n32 + n64);
        local_gemm2_kernel<<<grid, 256>>>(Ub, Vb, knn, g0_w2, pool,
                                          512, 2048, 128, 128, n16, n32, 384);
        reduce_m2_all_kernel<<<dim3(128, 3), 256>>>(n16, n32, n64, 128);
        pool_fin_all_kernel<<<dim3(4096, 3), 128>>>(pool, 384, 128);
        gemm_big(pool, g0_wc, nullptr, f0, 4096, 384, 128, 0);
        bn(f0, 4096, 128, 0);
    }

    // ---- Stage D gather ----
    gather_kernel<<<CEILDIV(8*256*128, 256), 256>>>(f0, fpsidx, newpts, 256, 512, 128, 8L*256*128);

    // ---- Stage E: local_op 1 (R16 fused) ----
    {
        split_w1_kernel<<<CEILDIV(256*128, 256), 256>>>(g1_w1, w1a, w1d, 256, 128, 256*128);
        gemm_big(f0, w1a, nullptr, Ub, 4096, 128, 256, 0);
        gemm_big(newpts, w1d, nullptr, Vb, 2048, 128, 256, 0);
        stats1_all_kernel<<<128, 256>>>(Ub, Vb, knn2, 256, 512, 256, 16, 128, s_part);
        stats1_fin_kernel<<<2, 128>>>(s_part, 128, 256, 8*256);
        int n16 = 8*256*16/128, n32 = 8*256*32/128, n64 = 8*256*64/128;   // 256,512,1024
        dim3 grid(2, n16 + n32 + n64);
        local_gemm2_kernel<<<grid, 256>>>(Ub, Vb, knn2, g1_w2, pool,
                                          256, 512, 256, 256, n16, n32, 768);
        reduce_m2_all_kernel<<<dim3(256, 3), 256>>>(n16, n32, n64, 256);
        pool_fin_all_kernel<<<dim3(2048, 3), 256>>>(pool, 768, 256);
        gemm_big(pool, g1_wc, nullptr, f1, 2048, 768, 256, 0);
        bn(f1, 2048, 256, 0);
    }

    // ---- Stage F ----
    gemm_old(newxyz2, pos_w, pos_b, pos, 2048, 3, 256);
    gemm_big(f1, pt_w, nullptr, xx, 2048, 256, 256, 0);
    bn(xx, 2048, 256, 0);

    // ---- Stage G: 4 offset self-attention layers ----
    for (int i = 0; i < 4; i++) {
        gemmqv_kernel<<<dim3(4, 16), 256>>>(xx, pos,
                                            sa_wqk + (long)i * 256 * 256,
                                            sa_wv + (long)i * 256 * 256,
                                            sa_bv + i * 256, qb, vb);
        gram64_kernel<<<dim3(4, 4, 32), 256>>>(qb, attn);
        softmax_row_kernel<<<8192, 256>>>(attn);
        colsm_kernel<<<dim3(4, 32), 256>>>(attn);
        xr_gemm_kernel<<<dim3(4, 32), 256>>>(attn, vb, xx, pos, xrb);
        gemm_big(xrb, sa_wt + (long)i * 256 * 256, sa_bt + i * 256, qb, 2048, 256, 256, 0);
        computeStats(qb, 2048, 256);
        addcat_bn_kernel<<<2048, 256>>>(qb, xx, pos, catb, i);
    }
    catf1_kernel<<<2048, 256>>>(f1, catb);

    // ---- Stage H ----
    gemm_big(catb, fuse_w, nullptr, fuseb, 2048, 1280, 1024, 0);
    bn(fuseb, 2048, 1024, 1);
    maxn_kernel<<<dim3(8, 4), 256>>>(fuseb, gmax);
    gemm_old(gmax, lin1_w, nullptr, l1, 8, 1024, 512);
    bn_small_kernel<<<2, 256>>>(l1, 512, 0.2f);
    gemm_old(l1, lin2_w, lin2_b, l2, 8, 512, 256);
    bn_small_kernel<<<1, 256>>>(l2, 256, 0.2f);
    gemm_old(l2, lin3_w, lin3_b, out, 8, 256, 40);
}

// round 17
// speedup vs baseline: 1.2331x; 1.0186x over previous
#include <cuda_runtime.h>
#include <math.h>
#include <float.h>

#define CEILDIV(a,b) (((a)+(b)-1)/(b))
#define BN_EPS 1e-5f

// ----------------------------------------------------------------------------
// Scratch (device globals)
// ----------------------------------------------------------------------------
__device__ float g_xyz[8*2048*3];
__device__ float g_h1[8*2048*64];
__device__ float g_points[8*2048*64];
__device__ int   g_fpsidx[8*512];
__device__ float g_newxyz[8*512*3];
__device__ float g_newxyz2[8*256*3];
__device__ float g_newpts[8*512*64];        // stage2: 8*256*128
__device__ int   g_knn[8*512*64];
__device__ int   g_knn2[8*256*64];
__device__ float g_U[16384*128];            // stage E: 4096x256
__device__ float g_V[4096*128];             // stage E: 2048x256
__device__ float g_w1a[256*128];
__device__ float g_w1d[256*128];
__device__ float g_part[2*2048*256];        // per-scale partial regions (disjoint)
__device__ float g_pool[8*512*384];         // stage2: 8*256*768
__device__ float g_f0[8*512*128];
__device__ float g_f1[8*256*256];
__device__ float g_pos[8*256*256];
__device__ float g_x[8*256*256];
__device__ float g_q[8*256*256];
__device__ float g_v[8*256*256];
__device__ float g_xr[8*256*256];
__device__ float g_attn[8*4*256*256];
__device__ float g_cat[8*256*1280];
__device__ float g_fuse[8*256*1024];
__device__ float g_gmax[8*1024];
__device__ float g_l1[8*512];
__device__ float g_l2[8*256];
__device__ float g_m1[1024];
__device__ float g_i1[1024];
__device__ float g_m2[3*256];
__device__ float g_i2[3*256];
__device__ float g_s1m[3*256];
__device__ float g_s1i[3*256];
__device__ float g_cmax[32*256];
__device__ float g_cinv[32*256];

// ----------------------------------------------------------------------------
// BN stats plumbing (R12/R13-record versions)
// ----------------------------------------------------------------------------
__global__ void stats_part_kernel(const float* __restrict__ X, int R, int C, int rpb,
                                  int nB, float* __restrict__ part) {
    int blk = blockIdx.x;
    int r0 = blk * rpb;
    int r1 = r0 + rpb; if (r1 > R) r1 = R;
    int nch = (C + 255) / 256;
    float acc[4] = {0.f, 0.f, 0.f, 0.f};
    float accsq[4] = {0.f, 0.f, 0.f, 0.f};
    for (int r = r0; r < r1; r++) {
        const float* row = X + (long)r * C;
        #pragma unroll
        for (int k = 0; k < 4; k++) {
            if (k < nch) {
                int c = threadIdx.x + k * 256;
                if (c < C) { float v = row[c]; acc[k] += v; accsq[k] += v * v; }
            }
        }
    }
    #pragma unroll
    for (int k = 0; k < 4; k++) {
        if (k < nch) {
            int c = threadIdx.x + k * 256;
            if (c < C) {
                part[(long)blk * C + c] = acc[k];
                part[(long)nB * C + (long)blk * C + c] = accsq[k];
            }
        }
    }
}

__global__ void reduce_m1_kernel(const float* __restrict__ part, int nB, int C, int statN) {
    int c = blockIdx.x;
    int t = threadIdx.x;
    float a = 0.f, b = 0.f;
    for (int r = t; r < nB; r += 256) {
        a += part[(long)r * C + c];
        b += part[(long)nB * C + (long)r * C + c];
    }
    __shared__ float sa[256], sb[256];
    sa[t] = a; sb[t] = b;
    __syncthreads();
    for (int s = 128; s > 0; s >>= 1) {
        if (t < s) { sa[t] += sa[t + s]; sb[t] += sb[t + s]; }
        __syncthreads();
    }
    if (t == 0) {
        double m = (double)sa[0] / statN;
        double var = (double)sb[0] / statN - m * m;
        if (var < 0.0) var = 0.0;
        g_m1[c] = (float)m;
        g_i1[c] = rsqrtf((float)var + BN_EPS);
    }
}

__global__ void bn_apply_kernel(float* __restrict__ X, long total, int C, int act) {
    long t = (long)blockIdx.x * blockDim.x + threadIdx.x;
    if (t >= total) return;
    int c = (int)(t % C);
    float y = (X[t] - g_m1[c]) * g_i1[c];
    X[t] = (act == 0) ? fmaxf(y, 0.f) : (y >= 0.f ? y : 0.2f * y);
}

__global__ void bn_small_kernel(float* __restrict__ X, int C, float slope) {
    int c = blockIdx.x * blockDim.x + threadIdx.x;
    if (c >= C) return;
    double s = 0.0, ss = 0.0;
    for (int r = 0; r < 8; r++) { double v = X[r * C + c]; s += v; ss += v * v; }
    double m = s / 8.0;
    double var = ss / 8.0 - m * m;
    if (var < 0.0) var = 0.0;
    float inv = rsqrtf((float)var + BN_EPS);
    for (int r = 0; r < 8; r++) {
        float y = (X[r * C + c] - (float)m) * inv;
        X[r * C + c] = y >= 0.f ? y : slope * y;
    }
}

// R16: combined BN2 reduce for all 3 scales. grid (O, 3).
__global__ void reduce_m2_all_kernel(int n16, int n32, int n64, int O) {
    int si = blockIdx.y;
    int c = blockIdx.x;
    int t = threadIdx.x;
    int nBy = (si == 0) ? n16 : (si == 1) ? n32 : n64;
    long base = (si == 0) ? 0L : (si == 1) ? 2L * n16 * O : 2L * (n16 + n32) * O;
    const float* ps = g_part + base;
    const float* pq = ps + (long)nBy * O;
    float a = 0.f, b = 0.f;
    for (int r = t; r < nBy; r += 256) {
        a += ps[(long)r * O + c];
        b += pq[(long)r * O + c];
    }
    __shared__ float sa[256], sb[256];
    sa[t] = a; sb[t] = b;
    __syncthreads();
    for (int s = 128; s > 0; s >>= 1) {
        if (t < s) { sa[t] += sa[t + s]; sb[t] += sb[t + s]; }
        __syncthreads();
    }
    if (t == 0) {
        long statN = (long)nBy * 128;
        double m = (double)sa[0] / statN;
        double var = (double)sb[0] / statN - m * m;
        if (var < 0.0) var = 0.0;
        g_m2[si * 256 + c] = (float)m;
        g_i2[si * 256 + c] = rsqrtf((float)var + BN_EPS);
    }
}

// R16: combined pool finalize: grid (S8, 3), blockDim = O.
__global__ void pool_fin_all_kernel(float* __restrict__ pool, int OC, int O) {
    int s = blockIdx.x;
    int si = blockIdx.y;
    int c = threadIdx.x;
    long p = (long)s * OC + si * O + c;
    pool[p] = fmaxf((pool[p] - g_m2[si * 256 + c]) * g_i2[si * 256 + c], 0.f);
}

// ----------------------------------------------------------------------------
// BN1 stats — one incremental pass over all 3 k-scales (R13 version)
// ----------------------------------------------------------------------------
__global__ void stats1_all_kernel(const float* __restrict__ U, const float* __restrict__ V,
                                  const int* __restrict__ knn, int S, int N, int C,
                                  int cpb, int nB, float* __restrict__ part) {
    int c = threadIdx.x;   // blockDim == C
    int blk = blockIdx.x;
    float s0 = 0.f, q0 = 0.f, s1 = 0.f, q1 = 0.f, s2 = 0.f, q2 = 0.f;
    for (int ss = 0; ss < cpb; ss++) {
        int s = blk * cpb + ss;
        int b = s / S;
        float v = V[(long)s * C + c];
        const int* kn = knn + (long)s * 64;
        for (int j = 0; j < 16; j++) {
            float x = U[((long)b * N + kn[j]) * C + c] + v;
            s0 += x; q0 += x * x;
        }
        for (int j = 16; j < 32; j++) {
            float x = U[((long)b * N + kn[j]) * C + c] + v;
            s1 += x; q1 += x * x;
        }
        for (int j = 32; j < 64; j++) {
            float x = U[((long)b * N + kn[j]) * C + c] + v;
            s2 += x; q2 += x * x;
        }
    }
    long base = (long)blk * C + c;
    long stride = (long)nB * C;
    part[0 * stride + base] = s0;
    part[1 * stride + base] = s1;
    part[2 * stride + base] = s2;
    part[3 * stride + base] = q0;
    part[4 * stride + base] = q1;
    part[5 * stride + base] = q2;
}

__global__ void stats1_fin_kernel(const float* __restrict__ part, int nB, int C, int S8) {
    int c = blockIdx.x * 128 + threadIdx.x;
    if (c >= C) return;
    long stride = (long)nB * C;
    float a0 = 0.f, a1 = 0.f, a2 = 0.f, b0 = 0.f, b1 = 0.f, b2 = 0.f;
    for (int r = 0; r < nB; r++) {
        long idx = (long)r * C + c;
        a0 += part[0 * stride + idx];
        a1 += part[1 * stride + idx];
        a2 += part[2 * stride + idx];
        b0 += part[3 * stride + idx];
        b1 += part[4 * stride + idx];
        b2 += part[5 * stride + idx];
    }
    double cs = a0, cq = b0;
    const int ks[3] = {16, 32, 64};
    double add_s[3] = {0.0, (double)a1, (double)a2};
    double add_q[3] = {0.0, (double)b1, (double)b2};
    for (int sc = 0; sc < 3; sc++) {
        cs += add_s[sc]; cq += add_q[sc];
        double n = (double)S8 * ks[sc];
        double m = cs / n;
        double var = cq / n - m * m;
        if (var < 0.0) var = 0.0;
        g_s1m[sc * 256 + c] = (float)m;
        g_s1i[sc * 256 + c] = rsqrtf((float)var + BN_EPS);
    }
}

// ----------------------------------------------------------------------------
// R14: 128x128 GEMM with double-buffered k-tiles
// ----------------------------------------------------------------------------
__global__ __launch_bounds__(256, 2)
void gemm128_kernel(const float* __restrict__ A, const float* __restrict__ W,
                    const float* __restrict__ bias, float* __restrict__ C,
                    int R, int D, int O, int useStats) {
    __shared__ float As[2][16][132];
    __shared__ float Ws[2][16][132];
    __shared__ float sM[256];
    __shared__ float sI[256];
    int tid = threadIdx.x;
    if (useStats) {
        for (int c = tid; c < D; c += 256) { sM[c] = g_m1[c]; sI[c] = g_i1[c]; }
        __syncthreads();
    }
    long rowBase = (long)blockIdx.y * 128;
    int colBase = blockIdx.x * 128;
    int tr = tid >> 4, tc = tid & 15;
    int lrow = tid >> 2;
    int kq = (tid & 3) * 4;
    float acc[8][8];
    #pragma unroll
    for (int i = 0; i < 8; i++)
        #pragma unroll
        for (int j = 0; j < 8; j++) acc[i][j] = 0.f;

    int nT = D >> 4;
    #pragma unroll
    for (int half = 0; half < 2; half++) {
        int row = lrow + 64 * half;
        float4 av = *(const float4*)(A + (rowBase + row) * D + kq);
        if (useStats) {
            av.x = fmaxf((av.x - sM[kq + 0]) * sI[kq + 0], 0.f);
            av.y = fmaxf((av.y - sM[kq + 1]) * sI[kq + 1], 0.f);
            av.z = fmaxf((av.z - sM[kq + 2]) * sI[kq + 2], 0.f);
            av.w = fmaxf((av.w - sM[kq + 3]) * sI[kq + 3], 0.f);
        }
        As[0][kq + 0][row] = av.x;
        As[0][kq + 1][row] = av.y;
        As[0][kq + 2][row] = av.z;
        As[0][kq + 3][row] = av.w;
        int wr = colBase + row;
        float4 wv = make_float4(0.f, 0.f, 0.f, 0.f);
        if (wr < O) wv = *(const float4*)(W + (long)wr * D + kq);
        Ws[0][kq + 0][row] = wv.x;
        Ws[0][kq + 1][row] = wv.y;
        Ws[0][kq + 2][row] = wv.z;
        Ws[0][kq + 3][row] = wv.w;
    }
    __syncthreads();

    int cur = 0;
    for (int t = 0; t < nT; t++) {
        float4 sa[2], sw[2];
        bool has = (t + 1) < nT;
        if (has) {
            int kc = (t + 1) * 16 + kq;
            #pragma unroll
            for (int half = 0; half < 2; half++) {
                int row = lrow + 64 * half;
                float4 av = *(const float4*)(A + (rowBase + row) * D + kc);
                if (useStats) {
                    av.x = fmaxf((av.x - sM[kc + 0]) * sI[kc + 0], 0.f);
                    av.y = fmaxf((av.y - sM[kc + 1]) * sI[kc + 1], 0.f);
                    av.z = fmaxf((av.z - sM[kc + 2]) * sI[kc + 2], 0.f);
                    av.w = fmaxf((av.w - sM[kc + 3]) * sI[kc + 3], 0.f);
                }
                sa[half] = av;
                int wr = colBase + row;
                float4 wv = make_float4(0.f, 0.f, 0.f, 0.f);
                if (wr < O) wv = *(const float4*)(W + (long)wr * D + kc);
                sw[half] = wv;
            }
        }
        #pragma unroll
        for (int kk = 0; kk < 16; kk++) {
            float a[8], w[8];
            *(float4*)(a + 0) = *(const float4*)&As[cur][kk][tr * 8 + 0];
            *(float4*)(a + 4) = *(const float4*)&As[cur][kk][tr * 8 + 4];
            *(float4*)(w + 0) = *(const float4*)&Ws[cur][kk][tc * 8 + 0];
            *(float4*)(w + 4) = *(const float4*)&Ws[cur][kk][tc * 8 + 4];
            #pragma unroll
            for (int i = 0; i < 8; i++)
                #pragma unroll
                for (int j = 0; j < 8; j++)
                    acc[i][j] += a[i] * w[j];
        }
        if (has) {
            int nxt = cur ^ 1;
            #pragma unroll
            for (int half = 0; half < 2; half++) {
                int row = lrow + 64 * half;
                As[nxt][kq + 0][row] = sa[half].x;
                As[nxt][kq + 1][row] = sa[half].y;
                As[nxt][kq + 2][row] = sa[half].z;
                As[nxt][kq + 3][row] = sa[half].w;
                Ws[nxt][kq + 0][row] = sw[half].x;
                Ws[nxt][kq + 1][row] = sw[half].y;
                Ws[nxt][kq + 2][row] = sw[half].z;
                Ws[nxt][kq + 3][row] = sw[half].w;
            }
        }
        __syncthreads();
        cur ^= 1;
    }
    #pragma unroll
    for (int i = 0; i < 8; i++) {
        long row = rowBase + tr * 8 + i;
        int col0 = colBase + tc * 8;
        if (col0 >= O) continue;
        float b0 = 0, b1 = 0, b2 = 0, b3 = 0, b4 = 0, b5 = 0, b6 = 0, b7 = 0;
        if (bias) {
            b0 = bias[col0 + 0]; b1 = bias[col0 + 1]; b2 = bias[col0 + 2]; b3 = bias[col0 + 3];
            b4 = bias[col0 + 4]; b5 = bias[col0 + 5]; b6 = bias[col0 + 6]; b7 = bias[col0 + 7];
        }
        float4 v0 = make_float4(acc[i][0] + b0, acc[i][1] + b1, acc[i][2] + b2, acc[i][3] + b3);
        float4 v1 = make_float4(acc[i][4] + b4, acc[i][5] + b5, acc[i][6] + b6, acc[i][7] + b7);
        *(float4*)(C + row * O + col0) = v0;
        *(float4*)(C + row * O + col0 + 4) = v1;
    }
}

// ----------------------------------------------------------------------------
// R16: fused local-op GEMM2, ALL THREE k-scales in one launch.
// ----------------------------------------------------------------------------
__global__ __launch_bounds__(256, 2)
void local_gemm2_kernel(const float* __restrict__ U, const float* __restrict__ V,
                        const int* __restrict__ knn, const float* __restrict__ W,
                        float* __restrict__ poolOut,
                        int S, int N, int D, int O,
                        int n16, int n32, int OC) {
    __shared__ float As[2][16][132];
    __shared__ float Ws[2][16][132];
    __shared__ float sRed[16][132];
    __shared__ float sM[256];
    __shared__ float sI[256];
    __shared__ int sP[128];
    __shared__ int sS[128];
    int tid = threadIdx.x;
    int by = blockIdx.y;
    int si, localY;
    if (by < n16)            { si = 0; localY = by; }
    else if (by < n16 + n32) { si = 1; localY = by - n16; }
    else                     { si = 2; localY = by - n16 - n32; }
    int kshift = 4 + si;
    int nBy = (si == 0) ? n16 : (si == 1) ? n32 : (gridDim.y - n16 - n32);
    long partBase = (si == 0) ? 0L : (si == 1) ? 2L * n16 * O : 2L * (n16 + n32) * O;
    float* part = g_part + partBase;
    const float* bn1M = g_s1m + si * 256;
    const float* bn1I = g_s1i + si * 256;
    int off = si * O;
    long rowBase = (long)localY * 128;
    int colBase = blockIdx.x * 128;

    for (int c = tid; c < D; c += 256) { sM[c] = bn1M[c]; sI[c] = bn1I[c]; }
    if (tid < 128) {
        long grow = rowBase + tid;
        int s = (int)(grow >> kshift);
        int j = (int)(grow & ((1 << kshift) - 1));
        int b = s / S;
        sS[tid] = s;
        sP[tid] = b * N + knn[(long)s * 64 + j];
    }
    __syncthreads();

    int tr = tid >> 4, tc = tid & 15;
    int lrow = tid >> 2;
    int kq = (tid & 3) * 4;
    float acc[8][8];
    #pragma unroll
    for (int i = 0; i < 8; i++)
        #pragma unroll
        for (int j = 0; j < 8; j++) acc[i][j] = 0.f;

    int nT = D >> 4;
    int p0 = sP[lrow], p1 = sP[lrow + 64];
    int s0i = sS[lrow], s1i = sS[lrow + 64];
    {
        #pragma unroll
        for (int half = 0; half < 2; half++) {
            int row = lrow + 64 * half;
            int pi = half ? p1 : p0;
            int sidx = half ? s1i : s0i;
            float4 uv = *(const float4*)(U + (long)pi * D + kq);
            float4 vv = *(const float4*)(V + (long)sidx * D + kq);
            As[0][kq + 0][row] = fmaxf((uv.x + vv.x - sM[kq + 0]) * sI[kq + 0], 0.f);
            As[0][kq + 1][row] = fmaxf((uv.y + vv.y - sM[kq + 1]) * sI[kq + 1], 0.f);
            As[0][kq + 2][row] = fmaxf((uv.z + vv.z - sM[kq + 2]) * sI[kq + 2], 0.f);
            As[0][kq + 3][row] = fmaxf((uv.w + vv.w - sM[kq + 3]) * sI[kq + 3], 0.f);
            float4 wv = *(const float4*)(W + (long)(colBase + row) * D + kq);
            Ws[0][kq + 0][row] = wv.x;
            Ws[0][kq + 1][row] = wv.y;
            Ws[0][kq + 2][row] = wv.z;
            Ws[0][kq + 3][row] = wv.w;
        }
    }
    __syncthreads();

    int cur = 0;
    for (int t = 0; t < nT; t++) {
        float4 sa[2], sw[2];
        bool has = (t + 1) < nT;
        if (has) {
            int kc = (t + 1) * 16 + kq;
            #pragma unroll
            for (int half = 0; half < 2; half++) {
                int row = lrow + 64 * half;
                int pi = half ? p1 : p0;
                int sidx = half ? s1i : s0i;
                float4 uv = *(const float4*)(U + (long)pi * D + kc);
                float4 vv = *(const float4*)(V + (long)sidx * D + kc);
                float4 av;
                av.x = fmaxf((uv.x + vv.x - sM[kc + 0]) * sI[kc + 0], 0.f);
                av.y = fmaxf((uv.y + vv.y - sM[kc + 1]) * sI[kc + 1], 0.f);
                av.z = fmaxf((uv.z + vv.z - sM[kc + 2]) * sI[kc + 2], 0.f);
                av.w = fmaxf((uv.w + vv.w - sM[kc + 3]) * sI[kc + 3], 0.f);
                sa[half] = av;
                sw[half] = *(const float4*)(W + (long)(colBase + row) * D + kc);
            }
        }
        #pragma unroll
        for (int kk = 0; kk < 16; kk++) {
            float a[8], w[8];
            *(float4*)(a + 0) = *(const float4*)&As[cur][kk][tr * 8 + 0];
            *(float4*)(a + 4) = *(const float4*)&As[cur][kk][tr * 8 + 4];
            *(float4*)(w + 0) = *(const float4*)&Ws[cur][kk][tc * 8 + 0];
            *(float4*)(w + 4) = *(const float4*)&Ws[cur][kk][tc * 8 + 4];
            #pragma unroll
            for (int i = 0; i < 8; i++)
                #pragma unroll
                for (int j = 0; j < 8; j++)
                    acc[i][j] += a[i] * w[j];
        }
        if (has) {
            int nxt = cur ^ 1;
            #pragma unroll
            for (int half = 0; half < 2; half++) {
                int row = lrow + 64 * half;
                As[nxt][kq + 0][row] = sa[half].x;
                As[nxt][kq + 1][row] = sa[half].y;
                As[nxt][kq + 2][row] = sa[half].z;
                As[nxt][kq + 3][row] = sa[half].w;
                Ws[nxt][kq + 0][row] = sw[half].x;
                Ws[nxt][kq + 1][row] = sw[half].y;
                Ws[nxt][kq + 2][row] = sw[half].z;
                Ws[nxt][kq + 3][row] = sw[half].w;
            }
        }
        __syncthreads();
        cur ^= 1;
    }

    // epilogue 1: per-center raw max -> poolOut
    int g = (1 << kshift) >> 3;
    #pragma unroll
    for (int j = 0; j < 8; j++) {
        float m = acc[0][j];
        #pragma unroll
        for (int i = 1; i < 8; i++) m = fmaxf(m, acc[i][j]);
        sRed[tr][tc * 8 + j] = m;
    }
    __syncthreads();
    if ((tr & (g - 1)) == 0) {
        int s = sS[tr * 8];
        #pragma unroll
        for (int j = 0; j < 8; j++) {
            float m = sRed[tr][tc * 8 + j];
            for (int q = 1; q < g; q++) m = fmaxf(m, sRed[tr + q][tc * 8 + j]);
            poolOut[(long)s * OC + off + colBase + tc * 8 + j] = m;
        }
    }
    __syncthreads();
    // epilogue 2: per-block channel sums -> this scale's partial region
    #pragma unroll
    for (int j = 0; j < 8; j++) {
        float sm = 0.f;
        #pragma unroll
        for (int i = 0; i < 8; i++) sm += acc[i][j];
        sRed[tr][tc * 8 + j] = sm;
    }
    __syncthreads();
    if (tr == 0) {
        #pragma unroll
        for (int j = 0; j < 8; j++) {
            float tot = 0.f;
            for (int q = 0; q < 16; q++) tot += sRed[q][tc * 8 + j];
            part[(long)localY * O + colBase + tc * 8 + j] = tot;
        }
    }
    __syncthreads();
    #pragma unroll
    for (int j = 0; j < 8; j++) {
        float sm = 0.f;
        #pragma unroll
        for (int i = 0; i < 8; i++) sm += acc[i][j] * acc[i][j];
        sRed[tr][tc * 8 + j] = sm;
    }
    __syncthreads();
    if (tr == 0) {
        #pragma unroll
        for (int j = 0; j < 8; j++) {
            float tot = 0.f;
            for (int q = 0; q < 16; q++) tot += sRed[q][tc * 8 + j];
            part[((long)nBy + localY) * O + colBase + tc * 8 + j] = tot;
        }
    }
}

__global__ void split_w1_kernel(const float* __restrict__ w1, float* __restrict__ wa,
                                float* __restrict__ wd, int O, int D, int total) {
    int t = blockIdx.x * 256 + threadIdx.x;
    if (t >= total) return;
    int d = t % D, o = t / D;
    float a = w1[(long)o * 2 * D + d];
    float b = w1[(long)o * 2 * D + D + d];
    wa[t] = a;
    wd[t] = b - a;
}

// ----------------------------------------------------------------------------
// Generic fallback GEMM (odd shapes)
// ----------------------------------------------------------------------------
__global__ void gemm_kernel(const float* __restrict__ A, const float* __restrict__ W,
                            const float* __restrict__ bias, float* __restrict__ C,
                            int R, int D, int O) {
    __shared__ float As[64][17];
    __shared__ float Ws[64][17];
    int tid = threadIdx.x;
    int tr = tid >> 4, tc = tid & 15;
    long rowBase = (long)blockIdx.y * 64;
    int colBase = blockIdx.x * 64;
    float acc[4][4] = {};
    for (int k0 = 0; k0 < D; k0 += 16) {
        #pragma unroll
        for (int e = tid; e < 1024; e += 256) {
            int rr = e >> 4, kk = e & 15;
            long ar = rowBase + rr; int ac = k0 + kk;
            As[rr][kk] = (ar < R && ac < D) ? A[ar * D + ac] : 0.f;
            int wr = colBase + rr;
            Ws[rr][kk] = (wr < O && ac < D) ? W[(long)wr * D + ac] : 0.f;
        }
        __syncthreads();
        #pragma unroll
        for (int kk = 0; kk < 16; kk++) {
            float a[4], w[4];
            #pragma unroll
            for (int i = 0; i < 4; i++) a[i] = As[tr + 16*i][kk];
            #pragma unroll
            for (int j = 0; j < 4; j++) w[j] = Ws[tc + 16*j][kk];
            #pragma unroll
            for (int i = 0; i < 4; i++)
                #pragma unroll
                for (int j = 0; j < 4; j++)
                    acc[i][j] += a[i] * w[j];
        }
        __syncthreads();
    }
    #pragma unroll
    for (int i = 0; i < 4; i++) {
        long row = rowBase + tr + 16*i;
        if (row >= R) continue;
        #pragma unroll
        for (int j = 0; j < 4; j++) {
            int col = colBase + tc + 16*j;
            if (col >= O) continue;
            float vv = acc[i][j];
            if (bias) vv += bias[col];
            C[row * O + col] = vv;
        }
    }
}

// ----------------------------------------------------------------------------
// Layout / elementwise helpers
// ----------------------------------------------------------------------------
__global__ void transpose_x_kernel(const float* __restrict__ x, float* __restrict__ xyz) {
    int t = blockIdx.x * 256 + threadIdx.x;
    if (t >= 8 * 2048 * 3) return;
    int c = t % 3; int n = (t / 3) % 2048; int b = t / (3 * 2048);
    xyz[t] = x[((long)b * 3 + c) * 2048 + n];
}

__global__ void gather_kernel(const float* __restrict__ src, const int* __restrict__ idx,
                              float* __restrict__ dst, int S, int N, int D, long total) {
    long t = (long)blockIdx.x * blockDim.x + threadIdx.x;
    if (t >= total) return;
    int c = (int)(t % D); long bs = t / D;
    int b = (int)(bs / S);
    dst[t] = src[((long)b * N + idx[bs]) * D + c];
}

__global__ void catf1_kernel(const float* __restrict__ f1, float* __restrict__ cat) {
    int t = blockIdx.x * 256 + threadIdx.x;
    int c = t & 255; int row = t >> 8;
    cat[(long)row * 1280 + 1024 + c] = f1[t];
}

__global__ void maxn_kernel(const float* __restrict__ X, float* __restrict__ G) {
    int b = blockIdx.x; int c = blockIdx.y * 256 + threadIdx.x;
    float m = -FLT_MAX;
    for (int n = 0; n < 256; n++) m = fmaxf(m, X[((long)b * 256 + n) * 1024 + c]);
    G[b * 1024 + c] = m;
}

// ----------------------------------------------------------------------------
// FPS / kNN with warp-shuffle reductions (tie order preserved)
// ----------------------------------------------------------------------------
__device__ __forceinline__ unsigned keymap(float f) {
    unsigned u = __float_as_uint(f);
    return (u & 0x80000000u) ? ~u : (u | 0x80000000u);
}

__device__ void fps_body(const float* __restrict__ xyz, int N, int npoint,
                         int* __restrict__ outIdx, int b,
                         float* sx, float* sy, float* sz, float* sd,
                         unsigned long long* warpBest, int* sFar) {
    int t = threadIdx.x;
    int nt = blockDim.x;
    int numWarps = nt >> 5;
    for (int n = t; n < N; n += nt) {
        sx[n] = xyz[((long)b * N + n) * 3 + 0];
        sy[n] = xyz[((long)b * N + n) * 3 + 1];
        sz[n] = xyz[((long)b * N + n) * 3 + 2];
        sd[n] = 1e10f;
    }
    __syncthreads();
    int far = 0;
    for (int it = 0; it < npoint; it++) {
        if (t == 0) outIdx[b * npoint + it] = far;
        float cx = sx[far], cy = sy[far], cz = sz[far];
        unsigned long long best = 0ull;
        for (int n = t; n < N; n += nt) {
            float dx = sx[n] - cx, dy = sy[n] - cy, dz = sz[n] - cz;
            float d = dx * dx + dy * dy + dz * dz;
            float dm = fminf(sd[n], d);
            sd[n] = dm;
            unsigned long long key = ((unsigned long long)keymap(dm) << 32) | (unsigned)(~n);
            if (key > best) best = key;
        }
        #pragma unroll
        for (int o = 16; o > 0; o >>= 1) {
            unsigned long long other = __shfl_xor_sync(0xffffffffu, best, o);
            if (other > best) best = other;
        }
        if ((t & 31) == 0) warpBest[t >> 5] = best;
        __syncthreads();
        if (t < 32) {
            unsigned long long v = (t < numWarps) ? warpBest[t] : 0ull;
            #pragma unroll
            for (int o = 16; o > 0; o >>= 1) {
                unsigned long long other = __shfl_xor_sync(0xffffffffu, v, o);
                if (other > v) v = other;
            }
            if (t == 0) *sFar = (int)(~((unsigned)(v & 0xffffffffu)));
        }
        __syncthreads();
        far = *sFar;
    }
}

__device__ void knn_body(const float* __restrict__ centers, const float* __restrict__ xyz,
                         int S, int N, int* __restrict__ knnOut, int bs,
                         float* sd, unsigned long long* warpBest) {
    int t = threadIdx.x;
    int nt = blockDim.x;
    int numWarps = nt >> 5;
    int b = bs / S;
    float cx = centers[(long)bs * 3 + 0];
    float cy = centers[(long)bs * 3 + 1];
    float cz = centers[(long)bs * 3 + 2];
    float cn = cx * cx + cy * cy + cz * cz;
    for (int n = t; n < N; n += nt) {
        float px = xyz[((long)b * N + n) * 3 + 0];
        float py = xyz[((long)b * N + n) * 3 + 1];
        float pz = xyz[((long)b * N + n) * 3 + 2];
        float pn = px * px + py * py + pz * pz;
        float dot = cx * px + cy * py + cz * pz;
        sd[n] = cn + pn - 2.f * dot;
    }
    __syncthreads();
    for (int j = 0; j < 64; j++) {
        unsigned long long best = 0xFFFFFFFFFFFFFFFFull;
        for (int n = t; n < N; n += nt) {
            unsigned long long key = ((unsigned long long)keymap(sd[n]) << 32) | (unsigned)n;
            if (key < best) best = key;
        }
        #pragma unroll
        for (int o = 16; o > 0; o >>= 1) {
            unsigned long long other = __shfl_xor_sync(0xffffffffu, best, o);
            if (other < best) best = other;
        }
        if ((t & 31) == 0) warpBest[t >> 5] = best;
        __syncthreads();
        if (t < 32) {
            unsigned long long v = (t < numWarps) ? warpBest[t] : 0xFFFFFFFFFFFFFFFFull;
            #pragma unroll
            for (int o = 16; o > 0; o >>= 1) {
                unsigned long long other = __shfl_xor_sync(0xffffffffu, v, o);
                if (other < v) v = other;
            }
            if (t == 0) {
                int sel = (int)(v & 0xffffffffu);
                knnOut[(long)bs * 64 + j] = sel;
                sd[sel] = FLT_MAX;
            }
        }
        __syncthreads();
    }
}

__global__ void fps_kernel(const float* xyz, int N, int npoint, int* outIdx) {
    __shared__ float buf[4 * 2048];
    __shared__ unsigned long long wb[32];
    __shared__ int sFar;
    fps_body(xyz, N, npoint, outIdx, blockIdx.x, buf, buf + N, buf + 2 * N, buf + 3 * N, wb, &sFar);
}

__global__ void knn_kernel(const float* centers, const float* xyz, int S, int N, int* knnOut) {
    __shared__ float buf[2048];
    __shared__ unsigned long long wb[32];
    knn_body(centers, xyz, S, N, knnOut, blockIdx.x, buf, wb);
}

__global__ void knn_fps_kernel(const float* centers, const float* xyz, int S, int N,
                               int* knnOut, int nKnn,
                               const float* xyz2, int N2, int np2, int* outIdx2) {
    __shared__ float buf[4 * 2048];
    __shared__ unsigned long long wb[32];
    __shared__ int sFar;
    if (blockIdx.x < nKnn) {
        knn_body(centers, xyz, S, N, knnOut, blockIdx.x, buf, wb);
    } else {
        int b = blockIdx.x - nKnn;
        fps_body(xyz2, N2, np2, outIdx2, b, buf, buf + N2, buf + 2 * N2, buf + 3 * N2, wb, &sFar);
    }
}

// ----------------------------------------------------------------------------
// Attention (reference reshape quirk preserved)
// ----------------------------------------------------------------------------
__global__ void gemmqv_kernel(const float* __restrict__ xx, const float* __restrict__ pos,
                              const float* __restrict__ wqk, const float* __restrict__ wv,
                              const float* __restrict__ bv,
                              float* __restrict__ qb, float* __restrict__ vb) {
    __shared__ float As[16][132];
    __shared__ float Ws[16][132];
    int tid = threadIdx.x;
    long rowBase = (long)blockIdx.y * 128;
    int colBase = blockIdx.x * 128;
    int tr = tid >> 4, tc = tid & 15;
    int lrow = tid >> 2;
    int lkq = tid & 3;
    const int D = 256;
    float acc[8][8];
    #pragma unroll
    for (int i = 0; i < 8; i++)
        #pragma unroll
        for (int j = 0; j < 8; j++) acc[i][j] = 0.f;

    for (int k0 = 0; k0 < D; k0 += 16) {
        #pragma unroll
        for (int half = 0; half < 2; half++) {
            int row = lrow + 64 * half;
            int kc = k0 + lkq * 4;
            float4 av = *(const float4*)(xx + (rowBase + row) * D + kc);
            float4 pv = *(const float4*)(pos + (rowBase + row) * D + kc);
            As[lkq * 4 + 0][row] = av.x + pv.x;
            As[lkq * 4 + 1][row] = av.y + pv.y;
            As[lkq * 4 + 2][row] = av.z + pv.z;
            As[lkq * 4 + 3][row] = av.w + pv.w;
            int ocol = colBase + row;
            const float* Wp = (ocol < 256) ? (wqk + (long)ocol * D) : (wv + (long)(ocol - 256) * D);
            float4 wvv = *(const float4*)(Wp + kc);
            Ws[lkq * 4 + 0][row] = wvv.x;
            Ws[lkq * 4 + 1][row] = wvv.y;
            Ws[lkq * 4 + 2][row] = wvv.z;
            Ws[lkq * 4 + 3][row] = wvv.w;
        }
        __syncthreads();
        #pragma unroll
        for (int kk = 0; kk < 16; kk++) {
            float a[8], w[8];
            *(float4*)(a + 0) = *(const float4*)&As[kk][tr * 8 + 0];
            *(float4*)(a + 4) = *(const float4*)&As[kk][tr * 8 + 4];
            *(float4*)(w + 0) = *(const float4*)&Ws[kk][tc * 8 + 0];
            *(float4*)(w + 4) = *(const float4*)&Ws[kk][tc * 8 + 4];
            #pragma unroll
            for (int i = 0; i < 8; i++)
                #pragma unroll
                for (int j = 0; j < 8; j++)
                    acc[i][j] += a[i] * w[j];
        }
        __syncthreads();
    }
    int col0 = colBase + tc * 8;
    #pragma unroll
    for (int i = 0; i < 8; i++) {
        long row = rowBase + tr * 8 + i;
        if (col0 < 256) {
            float4 v0 = make_float4(acc[i][0], acc[i][1], acc[i][2], acc[i][3]);
            float4 v1 = make_float4(acc[i][4], acc[i][5], acc[i][6], acc[i][7]);
            *(float4*)(qb + row * 256 + col0) = v0;
            *(float4*)(qb + row * 256 + col0 + 4) = v1;
        } else {
            int cc = col0 - 256;
            float4 v0 = make_float4(acc[i][0] + bv[cc + 0], acc[i][1] + bv[cc + 1],
                                    acc[i][2] + bv[cc + 2], acc[i][3] + bv[cc + 3]);
            float4 v1 = make_float4(acc[i][4] + bv[cc + 4], acc[i][5] + bv[cc + 5],
                                    acc[i][6] + bv[cc + 6], acc[i][7] + bv[cc + 7]);
            *(float4*)(vb + row * 256 + cc) = v0;
            *(float4*)(vb + row * 256 + cc + 4) = v1;
        }
    }
}

// R15: 64x64-tile gram (reference reshape quirk preserved)
__global__ void gram64_kernel(const float* __restrict__ Q, float* __restrict__ A) {
    int bh = blockIdx.z; int b = bh >> 2; int h = bh & 3;
    int i0 = blockIdx.y * 64, j0 = blockIdx.x * 64;
    __shared__ float Qi[64][68];
    __shared__ float Qj[64][68];
    int tid = threadIdx.x;
    #pragma unroll
    for (int it = 0; it < 4; it++) {
        int idx = tid + it * 256;
        int r = idx >> 4;
        int dq = (idx & 15) * 4;
        int i = i0 + r;
        float4 qi = *(const float4*)(Q + ((long)b * 256 + h * 64 + (i >> 2)) * 256 + (i & 3) * 64 + dq);
        Qi[dq + 0][r] = qi.x;
        Qi[dq + 1][r] = qi.y;
        Qi[dq + 2][r] = qi.z;
        Qi[dq + 3][r] = qi.w;
        float4 qj = *(const float4*)(Q + ((long)b * 256 + j0 + r) * 256 + h * 64 + dq);
        Qj[dq + 0][r] = qj.x;
        Qj[dq + 1][r] = qj.y;
        Qj[dq + 2][r] = qj.z;
        Qj[dq + 3][r] = qj.w;
    }
    __syncthreads();
    int tr = tid >> 4, tc = tid & 15;
    float acc[4][4] = {};
    #pragma unroll
    for (int d = 0; d < 64; d++) {
        float4 a4 = *(const float4*)&Qi[d][tr * 4];
        float4 b4 = *(const float4*)&Qj[d][tc * 4];
        float a[4] = {a4.x, a4.y, a4.z, a4.w};
        float w[4] = {b4.x, b4.y, b4.z, b4.w};
        #pragma unroll
        for (int ii = 0; ii < 4; ii++)
            #pragma unroll
            for (int jj = 0; jj < 4; jj++)
                acc[ii][jj] += a[ii] * w[jj];
    }
    #pragma unroll
    for (int ii = 0; ii < 4; ii++) {
        long row = (long)bh * 256 + i0 + tr * 4 + ii;
        #pragma unroll
        for (int jj = 0; jj < 4; jj++)
            A[row * 256 + j0 + tc * 4 + jj] = acc[ii][jj];
    }
}

// R17: warp-per-row softmax — 8 rows/block, shuffle reductions, no block barriers.
__global__ void softmax_row_kernel(float* __restrict__ A) {
    long row = (long)blockIdx.x * 8 + (threadIdx.x >> 5);
    int lane = threadIdx.x & 31;
    float* p = A + row * 256;
    float v[8];
    float mx = -FLT_MAX;
    #pragma unroll
    for (int i = 0; i < 8; i++) { v[i] = p[lane + 32 * i]; mx = fmaxf(mx, v[i]); }
    #pragma unroll
    for (int o = 16; o > 0; o >>= 1) mx = fmaxf(mx, __shfl_xor_sync(0xffffffffu, mx, o));
    float sm = 0.f;
    #pragma unroll
    for (int i = 0; i < 8; i++) { v[i] = expf(v[i] - mx); sm += v[i]; }
    #pragma unroll
    for (int o = 16; o > 0; o >>= 1) sm += __shfl_xor_sync(0xffffffffu, sm, o);
    float inv = 1.f / sm;
    #pragma unroll
    for (int i = 0; i < 8; i++) p[lane + 32 * i] = v[i] * inv;
}

// R17: column softmax STATS only (max + 1/sum over rows); normalization is
// applied on-the-fly in xr_gemm. Saves the full 8MB normalize pass.
__global__ void colstats_kernel(const float* __restrict__ A,
                                float* __restrict__ cmax, float* __restrict__ cinv) {
    int bh = blockIdx.y;
    int i0 = blockIdx.x * 64;
    int t = threadIdx.x;
    int jl = t >> 6, il = t & 63;
    __shared__ float red[4][64];
    __shared__ float smax[64];
    long base = (long)bh * 256 * 256 + i0 + il;
    float mx = -FLT_MAX;
    for (int r = jl; r < 256; r += 4)
        mx = fmaxf(mx, A[base + (long)r * 256]);
    red[jl][il] = mx;
    __syncthreads();
    if (jl == 0)
        smax[il] = fmaxf(fmaxf(red[0][il], red[1][il]), fmaxf(red[2][il], red[3][il]));
    __syncthreads();
    float sm = 0.f;
    for (int r = jl; r < 256; r += 4)
        sm += expf(A[base + (long)r * 256] - smax[il]);
    red[jl][il] = sm;
    __syncthreads();
    if (jl == 0) {
        float tot = red[0][il] + red[1][il] + red[2][il] + red[3][il];
        cmax[bh * 256 + i0 + il] = smax[il];
        cinv[bh * 256 + i0 + il] = 1.f / tot;
    }
}

// R17: XR GEMM with column-softmax applied on A-load (exp(a-max)*inv), fused
// xrb = xx + pos - XR epilogue. grid (4 i-tiles, 32 bh), 256 threads.
__global__ void xr_gemm_kernel(const float* __restrict__ A2, const float* __restrict__ Vb,
                               const float* __restrict__ cmax, const float* __restrict__ cinv,
                               const float* __restrict__ xx, const float* __restrict__ pos,
                               float* __restrict__ xrb) {
    int bh = blockIdx.y; int b = bh >> 2; int h = bh & 3;
    int i0 = blockIdx.x * 64;
    __shared__ float As[16][68];
    __shared__ float Vs[16][68];
    __shared__ float sMax[64], sInv[64];
    int tid = threadIdx.x;
    if (tid < 64) {
        sMax[tid] = cmax[bh * 256 + i0 + tid];
        sInv[tid] = cinv[bh * 256 + i0 + tid];
    }
    __syncthreads();
    int rk = tid >> 4;
    int cq = (tid & 15) * 4;
    int tr = tid >> 4, tc = tid & 15;
    float acc[4][4] = {};
    for (int j0 = 0; j0 < 256; j0 += 16) {
        float4 a4 = *(const float4*)(A2 + ((long)bh * 256 + j0 + rk) * 256 + i0 + cq);
        As[rk][cq + 0] = expf(a4.x - sMax[cq + 0]) * sInv[cq + 0];
        As[rk][cq + 1] = expf(a4.y - sMax[cq + 1]) * sInv[cq + 1];
        As[rk][cq + 2] = expf(a4.z - sMax[cq + 2]) * sInv[cq + 2];
        As[rk][cq + 3] = expf(a4.w - sMax[cq + 3]) * sInv[cq + 3];
        float4 v4 = *(const float4*)(Vb + ((long)b * 256 + j0 + rk) * 256 + h * 64 + cq);
        Vs[rk][cq + 0] = v4.x;
        Vs[rk][cq + 1] = v4.y;
        Vs[rk][cq + 2] = v4.z;
        Vs[rk][cq + 3] = v4.w;
        __syncthreads();
        #pragma unroll
        for (int jk = 0; jk < 16; jk++) {
            float4 aa = *(const float4*)&As[jk][tr * 4];
            float4 vv = *(const float4*)&Vs[jk][tc * 4];
            float a[4] = {aa.x, aa.y, aa.z, aa.w};
            float w[4] = {vv.x, vv.y, vv.z, vv.w};
            #pragma unroll
            for (int ii = 0; ii < 4; ii++)
                #pragma unroll
                for (int cc = 0; cc < 4; cc++)
                    acc[ii][cc] += a[ii] * w[cc];
        }
        __syncthreads();
    }
    #pragma unroll
    for (int ii = 0; ii < 4; ii++) {
        long row = (long)b * 256 + i0 + tr * 4 + ii;
        #pragma unroll
        for (int cc = 0; cc < 4; cc++) {
            long idx = row * 256 + h * 64 + tc * 4 + cc;
            xrb[idx] = xx[idx] + pos[idx] - acc[ii][cc];
        }
    }
}

__global__ void addcat_bn_kernel(const float* __restrict__ qb, float* __restrict__ xx,
                                 const float* __restrict__ pos, float* __restrict__ cat,
                                 int layer) {
    int t = blockIdx.x * 256 + threadIdx.x;
    int c = t & 255; int row = t >> 8;
    float y = fmaxf((qb[t] - g_m1[c]) * g_i1[c], 0.f);
    float v = xx[t] + pos[t] + y;
    xx[t] = v;
    cat[(long)row * 1280 + layer * 256 + c] = v;
}

// ----------------------------------------------------------------------------
// Host orchestration
// ----------------------------------------------------------------------------
static void gemm_old(const float* A, const float* W, const float* bias, float* C,
                     int R, int D, int O) {
    dim3 grid(CEILDIV(O, 64), CEILDIV(R, 64));
    gemm_kernel<<<grid, 256>>>(A, W, bias, C, R, D, O);
}

static void gemm_big(const float* A, const float* W, const float* bias, float* C,
                     int R, int D, int O, int useStats) {
    dim3 grid(CEILDIV(O, 128), R / 128);
    gemm128_kernel<<<grid, 256>>>(A, W, bias, C, R, D, O, useStats);
}

static float* s_part;

static void computeStats(const float* X, int R, int C) {
    int rpb = R / 512;
    if (rpb < 8) rpb = 8;
    int nB = R / rpb;
    stats_part_kernel<<<nB, 256>>>(X, R, C, rpb, nB, s_part);
    reduce_m1_kernel<<<C, 256>>>(s_part, nB, C, R);
}

static void bn(float* X, int R, int C, int act) {
    computeStats(X, R, C);
    long total = (long)R * C;
    bn_apply_kernel<<<(int)CEILDIV(total, 256), 256>>>(X, total, C, act);
}

extern "C" void kernel_launch(void* const* d_in, const int* in_sizes, int n_in,
                              void* d_out, int out_size) {
    const float* x       = (const float*)d_in[0];
    const float* conv1_w = (const float*)d_in[1];
    const float* conv2_w = (const float*)d_in[2];
    const float* g0_w1   = (const float*)d_in[3];
    const float* g0_w2   = (const float*)d_in[4];
    const float* g0_wc   = (const float*)d_in[5];
    const float* g1_w1   = (const float*)d_in[6];
    const float* g1_w2   = (const float*)d_in[7];
    const float* g1_wc   = (const float*)d_in[8];
    const float* pt_w    = (const float*)d_in[9];
    const float* pos_w   = (const float*)d_in[10];
    const float* pos_b   = (const float*)d_in[11];
    const float* sa_wqk  = (const float*)d_in[12];
    const float* sa_wv   = (const float*)d_in[13];
    const float* sa_bv   = (const float*)d_in[14];
    const float* sa_wt   = (const float*)d_in[15];
    const float* sa_bt   = (const float*)d_in[16];
    const float* fuse_w  = (const float*)d_in[17];
    const float* lin1_w  = (const float*)d_in[18];
    const float* lin2_w  = (const float*)d_in[19];
    const float* lin2_b  = (const float*)d_in[20];
    const float* lin3_w  = (const float*)d_in[21];
    const float* lin3_b  = (const float*)d_in[22];
    float* out = (float*)d_out;

    float *xyz, *h1, *points, *newxyz, *newxyz2, *newpts, *Ub, *Vb, *w1a, *w1d, *pool, *f0, *f1;
    float *pos, *xx, *qb, *vb, *xrb, *attn, *catb, *fuseb, *gmax, *l1, *l2, *cmax, *cinv;
    int *fpsidx, *knn, *knn2;
    cudaGetSymbolAddress((void**)&xyz, g_xyz);
    cudaGetSymbolAddress((void**)&h1, g_h1);
    cudaGetSymbolAddress((void**)&points, g_points);
    cudaGetSymbolAddress((void**)&fpsidx, g_fpsidx);
    cudaGetSymbolAddress((void**)&newxyz, g_newxyz);
    cudaGetSymbolAddress((void**)&newxyz2, g_newxyz2);
    cudaGetSymbolAddress((void**)&newpts, g_newpts);
    cudaGetSymbolAddress((void**)&knn, g_knn);
    cudaGetSymbolAddress((void**)&knn2, g_knn2);
    cudaGetSymbolAddress((void**)&Ub, g_U);
    cudaGetSymbolAddress((void**)&Vb, g_V);
    cudaGetSymbolAddress((void**)&w1a, g_w1a);
    cudaGetSymbolAddress((void**)&w1d, g_w1d);
    cudaGetSymbolAddress((void**)&s_part, g_part);
    cudaGetSymbolAddress((void**)&pool, g_pool);
    cudaGetSymbolAddress((void**)&f0, g_f0);
    cudaGetSymbolAddress((void**)&f1, g_f1);
    cudaGetSymbolAddress((void**)&pos, g_pos);
    cudaGetSymbolAddress((void**)&xx, g_x);
    cudaGetSymbolAddress((void**)&qb, g_q);
    cudaGetSymbolAddress((void**)&vb, g_v);
    cudaGetSymbolAddress((void**)&xrb, g_xr);
    cudaGetSymbolAddress((void**)&attn, g_attn);
    cudaGetSymbolAddress((void**)&catb, g_cat);
    cudaGetSymbolAddress((void**)&fuseb, g_fuse);
    cudaGetSymbolAddress((void**)&gmax, g_gmax);
    cudaGetSymbolAddress((void**)&l1, g_l1);
    cudaGetSymbolAddress((void**)&l2, g_l2);
    cudaGetSymbolAddress((void**)&cmax, g_cmax);
    cudaGetSymbolAddress((void**)&cinv, g_cinv);

    // ---- Stage A ----
    transpose_x_kernel<<<CEILDIV(8*2048*3, 256), 256>>>(x, xyz);
    gemm_old(xyz, conv1_w, nullptr, h1, 16384, 3, 64);
    computeStats(h1, 16384, 64);
    gemm_big(h1, conv2_w, nullptr, points, 16384, 64, 64, 1);
    bn(points, 16384, 64, 0);

    // ---- Stage B ----
    fps_kernel<<<8, 1024>>>(xyz, 2048, 512, fpsidx);
    gather_kernel<<<CEILDIV(8*512*3, 256), 256>>>(xyz, fpsidx, newxyz, 512, 2048, 3, 8L*512*3);
    gather_kernel<<<CEILDIV(8*512*64, 256), 256>>>(points, fpsidx, newpts, 512, 2048, 64, 8L*512*64);
    knn_fps_kernel<<<4096 + 8, 256>>>(newxyz, xyz, 512, 2048, knn, 4096,
                                      newxyz, 512, 256, fpsidx);
    gather_kernel<<<CEILDIV(8*256*3, 256), 256>>>(newxyz, fpsidx, newxyz2, 256, 512, 3, 8L*256*3);
    knn_kernel<<<2048, 256>>>(newxyz2, newxyz, 256, 512, knn2);

    // ---- Stage C: local_op 0 (R16 fused scales) ----
    {
        split_w1_kernel<<<CEILDIV(128*64, 256), 256>>>(g0_w1, w1a, w1d, 128, 64, 128*64);
        gemm_big(points, w1a, nullptr, Ub, 16384, 64, 128, 0);
        gemm_big(newpts, w1d, nullptr, Vb, 4096, 64, 128, 0);
        stats1_all_kernel<<<256, 128>>>(Ub, Vb, knn, 512, 2048, 128, 16, 256, s_part);
        stats1_fin_kernel<<<1, 128>>>(s_part, 256, 128, 8*512);
        int n16 = 8*512*16/128, n32 = 8*512*32/128, n64 = 8*512*64/128;
        dim3 grid(1, n16 + n32 + n64);
        local_gemm2_kernel<<<grid, 256>>>(Ub, Vb, knn, g0_w2, pool,
                                          512, 2048, 128, 128, n16, n32, 384);
        reduce_m2_all_kernel<<<dim3(128, 3), 256>>>(n16, n32, n64, 128);
        pool_fin_all_kernel<<<dim3(4096, 3), 128>>>(pool, 384, 128);
        gemm_big(pool, g0_wc, nullptr, f0, 4096, 384, 128, 0);
        bn(f0, 4096, 128, 0);
    }

    // ---- Stage D gather ----
    gather_kernel<<<CEILDIV(8*256*128, 256), 256>>>(f0, fpsidx, newpts, 256, 512, 128, 8L*256*128);

    // ---- Stage E: local_op 1 (R16 fused scales) ----
    {
        split_w1_kernel<<<CEILDIV(256*128, 256), 256>>>(g1_w1, w1a, w1d, 256, 128, 256*128);
        gemm_big(f0, w1a, nullptr, Ub, 4096, 128, 256, 0);
        gemm_big(newpts, w1d, nullptr, Vb, 2048, 128, 256, 0);
        stats1_all_kernel<<<128, 256>>>(Ub, Vb, knn2, 256, 512, 256, 16, 128, s_part);
        stats1_fin_kernel<<<2, 128>>>(s_part, 128, 256, 8*256);
        int n16 = 8*256*16/128, n32 = 8*256*32/128, n64 = 8*256*64/128;
        dim3 grid(2, n16 + n32 + n64);
        local_gemm2_kernel<<<grid, 256>>>(Ub, Vb, knn2, g1_w2, pool,
                                          256, 512, 256, 256, n16, n32, 768);
        reduce_m2_all_kernel<<<dim3(256, 3), 256>>>(n16, n32, n64, 256);
        pool_fin_all_kernel<<<dim3(2048, 3), 256>>>(pool, 768, 256);
        gemm_big(pool, g1_wc, nullptr, f1, 2048, 768, 256, 0);
        bn(f1, 2048, 256, 0);
    }

    // ---- Stage F ----
    gemm_old(newxyz2, pos_w, pos_b, pos, 2048, 3, 256);
    gemm_big(f1, pt_w, nullptr, xx, 2048, 256, 256, 0);
    bn(xx, 2048, 256, 0);

    // ---- Stage G: 4 offset self-attention layers (R17 attention middle) ----
    for (int i = 0; i < 4; i++) {
        gemmqv_kernel<<<dim3(4, 16), 256>>>(xx, pos,
                                            sa_wqk + (long)i * 256 * 256,
                                            sa_wv + (long)i * 256 * 256,
                                            sa_bv + i * 256, qb, vb);
        gram64_kernel<<<dim3(4, 4, 32), 256>>>(qb, attn);
        softmax_row_kernel<<<1024, 256>>>(attn);
        colstats_kernel<<<dim3(4, 32), 256>>>(attn, cmax, cinv);
        xr_gemm_kernel<<<dim3(4, 32), 256>>>(attn, vb, cmax, cinv, xx, pos, xrb);
        gemm_big(xrb, sa_wt + (long)i * 256 * 256, sa_bt + i * 256, qb, 2048, 256, 256, 0);
        computeStats(qb, 2048, 256);
        addcat_bn_kernel<<<2048, 256>>>(qb, xx, pos, catb, i);
    }
    catf1_kernel<<<2048, 256>>>(f1, catb);

    // ---- Stage H ----
    gemm_big(catb, fuse_w, nullptr, fuseb, 2048, 1280, 1024, 0);
    bn(fuseb, 2048, 1024, 1);
    maxn_kernel<<<dim3(8, 4), 256>>>(fuseb, gmax);
    gemm_old(gmax, lin1_w, nullptr, l1, 8, 1024, 512);
    bn_small_kernel<<<2, 256>>>(l1, 512, 0.2f);
    gemm_old(l1, lin2_w, lin2_b, l2, 8, 512, 256);
    bn_small_kernel<<<1, 256>>>(l2, 256, 0.2f);
    gemm_old(l2, lin3_w, lin3_b, out, 8, 256, 40);
}